// round 2
// baseline (speedup 1.0000x reference)
#include <cuda_runtime.h>
#include <math.h>

#define FULLMASK 0xffffffffu

namespace {
constexpr int kB = 4, kN = 16384, kC = 128, kMTOK = 65536, kMR = 1024;
constexpr size_t SZ    = (size_t)kMTOK * kC;        // 8,388,608 floats
constexpr size_t O_XA0 = 0;
constexpr size_t O_XA1 = SZ;
constexpr size_t O_SM0 = 2 * SZ;
constexpr size_t O_SM1 = 3 * SZ;
constexpr size_t O_T0  = 4 * SZ;
constexpr size_t O_T1  = 5 * SZ;
constexpr size_t O_T2  = 6 * SZ;
constexpr size_t O_T3  = 7 * SZ;
constexpr size_t O_T4  = 8 * SZ;
constexpr size_t O_T5  = 9 * SZ;
constexpr size_t O_PART = 10 * SZ;                  // 16*1024*128
constexpr size_t O_XLN  = O_PART + 16 * 1024 * 128;
constexpr size_t O_KB   = O_XLN + 1024 * 128;
constexpr size_t O_VB   = O_KB + 1024 * 128;
constexpr size_t O_SRWT = O_VB + 1024 * 128;        // 64*128*128
constexpr size_t O_BM   = O_SRWT + 64 * 128 * 128;  // 4*128
constexpr size_t TOT    = O_BM + 512;
}

__device__ float g_mem[TOT];

// ---------------------------------------------------------------------------
// Generic GEMM: Y[M x 128] = epi( (X .* Xmul?) @ W^T + bias? + resid? )
// K = 128 fixed, W row-major with row stride ldW (rows = output channels).
// epi: 0 none, 1 exact GELU, 2 row softmax (over the 128 output cols).
// 256 threads, 128x128 tile, 8x8 per-thread micro tile, BK=8.
// ---------------------------------------------------------------------------
__global__ __launch_bounds__(256) void gemm128(
    const float* __restrict__ X, const float* __restrict__ Xmul,
    const float* __restrict__ W, int ldW,
    const float* __restrict__ bias, const float* __restrict__ resid,
    float* __restrict__ Y, int epi)
{
    __shared__ float Xs[8][132];
    __shared__ float Ws[8][132];
    const int tid = threadIdx.x;
    const int tx = tid & 15, ty = tid >> 4;
    const int bm = blockIdx.x * 128;

    float acc[8][8] = {};
    const int lr = tid >> 1, lc = (tid & 1) * 4;
    const float* Xp = X + (size_t)(bm + lr) * kC + lc;
    const float* Mp = Xmul ? Xmul + (size_t)(bm + lr) * kC + lc : nullptr;
    const float* Wp = W + (size_t)lr * ldW + lc;

    for (int kt = 0; kt < 16; kt++) {
        float4 xv = *(const float4*)(Xp + kt * 8);
        if (Mp) {
            float4 mv = *(const float4*)(Mp + kt * 8);
            xv.x *= mv.x; xv.y *= mv.y; xv.z *= mv.z; xv.w *= mv.w;
        }
        float4 wv = *(const float4*)(Wp + kt * 8);
        Xs[lc + 0][lr] = xv.x; Xs[lc + 1][lr] = xv.y;
        Xs[lc + 2][lr] = xv.z; Xs[lc + 3][lr] = xv.w;
        Ws[lc + 0][lr] = wv.x; Ws[lc + 1][lr] = wv.y;
        Ws[lc + 2][lr] = wv.z; Ws[lc + 3][lr] = wv.w;
        __syncthreads();
#pragma unroll
        for (int k = 0; k < 8; k++) {
            float a[8], bb[8];
            *(float4*)(a)      = *(const float4*)&Xs[k][ty * 8];
            *(float4*)(a + 4)  = *(const float4*)&Xs[k][ty * 8 + 4];
            *(float4*)(bb)     = *(const float4*)&Ws[k][tx * 8];
            *(float4*)(bb + 4) = *(const float4*)&Ws[k][tx * 8 + 4];
#pragma unroll
            for (int i = 0; i < 8; i++)
#pragma unroll
                for (int j = 0; j < 8; j++) acc[i][j] = fmaf(a[i], bb[j], acc[i][j]);
        }
        __syncthreads();
    }

    float bv[8];
    if (bias) {
        *(float4*)(bv)     = *(const float4*)(bias + tx * 8);
        *(float4*)(bv + 4) = *(const float4*)(bias + tx * 8 + 4);
    } else {
#pragma unroll
        for (int j = 0; j < 8; j++) bv[j] = 0.0f;
    }

#pragma unroll
    for (int i = 0; i < 8; i++) {
        const int r = bm + ty * 8 + i;
        float v[8];
#pragma unroll
        for (int j = 0; j < 8; j++) v[j] = acc[i][j] + bv[j];
        if (resid) {
            const float* rr = resid + (size_t)r * kC + tx * 8;
#pragma unroll
            for (int j = 0; j < 8; j++) v[j] += rr[j];
        }
        if (epi == 1) {
#pragma unroll
            for (int j = 0; j < 8; j++)
                v[j] = 0.5f * v[j] * (1.0f + erff(v[j] * 0.70710678118654752f));
        } else if (epi == 2) {
            float mx = v[0];
#pragma unroll
            for (int j = 1; j < 8; j++) mx = fmaxf(mx, v[j]);
#pragma unroll
            for (int o = 8; o > 0; o >>= 1) mx = fmaxf(mx, __shfl_xor_sync(FULLMASK, mx, o, 16));
            float s = 0.0f;
#pragma unroll
            for (int j = 0; j < 8; j++) { v[j] = __expf(v[j] - mx); s += v[j]; }
#pragma unroll
            for (int o = 8; o > 0; o >>= 1) s += __shfl_xor_sync(FULLMASK, s, o, 16);
            const float inv = 1.0f / s;
#pragma unroll
            for (int j = 0; j < 8; j++) v[j] *= inv;
        }
        float* yr = Y + (size_t)r * kC + tx * 8;
        *(float4*)(yr)     = make_float4(v[0], v[1], v[2], v[3]);
        *(float4*)(yr + 4) = make_float4(v[4], v[5], v[6], v[7]);
    }
}

// ---------------------------------------------------------------------------
// Transpose sr_w (o,i,kh,kw) -> srwt[pos][i][o]  (pos = kh*8+kw)
// ---------------------------------------------------------------------------
__global__ void transpose_srw(const float* __restrict__ srw, float* __restrict__ out)
{
    int idx = blockIdx.x * 256 + threadIdx.x;           // 1048576 total
    int o = idx & 127, i = (idx >> 7) & 127, pos = idx >> 14;
    out[idx] = srw[(size_t)o * 8192 + i * 64 + pos];
}

// ---------------------------------------------------------------------------
// SR conv as split-K GEMM. Stride-8 8x8 kernel => non-overlapping patches.
// Grid: (b*2 rowtiles, 16 splits of 4 kernel positions). Partial sums out.
// ---------------------------------------------------------------------------
__global__ __launch_bounds__(256) void conv_partial(
    const float* __restrict__ x, const float* __restrict__ srwt,
    float* __restrict__ part)
{
    __shared__ float Xs[8][132];
    __shared__ float Ws[8][132];
    const int tid = threadIdx.x;
    const int tx = tid & 15, ty = tid >> 4;
    const int b = blockIdx.x >> 1, rt = blockIdx.x & 1, sp = blockIdx.y;

    float acc[8][8] = {};
    const int lr = tid >> 1, lc = (tid & 1) * 4;
    const int p = rt * 128 + lr;
    const int ph = p >> 4, pw = p & 15;
    const int wk = tid >> 5;          // 0..7 : k-row of W tile
    const int wo = (tid & 31) * 4;    // 0..124 : out-channel group

    for (int qq = 0; qq < 4; qq++) {
        const int pos = sp * 4 + qq;
        const int kh = pos >> 3, kw = pos & 7;
        const int pix = (ph * 8 + kh) * 128 + pw * 8 + kw;
        const float* Xp = x + ((size_t)b * kN + pix) * kC + lc;
        const float* Wp = srwt + (size_t)pos * 16384;
        for (int kt = 0; kt < 16; kt++) {
            float4 xv = *(const float4*)(Xp + kt * 8);
            float4 wv = *(const float4*)(Wp + (kt * 8 + wk) * 128 + wo);
            Xs[lc + 0][lr] = xv.x; Xs[lc + 1][lr] = xv.y;
            Xs[lc + 2][lr] = xv.z; Xs[lc + 3][lr] = xv.w;
            *(float4*)&Ws[wk][wo] = wv;
            __syncthreads();
#pragma unroll
            for (int k = 0; k < 8; k++) {
                float a[8], bb[8];
                *(float4*)(a)      = *(const float4*)&Xs[k][ty * 8];
                *(float4*)(a + 4)  = *(const float4*)&Xs[k][ty * 8 + 4];
                *(float4*)(bb)     = *(const float4*)&Ws[k][tx * 8];
                *(float4*)(bb + 4) = *(const float4*)&Ws[k][tx * 8 + 4];
#pragma unroll
                for (int i = 0; i < 8; i++)
#pragma unroll
                    for (int j = 0; j < 8; j++) acc[i][j] = fmaf(a[i], bb[j], acc[i][j]);
            }
            __syncthreads();
        }
    }
    const size_t base = ((size_t)sp * kMR + (size_t)b * 256 + rt * 128) * kC;
#pragma unroll
    for (int i = 0; i < 8; i++)
#pragma unroll
        for (int j = 0; j < 8; j++)
            part[base + (size_t)(ty * 8 + i) * kC + tx * 8 + j] = acc[i][j];
}

// ---------------------------------------------------------------------------
// Reduce conv split-K partials + bias, then LayerNorm. One block per row.
// ---------------------------------------------------------------------------
__global__ void conv_reduce_ln(const float* __restrict__ part,
                               const float* __restrict__ srb,
                               const float* __restrict__ gam,
                               const float* __restrict__ bet,
                               float* __restrict__ xln)
{
    const int row = blockIdx.x;
    const int c = threadIdx.x;   // 128 threads
    float v = srb[c];
#pragma unroll
    for (int sp = 0; sp < 16; sp++)
        v += part[((size_t)sp * kMR + row) * kC + c];

    __shared__ float red[4];
    float s = v;
#pragma unroll
    for (int o = 16; o > 0; o >>= 1) s += __shfl_xor_sync(FULLMASK, s, o);
    if ((c & 31) == 0) red[c >> 5] = s;
    __syncthreads();
    const float mean = (red[0] + red[1] + red[2] + red[3]) * (1.0f / 128.0f);
    __syncthreads();
    const float d = v - mean;
    float s2 = d * d;
#pragma unroll
    for (int o = 16; o > 0; o >>= 1) s2 += __shfl_xor_sync(FULLMASK, s2, o);
    if ((c & 31) == 0) red[c >> 5] = s2;
    __syncthreads();
    const float var = (red[0] + red[1] + red[2] + red[3]) * (1.0f / 128.0f);
    xln[(size_t)row * kC + c] = d * rsqrtf(var + 1e-5f) * gam[c] + bet[c];
}

// ---------------------------------------------------------------------------
// Fused SR attention: per (b, head) load K,V [256x64] to smem; each thread
// owns one query token; online-softmax over 256 keys in chunks of 8.
// Grid: (N/256, B*2). Dynamic smem = 128 KB.
// ---------------------------------------------------------------------------
__global__ __launch_bounds__(256) void sr_attn(
    const float* __restrict__ Q, const float* __restrict__ K,
    const float* __restrict__ V, float* __restrict__ XA)
{
    extern __shared__ float sh[];
    float4* K4 = (float4*)sh;              // 256 * 16 float4
    float4* V4 = (float4*)(sh + 16384);
    const int tid = threadIdx.x;
    const int b = blockIdx.y >> 1, h = blockIdx.y & 1;

    const float4* Kg = (const float4*)K + (size_t)b * 256 * 32 + h * 16;
    const float4* Vg = (const float4*)V + (size_t)b * 256 * 32 + h * 16;
#pragma unroll
    for (int jj = 0; jj < 16; jj++) {
        int e = jj * 256 + tid;
        int m = e >> 4, d4 = e & 15;
        K4[m * 16 + d4] = Kg[(size_t)m * 32 + d4];
        V4[m * 16 + d4] = Vg[(size_t)m * 32 + d4];
    }
    __syncthreads();

    const size_t row = (size_t)b * kN + (size_t)blockIdx.x * 256 + tid;
    float q[64];
    {
        const float4* Qg = (const float4*)(Q + row * kC + h * 64);
#pragma unroll
        for (int t = 0; t < 16; t++) *(float4*)&q[t * 4] = Qg[t];
    }
    float out[64];
#pragma unroll
    for (int d = 0; d < 64; d++) out[d] = 0.0f;
    float Mv = -1e30f, Sv = 0.0f;

    for (int c = 0; c < 32; c++) {
        float s[8];
#pragma unroll
        for (int mm = 0; mm < 8; mm++) {
            const float4* kr = &K4[(c * 8 + mm) * 16];
            float a = 0.0f;
#pragma unroll
            for (int t = 0; t < 16; t++) {
                float4 kk = kr[t];
                a = fmaf(q[t * 4 + 0], kk.x, a);
                a = fmaf(q[t * 4 + 1], kk.y, a);
                a = fmaf(q[t * 4 + 2], kk.z, a);
                a = fmaf(q[t * 4 + 3], kk.w, a);
            }
            s[mm] = a * 0.125f;
        }
        float cm = s[0];
#pragma unroll
        for (int mm = 1; mm < 8; mm++) cm = fmaxf(cm, s[mm]);
        const float nM = fmaxf(Mv, cm);
        const float sc = __expf(Mv - nM);
        Sv *= sc;
#pragma unroll
        for (int d = 0; d < 64; d++) out[d] *= sc;
#pragma unroll
        for (int mm = 0; mm < 8; mm++) {
            const float e = __expf(s[mm] - nM);
            Sv += e;
            const float4* vr = &V4[(c * 8 + mm) * 16];
#pragma unroll
            for (int t = 0; t < 16; t++) {
                float4 vv = vr[t];
                out[t * 4 + 0] = fmaf(e, vv.x, out[t * 4 + 0]);
                out[t * 4 + 1] = fmaf(e, vv.y, out[t * 4 + 1]);
                out[t * 4 + 2] = fmaf(e, vv.z, out[t * 4 + 2]);
                out[t * 4 + 3] = fmaf(e, vv.w, out[t * 4 + 3]);
            }
        }
        Mv = nM;
    }
    const float inv = 1.0f / Sv;
    float4* Og = (float4*)(XA + row * kC + h * 64);
#pragma unroll
    for (int t = 0; t < 16; t++)
        Og[t] = make_float4(out[t * 4] * inv, out[t * 4 + 1] * inv,
                            out[t * 4 + 2] * inv, out[t * 4 + 3] * inv);
}

// ---------------------------------------------------------------------------
// mha2 pointwise stage: per (token, xhead) 2-key softmax attention, d=16.
// ---------------------------------------------------------------------------
__global__ __launch_bounds__(256) void mha2_pw(
    const float* __restrict__ qp, const float* __restrict__ k0,
    const float* __restrict__ k1, const float* __restrict__ v0,
    const float* __restrict__ v1, float* __restrict__ o)
{
    const int idx = blockIdx.x * 256 + threadIdx.x;       // 65536*8
    const size_t base = (size_t)(idx >> 3) * kC + (idx & 7) * 16;
    const float4* qg  = (const float4*)(qp + base);
    const float4* k0g = (const float4*)(k0 + base);
    const float4* k1g = (const float4*)(k1 + base);
    float s0 = 0.0f, s1 = 0.0f;
#pragma unroll
    for (int t = 0; t < 4; t++) {
        float4 qv = qg[t], a0 = k0g[t], a1 = k1g[t];
        s0 += qv.x * a0.x + qv.y * a0.y + qv.z * a0.z + qv.w * a0.w;
        s1 += qv.x * a1.x + qv.y * a1.y + qv.z * a1.z + qv.w * a1.w;
    }
    s0 *= 0.25f; s1 *= 0.25f;
    const float m = fmaxf(s0, s1);
    float e0 = __expf(s0 - m), e1 = __expf(s1 - m);
    const float inv = 1.0f / (e0 + e1);
    e0 *= inv; e1 *= inv;
    const float4* v0g = (const float4*)(v0 + base);
    const float4* v1g = (const float4*)(v1 + base);
    float4* og = (float4*)(o + base);
#pragma unroll
    for (int t = 0; t < 4; t++) {
        float4 a = v0g[t], bb = v1g[t];
        og[t] = make_float4(e0 * a.x + e1 * bb.x, e0 * a.y + e1 * bb.y,
                            e0 * a.z + e1 * bb.z, e0 * a.w + e1 * bb.w);
    }
}

// ---------------------------------------------------------------------------
// Fold k/v noise into biases: bm[w*128+c] = b[off+c] + dot(noise, Wrow(off+c))
// which: 0 = (k, ca01), 1 = (v, ca01), 2 = (k, ca10), 3 = (v, ca10)
// ---------------------------------------------------------------------------
__global__ void fold_bias(
    const float* __restrict__ w01, const float* __restrict__ b01,
    const float* __restrict__ w10, const float* __restrict__ b10,
    const float* __restrict__ kn, const float* __restrict__ vn,
    float* __restrict__ bm)
{
    const int which = blockIdx.x, c = threadIdx.x;
    const float* W  = (which < 2) ? w01 : w10;
    const float* Bb = (which < 2) ? b01 : b10;
    const float* nz = ((which & 1) ? vn : kn) + (which >> 1) * kC;
    const int off = (which & 1) ? 256 : 128;
    float acc = Bb[off + c];
    const float* wr = W + (size_t)(off + c) * kC;
    for (int k = 0; k < kC; k++) acc += nz[k] * wr[k];
    bm[which * kC + c] = acc;
}

// ---------------------------------------------------------------------------
extern "C" void kernel_launch(void* const* d_in, const int* in_sizes, int n_in,
                              void* d_out, int out_size)
{
    (void)in_sizes; (void)n_in; (void)out_size;
    const float* x0   = (const float*)d_in[0];
    const float* x1   = (const float*)d_in[1];
    const float* Wq   = (const float*)d_in[2];
    const float* bq   = (const float*)d_in[3];
    const float* Wkv  = (const float*)d_in[4];
    const float* bkv  = (const float*)d_in[5];
    const float* srw  = (const float*)d_in[6];
    const float* srb  = (const float*)d_in[7];
    const float* lnG[2] = {(const float*)d_in[8],  (const float*)d_in[10]};
    const float* lnB[2] = {(const float*)d_in[9],  (const float*)d_in[11]};
    const float* cawI[2] = {(const float*)d_in[12], (const float*)d_in[16]};
    const float* cabI[2] = {(const float*)d_in[13], (const float*)d_in[17]};
    const float* cawO[2] = {(const float*)d_in[14], (const float*)d_in[18]};
    const float* cabO[2] = {(const float*)d_in[15], (const float*)d_in[19]};
    const float* rjw1 = (const float*)d_in[20];
    const float* rjb1 = (const float*)d_in[21];
    const float* rjw2 = (const float*)d_in[22];
    const float* rjb2 = (const float*)d_in[23];
    const float* kn   = (const float*)d_in[24];
    const float* vn   = (const float*)d_in[25];
    const float* pw   = (const float*)d_in[26];
    const float* pb   = (const float*)d_in[27];
    float* out = (float*)d_out;

    float* g = nullptr;
    cudaGetSymbolAddress((void**)&g, g_mem);
    float* XA[2] = {g + O_XA0, g + O_XA1};
    float* SM[2] = {g + O_SM0, g + O_SM1};
    float *T0 = g + O_T0, *T1 = g + O_T1, *T2 = g + O_T2;
    float *T3 = g + O_T3, *T4 = g + O_T4, *T5 = g + O_T5;
    float *PART = g + O_PART, *XLN = g + O_XLN, *KB = g + O_KB, *VB = g + O_VB;
    float *SRWT = g + O_SRWT, *BM = g + O_BM;

    cudaFuncSetAttribute(sr_attn, cudaFuncAttributeMaxDynamicSharedMemorySize, 131072);

    fold_bias<<<4, 128>>>(cawI[0], cabI[0], cawI[1], cabI[1], kn, vn, BM);
    transpose_srw<<<4096, 256>>>(srw, SRWT);

    const int GM = kMTOK / 128;  // 512 blocks for the big GEMMs

    // --- Stage A: SR attention per stream ---
    for (int s = 0; s < 2; s++) {
        const float* x = s ? x1 : x0;
        gemm128<<<GM, 256>>>(x, nullptr, Wq, 128, bq, nullptr, T0, 0);        // q
        conv_partial<<<dim3(8, 16), 256>>>(x, SRWT, PART);
        conv_reduce_ln<<<1024, 128>>>(PART, srb, lnG[s], lnB[s], XLN);
        gemm128<<<8, 256>>>(XLN, nullptr, Wkv, 128, bkv, nullptr, KB, 0);     // k
        gemm128<<<8, 256>>>(XLN, nullptr, Wkv + 128 * 128, 128, bkv + 128, nullptr, VB, 0);
        sr_attn<<<dim3(64, 8), 256, 131072>>>(T0, KB, VB, XA[s]);
    }

    // --- Stage B: judger softmaxes (s0 -> SM[0], s1 -> SM[1]) ---
    for (int s = 0; s < 2; s++) {
        gemm128<<<GM, 256>>>(XA[s],     nullptr, rjw1,       256, nullptr, nullptr, T0, 0);
        gemm128<<<GM, 256>>>(XA[s ^ 1], nullptr, rjw1 + 128, 256, rjb1,    T0,      T1, 1);
        gemm128<<<GM, 256>>>(T1,        nullptr, rjw2,       128, rjb2,    nullptr, SM[s], 2);
    }

    // --- Stage C: mha2 cross attention + residual + final projection ---
    for (int s = 0; s < 2; s++) {
        const float* W  = cawI[s];
        const float* Bb = cabI[s];
        float* bmk = BM + (2 * s) * kC;
        float* bmv = BM + (2 * s + 1) * kC;
        gemm128<<<GM, 256>>>(XA[s],     nullptr, W,             128, Bb,       nullptr, T0, 0); // qp
        gemm128<<<GM, 256>>>(XA[s],     nullptr, W + 128 * 128, 128, bmk,      nullptr, T1, 0); // k slot0
        gemm128<<<GM, 256>>>(XA[s],     SM[s],   W + 128 * 128, 128, Bb + 128, nullptr, T2, 0); // k slot1
        gemm128<<<GM, 256>>>(XA[s],     nullptr, W + 256 * 128, 128, bmv,      nullptr, T3, 0); // v slot0
        gemm128<<<GM, 256>>>(XA[s ^ 1], nullptr, W + 256 * 128, 128, Bb + 256, nullptr, T4, 0); // v slot1
        mha2_pw<<<2048, 256>>>(T0, T1, T2, T3, T4, T5);
        gemm128<<<GM, 256>>>(T5, nullptr, cawO[s], 128, cabO[s], XA[s], T0, 0);                 // n_s
        gemm128<<<GM, 256>>>(T0, nullptr, pw,      128, pb,      nullptr, out + (size_t)s * SZ, 0);
    }
}

// round 4
// speedup vs baseline: 1.1598x; 1.1598x over previous
#include <cuda_runtime.h>
#include <cuda_bf16.h>
#include <math.h>
#include <stdint.h>

#define FULLMASK 0xffffffffu

namespace {
constexpr int kB = 4, kN = 16384, kC = 128, kMTOK = 65536, kMR = 1024;
constexpr size_t SZ    = (size_t)kMTOK * kC;
constexpr size_t O_XA0 = 0;
constexpr size_t O_XA1 = SZ;
constexpr size_t O_SM0 = 2 * SZ;
constexpr size_t O_SM1 = 3 * SZ;
constexpr size_t O_T0  = 4 * SZ;
constexpr size_t O_T1  = 5 * SZ;
constexpr size_t O_T2  = 6 * SZ;
constexpr size_t O_T3  = 7 * SZ;
constexpr size_t O_T4  = 8 * SZ;
constexpr size_t O_T5  = 9 * SZ;
constexpr size_t O_PART = 10 * SZ;
constexpr size_t O_XLN  = O_PART + 16 * 1024 * 128;
constexpr size_t O_KB   = O_XLN + 1024 * 128;
constexpr size_t O_VB   = O_KB + 1024 * 128;
constexpr size_t O_SRWT = O_VB + 1024 * 128;
constexpr size_t O_BM   = O_SRWT + 64 * 128 * 128;
constexpr size_t TOT    = O_BM + 512;

// smem tiles for gemm128m: bf16 [128][136] padded (272 B rows), 4 tiles
constexpr int TSTRIDE = 136;                 // bf16 units per row
constexpr int TBYTES  = 128 * TSTRIDE * 2;   // 34816
constexpr int SM_AH = 0;
constexpr int SM_AL = TBYTES;
constexpr int SM_BH = 2 * TBYTES;
constexpr int SM_BL = 3 * TBYTES;
constexpr int SM_TOTAL = 4 * TBYTES;         // 139264
}

__device__ float g_mem[TOT];

// ---------------------------------------------------------------------------
__device__ __forceinline__ void cvt_pair(float a, float b,
                                         uint32_t& hi, uint32_t& lo) {
    __nv_bfloat16 ah = __float2bfloat16(a), bh = __float2bfloat16(b);
    __nv_bfloat16 al = __float2bfloat16(a - __bfloat162float(ah));
    __nv_bfloat16 bl = __float2bfloat16(b - __bfloat162float(bh));
    hi = (uint32_t)__bfloat16_as_ushort(ah) |
         ((uint32_t)__bfloat16_as_ushort(bh) << 16);
    lo = (uint32_t)__bfloat16_as_ushort(al) |
         ((uint32_t)__bfloat16_as_ushort(bl) << 16);
}

__device__ __forceinline__ void mma16816(float* d, const uint32_t* a,
                                         uint32_t b0, uint32_t b1) {
    asm volatile(
        "mma.sync.aligned.m16n8k16.row.col.f32.bf16.bf16.f32 "
        "{%0,%1,%2,%3}, {%4,%5,%6,%7}, {%8,%9}, {%0,%1,%2,%3};"
        : "+f"(d[0]), "+f"(d[1]), "+f"(d[2]), "+f"(d[3])
        : "r"(a[0]), "r"(a[1]), "r"(a[2]), "r"(a[3]), "r"(b0), "r"(b1));
}

// ---------------------------------------------------------------------------
// mma.sync bf16 split-precision GEMM:
// Y[M x 128] = epi( (X .* Xmul?) @ W^T + bias? + resid? ),  K = 128.
// 256 threads / CTA, one 128x128 tile; warp grid 4(M) x 2(N), warp = 32x64.
// C = Ah*Bh + Ah*Bl + Al*Bh  accumulated in fp32.
// epi: 0 none, 1 exact GELU, 2 row softmax (via smem pass).
// ---------------------------------------------------------------------------
__global__ __launch_bounds__(256, 1) void gemm128m(
    const float* __restrict__ X, const float* __restrict__ Xmul,
    const float* __restrict__ W, int ldW,
    const float* __restrict__ bias, const float* __restrict__ resid,
    float* __restrict__ Y, int epi)
{
    extern __shared__ char sm[];
    const int tid = threadIdx.x;
    const int lane = tid & 31, wid = tid >> 5;
    const int t4 = lane & 3, r8 = lane >> 2;
    const int wm = wid >> 1, wn = wid & 1;      // warp tile: rows wm*32, cols wn*64
    const int bm = blockIdx.x * 128;

    // --- prologue: convert fp32 -> bf16 hi/lo tiles in smem ---
    {
        const int row = tid >> 1;
        const int half = tid & 1;               // 64-col half
        const float4* Xr = (const float4*)(X + (size_t)(bm + row) * kC + half * 64);
        const float4* Mr = Xmul ? (const float4*)(Xmul + (size_t)(bm + row) * kC + half * 64) : nullptr;
        const float4* Wr = (const float4*)(W + (size_t)row * ldW + half * 64);
        char* const aH = sm + SM_AH + row * 272 + half * 128;
        char* const aL = sm + SM_AL + row * 272 + half * 128;
        char* const bH = sm + SM_BH + row * 272 + half * 128;
        char* const bL = sm + SM_BL + row * 272 + half * 128;
#pragma unroll
        for (int c4 = 0; c4 < 16; c4++) {
            float4 xv = Xr[c4];
            if (Mr) {
                float4 mv = Mr[c4];
                xv.x *= mv.x; xv.y *= mv.y; xv.z *= mv.z; xv.w *= mv.w;
            }
            uint32_t h0, l0, h1, l1;
            cvt_pair(xv.x, xv.y, h0, l0);
            cvt_pair(xv.z, xv.w, h1, l1);
            *(uint32_t*)(aH + c4 * 8)     = h0;
            *(uint32_t*)(aH + c4 * 8 + 4) = h1;
            *(uint32_t*)(aL + c4 * 8)     = l0;
            *(uint32_t*)(aL + c4 * 8 + 4) = l1;
            float4 wv = Wr[c4];
            cvt_pair(wv.x, wv.y, h0, l0);
            cvt_pair(wv.z, wv.w, h1, l1);
            *(uint32_t*)(bH + c4 * 8)     = h0;
            *(uint32_t*)(bH + c4 * 8 + 4) = h1;
            *(uint32_t*)(bL + c4 * 8)     = l0;
            *(uint32_t*)(bL + c4 * 8 + 4) = l1;
        }
    }
    __syncthreads();

    float acc[2][8][4];
#pragma unroll
    for (int mt = 0; mt < 2; mt++)
#pragma unroll
        for (int nt = 0; nt < 8; nt++)
#pragma unroll
            for (int e = 0; e < 4; e++) acc[mt][nt][e] = 0.0f;

#define LD32(base, row, col) \
    (*(const uint32_t*)(sm + (base) + (size_t)(row) * 272 + (size_t)(col) * 2))

#pragma unroll
    for (int kc = 0; kc < 8; kc++) {
        const int kq = kc * 16 + 2 * t4;
        uint32_t ah[2][4], al[2][4], bh[8][2], bl[8][2];
#pragma unroll
        for (int mt = 0; mt < 2; mt++) {
            const int m0 = wm * 32 + mt * 16 + r8;
            ah[mt][0] = LD32(SM_AH, m0,     kq);
            ah[mt][1] = LD32(SM_AH, m0 + 8, kq);
            ah[mt][2] = LD32(SM_AH, m0,     kq + 8);
            ah[mt][3] = LD32(SM_AH, m0 + 8, kq + 8);
            al[mt][0] = LD32(SM_AL, m0,     kq);
            al[mt][1] = LD32(SM_AL, m0 + 8, kq);
            al[mt][2] = LD32(SM_AL, m0,     kq + 8);
            al[mt][3] = LD32(SM_AL, m0 + 8, kq + 8);
        }
#pragma unroll
        for (int nt = 0; nt < 8; nt++) {
            const int n0 = wn * 64 + nt * 8 + r8;
            bh[nt][0] = LD32(SM_BH, n0, kq);
            bh[nt][1] = LD32(SM_BH, n0, kq + 8);
            bl[nt][0] = LD32(SM_BL, n0, kq);
            bl[nt][1] = LD32(SM_BL, n0, kq + 8);
        }
#pragma unroll
        for (int mt = 0; mt < 2; mt++)
#pragma unroll
            for (int nt = 0; nt < 8; nt++) {
                mma16816(acc[mt][nt], ah[mt], bh[nt][0], bh[nt][1]);
                mma16816(acc[mt][nt], ah[mt], bl[nt][0], bl[nt][1]);
                mma16816(acc[mt][nt], al[mt], bh[nt][0], bh[nt][1]);
            }
    }
#undef LD32

    if (epi != 2) {
        // in-register epilogue: bias + resid + optional GELU, direct stores
#pragma unroll
        for (int mt = 0; mt < 2; mt++) {
#pragma unroll
            for (int p = 0; p < 2; p++) {
                const int r = bm + wm * 32 + mt * 16 + r8 + p * 8;
#pragma unroll
                for (int nt = 0; nt < 8; nt++) {
                    const int c = wn * 64 + nt * 8 + 2 * t4;
                    float v0 = acc[mt][nt][2 * p];
                    float v1 = acc[mt][nt][2 * p + 1];
                    if (bias) {
                        float2 bv = *(const float2*)(bias + c);
                        v0 += bv.x; v1 += bv.y;
                    }
                    if (resid) {
                        float2 rv = *(const float2*)(resid + (size_t)r * kC + c);
                        v0 += rv.x; v1 += rv.y;
                    }
                    if (epi == 1) {
                        v0 = 0.5f * v0 * (1.0f + erff(v0 * 0.70710678118654752f));
                        v1 = 0.5f * v1 * (1.0f + erff(v1 * 0.70710678118654752f));
                    }
                    *(float2*)(Y + (size_t)r * kC + c) = make_float2(v0, v1);
                }
            }
        }
    } else {
        // softmax epilogue: stage in smem (stride 133 fp32), reduce per row
        float* Csm = (float*)sm;
        __syncthreads();   // tiles dead; safe to overwrite
#pragma unroll
        for (int mt = 0; mt < 2; mt++)
#pragma unroll
            for (int p = 0; p < 2; p++) {
                const int lr = wm * 32 + mt * 16 + r8 + p * 8;
#pragma unroll
                for (int nt = 0; nt < 8; nt++) {
                    const int c = wn * 64 + nt * 8 + 2 * t4;
                    float v0 = acc[mt][nt][2 * p];
                    float v1 = acc[mt][nt][2 * p + 1];
                    if (bias) {
                        float2 bv = *(const float2*)(bias + c);
                        v0 += bv.x; v1 += bv.y;
                    }
                    Csm[(size_t)lr * 133 + c]     = v0;
                    Csm[(size_t)lr * 133 + c + 1] = v1;
                }
            }
        __syncthreads();
        if (tid < 128) {
            float* rp = Csm + (size_t)tid * 133;
            float mx = rp[0];
#pragma unroll 4
            for (int c = 1; c < 128; c++) mx = fmaxf(mx, rp[c]);
            float s = 0.0f;
#pragma unroll 4
            for (int c = 0; c < 128; c++) { rp[c] = __expf(rp[c] - mx); s += rp[c]; }
            const float inv = 1.0f / s;
#pragma unroll 4
            for (int c = 0; c < 128; c++) rp[c] *= inv;
        }
        __syncthreads();
        for (int idx = tid; idx < 128 * 128; idx += 256) {
            const int lr = idx >> 7, c = idx & 127;
            Y[(size_t)(bm + lr) * kC + c] = Csm[(size_t)lr * 133 + c];
        }
    }
}

// ---------------------------------------------------------------------------
__global__ void transpose_srw(const float* __restrict__ srw, float* __restrict__ out)
{
    int idx = blockIdx.x * 256 + threadIdx.x;
    int o = idx & 127, i = (idx >> 7) & 127, pos = idx >> 14;
    out[idx] = srw[(size_t)o * 8192 + i * 64 + pos];
}

// ---------------------------------------------------------------------------
__global__ __launch_bounds__(256) void conv_partial(
    const float* __restrict__ x, const float* __restrict__ srwt,
    float* __restrict__ part)
{
    __shared__ float Xs[8][132];
    __shared__ float Ws[8][132];
    const int tid = threadIdx.x;
    const int tx = tid & 15, ty = tid >> 4;
    const int b = blockIdx.x >> 1, rt = blockIdx.x & 1, sp = blockIdx.y;

    float acc[8][8] = {};
    const int lr = tid >> 1, lc = (tid & 1) * 4;
    const int p = rt * 128 + lr;
    const int ph = p >> 4, pw = p & 15;
    const int wk = tid >> 5;
    const int wo = (tid & 31) * 4;

    for (int qq = 0; qq < 4; qq++) {
        const int pos = sp * 4 + qq;
        const int kh = pos >> 3, kw = pos & 7;
        const int pix = (ph * 8 + kh) * 128 + pw * 8 + kw;
        const float* Xp = x + ((size_t)b * kN + pix) * kC + lc;
        const float* Wp = srwt + (size_t)pos * 16384;
        for (int kt = 0; kt < 16; kt++) {
            float4 xv = *(const float4*)(Xp + kt * 8);
            float4 wv = *(const float4*)(Wp + (kt * 8 + wk) * 128 + wo);
            Xs[lc + 0][lr] = xv.x; Xs[lc + 1][lr] = xv.y;
            Xs[lc + 2][lr] = xv.z; Xs[lc + 3][lr] = xv.w;
            *(float4*)&Ws[wk][wo] = wv;
            __syncthreads();
#pragma unroll
            for (int k = 0; k < 8; k++) {
                float a[8], bb[8];
                *(float4*)(a)      = *(const float4*)&Xs[k][ty * 8];
                *(float4*)(a + 4)  = *(const float4*)&Xs[k][ty * 8 + 4];
                *(float4*)(bb)     = *(const float4*)&Ws[k][tx * 8];
                *(float4*)(bb + 4) = *(const float4*)&Ws[k][tx * 8 + 4];
#pragma unroll
                for (int i = 0; i < 8; i++)
#pragma unroll
                    for (int j = 0; j < 8; j++) acc[i][j] = fmaf(a[i], bb[j], acc[i][j]);
            }
            __syncthreads();
        }
    }
    const size_t base = ((size_t)sp * kMR + (size_t)b * 256 + rt * 128) * kC;
#pragma unroll
    for (int i = 0; i < 8; i++)
#pragma unroll
        for (int j = 0; j < 8; j++)
            part[base + (size_t)(ty * 8 + i) * kC + tx * 8 + j] = acc[i][j];
}

// ---------------------------------------------------------------------------
__global__ void conv_reduce_ln(const float* __restrict__ part,
                               const float* __restrict__ srb,
                               const float* __restrict__ gam,
                               const float* __restrict__ bet,
                               float* __restrict__ xln)
{
    const int row = blockIdx.x;
    const int c = threadIdx.x;
    float v = srb[c];
#pragma unroll
    for (int sp = 0; sp < 16; sp++)
        v += part[((size_t)sp * kMR + row) * kC + c];

    __shared__ float red[4];
    float s = v;
#pragma unroll
    for (int o = 16; o > 0; o >>= 1) s += __shfl_xor_sync(FULLMASK, s, o);
    if ((c & 31) == 0) red[c >> 5] = s;
    __syncthreads();
    const float mean = (red[0] + red[1] + red[2] + red[3]) * (1.0f / 128.0f);
    __syncthreads();
    const float d = v - mean;
    float s2 = d * d;
#pragma unroll
    for (int o = 16; o > 0; o >>= 1) s2 += __shfl_xor_sync(FULLMASK, s2, o);
    if ((c & 31) == 0) red[c >> 5] = s2;
    __syncthreads();
    const float var = (red[0] + red[1] + red[2] + red[3]) * (1.0f / 128.0f);
    xln[(size_t)row * kC + c] = d * rsqrtf(var + 1e-5f) * gam[c] + bet[c];
}

// ---------------------------------------------------------------------------
__global__ __launch_bounds__(256) void sr_attn(
    const float* __restrict__ Q, const float* __restrict__ K,
    const float* __restrict__ V, float* __restrict__ XA)
{
    extern __shared__ float sh[];
    float4* K4 = (float4*)sh;
    float4* V4 = (float4*)(sh + 16384);
    const int tid = threadIdx.x;
    const int b = blockIdx.y >> 1, h = blockIdx.y & 1;

    const float4* Kg = (const float4*)K + (size_t)b * 256 * 32 + h * 16;
    const float4* Vg = (const float4*)V + (size_t)b * 256 * 32 + h * 16;
#pragma unroll
    for (int jj = 0; jj < 16; jj++) {
        int e = jj * 256 + tid;
        int m = e >> 4, d4 = e & 15;
        K4[m * 16 + d4] = Kg[(size_t)m * 32 + d4];
        V4[m * 16 + d4] = Vg[(size_t)m * 32 + d4];
    }
    __syncthreads();

    const size_t row = (size_t)b * kN + (size_t)blockIdx.x * 256 + tid;
    float q[64];
    {
        const float4* Qg = (const float4*)(Q + row * kC + h * 64);
#pragma unroll
        for (int t = 0; t < 16; t++) *(float4*)&q[t * 4] = Qg[t];
    }
    float out[64];
#pragma unroll
    for (int d = 0; d < 64; d++) out[d] = 0.0f;
    float Mv = -1e30f, Sv = 0.0f;

    for (int c = 0; c < 32; c++) {
        float s[8];
#pragma unroll
        for (int mm = 0; mm < 8; mm++) {
            const float4* kr = &K4[(c * 8 + mm) * 16];
            float a = 0.0f;
#pragma unroll
            for (int t = 0; t < 16; t++) {
                float4 kk = kr[t];
                a = fmaf(q[t * 4 + 0], kk.x, a);
                a = fmaf(q[t * 4 + 1], kk.y, a);
                a = fmaf(q[t * 4 + 2], kk.z, a);
                a = fmaf(q[t * 4 + 3], kk.w, a);
            }
            s[mm] = a * 0.125f;
        }
        float cm = s[0];
#pragma unroll
        for (int mm = 1; mm < 8; mm++) cm = fmaxf(cm, s[mm]);
        const float nM = fmaxf(Mv, cm);
        const float sc = __expf(Mv - nM);
        Sv *= sc;
#pragma unroll
        for (int d = 0; d < 64; d++) out[d] *= sc;
#pragma unroll
        for (int mm = 0; mm < 8; mm++) {
            const float e = __expf(s[mm] - nM);
            Sv += e;
            const float4* vr = &V4[(c * 8 + mm) * 16];
#pragma unroll
            for (int t = 0; t < 16; t++) {
                float4 vv = vr[t];
                out[t * 4 + 0] = fmaf(e, vv.x, out[t * 4 + 0]);
                out[t * 4 + 1] = fmaf(e, vv.y, out[t * 4 + 1]);
                out[t * 4 + 2] = fmaf(e, vv.z, out[t * 4 + 2]);
                out[t * 4 + 3] = fmaf(e, vv.w, out[t * 4 + 3]);
            }
        }
        Mv = nM;
    }
    const float inv = 1.0f / Sv;
    float4* Og = (float4*)(XA + row * kC + h * 64);
#pragma unroll
    for (int t = 0; t < 16; t++)
        Og[t] = make_float4(out[t * 4] * inv, out[t * 4 + 1] * inv,
                            out[t * 4 + 2] * inv, out[t * 4 + 3] * inv);
}

// ---------------------------------------------------------------------------
__global__ __launch_bounds__(256) void mha2_pw(
    const float* __restrict__ qp, const float* __restrict__ k0,
    const float* __restrict__ k1, const float* __restrict__ v0,
    const float* __restrict__ v1, float* __restrict__ o)
{
    const int idx = blockIdx.x * 256 + threadIdx.x;
    const size_t base = (size_t)(idx >> 3) * kC + (idx & 7) * 16;
    const float4* qg  = (const float4*)(qp + base);
    const float4* k0g = (const float4*)(k0 + base);
    const float4* k1g = (const float4*)(k1 + base);
    float s0 = 0.0f, s1 = 0.0f;
#pragma unroll
    for (int t = 0; t < 4; t++) {
        float4 qv = qg[t], a0 = k0g[t], a1 = k1g[t];
        s0 += qv.x * a0.x + qv.y * a0.y + qv.z * a0.z + qv.w * a0.w;
        s1 += qv.x * a1.x + qv.y * a1.y + qv.z * a1.z + qv.w * a1.w;
    }
    s0 *= 0.25f; s1 *= 0.25f;
    const float m = fmaxf(s0, s1);
    float e0 = __expf(s0 - m), e1 = __expf(s1 - m);
    const float inv = 1.0f / (e0 + e1);
    e0 *= inv; e1 *= inv;
    const float4* v0g = (const float4*)(v0 + base);
    const float4* v1g = (const float4*)(v1 + base);
    float4* og = (float4*)(o + base);
#pragma unroll
    for (int t = 0; t < 4; t++) {
        float4 a = v0g[t], bb = v1g[t];
        og[t] = make_float4(e0 * a.x + e1 * bb.x, e0 * a.y + e1 * bb.y,
                            e0 * a.z + e1 * bb.z, e0 * a.w + e1 * bb.w);
    }
}

// ---------------------------------------------------------------------------
__global__ void fold_bias(
    const float* __restrict__ w01, const float* __restrict__ b01,
    const float* __restrict__ w10, const float* __restrict__ b10,
    const float* __restrict__ kn, const float* __restrict__ vn,
    float* __restrict__ bm)
{
    const int which = blockIdx.x, c = threadIdx.x;
    const float* W  = (which < 2) ? w01 : w10;
    const float* Bb = (which < 2) ? b01 : b10;
    const float* nz = ((which & 1) ? vn : kn) + (which >> 1) * kC;
    const int off = (which & 1) ? 256 : 128;
    float acc = Bb[off + c];
    const float* wr = W + (size_t)(off + c) * kC;
    for (int k = 0; k < kC; k++) acc += nz[k] * wr[k];
    bm[which * kC + c] = acc;
}

// ---------------------------------------------------------------------------
extern "C" void kernel_launch(void* const* d_in, const int* in_sizes, int n_in,
                              void* d_out, int out_size)
{
    (void)in_sizes; (void)n_in; (void)out_size;
    const float* x0   = (const float*)d_in[0];
    const float* x1   = (const float*)d_in[1];
    const float* Wq   = (const float*)d_in[2];
    const float* bq   = (const float*)d_in[3];
    const float* Wkv  = (const float*)d_in[4];
    const float* bkv  = (const float*)d_in[5];
    const float* srw  = (const float*)d_in[6];
    const float* srb  = (const float*)d_in[7];
    const float* lnG[2] = {(const float*)d_in[8],  (const float*)d_in[10]};
    const float* lnB[2] = {(const float*)d_in[9],  (const float*)d_in[11]};
    const float* cawI[2] = {(const float*)d_in[12], (const float*)d_in[16]};
    const float* cabI[2] = {(const float*)d_in[13], (const float*)d_in[17]};
    const float* cawO[2] = {(const float*)d_in[14], (const float*)d_in[18]};
    const float* cabO[2] = {(const float*)d_in[15], (const float*)d_in[19]};
    const float* rjw1 = (const float*)d_in[20];
    const float* rjb1 = (const float*)d_in[21];
    const float* rjw2 = (const float*)d_in[22];
    const float* rjb2 = (const float*)d_in[23];
    const float* kn   = (const float*)d_in[24];
    const float* vn   = (const float*)d_in[25];
    const float* pw   = (const float*)d_in[26];
    const float* pb   = (const float*)d_in[27];
    float* out = (float*)d_out;

    float* g = nullptr;
    cudaGetSymbolAddress((void**)&g, g_mem);
    float* XA[2] = {g + O_XA0, g + O_XA1};
    float* SM[2] = {g + O_SM0, g + O_SM1};
    float *T0 = g + O_T0, *T1 = g + O_T1, *T2 = g + O_T2;
    float *T3 = g + O_T3, *T4 = g + O_T4, *T5 = g + O_T5;
    float *PART = g + O_PART, *XLN = g + O_XLN, *KB = g + O_KB, *VB = g + O_VB;
    float *SRWT = g + O_SRWT, *BM = g + O_BM;

    cudaFuncSetAttribute(sr_attn, cudaFuncAttributeMaxDynamicSharedMemorySize, 131072);
    cudaFuncSetAttribute(gemm128m, cudaFuncAttributeMaxDynamicSharedMemorySize, SM_TOTAL);

    fold_bias<<<4, 128>>>(cawI[0], cabI[0], cawI[1], cabI[1], kn, vn, BM);
    transpose_srw<<<4096, 256>>>(srw, SRWT);

    const int GM = kMTOK / 128;

#define GEMM(GRID, Xp, Mp, Wp, LD, Bp, Rp, Yp, EPI) \
    gemm128m<<<GRID, 256, SM_TOTAL>>>(Xp, Mp, Wp, LD, Bp, Rp, Yp, EPI)

    // --- Stage A: SR attention per stream ---
    for (int s = 0; s < 2; s++) {
        const float* x = s ? x1 : x0;
        GEMM(GM, x, nullptr, Wq, 128, bq, nullptr, T0, 0);
        conv_partial<<<dim3(8, 16), 256>>>(x, SRWT, PART);
        conv_reduce_ln<<<1024, 128>>>(PART, srb, lnG[s], lnB[s], XLN);
        GEMM(8, XLN, nullptr, Wkv, 128, bkv, nullptr, KB, 0);
        GEMM(8, XLN, nullptr, Wkv + 128 * 128, 128, bkv + 128, nullptr, VB, 0);
        sr_attn<<<dim3(64, 8), 256, 131072>>>(T0, KB, VB, XA[s]);
    }

    // --- Stage B: judger softmaxes ---
    for (int s = 0; s < 2; s++) {
        GEMM(GM, XA[s],     nullptr, rjw1,       256, nullptr, nullptr, T0, 0);
        GEMM(GM, XA[s ^ 1], nullptr, rjw1 + 128, 256, rjb1,    T0,      T1, 1);
        GEMM(GM, T1,        nullptr, rjw2,       128, rjb2,    nullptr, SM[s], 2);
    }

    // --- Stage C: mha2 cross attention + residual + final projection ---
    for (int s = 0; s < 2; s++) {
        const float* W  = cawI[s];
        const float* Bb = cabI[s];
        float* bmk = BM + (2 * s) * kC;
        float* bmv = BM + (2 * s + 1) * kC;
        GEMM(GM, XA[s],     nullptr, W,             128, Bb,       nullptr, T0, 0);
        GEMM(GM, XA[s],     nullptr, W + 128 * 128, 128, bmk,      nullptr, T1, 0);
        GEMM(GM, XA[s],     SM[s],   W + 128 * 128, 128, Bb + 128, nullptr, T2, 0);
        GEMM(GM, XA[s],     nullptr, W + 256 * 128, 128, bmv,      nullptr, T3, 0);
        GEMM(GM, XA[s ^ 1], nullptr, W + 256 * 128, 128, Bb + 256, nullptr, T4, 0);
        mha2_pw<<<2048, 256>>>(T0, T1, T2, T3, T4, T5);
        GEMM(GM, T5, nullptr, cawO[s], 128, cabO[s], XA[s], T0, 0);
        GEMM(GM, T0, nullptr, pw,      128, pb,      nullptr, out + (size_t)s * SZ, 0);
    }
#undef GEMM
}

// round 5
// speedup vs baseline: 1.2855x; 1.1084x over previous
#include <cuda_runtime.h>
#include <cuda_bf16.h>
#include <math.h>
#include <stdint.h>

#define FULLMASK 0xffffffffu

namespace {
constexpr int kB = 4, kN = 16384, kC = 128, kMTOK = 65536, kMR = 1024;
constexpr size_t SZ    = (size_t)kMTOK * kC;
constexpr size_t O_XA0 = 0;
constexpr size_t O_XA1 = SZ;
constexpr size_t O_SM0 = 2 * SZ;
constexpr size_t O_SM1 = 3 * SZ;
constexpr size_t O_T0  = 4 * SZ;
constexpr size_t O_T1  = 5 * SZ;
constexpr size_t O_T2  = 6 * SZ;
constexpr size_t O_T3  = 7 * SZ;
constexpr size_t O_T4  = 8 * SZ;
constexpr size_t O_T5  = 9 * SZ;
constexpr size_t O_PART = 10 * SZ;                  // 64*1024*128 == SZ
constexpr size_t O_XLN  = 11 * SZ;
constexpr size_t O_KB   = O_XLN + 1024 * 128;
constexpr size_t O_VB   = O_KB + 1024 * 128;
constexpr size_t O_SRWT = O_VB + 1024 * 128;
constexpr size_t O_BM   = O_SRWT + 64 * 128 * 128;
constexpr size_t TOT    = O_BM + 512;

// gemm smem: 4 bf16 tiles [128][72] (stride 144 B), one 64-col K chunk
constexpr int TROW   = 144;               // bytes per row
constexpr int TBYTES = 128 * TROW;        // 18432
constexpr int SM_AH = 0;
constexpr int SM_AL = TBYTES;
constexpr int SM_BH = 2 * TBYTES;
constexpr int SM_BL = 3 * TBYTES;
constexpr int SM_TOTAL = 4 * TBYTES;      // 73728
}

__device__ float g_mem[TOT];

// ---------------------------------------------------------------------------
__device__ __forceinline__ uint32_t smem_u32(const void* p) {
    uint32_t a;
    asm("{ .reg .u64 t; cvta.to.shared.u64 t, %1; cvt.u32.u64 %0, t; }"
        : "=r"(a) : "l"(p));
    return a;
}
__device__ __forceinline__ void cvt_pair(float a, float b,
                                         uint32_t& hi, uint32_t& lo) {
    __nv_bfloat16 ah = __float2bfloat16(a), bh = __float2bfloat16(b);
    __nv_bfloat16 al = __float2bfloat16(a - __bfloat162float(ah));
    __nv_bfloat16 bl = __float2bfloat16(b - __bfloat162float(bh));
    hi = (uint32_t)__bfloat16_as_ushort(ah) |
         ((uint32_t)__bfloat16_as_ushort(bh) << 16);
    lo = (uint32_t)__bfloat16_as_ushort(al) |
         ((uint32_t)__bfloat16_as_ushort(bl) << 16);
}
__device__ __forceinline__ void mma16816(float* d, const uint32_t* a,
                                         uint32_t b0, uint32_t b1) {
    asm volatile(
        "mma.sync.aligned.m16n8k16.row.col.f32.bf16.bf16.f32 "
        "{%0,%1,%2,%3}, {%4,%5,%6,%7}, {%8,%9}, {%0,%1,%2,%3};"
        : "+f"(d[0]), "+f"(d[1]), "+f"(d[2]), "+f"(d[3])
        : "r"(a[0]), "r"(a[1]), "r"(a[2]), "r"(a[3]), "r"(b0), "r"(b1));
}
__device__ __forceinline__ void ldsm4(uint32_t& r0, uint32_t& r1,
                                      uint32_t& r2, uint32_t& r3, uint32_t addr) {
    asm volatile("ldmatrix.sync.aligned.m8n8.x4.shared.b16 {%0,%1,%2,%3}, [%4];"
                 : "=r"(r0), "=r"(r1), "=r"(r2), "=r"(r3) : "r"(addr));
}

// ---------------------------------------------------------------------------
// mma.sync bf16 split-precision GEMM, K=128 in two 64-col chunks.
// Y[M x 128] = epi( (X .* Xmul?) @ W^T + bias? + resid? )
// 256 thr, warp grid 4(M)x2(N), warp tile 32x64. ldmatrix fragment loads.
// C = Ah*Bh + Ah*Bl + Al*Bh.  epi: 0 none, 1 GELU, 2 row softmax.
// ---------------------------------------------------------------------------
__global__ __launch_bounds__(256, 2) void gemm128m(
    const float* __restrict__ X, const float* __restrict__ Xmul,
    const float* __restrict__ W, int ldW,
    const float* __restrict__ bias, const float* __restrict__ resid,
    float* __restrict__ Y, int epi)
{
    extern __shared__ char sm[];
    const uint32_t smb = smem_u32(sm);
    const int tid = threadIdx.x;
    const int lane = tid & 31, wid = tid >> 5;
    const int t4 = lane & 3, r8 = lane >> 2;
    const int wm = wid >> 1, wn = wid & 1;
    const int bm = blockIdx.x * 128;

    // ldmatrix per-thread offsets (bytes), within a [128][72] bf16 tile
    const int rA  = (lane & 7) + ((lane >> 3) & 1) * 8;
    const int cA  = (lane >> 4) * 16;
    uint32_t aoff[2];
#pragma unroll
    for (int mt = 0; mt < 2; mt++)
        aoff[mt] = (uint32_t)((wm * 32 + mt * 16 + rA) * TROW + cA);
    const int rB  = (lane & 7) + ((lane >> 4) & 1) * 8;
    const int cB  = ((lane >> 3) & 1) * 16;
    uint32_t boff[4];
#pragma unroll
    for (int np = 0; np < 4; np++)
        boff[np] = (uint32_t)((wn * 64 + np * 16 + rB) * TROW + cB);

    float acc[2][8][4];
#pragma unroll
    for (int mt = 0; mt < 2; mt++)
#pragma unroll
        for (int nt = 0; nt < 8; nt++)
#pragma unroll
            for (int e = 0; e < 4; e++) acc[mt][nt][e] = 0.0f;

    const int prow = tid >> 1;           // 0..127
    const int phalf = tid & 1;           // 32-col half of the 64-col chunk

    for (int ch = 0; ch < 2; ch++) {
        // ---- prologue: convert this K-chunk (64 cols) to bf16 hi/lo smem ----
        {
            const int cg = ch * 64 + phalf * 32;   // global col
            const int cl = phalf * 32;             // local col in chunk
            const float4* Xr = (const float4*)(X + (size_t)(bm + prow) * kC + cg);
            const float4* Mr = Xmul ? (const float4*)(Xmul + (size_t)(bm + prow) * kC + cg) : nullptr;
            const float4* Wr = (const float4*)(W + (size_t)prow * ldW + cg);
            char* aH = sm + SM_AH + prow * TROW + cl * 2;
            char* aL = sm + SM_AL + prow * TROW + cl * 2;
            char* bH = sm + SM_BH + prow * TROW + cl * 2;
            char* bL = sm + SM_BL + prow * TROW + cl * 2;
#pragma unroll
            for (int c4 = 0; c4 < 8; c4++) {
                float4 xv = Xr[c4];
                if (Mr) {
                    float4 mv = Mr[c4];
                    xv.x *= mv.x; xv.y *= mv.y; xv.z *= mv.z; xv.w *= mv.w;
                }
                uint32_t h0, l0, h1, l1;
                cvt_pair(xv.x, xv.y, h0, l0);
                cvt_pair(xv.z, xv.w, h1, l1);
                *(uint2*)(aH + c4 * 8) = make_uint2(h0, h1);
                *(uint2*)(aL + c4 * 8) = make_uint2(l0, l1);
                float4 wv = Wr[c4];
                cvt_pair(wv.x, wv.y, h0, l0);
                cvt_pair(wv.z, wv.w, h1, l1);
                *(uint2*)(bH + c4 * 8) = make_uint2(h0, h1);
                *(uint2*)(bL + c4 * 8) = make_uint2(l0, l1);
            }
        }
        __syncthreads();

        // ---- mainloop over 4 k-slices of 16 within the chunk ----
#pragma unroll
        for (int kc = 0; kc < 4; kc++) {
            const uint32_t kb = (uint32_t)kc * 32;
            uint32_t ah[2][4], al[2][4];
#pragma unroll
            for (int mt = 0; mt < 2; mt++) {
                ldsm4(ah[mt][0], ah[mt][1], ah[mt][2], ah[mt][3],
                      smb + SM_AH + aoff[mt] + kb);
                ldsm4(al[mt][0], al[mt][1], al[mt][2], al[mt][3],
                      smb + SM_AL + aoff[mt] + kb);
            }
#pragma unroll
            for (int np = 0; np < 4; np++) {
                uint32_t bh0, bh1, bh2, bh3, bl0, bl1, bl2, bl3;
                ldsm4(bh0, bh1, bh2, bh3, smb + SM_BH + boff[np] + kb);
                ldsm4(bl0, bl1, bl2, bl3, smb + SM_BL + boff[np] + kb);
#pragma unroll
                for (int mt = 0; mt < 2; mt++) {
                    mma16816(acc[mt][np * 2],     ah[mt], bh0, bh1);
                    mma16816(acc[mt][np * 2],     ah[mt], bl0, bl1);
                    mma16816(acc[mt][np * 2],     al[mt], bh0, bh1);
                    mma16816(acc[mt][np * 2 + 1], ah[mt], bh2, bh3);
                    mma16816(acc[mt][np * 2 + 1], ah[mt], bl2, bl3);
                    mma16816(acc[mt][np * 2 + 1], al[mt], bh2, bh3);
                }
            }
        }
        __syncthreads();
    }

    if (epi != 2) {
#pragma unroll
        for (int mt = 0; mt < 2; mt++)
#pragma unroll
            for (int p = 0; p < 2; p++) {
                const int r = bm + wm * 32 + mt * 16 + r8 + p * 8;
#pragma unroll
                for (int nt = 0; nt < 8; nt++) {
                    const int c = wn * 64 + nt * 8 + 2 * t4;
                    float v0 = acc[mt][nt][2 * p];
                    float v1 = acc[mt][nt][2 * p + 1];
                    if (bias) {
                        float2 bv = *(const float2*)(bias + c);
                        v0 += bv.x; v1 += bv.y;
                    }
                    if (resid) {
                        float2 rv = *(const float2*)(resid + (size_t)r * kC + c);
                        v0 += rv.x; v1 += rv.y;
                    }
                    if (epi == 1) {
                        v0 = 0.5f * v0 * (1.0f + erff(v0 * 0.70710678118654752f));
                        v1 = 0.5f * v1 * (1.0f + erff(v1 * 0.70710678118654752f));
                    }
                    *(float2*)(Y + (size_t)r * kC + c) = make_float2(v0, v1);
                }
            }
    } else {
        float* Csm = (float*)sm;
#pragma unroll
        for (int mt = 0; mt < 2; mt++)
#pragma unroll
            for (int p = 0; p < 2; p++) {
                const int lr = wm * 32 + mt * 16 + r8 + p * 8;
#pragma unroll
                for (int nt = 0; nt < 8; nt++) {
                    const int c = wn * 64 + nt * 8 + 2 * t4;
                    float v0 = acc[mt][nt][2 * p];
                    float v1 = acc[mt][nt][2 * p + 1];
                    if (bias) {
                        float2 bv = *(const float2*)(bias + c);
                        v0 += bv.x; v1 += bv.y;
                    }
                    Csm[(size_t)lr * 133 + c]     = v0;
                    Csm[(size_t)lr * 133 + c + 1] = v1;
                }
            }
        __syncthreads();
        if (tid < 128) {
            float* rp = Csm + (size_t)tid * 133;
            float mx = rp[0];
#pragma unroll 4
            for (int c = 1; c < 128; c++) mx = fmaxf(mx, rp[c]);
            float s = 0.0f;
#pragma unroll 4
            for (int c = 0; c < 128; c++) { rp[c] = __expf(rp[c] - mx); s += rp[c]; }
            const float inv = 1.0f / s;
#pragma unroll 4
            for (int c = 0; c < 128; c++) rp[c] *= inv;
        }
        __syncthreads();
        for (int idx = tid; idx < 128 * 128; idx += 256) {
            const int lr = idx >> 7, c = idx & 127;
            Y[(size_t)(bm + lr) * kC + c] = Csm[(size_t)lr * 133 + c];
        }
    }
}

// ---------------------------------------------------------------------------
__global__ void transpose_srw(const float* __restrict__ srw, float* __restrict__ out)
{
    int idx = blockIdx.x * 256 + threadIdx.x;
    int o = idx & 127, i = (idx >> 7) & 127, pos = idx >> 14;
    out[idx] = srw[(size_t)o * 8192 + i * 64 + pos];
}

// ---------------------------------------------------------------------------
// SR conv split-K GEMM: grid (8, 64), one kernel position per block.
// ---------------------------------------------------------------------------
__global__ __launch_bounds__(256) void conv_partial(
    const float* __restrict__ x, const float* __restrict__ srwt,
    float* __restrict__ part)
{
    __shared__ float Xs[8][132];
    __shared__ float Ws[8][132];
    const int tid = threadIdx.x;
    const int tx = tid & 15, ty = tid >> 4;
    const int b = blockIdx.x >> 1, rt = blockIdx.x & 1, pos = blockIdx.y;

    float acc[8][8] = {};
    const int lr = tid >> 1, lc = (tid & 1) * 4;
    const int p = rt * 128 + lr;
    const int ph = p >> 4, pw = p & 15;
    const int wk = tid >> 5;
    const int wo = (tid & 31) * 4;

    const int kh = pos >> 3, kw = pos & 7;
    const int pix = (ph * 8 + kh) * 128 + pw * 8 + kw;
    const float* Xp = x + ((size_t)b * kN + pix) * kC + lc;
    const float* Wp = srwt + (size_t)pos * 16384;
    for (int kt = 0; kt < 16; kt++) {
        float4 xv = *(const float4*)(Xp + kt * 8);
        float4 wv = *(const float4*)(Wp + (kt * 8 + wk) * 128 + wo);
        Xs[lc + 0][lr] = xv.x; Xs[lc + 1][lr] = xv.y;
        Xs[lc + 2][lr] = xv.z; Xs[lc + 3][lr] = xv.w;
        *(float4*)&Ws[wk][wo] = wv;
        __syncthreads();
#pragma unroll
        for (int k = 0; k < 8; k++) {
            float a[8], bb[8];
            *(float4*)(a)      = *(const float4*)&Xs[k][ty * 8];
            *(float4*)(a + 4)  = *(const float4*)&Xs[k][ty * 8 + 4];
            *(float4*)(bb)     = *(const float4*)&Ws[k][tx * 8];
            *(float4*)(bb + 4) = *(const float4*)&Ws[k][tx * 8 + 4];
#pragma unroll
            for (int i = 0; i < 8; i++)
#pragma unroll
                for (int j = 0; j < 8; j++) acc[i][j] = fmaf(a[i], bb[j], acc[i][j]);
        }
        __syncthreads();
    }
    const size_t base = ((size_t)pos * kMR + (size_t)b * 256 + rt * 128) * kC;
#pragma unroll
    for (int i = 0; i < 8; i++)
#pragma unroll
        for (int j = 0; j < 8; j++)
            part[base + (size_t)(ty * 8 + i) * kC + tx * 8 + j] = acc[i][j];
}

// ---------------------------------------------------------------------------
__global__ void conv_reduce_ln(const float* __restrict__ part,
                               const float* __restrict__ srb,
                               const float* __restrict__ gam,
                               const float* __restrict__ bet,
                               float* __restrict__ xln)
{
    const int row = blockIdx.x;
    const int c = threadIdx.x;
    float v = srb[c];
#pragma unroll 8
    for (int sp = 0; sp < 64; sp++)
        v += part[((size_t)sp * kMR + row) * kC + c];

    __shared__ float red[4];
    float s = v;
#pragma unroll
    for (int o = 16; o > 0; o >>= 1) s += __shfl_xor_sync(FULLMASK, s, o);
    if ((c & 31) == 0) red[c >> 5] = s;
    __syncthreads();
    const float mean = (red[0] + red[1] + red[2] + red[3]) * (1.0f / 128.0f);
    __syncthreads();
    const float d = v - mean;
    float s2 = d * d;
#pragma unroll
    for (int o = 16; o > 0; o >>= 1) s2 += __shfl_xor_sync(FULLMASK, s2, o);
    if ((c & 31) == 0) red[c >> 5] = s2;
    __syncthreads();
    const float var = (red[0] + red[1] + red[2] + red[3]) * (1.0f / 128.0f);
    xln[(size_t)row * kC + c] = d * rsqrtf(var + 1e-5f) * gam[c] + bet[c];
}

// ---------------------------------------------------------------------------
__global__ __launch_bounds__(256) void sr_attn(
    const float* __restrict__ Q, const float* __restrict__ K,
    const float* __restrict__ V, float* __restrict__ XA)
{
    extern __shared__ float sh[];
    float4* K4 = (float4*)sh;
    float4* V4 = (float4*)(sh + 16384);
    const int tid = threadIdx.x;
    const int b = blockIdx.y >> 1, h = blockIdx.y & 1;

    const float4* Kg = (const float4*)K + (size_t)b * 256 * 32 + h * 16;
    const float4* Vg = (const float4*)V + (size_t)b * 256 * 32 + h * 16;
#pragma unroll
    for (int jj = 0; jj < 16; jj++) {
        int e = jj * 256 + tid;
        int m = e >> 4, d4 = e & 15;
        K4[m * 16 + d4] = Kg[(size_t)m * 32 + d4];
        V4[m * 16 + d4] = Vg[(size_t)m * 32 + d4];
    }
    __syncthreads();

    const size_t row = (size_t)b * kN + (size_t)blockIdx.x * 256 + tid;
    float q[64];
    {
        const float4* Qg = (const float4*)(Q + row * kC + h * 64);
#pragma unroll
        for (int t = 0; t < 16; t++) *(float4*)&q[t * 4] = Qg[t];
    }
    float out[64];
#pragma unroll
    for (int d = 0; d < 64; d++) out[d] = 0.0f;
    float Mv = -1e30f, Sv = 0.0f;

    for (int c = 0; c < 32; c++) {
        float s[8];
#pragma unroll
        for (int mm = 0; mm < 8; mm++) {
            const float4* kr = &K4[(c * 8 + mm) * 16];
            float a = 0.0f;
#pragma unroll
            for (int t = 0; t < 16; t++) {
                float4 kk = kr[t];
                a = fmaf(q[t * 4 + 0], kk.x, a);
                a = fmaf(q[t * 4 + 1], kk.y, a);
                a = fmaf(q[t * 4 + 2], kk.z, a);
                a = fmaf(q[t * 4 + 3], kk.w, a);
            }
            s[mm] = a * 0.125f;
        }
        float cm = s[0];
#pragma unroll
        for (int mm = 1; mm < 8; mm++) cm = fmaxf(cm, s[mm]);
        const float nM = fmaxf(Mv, cm);
        const float sc = __expf(Mv - nM);
        Sv *= sc;
#pragma unroll
        for (int d = 0; d < 64; d++) out[d] *= sc;
#pragma unroll
        for (int mm = 0; mm < 8; mm++) {
            const float e = __expf(s[mm] - nM);
            Sv += e;
            const float4* vr = &V4[(c * 8 + mm) * 16];
#pragma unroll
            for (int t = 0; t < 16; t++) {
                float4 vv = vr[t];
                out[t * 4 + 0] = fmaf(e, vv.x, out[t * 4 + 0]);
                out[t * 4 + 1] = fmaf(e, vv.y, out[t * 4 + 1]);
                out[t * 4 + 2] = fmaf(e, vv.z, out[t * 4 + 2]);
                out[t * 4 + 3] = fmaf(e, vv.w, out[t * 4 + 3]);
            }
        }
        Mv = nM;
    }
    const float inv = 1.0f / Sv;
    float4* Og = (float4*)(XA + row * kC + h * 64);
#pragma unroll
    for (int t = 0; t < 16; t++)
        Og[t] = make_float4(out[t * 4] * inv, out[t * 4 + 1] * inv,
                            out[t * 4 + 2] * inv, out[t * 4 + 3] * inv);
}

// ---------------------------------------------------------------------------
__global__ __launch_bounds__(256) void mha2_pw(
    const float* __restrict__ qp, const float* __restrict__ k0,
    const float* __restrict__ k1, const float* __restrict__ v0,
    const float* __restrict__ v1, float* __restrict__ o)
{
    const int idx = blockIdx.x * 256 + threadIdx.x;
    const size_t base = (size_t)(idx >> 3) * kC + (idx & 7) * 16;
    const float4* qg  = (const float4*)(qp + base);
    const float4* k0g = (const float4*)(k0 + base);
    const float4* k1g = (const float4*)(k1 + base);
    float s0 = 0.0f, s1 = 0.0f;
#pragma unroll
    for (int t = 0; t < 4; t++) {
        float4 qv = qg[t], a0 = k0g[t], a1 = k1g[t];
        s0 += qv.x * a0.x + qv.y * a0.y + qv.z * a0.z + qv.w * a0.w;
        s1 += qv.x * a1.x + qv.y * a1.y + qv.z * a1.z + qv.w * a1.w;
    }
    s0 *= 0.25f; s1 *= 0.25f;
    const float m = fmaxf(s0, s1);
    float e0 = __expf(s0 - m), e1 = __expf(s1 - m);
    const float inv = 1.0f / (e0 + e1);
    e0 *= inv; e1 *= inv;
    const float4* v0g = (const float4*)(v0 + base);
    const float4* v1g = (const float4*)(v1 + base);
    float4* og = (float4*)(o + base);
#pragma unroll
    for (int t = 0; t < 4; t++) {
        float4 a = v0g[t], bb = v1g[t];
        og[t] = make_float4(e0 * a.x + e1 * bb.x, e0 * a.y + e1 * bb.y,
                            e0 * a.z + e1 * bb.z, e0 * a.w + e1 * bb.w);
    }
}

// ---------------------------------------------------------------------------
__global__ void fold_bias(
    const float* __restrict__ w01, const float* __restrict__ b01,
    const float* __restrict__ w10, const float* __restrict__ b10,
    const float* __restrict__ kn, const float* __restrict__ vn,
    float* __restrict__ bm)
{
    const int which = blockIdx.x, c = threadIdx.x;
    const float* W  = (which < 2) ? w01 : w10;
    const float* Bb = (which < 2) ? b01 : b10;
    const float* nz = ((which & 1) ? vn : kn) + (which >> 1) * kC;
    const int off = (which & 1) ? 256 : 128;
    float acc = Bb[off + c];
    const float* wr = W + (size_t)(off + c) * kC;
    for (int k = 0; k < kC; k++) acc += nz[k] * wr[k];
    bm[which * kC + c] = acc;
}

// ---------------------------------------------------------------------------
extern "C" void kernel_launch(void* const* d_in, const int* in_sizes, int n_in,
                              void* d_out, int out_size)
{
    (void)in_sizes; (void)n_in; (void)out_size;
    const float* x0   = (const float*)d_in[0];
    const float* x1   = (const float*)d_in[1];
    const float* Wq   = (const float*)d_in[2];
    const float* bq   = (const float*)d_in[3];
    const float* Wkv  = (const float*)d_in[4];
    const float* bkv  = (const float*)d_in[5];
    const float* srw  = (const float*)d_in[6];
    const float* srb  = (const float*)d_in[7];
    const float* lnG[2] = {(const float*)d_in[8],  (const float*)d_in[10]};
    const float* lnB[2] = {(const float*)d_in[9],  (const float*)d_in[11]};
    const float* cawI[2] = {(const float*)d_in[12], (const float*)d_in[16]};
    const float* cabI[2] = {(const float*)d_in[13], (const float*)d_in[17]};
    const float* cawO[2] = {(const float*)d_in[14], (const float*)d_in[18]};
    const float* cabO[2] = {(const float*)d_in[15], (const float*)d_in[19]};
    const float* rjw1 = (const float*)d_in[20];
    const float* rjb1 = (const float*)d_in[21];
    const float* rjw2 = (const float*)d_in[22];
    const float* rjb2 = (const float*)d_in[23];
    const float* kn   = (const float*)d_in[24];
    const float* vn   = (const float*)d_in[25];
    const float* pw   = (const float*)d_in[26];
    const float* pb   = (const float*)d_in[27];
    float* out = (float*)d_out;

    float* g = nullptr;
    cudaGetSymbolAddress((void**)&g, g_mem);
    float* XA[2] = {g + O_XA0, g + O_XA1};
    float* SM[2] = {g + O_SM0, g + O_SM1};
    float *T0 = g + O_T0, *T1 = g + O_T1, *T2 = g + O_T2;
    float *T3 = g + O_T3, *T4 = g + O_T4, *T5 = g + O_T5;
    float *PART = g + O_PART, *XLN = g + O_XLN, *KB = g + O_KB, *VB = g + O_VB;
    float *SRWT = g + O_SRWT, *BM = g + O_BM;

    cudaFuncSetAttribute(sr_attn, cudaFuncAttributeMaxDynamicSharedMemorySize, 131072);
    cudaFuncSetAttribute(gemm128m, cudaFuncAttributeMaxDynamicSharedMemorySize, SM_TOTAL);

    fold_bias<<<4, 128>>>(cawI[0], cabI[0], cawI[1], cabI[1], kn, vn, BM);
    transpose_srw<<<4096, 256>>>(srw, SRWT);

    const int GM = kMTOK / 128;

#define GEMM(GRID, Xp, Mp, Wp, LD, Bp, Rp, Yp, EPI) \
    gemm128m<<<GRID, 256, SM_TOTAL>>>(Xp, Mp, Wp, LD, Bp, Rp, Yp, EPI)

    // --- Stage A: SR attention per stream ---
    for (int s = 0; s < 2; s++) {
        const float* x = s ? x1 : x0;
        GEMM(GM, x, nullptr, Wq, 128, bq, nullptr, T0, 0);
        conv_partial<<<dim3(8, 64), 256>>>(x, SRWT, PART);
        conv_reduce_ln<<<1024, 128>>>(PART, srb, lnG[s], lnB[s], XLN);
        GEMM(8, XLN, nullptr, Wkv, 128, bkv, nullptr, KB, 0);
        GEMM(8, XLN, nullptr, Wkv + 128 * 128, 128, bkv + 128, nullptr, VB, 0);
        sr_attn<<<dim3(64, 8), 256, 131072>>>(T0, KB, VB, XA[s]);
    }

    // --- Stage B: judger softmaxes ---
    for (int s = 0; s < 2; s++) {
        GEMM(GM, XA[s],     nullptr, rjw1,       256, nullptr, nullptr, T0, 0);
        GEMM(GM, XA[s ^ 1], nullptr, rjw1 + 128, 256, rjb1,    T0,      T1, 1);
        GEMM(GM, T1,        nullptr, rjw2,       128, rjb2,    nullptr, SM[s], 2);
    }

    // --- Stage C: mha2 cross attention + residual + final projection ---
    for (int s = 0; s < 2; s++) {
        const float* W  = cawI[s];
        const float* Bb = cabI[s];
        float* bmk = BM + (2 * s) * kC;
        float* bmv = BM + (2 * s + 1) * kC;
        GEMM(GM, XA[s],     nullptr, W,             128, Bb,       nullptr, T0, 0);
        GEMM(GM, XA[s],     nullptr, W + 128 * 128, 128, bmk,      nullptr, T1, 0);
        GEMM(GM, XA[s],     SM[s],   W + 128 * 128, 128, Bb + 128, nullptr, T2, 0);
        GEMM(GM, XA[s],     nullptr, W + 256 * 128, 128, bmv,      nullptr, T3, 0);
        GEMM(GM, XA[s ^ 1], nullptr, W + 256 * 128, 128, Bb + 256, nullptr, T4, 0);
        mha2_pw<<<2048, 256>>>(T0, T1, T2, T3, T4, T5);
        GEMM(GM, T5, nullptr, cawO[s], 128, cabO[s], XA[s], T0, 0);
        GEMM(GM, T0, nullptr, pw,      128, pb,      nullptr, out + (size_t)s * SZ, 0);
    }
#undef GEMM
}

// round 6
// speedup vs baseline: 1.4432x; 1.1226x over previous
#include <cuda_runtime.h>
#include <cuda_bf16.h>
#include <math.h>
#include <stdint.h>

#define FULLMASK 0xffffffffu

namespace {
constexpr int kB = 4, kN = 16384, kC = 128, kMTOK = 65536, kMR = 1024;
constexpr size_t SZ = (size_t)kMTOK * kC;   // 8,388,608

// fp32 scratch
constexpr size_t O_XA0 = 0;
constexpr size_t O_XA1 = SZ;
constexpr size_t O_T0  = 2 * SZ;
constexpr size_t O_T1  = 3 * SZ;
constexpr size_t O_T2  = 4 * SZ;
constexpr size_t O_T3  = 5 * SZ;
constexpr size_t O_T4  = 6 * SZ;
constexpr size_t O_PART = 7 * SZ;           // 64*1024*128 == SZ
constexpr size_t O_KB  = 8 * SZ;
constexpr size_t O_VB  = O_KB + 131072;
constexpr size_t O_BM  = O_VB + 131072;
constexpr size_t TOTF  = O_BM + 512;

// bf16 split buffers (element offsets)
constexpr size_t H_X0  = 0;
constexpr size_t L_X0  = SZ;
constexpr size_t H_X1  = 2 * SZ;
constexpr size_t L_X1  = 3 * SZ;
constexpr size_t H_XA0 = 4 * SZ;
constexpr size_t L_XA0 = 5 * SZ;
constexpr size_t H_XA1 = 6 * SZ;
constexpr size_t L_XA1 = 7 * SZ;
constexpr size_t H_T1  = 8 * SZ;
constexpr size_t L_T1  = 9 * SZ;
constexpr size_t H_XAS = 10 * SZ;
constexpr size_t L_XAS = 11 * SZ;
constexpr size_t H_T5  = 12 * SZ;
constexpr size_t L_T5  = 13 * SZ;
constexpr size_t H_NS  = 14 * SZ;
constexpr size_t L_NS  = 15 * SZ;
constexpr size_t H_XLN = 16 * SZ;
constexpr size_t L_XLN = H_XLN + 131072;
constexpr size_t H_WS  = L_XLN + 131072;            // 15 blocks of 16384
constexpr size_t L_WS  = H_WS + 15 * 16384;
constexpr size_t H_CW  = L_WS + 15 * 16384;         // 64 blocks of 16384
constexpr size_t L_CW  = H_CW + 64 * 16384;
constexpr size_t TOTH  = L_CW + 64 * 16384;

// gemm smem: 4 bf16 tiles [128][72] (row stride 144 B), one 64-col K chunk
constexpr int TROW   = 144;
constexpr int TBYTES = 128 * TROW;          // 18432
constexpr int SM_AH = 0;
constexpr int SM_AL = TBYTES;
constexpr int SM_BH = 2 * TBYTES;
constexpr int SM_BL = 3 * TBYTES;
constexpr int SM_TOTAL = 4 * TBYTES;        // 73728
}

__device__ float g_mem[TOTF];
__device__ __nv_bfloat16 h_mem[TOTH];

// ---------------------------------------------------------------------------
__device__ __forceinline__ uint32_t smem_u32(const void* p) {
    uint32_t a;
    asm("{ .reg .u64 t; cvta.to.shared.u64 t, %1; cvt.u32.u64 %0, t; }"
        : "=r"(a) : "l"(p));
    return a;
}
__device__ __forceinline__ void cvt_pair(float a, float b,
                                         uint32_t& hi, uint32_t& lo) {
    __nv_bfloat16 ah = __float2bfloat16(a), bh = __float2bfloat16(b);
    __nv_bfloat16 al = __float2bfloat16(a - __bfloat162float(ah));
    __nv_bfloat16 bl = __float2bfloat16(b - __bfloat162float(bh));
    hi = (uint32_t)__bfloat16_as_ushort(ah) |
         ((uint32_t)__bfloat16_as_ushort(bh) << 16);
    lo = (uint32_t)__bfloat16_as_ushort(al) |
         ((uint32_t)__bfloat16_as_ushort(bl) << 16);
}
__device__ __forceinline__ void mma16816(float* d, const uint32_t* a,
                                         uint32_t b0, uint32_t b1) {
    asm volatile(
        "mma.sync.aligned.m16n8k16.row.col.f32.bf16.bf16.f32 "
        "{%0,%1,%2,%3}, {%4,%5,%6,%7}, {%8,%9}, {%0,%1,%2,%3};"
        : "+f"(d[0]), "+f"(d[1]), "+f"(d[2]), "+f"(d[3])
        : "r"(a[0]), "r"(a[1]), "r"(a[2]), "r"(a[3]), "r"(b0), "r"(b1));
}
__device__ __forceinline__ void ldsm4(uint32_t& r0, uint32_t& r1,
                                      uint32_t& r2, uint32_t& r3, uint32_t addr) {
    asm volatile("ldmatrix.sync.aligned.m8n8.x4.shared.b16 {%0,%1,%2,%3}, [%4];"
                 : "=r"(r0), "=r"(r1), "=r"(r2), "=r"(r3) : "r"(addr));
}
__device__ __forceinline__ void cpa16(uint32_t dst, const void* src) {
    asm volatile("cp.async.cg.shared.global [%0], [%1], 16;"
                 :: "r"(dst), "l"(src));
}
__device__ __forceinline__ void cpa_wait() {
    asm volatile("cp.async.commit_group;\ncp.async.wait_group 0;" ::: "memory");
}

// ---------------------------------------------------------------------------
// shared mainloop body (one 64-col K chunk already staged in smem)
// ---------------------------------------------------------------------------
struct FragCtx {
    uint32_t aoff[2];
    uint32_t boff[4];
};
__device__ __forceinline__ void mainloop_chunk(uint32_t smb, const FragCtx& fc,
                                               float acc[2][8][4]) {
#pragma unroll
    for (int kc = 0; kc < 4; kc++) {
        const uint32_t kb = (uint32_t)kc * 32;
        uint32_t ah[2][4], al[2][4];
#pragma unroll
        for (int mt = 0; mt < 2; mt++) {
            ldsm4(ah[mt][0], ah[mt][1], ah[mt][2], ah[mt][3],
                  smb + SM_AH + fc.aoff[mt] + kb);
            ldsm4(al[mt][0], al[mt][1], al[mt][2], al[mt][3],
                  smb + SM_AL + fc.aoff[mt] + kb);
        }
#pragma unroll
        for (int np = 0; np < 4; np++) {
            uint32_t bh0, bh1, bh2, bh3, bl0, bl1, bl2, bl3;
            ldsm4(bh0, bh1, bh2, bh3, smb + SM_BH + fc.boff[np] + kb);
            ldsm4(bl0, bl1, bl2, bl3, smb + SM_BL + fc.boff[np] + kb);
#pragma unroll
            for (int mt = 0; mt < 2; mt++) {
                mma16816(acc[mt][np * 2],     ah[mt], bh0, bh1);
                mma16816(acc[mt][np * 2],     ah[mt], bl0, bl1);
                mma16816(acc[mt][np * 2],     al[mt], bh0, bh1);
                mma16816(acc[mt][np * 2 + 1], ah[mt], bh2, bh3);
                mma16816(acc[mt][np * 2 + 1], ah[mt], bl2, bl3);
                mma16816(acc[mt][np * 2 + 1], al[mt], bh2, bh3);
            }
        }
    }
}
__device__ __forceinline__ FragCtx make_frag_ctx(int lane, int wm, int wn) {
    FragCtx fc;
    const int rA = (lane & 7) + ((lane >> 3) & 1) * 8;
    const int cA = (lane >> 4) * 16;
#pragma unroll
    for (int mt = 0; mt < 2; mt++)
        fc.aoff[mt] = (uint32_t)((wm * 32 + mt * 16 + rA) * TROW + cA);
    const int rB = (lane & 7) + ((lane >> 4) & 1) * 8;
    const int cB = ((lane >> 3) & 1) * 16;
#pragma unroll
    for (int np = 0; np < 4; np++)
        fc.boff[np] = (uint32_t)((wn * 64 + np * 16 + rB) * TROW + cB);
    return fc;
}

// ---------------------------------------------------------------------------
// GEMM v2: all operands pre-split bf16. Y = epi(A @ B^T + bias? + resid?)
// A: [M][128] hi/lo, B: [128][128] hi/lo packed weight block.
// epi 0: none, 1: GELU, 2: row-softmax then *postmul.
// Outputs: fp32 Yf (optional), split Yh/Yl (optional).
// ---------------------------------------------------------------------------
__global__ __launch_bounds__(256, 2) void gemm2(
    const __nv_bfloat16* __restrict__ Ah, const __nv_bfloat16* __restrict__ Al,
    const __nv_bfloat16* __restrict__ Bh, const __nv_bfloat16* __restrict__ Bl,
    const float* __restrict__ bias, const float* __restrict__ resid,
    const float* __restrict__ postmul,
    float* __restrict__ Yf, __nv_bfloat16* __restrict__ Yh,
    __nv_bfloat16* __restrict__ Yl, int epi)
{
    extern __shared__ char sm[];
    const uint32_t smb = smem_u32(sm);
    const int tid = threadIdx.x;
    const int lane = tid & 31, wid = tid >> 5;
    const int t4 = lane & 3, r8 = lane >> 2;
    const int wm = wid >> 1, wn = wid & 1;
    const int bm = blockIdx.x * 128;
    const FragCtx fc = make_frag_ctx(lane, wm, wn);

    float acc[2][8][4];
#pragma unroll
    for (int mt = 0; mt < 2; mt++)
#pragma unroll
        for (int nt = 0; nt < 8; nt++)
#pragma unroll
            for (int e = 0; e < 4; e++) acc[mt][nt][e] = 0.0f;

    const int pr = tid >> 1, hf = tid & 1;

    for (int ch = 0; ch < 2; ch++) {
        const size_t arow = (size_t)(bm + pr) * kC + ch * 64 + hf * 32;
        const size_t brow = (size_t)pr * kC + ch * 64 + hf * 32;
        const uint32_t so = (uint32_t)(pr * TROW + hf * 64);
#pragma unroll
        for (int gq = 0; gq < 4; gq++) {
            cpa16(smb + SM_AH + so + gq * 16, Ah + arow + gq * 8);
            cpa16(smb + SM_AL + so + gq * 16, Al + arow + gq * 8);
            cpa16(smb + SM_BH + so + gq * 16, Bh + brow + gq * 8);
            cpa16(smb + SM_BL + so + gq * 16, Bl + brow + gq * 8);
        }
        cpa_wait();
        __syncthreads();
        mainloop_chunk(smb, fc, acc);
        __syncthreads();
    }

    if (epi != 2) {
#pragma unroll
        for (int mt = 0; mt < 2; mt++)
#pragma unroll
            for (int p = 0; p < 2; p++) {
                const int r = bm + wm * 32 + mt * 16 + r8 + p * 8;
#pragma unroll
                for (int nt = 0; nt < 8; nt++) {
                    const int c = wn * 64 + nt * 8 + 2 * t4;
                    float v0 = acc[mt][nt][2 * p];
                    float v1 = acc[mt][nt][2 * p + 1];
                    if (bias) {
                        float2 bv = *(const float2*)(bias + c);
                        v0 += bv.x; v1 += bv.y;
                    }
                    if (resid) {
                        float2 rv = *(const float2*)(resid + (size_t)r * kC + c);
                        v0 += rv.x; v1 += rv.y;
                    }
                    if (epi == 1) {
                        v0 = 0.5f * v0 * (1.0f + erff(v0 * 0.70710678118654752f));
                        v1 = 0.5f * v1 * (1.0f + erff(v1 * 0.70710678118654752f));
                    }
                    if (Yf)
                        *(float2*)(Yf + (size_t)r * kC + c) = make_float2(v0, v1);
                    if (Yh) {
                        uint32_t hh, ll;
                        cvt_pair(v0, v1, hh, ll);
                        *(uint32_t*)(Yh + (size_t)r * kC + c) = hh;
                        *(uint32_t*)(Yl + (size_t)r * kC + c) = ll;
                    }
                }
            }
    } else {
        float* Csm = (float*)sm;
#pragma unroll
        for (int mt = 0; mt < 2; mt++)
#pragma unroll
            for (int p = 0; p < 2; p++) {
                const int lr = wm * 32 + mt * 16 + r8 + p * 8;
#pragma unroll
                for (int nt = 0; nt < 8; nt++) {
                    const int c = wn * 64 + nt * 8 + 2 * t4;
                    float v0 = acc[mt][nt][2 * p];
                    float v1 = acc[mt][nt][2 * p + 1];
                    if (bias) {
                        float2 bv = *(const float2*)(bias + c);
                        v0 += bv.x; v1 += bv.y;
                    }
                    Csm[(size_t)lr * 133 + c]     = v0;
                    Csm[(size_t)lr * 133 + c + 1] = v1;
                }
            }
        __syncthreads();
        if (tid < 128) {
            float* rp = Csm + (size_t)tid * 133;
            float mx = rp[0];
#pragma unroll 4
            for (int c = 1; c < 128; c++) mx = fmaxf(mx, rp[c]);
            float s = 0.0f;
#pragma unroll 4
            for (int c = 0; c < 128; c++) { rp[c] = __expf(rp[c] - mx); s += rp[c]; }
            const float inv = 1.0f / s;
#pragma unroll 4
            for (int c = 0; c < 128; c++) rp[c] *= inv;
        }
        __syncthreads();
        for (int idx = tid; idx < 128 * 64; idx += 256) {
            const int lr = idx >> 6, c = (idx & 63) * 2;
            const size_t go = (size_t)(bm + lr) * kC + c;
            float v0 = Csm[(size_t)lr * 133 + c]     * postmul[go];
            float v1 = Csm[(size_t)lr * 133 + c + 1] * postmul[go + 1];
            uint32_t hh, ll;
            cvt_pair(v0, v1, hh, ll);
            *(uint32_t*)(Yh + go) = hh;
            *(uint32_t*)(Yl + go) = ll;
        }
    }
}

// ---------------------------------------------------------------------------
// Conv via mma: grid (8, 64) — one kernel position per block, gathered A rows.
// ---------------------------------------------------------------------------
__global__ __launch_bounds__(256, 2) void conv_mma(
    const __nv_bfloat16* __restrict__ xh, const __nv_bfloat16* __restrict__ xl,
    const __nv_bfloat16* __restrict__ cwh, const __nv_bfloat16* __restrict__ cwl,
    float* __restrict__ part)
{
    extern __shared__ char sm[];
    const uint32_t smb = smem_u32(sm);
    const int tid = threadIdx.x;
    const int lane = tid & 31, wid = tid >> 5;
    const int t4 = lane & 3, r8 = lane >> 2;
    const int wm = wid >> 1, wn = wid & 1;
    const int b = blockIdx.x >> 1, rt = blockIdx.x & 1, pos = blockIdx.y;
    const FragCtx fc = make_frag_ctx(lane, wm, wn);

    float acc[2][8][4];
#pragma unroll
    for (int mt = 0; mt < 2; mt++)
#pragma unroll
        for (int nt = 0; nt < 8; nt++)
#pragma unroll
            for (int e = 0; e < 4; e++) acc[mt][nt][e] = 0.0f;

    const int pr = tid >> 1, hf = tid & 1;
    const int p = rt * 128 + pr;
    const int ph = p >> 4, pwd = p & 15;
    const int kh = pos >> 3, kw = pos & 7;
    const size_t xrow = ((size_t)b * kN + (ph * 8 + kh) * 128 + pwd * 8 + kw) * kC;
    const size_t wbase = (size_t)pos * 16384 + (size_t)pr * kC;

    for (int ch = 0; ch < 2; ch++) {
        const size_t arow = xrow + ch * 64 + hf * 32;
        const size_t brow = wbase + ch * 64 + hf * 32;
        const uint32_t so = (uint32_t)(pr * TROW + hf * 64);
#pragma unroll
        for (int gq = 0; gq < 4; gq++) {
            cpa16(smb + SM_AH + so + gq * 16, xh + arow + gq * 8);
            cpa16(smb + SM_AL + so + gq * 16, xl + arow + gq * 8);
            cpa16(smb + SM_BH + so + gq * 16, cwh + brow + gq * 8);
            cpa16(smb + SM_BL + so + gq * 16, cwl + brow + gq * 8);
        }
        cpa_wait();
        __syncthreads();
        mainloop_chunk(smb, fc, acc);
        __syncthreads();
    }

    const size_t base = ((size_t)pos * kMR + (size_t)b * 256 + rt * 128) * kC;
#pragma unroll
    for (int mt = 0; mt < 2; mt++)
#pragma unroll
        for (int pq = 0; pq < 2; pq++) {
            const int lr = wm * 32 + mt * 16 + r8 + pq * 8;
#pragma unroll
            for (int nt = 0; nt < 8; nt++) {
                const int c = wn * 64 + nt * 8 + 2 * t4;
                *(float2*)(part + base + (size_t)lr * kC + c) =
                    make_float2(acc[mt][nt][2 * pq], acc[mt][nt][2 * pq + 1]);
            }
        }
}

// ---------------------------------------------------------------------------
// Reduce 64 conv partials + bias, LayerNorm, write split bf16.
// ---------------------------------------------------------------------------
__global__ void conv_reduce_ln(const float* __restrict__ part,
                               const float* __restrict__ srb,
                               const float* __restrict__ gam,
                               const float* __restrict__ bet,
                               __nv_bfloat16* __restrict__ xh,
                               __nv_bfloat16* __restrict__ xl)
{
    const int row = blockIdx.x;
    const int c = threadIdx.x;
    float v = srb[c];
#pragma unroll 8
    for (int sp = 0; sp < 64; sp++)
        v += part[((size_t)sp * kMR + row) * kC + c];

    __shared__ float red[4];
    float s = v;
#pragma unroll
    for (int o = 16; o > 0; o >>= 1) s += __shfl_xor_sync(FULLMASK, s, o);
    if ((c & 31) == 0) red[c >> 5] = s;
    __syncthreads();
    const float mean = (red[0] + red[1] + red[2] + red[3]) * (1.0f / 128.0f);
    __syncthreads();
    const float d = v - mean;
    float s2 = d * d;
#pragma unroll
    for (int o = 16; o > 0; o >>= 1) s2 += __shfl_xor_sync(FULLMASK, s2, o);
    if ((c & 31) == 0) red[c >> 5] = s2;
    __syncthreads();
    const float var = (red[0] + red[1] + red[2] + red[3]) * (1.0f / 128.0f);
    const float val = d * rsqrtf(var + 1e-5f) * gam[c] + bet[c];
    __nv_bfloat16 hh = __float2bfloat16(val);
    xh[(size_t)row * kC + c] = hh;
    xl[(size_t)row * kC + c] = __float2bfloat16(val - __bfloat162float(hh));
}

// ---------------------------------------------------------------------------
// Fused SR attention; writes XA fp32 + split bf16.
// ---------------------------------------------------------------------------
__global__ __launch_bounds__(256) void sr_attn(
    const float* __restrict__ Q, const float* __restrict__ K,
    const float* __restrict__ V, float* __restrict__ XA,
    __nv_bfloat16* __restrict__ XAh, __nv_bfloat16* __restrict__ XAl)
{
    extern __shared__ float sh[];
    float4* K4 = (float4*)sh;
    float4* V4 = (float4*)(sh + 16384);
    const int tid = threadIdx.x;
    const int b = blockIdx.y >> 1, h = blockIdx.y & 1;

    const float4* Kg = (const float4*)K + (size_t)b * 256 * 32 + h * 16;
    const float4* Vg = (const float4*)V + (size_t)b * 256 * 32 + h * 16;
#pragma unroll
    for (int jj = 0; jj < 16; jj++) {
        int e = jj * 256 + tid;
        int m = e >> 4, d4 = e & 15;
        K4[m * 16 + d4] = Kg[(size_t)m * 32 + d4];
        V4[m * 16 + d4] = Vg[(size_t)m * 32 + d4];
    }
    __syncthreads();

    const size_t row = (size_t)b * kN + (size_t)blockIdx.x * 256 + tid;
    float q[64];
    {
        const float4* Qg = (const float4*)(Q + row * kC + h * 64);
#pragma unroll
        for (int t = 0; t < 16; t++) *(float4*)&q[t * 4] = Qg[t];
    }
    float out[64];
#pragma unroll
    for (int d = 0; d < 64; d++) out[d] = 0.0f;
    float Mv = -1e30f, Sv = 0.0f;

    for (int c = 0; c < 32; c++) {
        float s[8];
#pragma unroll
        for (int mm = 0; mm < 8; mm++) {
            const float4* kr = &K4[(c * 8 + mm) * 16];
            float a = 0.0f;
#pragma unroll
            for (int t = 0; t < 16; t++) {
                float4 kk = kr[t];
                a = fmaf(q[t * 4 + 0], kk.x, a);
                a = fmaf(q[t * 4 + 1], kk.y, a);
                a = fmaf(q[t * 4 + 2], kk.z, a);
                a = fmaf(q[t * 4 + 3], kk.w, a);
            }
            s[mm] = a * 0.125f;
        }
        float cm = s[0];
#pragma unroll
        for (int mm = 1; mm < 8; mm++) cm = fmaxf(cm, s[mm]);
        const float nM = fmaxf(Mv, cm);
        const float sc = __expf(Mv - nM);
        Sv *= sc;
#pragma unroll
        for (int d = 0; d < 64; d++) out[d] *= sc;
#pragma unroll
        for (int mm = 0; mm < 8; mm++) {
            const float e = __expf(s[mm] - nM);
            Sv += e;
            const float4* vr = &V4[(c * 8 + mm) * 16];
#pragma unroll
            for (int t = 0; t < 16; t++) {
                float4 vv = vr[t];
                out[t * 4 + 0] = fmaf(e, vv.x, out[t * 4 + 0]);
                out[t * 4 + 1] = fmaf(e, vv.y, out[t * 4 + 1]);
                out[t * 4 + 2] = fmaf(e, vv.z, out[t * 4 + 2]);
                out[t * 4 + 3] = fmaf(e, vv.w, out[t * 4 + 3]);
            }
        }
        Mv = nM;
    }
    const float inv = 1.0f / Sv;
    float4* Og = (float4*)(XA + row * kC + h * 64);
    uint2* Oh = (uint2*)(XAh + row * kC + h * 64);
    uint2* Ol = (uint2*)(XAl + row * kC + h * 64);
#pragma unroll
    for (int t = 0; t < 16; t++) {
        float o0 = out[t * 4] * inv, o1 = out[t * 4 + 1] * inv;
        float o2 = out[t * 4 + 2] * inv, o3 = out[t * 4 + 3] * inv;
        Og[t] = make_float4(o0, o1, o2, o3);
        uint32_t h0, l0, h1, l1;
        cvt_pair(o0, o1, h0, l0);
        cvt_pair(o2, o3, h1, l1);
        Oh[t] = make_uint2(h0, h1);
        Ol[t] = make_uint2(l0, l1);
    }
}

// ---------------------------------------------------------------------------
// mha2 pointwise; writes T5 split only.
// ---------------------------------------------------------------------------
__global__ __launch_bounds__(256) void mha2_pw(
    const float* __restrict__ qp, const float* __restrict__ k0,
    const float* __restrict__ k1, const float* __restrict__ v0,
    const float* __restrict__ v1,
    __nv_bfloat16* __restrict__ oh, __nv_bfloat16* __restrict__ ol)
{
    const int idx = blockIdx.x * 256 + threadIdx.x;
    const size_t base = (size_t)(idx >> 3) * kC + (idx & 7) * 16;
    const float4* qg  = (const float4*)(qp + base);
    const float4* k0g = (const float4*)(k0 + base);
    const float4* k1g = (const float4*)(k1 + base);
    float s0 = 0.0f, s1 = 0.0f;
#pragma unroll
    for (int t = 0; t < 4; t++) {
        float4 qv = qg[t], a0 = k0g[t], a1 = k1g[t];
        s0 += qv.x * a0.x + qv.y * a0.y + qv.z * a0.z + qv.w * a0.w;
        s1 += qv.x * a1.x + qv.y * a1.y + qv.z * a1.z + qv.w * a1.w;
    }
    s0 *= 0.25f; s1 *= 0.25f;
    const float m = fmaxf(s0, s1);
    float e0 = __expf(s0 - m), e1 = __expf(s1 - m);
    const float inv = 1.0f / (e0 + e1);
    e0 *= inv; e1 *= inv;
    const float4* v0g = (const float4*)(v0 + base);
    const float4* v1g = (const float4*)(v1 + base);
    uint2* ohg = (uint2*)(oh + base);
    uint2* olg = (uint2*)(ol + base);
#pragma unroll
    for (int t = 0; t < 4; t++) {
        float4 a = v0g[t], bb = v1g[t];
        float o0 = e0 * a.x + e1 * bb.x, o1 = e0 * a.y + e1 * bb.y;
        float o2 = e0 * a.z + e1 * bb.z, o3 = e0 * a.w + e1 * bb.w;
        uint32_t h0, l0, h1, l1;
        cvt_pair(o0, o1, h0, l0);
        cvt_pair(o2, o3, h1, l1);
        ohg[t] = make_uint2(h0, h1);
        olg[t] = make_uint2(l0, l1);
    }
}

// ---------------------------------------------------------------------------
__global__ void cvt_split(const float* __restrict__ src,
                          __nv_bfloat16* __restrict__ dh,
                          __nv_bfloat16* __restrict__ dl)
{
    const int i = blockIdx.x * 256 + threadIdx.x;
    float4 v = ((const float4*)src)[i];
    uint32_t h0, l0, h1, l1;
    cvt_pair(v.x, v.y, h0, l0);
    cvt_pair(v.z, v.w, h1, l1);
    ((uint2*)dh)[i] = make_uint2(h0, h1);
    ((uint2*)dl)[i] = make_uint2(l0, l1);
}

__global__ void split_w(const float* __restrict__ src, int ldW,
                        __nv_bfloat16* __restrict__ dh,
                        __nv_bfloat16* __restrict__ dl)
{
    const int i = blockIdx.x * 256 + threadIdx.x;   // 8192 pairs
    const int o = i >> 6, k = (i & 63) * 2;
    uint32_t h, l;
    cvt_pair(src[(size_t)o * ldW + k], src[(size_t)o * ldW + k + 1], h, l);
    *(uint32_t*)(dh + o * kC + k) = h;
    *(uint32_t*)(dl + o * kC + k) = l;
}

__global__ void split_convw(const float* __restrict__ srw,
                            __nv_bfloat16* __restrict__ dh,
                            __nv_bfloat16* __restrict__ dl)
{
    const int t = blockIdx.x * 256 + threadIdx.x;   // 64*8192
    const int pos = t >> 13, o = (t >> 6) & 127, i2 = (t & 63) * 2;
    uint32_t h, l;
    cvt_pair(srw[(size_t)o * 8192 + i2 * 64 + pos],
             srw[(size_t)o * 8192 + (i2 + 1) * 64 + pos], h, l);
    const size_t d = (size_t)pos * 16384 + (size_t)o * kC + i2;
    *(uint32_t*)(dh + d) = h;
    *(uint32_t*)(dl + d) = l;
}

__global__ void fold_bias(
    const float* __restrict__ w01, const float* __restrict__ b01,
    const float* __restrict__ w10, const float* __restrict__ b10,
    const float* __restrict__ kn, const float* __restrict__ vn,
    float* __restrict__ bm)
{
    const int which = blockIdx.x, c = threadIdx.x;
    const float* W  = (which < 2) ? w01 : w10;
    const float* Bb = (which < 2) ? b01 : b10;
    const float* nz = ((which & 1) ? vn : kn) + (which >> 1) * kC;
    const int off = (which & 1) ? 256 : 128;
    float acc = Bb[off + c];
    const float* wr = W + (size_t)(off + c) * kC;
    for (int k = 0; k < kC; k++) acc += nz[k] * wr[k];
    bm[which * kC + c] = acc;
}

// ---------------------------------------------------------------------------
extern "C" void kernel_launch(void* const* d_in, const int* in_sizes, int n_in,
                              void* d_out, int out_size)
{
    (void)in_sizes; (void)n_in; (void)out_size;
    const float* x0   = (const float*)d_in[0];
    const float* x1   = (const float*)d_in[1];
    const float* Wq   = (const float*)d_in[2];
    const float* bq   = (const float*)d_in[3];
    const float* Wkv  = (const float*)d_in[4];
    const float* bkv  = (const float*)d_in[5];
    const float* srw  = (const float*)d_in[6];
    const float* srb  = (const float*)d_in[7];
    const float* lnG[2] = {(const float*)d_in[8],  (const float*)d_in[10]};
    const float* lnB[2] = {(const float*)d_in[9],  (const float*)d_in[11]};
    const float* cawI[2] = {(const float*)d_in[12], (const float*)d_in[16]};
    const float* cabI[2] = {(const float*)d_in[13], (const float*)d_in[17]};
    const float* cawO[2] = {(const float*)d_in[14], (const float*)d_in[18]};
    const float* cabO[2] = {(const float*)d_in[15], (const float*)d_in[19]};
    const float* rjw1 = (const float*)d_in[20];
    const float* rjb1 = (const float*)d_in[21];
    const float* rjw2 = (const float*)d_in[22];
    const float* rjb2 = (const float*)d_in[23];
    const float* kn   = (const float*)d_in[24];
    const float* vn   = (const float*)d_in[25];
    const float* pw   = (const float*)d_in[26];
    const float* pb   = (const float*)d_in[27];
    float* out = (float*)d_out;

    float* g = nullptr;
    cudaGetSymbolAddress((void**)&g, g_mem);
    __nv_bfloat16* hm = nullptr;
    cudaGetSymbolAddress((void**)&hm, h_mem);

    float* XA[2] = {g + O_XA0, g + O_XA1};
    float *T0 = g + O_T0, *T1 = g + O_T1, *T2 = g + O_T2;
    float *T3 = g + O_T3, *T4 = g + O_T4;
    float *PART = g + O_PART, *KB = g + O_KB, *VB = g + O_VB, *BM = g + O_BM;

    __nv_bfloat16 *XH[2] = {hm + H_X0, hm + H_X1};
    __nv_bfloat16 *XL[2] = {hm + L_X0, hm + L_X1};
    __nv_bfloat16 *XAH[2] = {hm + H_XA0, hm + H_XA1};
    __nv_bfloat16 *XAL[2] = {hm + L_XA0, hm + L_XA1};
    __nv_bfloat16 *T1H = hm + H_T1, *T1L = hm + L_T1;
    __nv_bfloat16 *XASH = hm + H_XAS, *XASL = hm + L_XAS;
    __nv_bfloat16 *T5H = hm + H_T5, *T5L = hm + L_T5;
    __nv_bfloat16 *NSH = hm + H_NS, *NSL = hm + L_NS;
    __nv_bfloat16 *XLNH = hm + H_XLN, *XLNL = hm + L_XLN;
    __nv_bfloat16 *WSH = hm + H_WS, *WSL = hm + L_WS;
    __nv_bfloat16 *CWH = hm + H_CW, *CWL = hm + L_CW;

    cudaFuncSetAttribute(sr_attn, cudaFuncAttributeMaxDynamicSharedMemorySize, 131072);
    cudaFuncSetAttribute(gemm2, cudaFuncAttributeMaxDynamicSharedMemorySize, SM_TOTAL);
    cudaFuncSetAttribute(conv_mma, cudaFuncAttributeMaxDynamicSharedMemorySize, SM_TOTAL);

    // --- one-time prep ---
    fold_bias<<<4, 128>>>(cawI[0], cabI[0], cawI[1], cabI[1], kn, vn, BM);
    cvt_split<<<8192, 256>>>(x0, XH[0], XL[0]);
    cvt_split<<<8192, 256>>>(x1, XH[1], XL[1]);
    split_convw<<<2048, 256>>>(srw, CWH, CWL);
#define SW(SRC, LD, IDX) \
    split_w<<<32, 256>>>(SRC, LD, WSH + (IDX) * 16384, WSL + (IDX) * 16384)
    SW(Wq, 128, 0);
    SW(Wkv, 128, 1);          SW(Wkv + 16384, 128, 2);
    SW(rjw1, 256, 3);         SW(rjw1 + 128, 256, 4);
    SW(rjw2, 128, 5);
    SW(cawI[0], 128, 6);      SW(cawI[0] + 16384, 128, 7);  SW(cawI[0] + 32768, 128, 8);
    SW(cawI[1], 128, 9);      SW(cawI[1] + 16384, 128, 10); SW(cawI[1] + 32768, 128, 11);
    SW(cawO[0], 128, 12);     SW(cawO[1], 128, 13);
    SW(pw, 128, 14);
#undef SW

    const int GM = kMTOK / 128;
#define WB(i) (WSH + (i) * 16384), (WSL + (i) * 16384)
#define G2(GRID, AH, AL, WI, BIAS, RESID, PMUL, YF, YH, YL, EPI) \
    gemm2<<<GRID, 256, SM_TOTAL>>>(AH, AL, WB(WI), BIAS, RESID, PMUL, YF, YH, YL, EPI)

    // --- Stage A ---
    for (int s = 0; s < 2; s++) {
        G2(GM, XH[s], XL[s], 0, bq, nullptr, nullptr, T0, nullptr, nullptr, 0);
        conv_mma<<<dim3(8, 64), 256, SM_TOTAL>>>(XH[s], XL[s], CWH, CWL, PART);
        conv_reduce_ln<<<1024, 128>>>(PART, srb, lnG[s], lnB[s], XLNH, XLNL);
        G2(8, XLNH, XLNL, 1, bkv,       nullptr, nullptr, KB, nullptr, nullptr, 0);
        G2(8, XLNH, XLNL, 2, bkv + 128, nullptr, nullptr, VB, nullptr, nullptr, 0);
        sr_attn<<<dim3(64, 8), 256, 131072>>>(T0, KB, VB, XA[s], XAH[s], XAL[s]);
    }

    // --- Stage B + C per stream ---
    for (int s = 0; s < 2; s++) {
        // judger
        G2(GM, XAH[s],     XAL[s],     3, nullptr, nullptr, nullptr, T0, nullptr, nullptr, 0);
        G2(GM, XAH[s ^ 1], XAL[s ^ 1], 4, rjb1,    T0,      nullptr, nullptr, T1H, T1L, 1);
        G2(GM, T1H,        T1L,        5, rjb2,    nullptr, XA[s],   nullptr, XASH, XASL, 2);
        // mha2 projections
        const float* Bb = cabI[s];
        float* bmk = BM + (2 * s) * kC;
        float* bmv = BM + (2 * s + 1) * kC;
        G2(GM, XAH[s],     XAL[s],     6 + 3 * s, Bb,       nullptr, nullptr, T0, nullptr, nullptr, 0);
        G2(GM, XAH[s],     XAL[s],     7 + 3 * s, bmk,      nullptr, nullptr, T1, nullptr, nullptr, 0);
        G2(GM, XASH,       XASL,       7 + 3 * s, Bb + 128, nullptr, nullptr, T2, nullptr, nullptr, 0);
        G2(GM, XAH[s],     XAL[s],     8 + 3 * s, bmv,      nullptr, nullptr, T3, nullptr, nullptr, 0);
        G2(GM, XAH[s ^ 1], XAL[s ^ 1], 8 + 3 * s, Bb + 256, nullptr, nullptr, T4, nullptr, nullptr, 0);
        mha2_pw<<<2048, 256>>>(T0, T1, T2, T3, T4, T5H, T5L);
        G2(GM, T5H, T5L, 12 + s, cabO[s], XA[s], nullptr, nullptr, NSH, NSL, 0);
        G2(GM, NSH, NSL, 14,     pb,      nullptr, nullptr, out + (size_t)s * SZ, nullptr, nullptr, 0);
    }
#undef G2
#undef WB
}

// round 8
// speedup vs baseline: 1.6662x; 1.1545x over previous
#include <cuda_runtime.h>
#include <cuda_fp16.h>
#include <math.h>
#include <stdint.h>

#define FULLMASK 0xffffffffu

namespace {
constexpr int kB = 4, kN = 16384, kC = 128, kMTOK = 65536, kMR = 1024;
constexpr size_t SZ = (size_t)kMTOK * kC;   // 8,388,608

// fp32 scratch
constexpr size_t O_XA0 = 0;
constexpr size_t O_XA1 = SZ;
constexpr size_t O_T0  = 2 * SZ;
constexpr size_t O_T1  = 3 * SZ;
constexpr size_t O_T2  = 4 * SZ;
constexpr size_t O_T3  = 5 * SZ;
constexpr size_t O_T4  = 6 * SZ;
constexpr size_t O_PART = 7 * SZ;           // 64*1024*128 == SZ
constexpr size_t O_KB  = 8 * SZ;
constexpr size_t O_VB  = O_KB + 131072;
constexpr size_t O_BM  = O_VB + 131072;
constexpr size_t TOTF  = O_BM + 512;

// fp16 buffers (element offsets in h_mem)
constexpr size_t H_X0  = 0;
constexpr size_t H_X1  = SZ;
constexpr size_t H_XA0 = 2 * SZ;
constexpr size_t H_XA1 = 3 * SZ;
constexpr size_t H_T1  = 4 * SZ;
constexpr size_t H_XAS = 5 * SZ;
constexpr size_t H_T5  = 6 * SZ;
constexpr size_t H_NS  = 7 * SZ;
constexpr size_t H_XLN = 8 * SZ;                     // 131072
constexpr size_t H_WS  = H_XLN + 131072;             // 15 hi blocks
constexpr size_t L_WS  = H_WS + 15 * 16384;          // 15 lo blocks
constexpr size_t H_CW  = L_WS + 15 * 16384;          // 64 hi blocks
constexpr size_t L_CW  = H_CW + 64 * 16384;          // 64 lo blocks
constexpr size_t TOTH  = L_CW + 64 * 16384;

// gemm smem: 3 fp16 tiles [128][72] (row stride 144 B), one 64-col K chunk
constexpr int TROW   = 144;
constexpr int TBYTES = 128 * TROW;          // 18432
constexpr int SM_A  = 0;
constexpr int SM_BH = TBYTES;
constexpr int SM_BL = 2 * TBYTES;
constexpr int SM_TOTAL = 73728;             // covers tiles (55296) + softmax smem
}

__device__ float g_mem[TOTF];
__device__ __half h_mem[TOTH];

// ---------------------------------------------------------------------------
__device__ __forceinline__ uint32_t smem_u32(const void* p) {
    uint32_t a;
    asm("{ .reg .u64 t; cvta.to.shared.u64 t, %1; cvt.u32.u64 %0, t; }"
        : "=r"(a) : "l"(p));
    return a;
}
__device__ __forceinline__ uint32_t pack_h2(float a, float b) {
    __half2 h = __floats2half2_rn(a, b);
    return *(uint32_t*)&h;
}
__device__ __forceinline__ void split_pair(float a, float b,
                                           uint32_t& hi, uint32_t& lo) {
    __half ah = __float2half_rn(a), bh = __float2half_rn(b);
    __half al = __float2half_rn(a - __half2float(ah));
    __half bl = __float2half_rn(b - __half2float(bh));
    hi = (uint32_t)*(uint16_t*)&ah | ((uint32_t)*(uint16_t*)&bh << 16);
    lo = (uint32_t)*(uint16_t*)&al | ((uint32_t)*(uint16_t*)&bl << 16);
}
__device__ __forceinline__ void mma16816(float* d, const uint32_t* a,
                                         uint32_t b0, uint32_t b1) {
    asm volatile(
        "mma.sync.aligned.m16n8k16.row.col.f32.f16.f16.f32 "
        "{%0,%1,%2,%3}, {%4,%5,%6,%7}, {%8,%9}, {%0,%1,%2,%3};"
        : "+f"(d[0]), "+f"(d[1]), "+f"(d[2]), "+f"(d[3])
        : "r"(a[0]), "r"(a[1]), "r"(a[2]), "r"(a[3]), "r"(b0), "r"(b1));
}
__device__ __forceinline__ void ldsm4(uint32_t& r0, uint32_t& r1,
                                      uint32_t& r2, uint32_t& r3, uint32_t addr) {
    asm volatile("ldmatrix.sync.aligned.m8n8.x4.shared.b16 {%0,%1,%2,%3}, [%4];"
                 : "=r"(r0), "=r"(r1), "=r"(r2), "=r"(r3) : "r"(addr));
}
__device__ __forceinline__ void cpa16(uint32_t dst, const void* src) {
    asm volatile("cp.async.cg.shared.global [%0], [%1], 16;"
                 :: "r"(dst), "l"(src));
}
__device__ __forceinline__ void cpa_wait() {
    asm volatile("cp.async.commit_group;\ncp.async.wait_group 0;" ::: "memory");
}

// ---------------------------------------------------------------------------
struct FragCtx {
    uint32_t aoff[2];
    uint32_t boff[4];
};
__device__ __forceinline__ FragCtx make_frag_ctx(int lane, int wm, int wn) {
    FragCtx fc;
    const int rA = (lane & 7) + ((lane >> 3) & 1) * 8;
    const int cA = (lane >> 4) * 16;
#pragma unroll
    for (int mt = 0; mt < 2; mt++)
        fc.aoff[mt] = (uint32_t)((wm * 32 + mt * 16 + rA) * TROW + cA);
    const int rB = (lane & 7) + ((lane >> 4) & 1) * 8;
    const int cB = ((lane >> 3) & 1) * 16;
#pragma unroll
    for (int np = 0; np < 4; np++)
        fc.boff[np] = (uint32_t)((wn * 64 + np * 16 + rB) * TROW + cB);
    return fc;
}
// one 64-col K chunk staged in smem: C += A·Bh + A·Bl
__device__ __forceinline__ void mainloop_chunk(uint32_t smb, const FragCtx& fc,
                                               float acc[2][8][4]) {
#pragma unroll
    for (int kc = 0; kc < 4; kc++) {
        const uint32_t kb = (uint32_t)kc * 32;
        uint32_t ah[2][4];
#pragma unroll
        for (int mt = 0; mt < 2; mt++)
            ldsm4(ah[mt][0], ah[mt][1], ah[mt][2], ah[mt][3],
                  smb + SM_A + fc.aoff[mt] + kb);
#pragma unroll
        for (int np = 0; np < 4; np++) {
            uint32_t bh0, bh1, bh2, bh3, bl0, bl1, bl2, bl3;
            ldsm4(bh0, bh1, bh2, bh3, smb + SM_BH + fc.boff[np] + kb);
            ldsm4(bl0, bl1, bl2, bl3, smb + SM_BL + fc.boff[np] + kb);
#pragma unroll
            for (int mt = 0; mt < 2; mt++) {
                mma16816(acc[mt][np * 2],     ah[mt], bh0, bh1);
                mma16816(acc[mt][np * 2],     ah[mt], bl0, bl1);
                mma16816(acc[mt][np * 2 + 1], ah[mt], bh2, bh3);
                mma16816(acc[mt][np * 2 + 1], ah[mt], bl2, bl3);
            }
        }
    }
}

// ---------------------------------------------------------------------------
// GEMM v3: A fp16 single, B fp16 hi/lo. Y = epi(A @ B^T + bias? + resid?)
// epi 0: none, 1: GELU, 2: row-softmax then *postmul.
// Outputs: fp32 Yf (optional), fp16 Yh (optional).
// ---------------------------------------------------------------------------
__global__ __launch_bounds__(256, 2) void gemm3(
    const __half* __restrict__ A,
    const __half* __restrict__ Bh, const __half* __restrict__ Bl,
    const float* __restrict__ bias, const float* __restrict__ resid,
    const float* __restrict__ postmul,
    float* __restrict__ Yf, __half* __restrict__ Yh, int epi)
{
    extern __shared__ char sm[];
    const uint32_t smb = smem_u32(sm);
    const int tid = threadIdx.x;
    const int lane = tid & 31, wid = tid >> 5;
    const int t4 = lane & 3, r8 = lane >> 2;
    const int wm = wid >> 1, wn = wid & 1;
    const int bm = blockIdx.x * 128;
    const FragCtx fc = make_frag_ctx(lane, wm, wn);

    float acc[2][8][4];
#pragma unroll
    for (int mt = 0; mt < 2; mt++)
#pragma unroll
        for (int nt = 0; nt < 8; nt++)
#pragma unroll
            for (int e = 0; e < 4; e++) acc[mt][nt][e] = 0.0f;

    const int pr = tid >> 1, hf = tid & 1;

    for (int ch = 0; ch < 2; ch++) {
        const size_t arow = (size_t)(bm + pr) * kC + ch * 64 + hf * 32;
        const size_t brow = (size_t)pr * kC + ch * 64 + hf * 32;
        const uint32_t so = (uint32_t)(pr * TROW + hf * 64);
#pragma unroll
        for (int gq = 0; gq < 4; gq++) {
            cpa16(smb + SM_A  + so + gq * 16, A  + arow + gq * 8);
            cpa16(smb + SM_BH + so + gq * 16, Bh + brow + gq * 8);
            cpa16(smb + SM_BL + so + gq * 16, Bl + brow + gq * 8);
        }
        cpa_wait();
        __syncthreads();
        mainloop_chunk(smb, fc, acc);
        __syncthreads();
    }

    if (epi != 2) {
#pragma unroll
        for (int mt = 0; mt < 2; mt++)
#pragma unroll
            for (int p = 0; p < 2; p++) {
                const int r = bm + wm * 32 + mt * 16 + r8 + p * 8;
#pragma unroll
                for (int nt = 0; nt < 8; nt++) {
                    const int c = wn * 64 + nt * 8 + 2 * t4;
                    float v0 = acc[mt][nt][2 * p];
                    float v1 = acc[mt][nt][2 * p + 1];
                    if (bias) {
                        float2 bv = *(const float2*)(bias + c);
                        v0 += bv.x; v1 += bv.y;
                    }
                    if (resid) {
                        float2 rv = *(const float2*)(resid + (size_t)r * kC + c);
                        v0 += rv.x; v1 += rv.y;
                    }
                    if (epi == 1) {
                        v0 = 0.5f * v0 * (1.0f + erff(v0 * 0.70710678118654752f));
                        v1 = 0.5f * v1 * (1.0f + erff(v1 * 0.70710678118654752f));
                    }
                    if (Yf)
                        *(float2*)(Yf + (size_t)r * kC + c) = make_float2(v0, v1);
                    if (Yh)
                        *(uint32_t*)(Yh + (size_t)r * kC + c) = pack_h2(v0, v1);
                }
            }
    } else {
        float* Csm = (float*)sm;
#pragma unroll
        for (int mt = 0; mt < 2; mt++)
#pragma unroll
            for (int p = 0; p < 2; p++) {
                const int lr = wm * 32 + mt * 16 + r8 + p * 8;
#pragma unroll
                for (int nt = 0; nt < 8; nt++) {
                    const int c = wn * 64 + nt * 8 + 2 * t4;
                    float v0 = acc[mt][nt][2 * p];
                    float v1 = acc[mt][nt][2 * p + 1];
                    if (bias) {
                        float2 bv = *(const float2*)(bias + c);
                        v0 += bv.x; v1 += bv.y;
                    }
                    Csm[(size_t)lr * 133 + c]     = v0;
                    Csm[(size_t)lr * 133 + c + 1] = v1;
                }
            }
        __syncthreads();
        if (tid < 128) {
            float* rp = Csm + (size_t)tid * 133;
            float mx = rp[0];
#pragma unroll 4
            for (int c = 1; c < 128; c++) mx = fmaxf(mx, rp[c]);
            float s = 0.0f;
#pragma unroll 4
            for (int c = 0; c < 128; c++) { rp[c] = __expf(rp[c] - mx); s += rp[c]; }
            const float inv = 1.0f / s;
#pragma unroll 4
            for (int c = 0; c < 128; c++) rp[c] *= inv;
        }
        __syncthreads();
        for (int idx = tid; idx < 128 * 64; idx += 256) {
            const int lr = idx >> 6, c = (idx & 63) * 2;
            const size_t go = (size_t)(bm + lr) * kC + c;
            float v0 = Csm[(size_t)lr * 133 + c]     * postmul[go];
            float v1 = Csm[(size_t)lr * 133 + c + 1] * postmul[go + 1];
            *(uint32_t*)(Yh + go) = pack_h2(v0, v1);
        }
    }
}

// ---------------------------------------------------------------------------
// Conv via mma: grid (8, 64), one kernel position per block, gathered A rows.
// ---------------------------------------------------------------------------
__global__ __launch_bounds__(256, 2) void conv_mma(
    const __half* __restrict__ xh,
    const __half* __restrict__ cwh, const __half* __restrict__ cwl,
    float* __restrict__ part)
{
    extern __shared__ char sm[];
    const uint32_t smb = smem_u32(sm);
    const int tid = threadIdx.x;
    const int lane = tid & 31, wid = tid >> 5;
    const int t4 = lane & 3, r8 = lane >> 2;
    const int wm = wid >> 1, wn = wid & 1;
    const int b = blockIdx.x >> 1, rt = blockIdx.x & 1, pos = blockIdx.y;
    const FragCtx fc = make_frag_ctx(lane, wm, wn);

    float acc[2][8][4];
#pragma unroll
    for (int mt = 0; mt < 2; mt++)
#pragma unroll
        for (int nt = 0; nt < 8; nt++)
#pragma unroll
            for (int e = 0; e < 4; e++) acc[mt][nt][e] = 0.0f;

    const int pr = tid >> 1, hf = tid & 1;
    const int p = rt * 128 + pr;
    const int ph = p >> 4, pwd = p & 15;
    const int kh = pos >> 3, kw = pos & 7;
    const size_t xrow = ((size_t)b * kN + (ph * 8 + kh) * 128 + pwd * 8 + kw) * kC;
    const size_t wbase = (size_t)pos * 16384 + (size_t)pr * kC;

    for (int ch = 0; ch < 2; ch++) {
        const size_t arow = xrow + ch * 64 + hf * 32;
        const size_t brow = wbase + ch * 64 + hf * 32;
        const uint32_t so = (uint32_t)(pr * TROW + hf * 64);
#pragma unroll
        for (int gq = 0; gq < 4; gq++) {
            cpa16(smb + SM_A  + so + gq * 16, xh  + arow + gq * 8);
            cpa16(smb + SM_BH + so + gq * 16, cwh + brow + gq * 8);
            cpa16(smb + SM_BL + so + gq * 16, cwl + brow + gq * 8);
        }
        cpa_wait();
        __syncthreads();
        mainloop_chunk(smb, fc, acc);
        __syncthreads();
    }

    const size_t base = ((size_t)pos * kMR + (size_t)b * 256 + rt * 128) * kC;
#pragma unroll
    for (int mt = 0; mt < 2; mt++)
#pragma unroll
        for (int pq = 0; pq < 2; pq++) {
            const int lr = wm * 32 + mt * 16 + r8 + pq * 8;
#pragma unroll
            for (int nt = 0; nt < 8; nt++) {
                const int c = wn * 64 + nt * 8 + 2 * t4;
                *(float2*)(part + base + (size_t)lr * kC + c) =
                    make_float2(acc[mt][nt][2 * pq], acc[mt][nt][2 * pq + 1]);
            }
        }
}

// ---------------------------------------------------------------------------
__global__ void conv_reduce_ln(const float* __restrict__ part,
                               const float* __restrict__ srb,
                               const float* __restrict__ gam,
                               const float* __restrict__ bet,
                               __half* __restrict__ xlnh)
{
    const int row = blockIdx.x;
    const int c = threadIdx.x;
    float v = srb[c];
#pragma unroll 8
    for (int sp = 0; sp < 64; sp++)
        v += part[((size_t)sp * kMR + row) * kC + c];

    __shared__ float red[4];
    float s = v;
#pragma unroll
    for (int o = 16; o > 0; o >>= 1) s += __shfl_xor_sync(FULLMASK, s, o);
    if ((c & 31) == 0) red[c >> 5] = s;
    __syncthreads();
    const float mean = (red[0] + red[1] + red[2] + red[3]) * (1.0f / 128.0f);
    __syncthreads();
    const float d = v - mean;
    float s2 = d * d;
#pragma unroll
    for (int o = 16; o > 0; o >>= 1) s2 += __shfl_xor_sync(FULLMASK, s2, o);
    if ((c & 31) == 0) red[c >> 5] = s2;
    __syncthreads();
    const float var = (red[0] + red[1] + red[2] + red[3]) * (1.0f / 128.0f);
    xlnh[(size_t)row * kC + c] =
        __float2half_rn(d * rsqrtf(var + 1e-5f) * gam[c] + bet[c]);
}

// ---------------------------------------------------------------------------
// Fused SR attention; writes XA fp32 + fp16.
// ---------------------------------------------------------------------------
__global__ __launch_bounds__(256) void sr_attn(
    const float* __restrict__ Q, const float* __restrict__ K,
    const float* __restrict__ V, float* __restrict__ XA,
    __half* __restrict__ XAh)
{
    extern __shared__ float sh[];
    float4* K4 = (float4*)sh;
    float4* V4 = (float4*)(sh + 16384);
    const int tid = threadIdx.x;
    const int b = blockIdx.y >> 1, h = blockIdx.y & 1;

    const float4* Kg = (const float4*)K + (size_t)b * 256 * 32 + h * 16;
    const float4* Vg = (const float4*)V + (size_t)b * 256 * 32 + h * 16;
#pragma unroll
    for (int jj = 0; jj < 16; jj++) {
        int e = jj * 256 + tid;
        int m = e >> 4, d4 = e & 15;
        K4[m * 16 + d4] = Kg[(size_t)m * 32 + d4];
        V4[m * 16 + d4] = Vg[(size_t)m * 32 + d4];
    }
    __syncthreads();

    const size_t row = (size_t)b * kN + (size_t)blockIdx.x * 256 + tid;
    float q[64];
    {
        const float4* Qg = (const float4*)(Q + row * kC + h * 64);
#pragma unroll
        for (int t = 0; t < 16; t++) *(float4*)&q[t * 4] = Qg[t];
    }
    float out[64];
#pragma unroll
    for (int d = 0; d < 64; d++) out[d] = 0.0f;
    float Mv = -1e30f, Sv = 0.0f;

    for (int c = 0; c < 32; c++) {
        float s[8];
#pragma unroll
        for (int mm = 0; mm < 8; mm++) {
            const float4* kr = &K4[(c * 8 + mm) * 16];
            float a = 0.0f;
#pragma unroll
            for (int t = 0; t < 16; t++) {
                float4 kk = kr[t];
                a = fmaf(q[t * 4 + 0], kk.x, a);
                a = fmaf(q[t * 4 + 1], kk.y, a);
                a = fmaf(q[t * 4 + 2], kk.z, a);
                a = fmaf(q[t * 4 + 3], kk.w, a);
            }
            s[mm] = a * 0.125f;
        }
        float cm = s[0];
#pragma unroll
        for (int mm = 1; mm < 8; mm++) cm = fmaxf(cm, s[mm]);
        const float nM = fmaxf(Mv, cm);
        const float sc = __expf(Mv - nM);
        Sv *= sc;
#pragma unroll
        for (int d = 0; d < 64; d++) out[d] *= sc;
#pragma unroll
        for (int mm = 0; mm < 8; mm++) {
            const float e = __expf(s[mm] - nM);
            Sv += e;
            const float4* vr = &V4[(c * 8 + mm) * 16];
#pragma unroll
            for (int t = 0; t < 16; t++) {
                float4 vv = vr[t];
                out[t * 4 + 0] = fmaf(e, vv.x, out[t * 4 + 0]);
                out[t * 4 + 1] = fmaf(e, vv.y, out[t * 4 + 1]);
                out[t * 4 + 2] = fmaf(e, vv.z, out[t * 4 + 2]);
                out[t * 4 + 3] = fmaf(e, vv.w, out[t * 4 + 3]);
            }
        }
        Mv = nM;
    }
    const float inv = 1.0f / Sv;
    float4* Og = (float4*)(XA + row * kC + h * 64);
    uint2* Oh = (uint2*)(XAh + row * kC + h * 64);
#pragma unroll
    for (int t = 0; t < 16; t++) {
        float o0 = out[t * 4] * inv, o1 = out[t * 4 + 1] * inv;
        float o2 = out[t * 4 + 2] * inv, o3 = out[t * 4 + 3] * inv;
        Og[t] = make_float4(o0, o1, o2, o3);
        Oh[t] = make_uint2(pack_h2(o0, o1), pack_h2(o2, o3));
    }
}

// ---------------------------------------------------------------------------
__global__ __launch_bounds__(256) void mha2_pw(
    const float* __restrict__ qp, const float* __restrict__ k0,
    const float* __restrict__ k1, const float* __restrict__ v0,
    const float* __restrict__ v1, __half* __restrict__ oh)
{
    const int idx = blockIdx.x * 256 + threadIdx.x;
    const size_t base = (size_t)(idx >> 3) * kC + (idx & 7) * 16;
    const float4* qg  = (const float4*)(qp + base);
    const float4* k0g = (const float4*)(k0 + base);
    const float4* k1g = (const float4*)(k1 + base);
    float s0 = 0.0f, s1 = 0.0f;
#pragma unroll
    for (int t = 0; t < 4; t++) {
        float4 qv = qg[t], a0 = k0g[t], a1 = k1g[t];
        s0 += qv.x * a0.x + qv.y * a0.y + qv.z * a0.z + qv.w * a0.w;
        s1 += qv.x * a1.x + qv.y * a1.y + qv.z * a1.z + qv.w * a1.w;
    }
    s0 *= 0.25f; s1 *= 0.25f;
    const float m = fmaxf(s0, s1);
    float e0 = __expf(s0 - m), e1 = __expf(s1 - m);
    const float inv = 1.0f / (e0 + e1);
    e0 *= inv; e1 *= inv;
    const float4* v0g = (const float4*)(v0 + base);
    const float4* v1g = (const float4*)(v1 + base);
    uint2* ohg = (uint2*)(oh + base);
#pragma unroll
    for (int t = 0; t < 4; t++) {
        float4 a = v0g[t], bb = v1g[t];
        ohg[t] = make_uint2(
            pack_h2(e0 * a.x + e1 * bb.x, e0 * a.y + e1 * bb.y),
            pack_h2(e0 * a.z + e1 * bb.z, e0 * a.w + e1 * bb.w));
    }
}

// ---------------------------------------------------------------------------
__global__ void cvt_half(const float* __restrict__ src, __half* __restrict__ dst)
{
    const int i = blockIdx.x * 256 + threadIdx.x;
    float4 v = ((const float4*)src)[i];
    ((uint2*)dst)[i] = make_uint2(pack_h2(v.x, v.y), pack_h2(v.z, v.w));
}

__global__ void split_w(const float* __restrict__ src, int ldW,
                        __half* __restrict__ dh, __half* __restrict__ dl)
{
    const int i = blockIdx.x * 256 + threadIdx.x;   // 8192 pairs
    const int o = i >> 6, k = (i & 63) * 2;
    uint32_t h, l;
    split_pair(src[(size_t)o * ldW + k], src[(size_t)o * ldW + k + 1], h, l);
    *(uint32_t*)(dh + o * kC + k) = h;
    *(uint32_t*)(dl + o * kC + k) = l;
}

__global__ void split_convw(const float* __restrict__ srw,
                            __half* __restrict__ dh, __half* __restrict__ dl)
{
    const int t = blockIdx.x * 256 + threadIdx.x;   // 64*8192
    const int pos = t >> 13, o = (t >> 6) & 127, i2 = (t & 63) * 2;
    uint32_t h, l;
    split_pair(srw[(size_t)o * 8192 + i2 * 64 + pos],
               srw[(size_t)o * 8192 + (i2 + 1) * 64 + pos], h, l);
    const size_t d = (size_t)pos * 16384 + (size_t)o * kC + i2;
    *(uint32_t*)(dh + d) = h;
    *(uint32_t*)(dl + d) = l;
}

__global__ void fold_bias(
    const float* __restrict__ w01, const float* __restrict__ b01,
    const float* __restrict__ w10, const float* __restrict__ b10,
    const float* __restrict__ kn, const float* __restrict__ vn,
    float* __restrict__ bm)
{
    const int which = blockIdx.x, c = threadIdx.x;
    const float* W  = (which < 2) ? w01 : w10;
    const float* Bb = (which < 2) ? b01 : b10;
    const float* nz = ((which & 1) ? vn : kn) + (which >> 1) * kC;
    const int off = (which & 1) ? 256 : 128;
    float acc = Bb[off + c];
    const float* wr = W + (size_t)(off + c) * kC;
    for (int k = 0; k < kC; k++) acc += nz[k] * wr[k];
    bm[which * kC + c] = acc;
}

// ---------------------------------------------------------------------------
extern "C" void kernel_launch(void* const* d_in, const int* in_sizes, int n_in,
                              void* d_out, int out_size)
{
    (void)in_sizes; (void)n_in; (void)out_size;
    const float* x0   = (const float*)d_in[0];
    const float* x1   = (const float*)d_in[1];
    const float* Wq   = (const float*)d_in[2];
    const float* bq   = (const float*)d_in[3];
    const float* Wkv  = (const float*)d_in[4];
    const float* bkv  = (const float*)d_in[5];
    const float* srw  = (const float*)d_in[6];
    const float* srb  = (const float*)d_in[7];
    const float* lnG[2] = {(const float*)d_in[8],  (const float*)d_in[10]};
    const float* lnB[2] = {(const float*)d_in[9],  (const float*)d_in[11]};
    const float* cawI[2] = {(const float*)d_in[12], (const float*)d_in[16]};
    const float* cabI[2] = {(const float*)d_in[13], (const float*)d_in[17]};
    const float* cawO[2] = {(const float*)d_in[14], (const float*)d_in[18]};
    const float* cabO[2] = {(const float*)d_in[15], (const float*)d_in[19]};
    const float* rjw1 = (const float*)d_in[20];
    const float* rjb1 = (const float*)d_in[21];
    const float* rjw2 = (const float*)d_in[22];
    const float* rjb2 = (const float*)d_in[23];
    const float* kn   = (const float*)d_in[24];
    const float* vn   = (const float*)d_in[25];
    const float* pw   = (const float*)d_in[26];
    const float* pb   = (const float*)d_in[27];
    float* out = (float*)d_out;

    float* g = nullptr;
    cudaGetSymbolAddress((void**)&g, g_mem);
    __half* hm = nullptr;
    cudaGetSymbolAddress((void**)&hm, h_mem);

    float* XA[2] = {g + O_XA0, g + O_XA1};
    float *T0 = g + O_T0, *T1 = g + O_T1, *T2 = g + O_T2;
    float *T3 = g + O_T3, *T4 = g + O_T4;
    float *PART = g + O_PART, *KB = g + O_KB, *VB = g + O_VB, *BM = g + O_BM;

    __half *XH[2]  = {hm + H_X0, hm + H_X1};
    __half *XAH[2] = {hm + H_XA0, hm + H_XA1};
    __half *T1H = hm + H_T1, *XASH = hm + H_XAS;
    __half *T5H = hm + H_T5, *NSH = hm + H_NS;
    __half *XLNH = hm + H_XLN;
    __half *WSH = hm + H_WS, *WSL = hm + L_WS;
    __half *CWH = hm + H_CW, *CWL = hm + L_CW;

    cudaFuncSetAttribute(sr_attn, cudaFuncAttributeMaxDynamicSharedMemorySize, 131072);
    cudaFuncSetAttribute(gemm3, cudaFuncAttributeMaxDynamicSharedMemorySize, SM_TOTAL);
    cudaFuncSetAttribute(conv_mma, cudaFuncAttributeMaxDynamicSharedMemorySize, SM_TOTAL);

    // --- one-time prep ---
    fold_bias<<<4, 128>>>(cawI[0], cabI[0], cawI[1], cabI[1], kn, vn, BM);
    cvt_half<<<8192, 256>>>(x0, XH[0]);
    cvt_half<<<8192, 256>>>(x1, XH[1]);
    split_convw<<<2048, 256>>>(srw, CWH, CWL);
#define SW(SRC, LD, IDX) \
    split_w<<<32, 256>>>(SRC, LD, WSH + (IDX) * 16384, WSL + (IDX) * 16384)
    SW(Wq, 128, 0);
    SW(Wkv, 128, 1);          SW(Wkv + 16384, 128, 2);
    SW(rjw1, 256, 3);         SW(rjw1 + 128, 256, 4);
    SW(rjw2, 128, 5);
    SW(cawI[0], 128, 6);      SW(cawI[0] + 16384, 128, 7);  SW(cawI[0] + 32768, 128, 8);
    SW(cawI[1], 128, 9);      SW(cawI[1] + 16384, 128, 10); SW(cawI[1] + 32768, 128, 11);
    SW(cawO[0], 128, 12);     SW(cawO[1], 128, 13);
    SW(pw, 128, 14);
#undef SW

    const int GM = kMTOK / 128;
#define WB(i) (WSH + (i) * 16384), (WSL + (i) * 16384)
#define G3(GRID, AH, WI, BIAS, RESID, PMUL, YF, YH, EPI) \
    gemm3<<<GRID, 256, SM_TOTAL>>>(AH, WB(WI), BIAS, RESID, PMUL, YF, YH, EPI)

    // --- Stage A ---
    for (int s = 0; s < 2; s++) {
        G3(GM, XH[s], 0, bq, nullptr, nullptr, T0, nullptr, 0);
        conv_mma<<<dim3(8, 64), 256, SM_TOTAL>>>(XH[s], CWH, CWL, PART);
        conv_reduce_ln<<<1024, 128>>>(PART, srb, lnG[s], lnB[s], XLNH);
        G3(8, XLNH, 1, bkv,       nullptr, nullptr, KB, nullptr, 0);
        G3(8, XLNH, 2, bkv + 128, nullptr, nullptr, VB, nullptr, 0);
        sr_attn<<<dim3(64, 8), 256, 131072>>>(T0, KB, VB, XA[s], XAH[s]);
    }

    // --- Stage B + C per stream ---
    for (int s = 0; s < 2; s++) {
        // judger
        G3(GM, XAH[s],     3, nullptr, nullptr, nullptr, T0, nullptr, 0);
        G3(GM, XAH[s ^ 1], 4, rjb1,    T0,      nullptr, nullptr, T1H, 1);
        G3(GM, T1H,        5, rjb2,    nullptr, XA[s],   nullptr, XASH, 2);
        // mha2 projections
        const float* Bb = cabI[s];
        float* bmk = BM + (2 * s) * kC;
        float* bmv = BM + (2 * s + 1) * kC;
        G3(GM, XAH[s],     6 + 3 * s, Bb,       nullptr, nullptr, T0, nullptr, 0);
        G3(GM, XAH[s],     7 + 3 * s, bmk,      nullptr, nullptr, T1, nullptr, 0);
        G3(GM, XASH,       7 + 3 * s, Bb + 128, nullptr, nullptr, T2, nullptr, 0);
        G3(GM, XAH[s],     8 + 3 * s, bmv,      nullptr, nullptr, T3, nullptr, 0);
        G3(GM, XAH[s ^ 1], 8 + 3 * s, Bb + 256, nullptr, nullptr, T4, nullptr, 0);
        mha2_pw<<<2048, 256>>>(T0, T1, T2, T3, T4, T5H);
        G3(GM, T5H, 12 + s, cabO[s], XA[s], nullptr, nullptr, NSH, 0);
        G3(GM, NSH, 14,     pb,      nullptr, nullptr, out + (size_t)s * SZ, nullptr, 0);
    }
#undef G3
#undef WB
}

// round 10
// speedup vs baseline: 2.4760x; 1.4861x over previous
#include <cuda_runtime.h>
#include <cuda_fp16.h>
#include <math.h>
#include <stdint.h>

#define FULLMASK 0xffffffffu

namespace {
constexpr int kB = 4, kN = 16384, kC = 128, kMTOK = 65536, kMR = 1024;
constexpr size_t SZ = (size_t)kMTOK * kC;   // 8,388,608

// fp32 scratch
constexpr size_t O_XA0 = 0;
constexpr size_t O_XA1 = SZ;
constexpr size_t O_T0  = 2 * SZ;
constexpr size_t O_PART = 3 * SZ;           // 64*1024*128 == SZ
constexpr size_t O_KB  = 4 * SZ;
constexpr size_t O_VB  = O_KB + 131072;
constexpr size_t O_BM  = O_VB + 131072;
constexpr size_t TOTF  = O_BM + 512;

// fp16 buffers (element offsets in h_mem)
constexpr size_t H_X0  = 0;
constexpr size_t H_X1  = SZ;
constexpr size_t H_XA0 = 2 * SZ;
constexpr size_t H_XA1 = 3 * SZ;
constexpr size_t H_T1  = 4 * SZ;            // judger hidden
constexpr size_t H_XAS = 5 * SZ;
constexpr size_t H_T5  = 6 * SZ;
constexpr size_t H_NS  = 7 * SZ;
constexpr size_t H_XLN = 8 * SZ;                     // 131072
constexpr size_t H_WS  = H_XLN + 131072;             // 15 hi blocks
constexpr size_t L_WS  = H_WS + 15 * 16384;          // 15 lo blocks
constexpr size_t H_CW  = L_WS + 15 * 16384;          // 64 hi blocks
constexpr size_t L_CW  = H_CW + 64 * 16384;          // 64 lo blocks
constexpr size_t H_QH  = L_CW + 64 * 16384;          // q fp16 (one stream)
constexpr size_t H_P   = H_QH + SZ;                  // P [8][16384][256] = 4*SZ
constexpr size_t H_KH  = H_P + 4 * SZ;               // K fp16 [8][256][64]
constexpr size_t H_VT  = H_KH + 131072;              // V^T fp16 [8][64][256]
constexpr size_t H_PT0 = H_VT + 131072;              // stage-C fp16 temps
constexpr size_t H_PT1 = H_PT0 + SZ;
constexpr size_t H_PT2 = H_PT1 + SZ;
constexpr size_t H_PT3 = H_PT2 + SZ;
constexpr size_t H_PT4 = H_PT3 + SZ;
constexpr size_t TOTH  = H_PT4 + SZ;

// gemm smem: 3 fp16 tiles [128][72] (row stride 144 B), one 64-col K chunk
constexpr int TROW   = 144;
constexpr int TBYTES = 128 * TROW;          // 18432
constexpr int SM_A  = 0;
constexpr int SM_BH = TBYTES;
constexpr int SM_BL = 2 * TBYTES;
constexpr int SM_TOTAL = 73728;             // tiles (55296) + softmax staging

// attn_s smem: A 128x144 + B 256x144
constexpr int SMB_S = TBYTES;
constexpr int SM_S_TOTAL = TBYTES + 256 * TROW;   // 55296
// attn_pv smem: A 128x144 + B 64x144
constexpr int SMB_PV = TBYTES;
constexpr int SM_PV_TOTAL = TBYTES + 64 * TROW;   // 27648
}

__device__ float g_mem[TOTF];
__device__ __half h_mem[TOTH];

// ---------------------------------------------------------------------------
__device__ __forceinline__ uint32_t smem_u32(const void* p) {
    uint32_t a;
    asm("{ .reg .u64 t; cvta.to.shared.u64 t, %1; cvt.u32.u64 %0, t; }"
        : "=r"(a) : "l"(p));
    return a;
}
__device__ __forceinline__ uint32_t pack_h2(float a, float b) {
    __half2 h = __floats2half2_rn(a, b);
    return *(uint32_t*)&h;
}
__device__ __forceinline__ void split_pair(float a, float b,
                                           uint32_t& hi, uint32_t& lo) {
    __half ah = __float2half_rn(a), bh = __float2half_rn(b);
    __half al = __float2half_rn(a - __half2float(ah));
    __half bl = __float2half_rn(b - __half2float(bh));
    hi = (uint32_t)*(uint16_t*)&ah | ((uint32_t)*(uint16_t*)&bh << 16);
    lo = (uint32_t)*(uint16_t*)&al | ((uint32_t)*(uint16_t*)&bl << 16);
}
__device__ __forceinline__ void mma16816(float* d, const uint32_t* a,
                                         uint32_t b0, uint32_t b1) {
    asm volatile(
        "mma.sync.aligned.m16n8k16.row.col.f32.f16.f16.f32 "
        "{%0,%1,%2,%3}, {%4,%5,%6,%7}, {%8,%9}, {%0,%1,%2,%3};"
        : "+f"(d[0]), "+f"(d[1]), "+f"(d[2]), "+f"(d[3])
        : "r"(a[0]), "r"(a[1]), "r"(a[2]), "r"(a[3]), "r"(b0), "r"(b1));
}
__device__ __forceinline__ void ldsm4(uint32_t& r0, uint32_t& r1,
                                      uint32_t& r2, uint32_t& r3, uint32_t addr) {
    asm volatile("ldmatrix.sync.aligned.m8n8.x4.shared.b16 {%0,%1,%2,%3}, [%4];"
                 : "=r"(r0), "=r"(r1), "=r"(r2), "=r"(r3) : "r"(addr));
}
__device__ __forceinline__ void cpa16(uint32_t dst, const void* src) {
    asm volatile("cp.async.cg.shared.global [%0], [%1], 16;"
                 :: "r"(dst), "l"(src));
}
__device__ __forceinline__ void cpa_wait() {
    asm volatile("cp.async.commit_group;\ncp.async.wait_group 0;" ::: "memory");
}
__device__ __forceinline__ float dot8h(uint4 a, uint4 b) {
    const __half2* pa = (const __half2*)&a;
    const __half2* pb = (const __half2*)&b;
    float s = 0.0f;
#pragma unroll
    for (int i = 0; i < 4; i++) {
        float2 fa = __half22float2(pa[i]);
        float2 fb = __half22float2(pb[i]);
        s += fa.x * fb.x + fa.y * fb.y;
    }
    return s;
}

// ---------------------------------------------------------------------------
struct FragCtx {
    uint32_t aoff[2];
    uint32_t boff[4];
};
__device__ __forceinline__ FragCtx make_frag_ctx(int lane, int wm, int wn) {
    FragCtx fc;
    const int rA = (lane & 7) + ((lane >> 3) & 1) * 8;
    const int cA = (lane >> 4) * 16;
#pragma unroll
    for (int mt = 0; mt < 2; mt++)
        fc.aoff[mt] = (uint32_t)((wm * 32 + mt * 16 + rA) * TROW + cA);
    const int rB = (lane & 7) + ((lane >> 4) & 1) * 8;
    const int cB = ((lane >> 3) & 1) * 16;
#pragma unroll
    for (int np = 0; np < 4; np++)
        fc.boff[np] = (uint32_t)((wn * 64 + np * 16 + rB) * TROW + cB);
    return fc;
}
// one 64-col K chunk staged in smem: C += A·Bh + A·Bl
__device__ __forceinline__ void mainloop_chunk(uint32_t smb, const FragCtx& fc,
                                               float acc[2][8][4]) {
#pragma unroll
    for (int kc = 0; kc < 4; kc++) {
        const uint32_t kb = (uint32_t)kc * 32;
        uint32_t ah[2][4];
#pragma unroll
        for (int mt = 0; mt < 2; mt++)
            ldsm4(ah[mt][0], ah[mt][1], ah[mt][2], ah[mt][3],
                  smb + SM_A + fc.aoff[mt] + kb);
#pragma unroll
        for (int np = 0; np < 4; np++) {
            uint32_t bh0, bh1, bh2, bh3, bl0, bl1, bl2, bl3;
            ldsm4(bh0, bh1, bh2, bh3, smb + SM_BH + fc.boff[np] + kb);
            ldsm4(bl0, bl1, bl2, bl3, smb + SM_BL + fc.boff[np] + kb);
#pragma unroll
            for (int mt = 0; mt < 2; mt++) {
                mma16816(acc[mt][np * 2],     ah[mt], bh0, bh1);
                mma16816(acc[mt][np * 2],     ah[mt], bl0, bl1);
                mma16816(acc[mt][np * 2 + 1], ah[mt], bh2, bh3);
                mma16816(acc[mt][np * 2 + 1], ah[mt], bl2, bl3);
            }
        }
    }
}

// ---------------------------------------------------------------------------
// GEMM v3: A fp16 single, B fp16 hi/lo. Y = epi(A @ B^T + bias? + resid?)
// epi 0: none, 1: GELU, 2: row-softmax then *postmul.
// ---------------------------------------------------------------------------
__global__ __launch_bounds__(256, 2) void gemm3(
    const __half* __restrict__ A,
    const __half* __restrict__ Bh, const __half* __restrict__ Bl,
    const float* __restrict__ bias, const float* __restrict__ resid,
    const float* __restrict__ postmul,
    float* __restrict__ Yf, __half* __restrict__ Yh, int epi)
{
    extern __shared__ char sm[];
    const uint32_t smb = smem_u32(sm);
    const int tid = threadIdx.x;
    const int lane = tid & 31, wid = tid >> 5;
    const int t4 = lane & 3, r8 = lane >> 2;
    const int wm = wid >> 1, wn = wid & 1;
    const int bm = blockIdx.x * 128;
    const FragCtx fc = make_frag_ctx(lane, wm, wn);

    float acc[2][8][4];
#pragma unroll
    for (int mt = 0; mt < 2; mt++)
#pragma unroll
        for (int nt = 0; nt < 8; nt++)
#pragma unroll
            for (int e = 0; e < 4; e++) acc[mt][nt][e] = 0.0f;

    const int pr = tid >> 1, hf = tid & 1;

    for (int ch = 0; ch < 2; ch++) {
        const size_t arow = (size_t)(bm + pr) * kC + ch * 64 + hf * 32;
        const size_t brow = (size_t)pr * kC + ch * 64 + hf * 32;
        const uint32_t so = (uint32_t)(pr * TROW + hf * 64);
#pragma unroll
        for (int gq = 0; gq < 4; gq++) {
            cpa16(smb + SM_A  + so + gq * 16, A  + arow + gq * 8);
            cpa16(smb + SM_BH + so + gq * 16, Bh + brow + gq * 8);
            cpa16(smb + SM_BL + so + gq * 16, Bl + brow + gq * 8);
        }
        cpa_wait();
        __syncthreads();
        mainloop_chunk(smb, fc, acc);
        __syncthreads();
    }

    if (epi != 2) {
#pragma unroll
        for (int mt = 0; mt < 2; mt++)
#pragma unroll
            for (int p = 0; p < 2; p++) {
                const int r = bm + wm * 32 + mt * 16 + r8 + p * 8;
#pragma unroll
                for (int nt = 0; nt < 8; nt++) {
                    const int c = wn * 64 + nt * 8 + 2 * t4;
                    float v0 = acc[mt][nt][2 * p];
                    float v1 = acc[mt][nt][2 * p + 1];
                    if (bias) {
                        float2 bv = *(const float2*)(bias + c);
                        v0 += bv.x; v1 += bv.y;
                    }
                    if (resid) {
                        float2 rv = *(const float2*)(resid + (size_t)r * kC + c);
                        v0 += rv.x; v1 += rv.y;
                    }
                    if (epi == 1) {
                        v0 = 0.5f * v0 * (1.0f + erff(v0 * 0.70710678118654752f));
                        v1 = 0.5f * v1 * (1.0f + erff(v1 * 0.70710678118654752f));
                    }
                    if (Yf)
                        *(float2*)(Yf + (size_t)r * kC + c) = make_float2(v0, v1);
                    if (Yh)
                        *(uint32_t*)(Yh + (size_t)r * kC + c) = pack_h2(v0, v1);
                }
            }
    } else {
        float* Csm = (float*)sm;
#pragma unroll
        for (int mt = 0; mt < 2; mt++)
#pragma unroll
            for (int p = 0; p < 2; p++) {
                const int lr = wm * 32 + mt * 16 + r8 + p * 8;
#pragma unroll
                for (int nt = 0; nt < 8; nt++) {
                    const int c = wn * 64 + nt * 8 + 2 * t4;
                    float v0 = acc[mt][nt][2 * p];
                    float v1 = acc[mt][nt][2 * p + 1];
                    if (bias) {
                        float2 bv = *(const float2*)(bias + c);
                        v0 += bv.x; v1 += bv.y;
                    }
                    Csm[(size_t)lr * 133 + c]     = v0;
                    Csm[(size_t)lr * 133 + c + 1] = v1;
                }
            }
        __syncthreads();
        if (tid < 128) {
            float* rp = Csm + (size_t)tid * 133;
            float mx = rp[0];
#pragma unroll 4
            for (int c = 1; c < 128; c++) mx = fmaxf(mx, rp[c]);
            float s = 0.0f;
#pragma unroll 4
            for (int c = 0; c < 128; c++) { rp[c] = __expf(rp[c] - mx); s += rp[c]; }
            const float inv = 1.0f / s;
#pragma unroll 4
            for (int c = 0; c < 128; c++) rp[c] *= inv;
        }
        __syncthreads();
        for (int idx = tid; idx < 128 * 64; idx += 256) {
            const int lr = idx >> 6, c = (idx & 63) * 2;
            const size_t go = (size_t)(bm + lr) * kC + c;
            float v0 = Csm[(size_t)lr * 133 + c]     * postmul[go];
            float v1 = Csm[(size_t)lr * 133 + c + 1] * postmul[go + 1];
            *(uint32_t*)(Yh + go) = pack_h2(v0, v1);
        }
    }
}

// ---------------------------------------------------------------------------
// Conv via mma: grid (8, 64), one kernel position per block.
// ---------------------------------------------------------------------------
__global__ __launch_bounds__(256, 2) void conv_mma(
    const __half* __restrict__ xh,
    const __half* __restrict__ cwh, const __half* __restrict__ cwl,
    float* __restrict__ part)
{
    extern __shared__ char sm[];
    const uint32_t smb = smem_u32(sm);
    const int tid = threadIdx.x;
    const int lane = tid & 31, wid = tid >> 5;
    const int t4 = lane & 3, r8 = lane >> 2;
    const int wm = wid >> 1, wn = wid & 1;
    const int b = blockIdx.x >> 1, rt = blockIdx.x & 1, pos = blockIdx.y;
    const FragCtx fc = make_frag_ctx(lane, wm, wn);

    float acc[2][8][4];
#pragma unroll
    for (int mt = 0; mt < 2; mt++)
#pragma unroll
        for (int nt = 0; nt < 8; nt++)
#pragma unroll
            for (int e = 0; e < 4; e++) acc[mt][nt][e] = 0.0f;

    const int pr = tid >> 1, hf = tid & 1;
    const int p = rt * 128 + pr;
    const int ph = p >> 4, pwd = p & 15;
    const int kh = pos >> 3, kw = pos & 7;
    const size_t xrow = ((size_t)b * kN + (ph * 8 + kh) * 128 + pwd * 8 + kw) * kC;
    const size_t wbase = (size_t)pos * 16384 + (size_t)pr * kC;

    for (int ch = 0; ch < 2; ch++) {
        const size_t arow = xrow + ch * 64 + hf * 32;
        const size_t brow = wbase + ch * 64 + hf * 32;
        const uint32_t so = (uint32_t)(pr * TROW + hf * 64);
#pragma unroll
        for (int gq = 0; gq < 4; gq++) {
            cpa16(smb + SM_A  + so + gq * 16, xh  + arow + gq * 8);
            cpa16(smb + SM_BH + so + gq * 16, cwh + brow + gq * 8);
            cpa16(smb + SM_BL + so + gq * 16, cwl + brow + gq * 8);
        }
        cpa_wait();
        __syncthreads();
        mainloop_chunk(smb, fc, acc);
        __syncthreads();
    }

    const size_t base = ((size_t)pos * kMR + (size_t)b * 256 + rt * 128) * kC;
#pragma unroll
    for (int mt = 0; mt < 2; mt++)
#pragma unroll
        for (int pq = 0; pq < 2; pq++) {
            const int lr = wm * 32 + mt * 16 + r8 + pq * 8;
#pragma unroll
            for (int nt = 0; nt < 8; nt++) {
                const int c = wn * 64 + nt * 8 + 2 * t4;
                *(float2*)(part + base + (size_t)lr * kC + c) =
                    make_float2(acc[mt][nt][2 * pq], acc[mt][nt][2 * pq + 1]);
            }
        }
}

// ---------------------------------------------------------------------------
__global__ void conv_reduce_ln(const float* __restrict__ part,
                               const float* __restrict__ srb,
                               const float* __restrict__ gam,
                               const float* __restrict__ bet,
                               __half* __restrict__ xlnh)
{
    const int row = blockIdx.x;
    const int c = threadIdx.x;
    float v = srb[c];
#pragma unroll 8
    for (int sp = 0; sp < 64; sp++)
        v += part[((size_t)sp * kMR + row) * kC + c];

    __shared__ float red[4];
    float s = v;
#pragma unroll
    for (int o = 16; o > 0; o >>= 1) s += __shfl_xor_sync(FULLMASK, s, o);
    if ((c & 31) == 0) red[c >> 5] = s;
    __syncthreads();
    const float mean = (red[0] + red[1] + red[2] + red[3]) * (1.0f / 128.0f);
    __syncthreads();
    const float d = v - mean;
    float s2 = d * d;
#pragma unroll
    for (int o = 16; o > 0; o >>= 1) s2 += __shfl_xor_sync(FULLMASK, s2, o);
    if ((c & 31) == 0) red[c >> 5] = s2;
    __syncthreads();
    const float var = (red[0] + red[1] + red[2] + red[3]) * (1.0f / 128.0f);
    xlnh[(size_t)row * kC + c] =
        __float2half_rn(d * rsqrtf(var + 1e-5f) * gam[c] + bet[c]);
}

// ---------------------------------------------------------------------------
// kv_pack: KB/VB fp32 [b*256+m][128] -> Kh [bh][256][64], Vt [bh][64][256]
// ---------------------------------------------------------------------------
__global__ void kv_pack(const float* __restrict__ KB, const float* __restrict__ VB,
                        __half* __restrict__ Kh, __half* __restrict__ Vt)
{
    const int idx = blockIdx.x * 256 + threadIdx.x;   // 131072
    const int b = idx >> 15, rem = idx & 32767;
    const int m = rem >> 7, c = rem & 127;
    const int h = c >> 6, d = c & 63;
    const int bh = b * 2 + h;
    Kh[((size_t)bh * 256 + m) * 64 + d] = __float2half_rn(KB[idx]);
    Vt[((size_t)bh * 64 + d) * 256 + m] = __float2half_rn(VB[idx]);
}

// ---------------------------------------------------------------------------
// attn_s: per CTA 128 q-rows x 256 keys, K=64. Warp = 16 rows x 256 cols.
// Fused softmax (t4-group shfl), P written fp16.
// ---------------------------------------------------------------------------
__global__ __launch_bounds__(256, 1) void attn_s(
    const __half* __restrict__ Qh, const __half* __restrict__ Kh,
    __half* __restrict__ P)
{
    extern __shared__ char sm[];
    const uint32_t smb = smem_u32(sm);
    const int tid = threadIdx.x;
    const int lane = tid & 31, wid = tid >> 5;
    const int t4 = lane & 3, r8 = lane >> 2;
    const int bh = blockIdx.y;
    const int b = bh >> 1, h = bh & 1;
    const int qt = blockIdx.x;

    const int rA = (lane & 7) + ((lane >> 3) & 1) * 8;
    const int cA = (lane >> 4) * 16;
    const uint32_t aoff = (uint32_t)((wid * 16 + rA) * TROW + cA);
    const int rB = (lane & 7) + ((lane >> 4) & 1) * 8;
    const int cB = ((lane >> 3) & 1) * 16;
    const uint32_t boffb = (uint32_t)(rB * TROW + cB);

    // loads: A = Q tile (128x64 at head offset), B = K (256 rows x 64 halves:
    // one thread per row -> 8 x 16B = full 128-byte row)
    {
        const int pr = tid >> 1, hf = tid & 1;
        const __half* qsrc = Qh +
            ((size_t)(b * kN + qt * 128 + pr) * kC + h * 64 + hf * 32);
        const uint32_t so = (uint32_t)(pr * TROW + hf * 64);
#pragma unroll
        for (int gq = 0; gq < 4; gq++)
            cpa16(smb + so + gq * 16, qsrc + gq * 8);
        const __half* ksrc = Kh + ((size_t)bh * 256 + tid) * 64;
        const uint32_t sob = (uint32_t)(tid * TROW);
#pragma unroll
        for (int gq = 0; gq < 8; gq++)
            cpa16(smb + SMB_S + sob + gq * 16, ksrc + gq * 8);
    }
    cpa_wait();
    __syncthreads();

    float acc[32][4];
#pragma unroll
    for (int nt = 0; nt < 32; nt++)
#pragma unroll
        for (int e = 0; e < 4; e++) acc[nt][e] = 0.0f;

#pragma unroll
    for (int kc = 0; kc < 4; kc++) {
        uint32_t af[4];
        ldsm4(af[0], af[1], af[2], af[3], smb + aoff + kc * 32);
#pragma unroll
        for (int np = 0; np < 16; np++) {
            uint32_t b0, b1, b2, b3;
            ldsm4(b0, b1, b2, b3, smb + SMB_S + boffb + np * (16 * TROW) + kc * 32);
            mma16816(acc[np * 2],     af, b0, b1);
            mma16816(acc[np * 2 + 1], af, b2, b3);
        }
    }

    // softmax rows: row0 = wid*16 + r8 (elems 0,1), row1 = row0+8 (elems 2,3)
    float mx0 = -1e30f, mx1 = -1e30f;
#pragma unroll
    for (int nt = 0; nt < 32; nt++) {
#pragma unroll
        for (int e = 0; e < 4; e++) acc[nt][e] *= 0.125f;
        mx0 = fmaxf(mx0, fmaxf(acc[nt][0], acc[nt][1]));
        mx1 = fmaxf(mx1, fmaxf(acc[nt][2], acc[nt][3]));
    }
    mx0 = fmaxf(mx0, __shfl_xor_sync(FULLMASK, mx0, 1));
    mx0 = fmaxf(mx0, __shfl_xor_sync(FULLMASK, mx0, 2));
    mx1 = fmaxf(mx1, __shfl_xor_sync(FULLMASK, mx1, 1));
    mx1 = fmaxf(mx1, __shfl_xor_sync(FULLMASK, mx1, 2));
    float s0 = 0.0f, s1 = 0.0f;
#pragma unroll
    for (int nt = 0; nt < 32; nt++) {
        acc[nt][0] = __expf(acc[nt][0] - mx0);
        acc[nt][1] = __expf(acc[nt][1] - mx0);
        acc[nt][2] = __expf(acc[nt][2] - mx1);
        acc[nt][3] = __expf(acc[nt][3] - mx1);
        s0 += acc[nt][0] + acc[nt][1];
        s1 += acc[nt][2] + acc[nt][3];
    }
    s0 += __shfl_xor_sync(FULLMASK, s0, 1);
    s0 += __shfl_xor_sync(FULLMASK, s0, 2);
    s1 += __shfl_xor_sync(FULLMASK, s1, 1);
    s1 += __shfl_xor_sync(FULLMASK, s1, 2);
    const float i0 = 1.0f / s0, i1 = 1.0f / s1;

    const size_t p0 = ((size_t)bh * kN + qt * 128 + wid * 16 + r8) * 256;
    const size_t p1 = p0 + 8 * 256;
#pragma unroll
    for (int nt = 0; nt < 32; nt++) {
        const int c = nt * 8 + 2 * t4;
        *(uint32_t*)(P + p0 + c) = pack_h2(acc[nt][0] * i0, acc[nt][1] * i0);
        *(uint32_t*)(P + p1 + c) = pack_h2(acc[nt][2] * i1, acc[nt][3] * i1);
    }
}

// ---------------------------------------------------------------------------
// attn_pv: XA[128 rows x 64 cols] = P(128x256) @ Vt^T, K=256 in 4 chunks.
// ---------------------------------------------------------------------------
__global__ __launch_bounds__(256, 2) void attn_pv(
    const __half* __restrict__ P, const __half* __restrict__ Vt,
    float* __restrict__ XA, __half* __restrict__ XAh)
{
    extern __shared__ char sm[];
    const uint32_t smb = smem_u32(sm);
    const int tid = threadIdx.x;
    const int lane = tid & 31, wid = tid >> 5;
    const int t4 = lane & 3, r8 = lane >> 2;
    const int wm = wid >> 1, wn = wid & 1;
    const int bh = blockIdx.y;
    const int b = bh >> 1, h = bh & 1;
    const int qt = blockIdx.x;

    const int rA = (lane & 7) + ((lane >> 3) & 1) * 8;
    const int cA = (lane >> 4) * 16;
    uint32_t aoff[2];
#pragma unroll
    for (int mt = 0; mt < 2; mt++)
        aoff[mt] = (uint32_t)((wm * 32 + mt * 16 + rA) * TROW + cA);
    const int rB = (lane & 7) + ((lane >> 4) & 1) * 8;
    const int cB = ((lane >> 3) & 1) * 16;
    uint32_t boff[2];
#pragma unroll
    for (int np = 0; np < 2; np++)
        boff[np] = (uint32_t)((wn * 32 + np * 16 + rB) * TROW + cB);

    float acc[2][4][4];
#pragma unroll
    for (int mt = 0; mt < 2; mt++)
#pragma unroll
        for (int nt = 0; nt < 4; nt++)
#pragma unroll
            for (int e = 0; e < 4; e++) acc[mt][nt][e] = 0.0f;

    const int pr = tid >> 1, hf = tid & 1;

    for (int ch = 0; ch < 4; ch++) {
        const __half* asrc = P +
            (((size_t)bh * kN + qt * 128 + pr) * 256 + ch * 64 + hf * 32);
        const uint32_t so = (uint32_t)(pr * TROW + hf * 64);
#pragma unroll
        for (int gq = 0; gq < 4; gq++)
            cpa16(smb + so + gq * 16, asrc + gq * 8);
        if (tid < 128) {
            const int d = tid >> 1, hfb = tid & 1;
            const __half* vsrc = Vt +
                (((size_t)bh * 64 + d) * 256 + ch * 64 + hfb * 32);
            const uint32_t sob = (uint32_t)(d * TROW + hfb * 64);
#pragma unroll
            for (int gq = 0; gq < 4; gq++)
                cpa16(smb + SMB_PV + sob + gq * 16, vsrc + gq * 8);
        }
        cpa_wait();
        __syncthreads();
#pragma unroll
        for (int kc = 0; kc < 4; kc++) {
            const uint32_t kb = (uint32_t)kc * 32;
            uint32_t ah[2][4];
#pragma unroll
            for (int mt = 0; mt < 2; mt++)
                ldsm4(ah[mt][0], ah[mt][1], ah[mt][2], ah[mt][3],
                      smb + aoff[mt] + kb);
#pragma unroll
            for (int np = 0; np < 2; np++) {
                uint32_t b0, b1, b2, b3;
                ldsm4(b0, b1, b2, b3, smb + SMB_PV + boff[np] + kb);
#pragma unroll
                for (int mt = 0; mt < 2; mt++) {
                    mma16816(acc[mt][np * 2],     ah[mt], b0, b1);
                    mma16816(acc[mt][np * 2 + 1], ah[mt], b2, b3);
                }
            }
        }
        __syncthreads();
    }

#pragma unroll
    for (int mt = 0; mt < 2; mt++)
#pragma unroll
        for (int p = 0; p < 2; p++) {
            const int lr = qt * 128 + wm * 32 + mt * 16 + r8 + p * 8;
            const size_t g = ((size_t)b * kN + lr) * kC + h * 64;
#pragma unroll
            for (int nt = 0; nt < 4; nt++) {
                const int c = wn * 32 + nt * 8 + 2 * t4;
                float v0 = acc[mt][nt][2 * p];
                float v1 = acc[mt][nt][2 * p + 1];
                *(float2*)(XA + g + c) = make_float2(v0, v1);
                *(uint32_t*)(XAh + g + c) = pack_h2(v0, v1);
            }
        }
}

// ---------------------------------------------------------------------------
// mha2 pointwise, fp16 inputs.
// ---------------------------------------------------------------------------
__global__ __launch_bounds__(256) void mha2_pw(
    const __half* __restrict__ qp, const __half* __restrict__ k0,
    const __half* __restrict__ k1, const __half* __restrict__ v0,
    const __half* __restrict__ v1, __half* __restrict__ oh)
{
    const int idx = blockIdx.x * 256 + threadIdx.x;
    const size_t base = (size_t)(idx >> 3) * kC + (idx & 7) * 16;
    const uint4* qg  = (const uint4*)(qp + base);
    const uint4* k0g = (const uint4*)(k0 + base);
    const uint4* k1g = (const uint4*)(k1 + base);
    uint4 qa = qg[0], qb = qg[1];
    float s0 = dot8h(qa, k0g[0]) + dot8h(qb, k0g[1]);
    float s1 = dot8h(qa, k1g[0]) + dot8h(qb, k1g[1]);
    s0 *= 0.25f; s1 *= 0.25f;
    const float m = fmaxf(s0, s1);
    float e0 = __expf(s0 - m), e1 = __expf(s1 - m);
    const float inv = 1.0f / (e0 + e1);
    e0 *= inv; e1 *= inv;
    const uint4* v0g = (const uint4*)(v0 + base);
    const uint4* v1g = (const uint4*)(v1 + base);
    uint4* ohg = (uint4*)(oh + base);
#pragma unroll
    for (int t = 0; t < 2; t++) {
        uint4 a = v0g[t], bb = v1g[t];
        const __half2* pa = (const __half2*)&a;
        const __half2* pb = (const __half2*)&bb;
        uint4 o;
        uint32_t* po = (uint32_t*)&o;
#pragma unroll
        for (int i = 0; i < 4; i++) {
            float2 fa = __half22float2(pa[i]);
            float2 fb = __half22float2(pb[i]);
            po[i] = pack_h2(e0 * fa.x + e1 * fb.x, e0 * fa.y + e1 * fb.y);
        }
        ohg[t] = o;
    }
}

// ---------------------------------------------------------------------------
__global__ void cvt_half(const float* __restrict__ src, __half* __restrict__ dst)
{
    const int i = blockIdx.x * 256 + threadIdx.x;
    float4 v = ((const float4*)src)[i];
    ((uint2*)dst)[i] = make_uint2(pack_h2(v.x, v.y), pack_h2(v.z, v.w));
}

__global__ void split_w(const float* __restrict__ src, int ldW,
                        __half* __restrict__ dh, __half* __restrict__ dl)
{
    const int i = blockIdx.x * 256 + threadIdx.x;   // 8192 pairs
    const int o = i >> 6, k = (i & 63) * 2;
    uint32_t h, l;
    split_pair(src[(size_t)o * ldW + k], src[(size_t)o * ldW + k + 1], h, l);
    *(uint32_t*)(dh + o * kC + k) = h;
    *(uint32_t*)(dl + o * kC + k) = l;
}

__global__ void split_convw(const float* __restrict__ srw,
                            __half* __restrict__ dh, __half* __restrict__ dl)
{
    const int t = blockIdx.x * 256 + threadIdx.x;   // 64*8192
    const int pos = t >> 13, o = (t >> 6) & 127, i2 = (t & 63) * 2;
    uint32_t h, l;
    split_pair(srw[(size_t)o * 8192 + i2 * 64 + pos],
               srw[(size_t)o * 8192 + (i2 + 1) * 64 + pos], h, l);
    const size_t d = (size_t)pos * 16384 + (size_t)o * kC + i2;
    *(uint32_t*)(dh + d) = h;
    *(uint32_t*)(dl + d) = l;
}

__global__ void fold_bias(
    const float* __restrict__ w01, const float* __restrict__ b01,
    const float* __restrict__ w10, const float* __restrict__ b10,
    const float* __restrict__ kn, const float* __restrict__ vn,
    float* __restrict__ bm)
{
    const int which = blockIdx.x, c = threadIdx.x;
    const float* W  = (which < 2) ? w01 : w10;
    const float* Bb = (which < 2) ? b01 : b10;
    const float* nz = ((which & 1) ? vn : kn) + (which >> 1) * kC;
    const int off = (which & 1) ? 256 : 128;
    float acc = Bb[off + c];
    const float* wr = W + (size_t)(off + c) * kC;
    for (int k = 0; k < kC; k++) acc += nz[k] * wr[k];
    bm[which * kC + c] = acc;
}

// ---------------------------------------------------------------------------
extern "C" void kernel_launch(void* const* d_in, const int* in_sizes, int n_in,
                              void* d_out, int out_size)
{
    (void)in_sizes; (void)n_in; (void)out_size;
    const float* x0   = (const float*)d_in[0];
    const float* x1   = (const float*)d_in[1];
    const float* Wq   = (const float*)d_in[2];
    const float* bq   = (const float*)d_in[3];
    const float* Wkv  = (const float*)d_in[4];
    const float* bkv  = (const float*)d_in[5];
    const float* srw  = (const float*)d_in[6];
    const float* srb  = (const float*)d_in[7];
    const float* lnG[2] = {(const float*)d_in[8],  (const float*)d_in[10]};
    const float* lnB[2] = {(const float*)d_in[9],  (const float*)d_in[11]};
    const float* cawI[2] = {(const float*)d_in[12], (const float*)d_in[16]};
    const float* cabI[2] = {(const float*)d_in[13], (const float*)d_in[17]};
    const float* cawO[2] = {(const float*)d_in[14], (const float*)d_in[18]};
    const float* cabO[2] = {(const float*)d_in[15], (const float*)d_in[19]};
    const float* rjw1 = (const float*)d_in[20];
    const float* rjb1 = (const float*)d_in[21];
    const float* rjw2 = (const float*)d_in[22];
    const float* rjb2 = (const float*)d_in[23];
    const float* kn   = (const float*)d_in[24];
    const float* vn   = (const float*)d_in[25];
    const float* pw   = (const float*)d_in[26];
    const float* pb   = (const float*)d_in[27];
    float* out = (float*)d_out;

    float* g = nullptr;
    cudaGetSymbolAddress((void**)&g, g_mem);
    __half* hm = nullptr;
    cudaGetSymbolAddress((void**)&hm, h_mem);

    float* XA[2] = {g + O_XA0, g + O_XA1};
    float* T0 = g + O_T0;
    float *PART = g + O_PART, *KB = g + O_KB, *VB = g + O_VB, *BM = g + O_BM;

    __half *XH[2]  = {hm + H_X0, hm + H_X1};
    __half *XAH[2] = {hm + H_XA0, hm + H_XA1};
    __half *T1H = hm + H_T1, *XASH = hm + H_XAS;
    __half *T5H = hm + H_T5, *NSH = hm + H_NS;
    __half *XLNH = hm + H_XLN;
    __half *WSH = hm + H_WS, *WSL = hm + L_WS;
    __half *CWH = hm + H_CW, *CWL = hm + L_CW;
    __half *QH = hm + H_QH, *PB = hm + H_P;
    __half *KH = hm + H_KH, *VT = hm + H_VT;
    __half *PT0 = hm + H_PT0, *PT1 = hm + H_PT1, *PT2 = hm + H_PT2;
    __half *PT3 = hm + H_PT3, *PT4 = hm + H_PT4;

    cudaFuncSetAttribute(gemm3, cudaFuncAttributeMaxDynamicSharedMemorySize, SM_TOTAL);
    cudaFuncSetAttribute(conv_mma, cudaFuncAttributeMaxDynamicSharedMemorySize, SM_TOTAL);
    cudaFuncSetAttribute(attn_s, cudaFuncAttributeMaxDynamicSharedMemorySize, SM_S_TOTAL);
    cudaFuncSetAttribute(attn_pv, cudaFuncAttributeMaxDynamicSharedMemorySize, SM_PV_TOTAL);

    // --- one-time prep ---
    fold_bias<<<4, 128>>>(cawI[0], cabI[0], cawI[1], cabI[1], kn, vn, BM);
    cvt_half<<<8192, 256>>>(x0, XH[0]);
    cvt_half<<<8192, 256>>>(x1, XH[1]);
    split_convw<<<2048, 256>>>(srw, CWH, CWL);
#define SW(SRC, LD, IDX) \
    split_w<<<32, 256>>>(SRC, LD, WSH + (IDX) * 16384, WSL + (IDX) * 16384)
    SW(Wq, 128, 0);
    SW(Wkv, 128, 1);          SW(Wkv + 16384, 128, 2);
    SW(rjw1, 256, 3);         SW(rjw1 + 128, 256, 4);
    SW(rjw2, 128, 5);
    SW(cawI[0], 128, 6);      SW(cawI[0] + 16384, 128, 7);  SW(cawI[0] + 32768, 128, 8);
    SW(cawI[1], 128, 9);      SW(cawI[1] + 16384, 128, 10); SW(cawI[1] + 32768, 128, 11);
    SW(cawO[0], 128, 12);     SW(cawO[1], 128, 13);
    SW(pw, 128, 14);
#undef SW

    const int GM = kMTOK / 128;
#define WB(i) (WSH + (i) * 16384), (WSL + (i) * 16384)
#define G3(GRID, AH, WI, BIAS, RESID, PMUL, YF, YH, EPI) \
    gemm3<<<GRID, 256, SM_TOTAL>>>(AH, WB(WI), BIAS, RESID, PMUL, YF, YH, EPI)

    // --- Stage A: SR attention per stream (tensor-core path) ---
    for (int s = 0; s < 2; s++) {
        G3(GM, XH[s], 0, bq, nullptr, nullptr, nullptr, QH, 0);          // q fp16
        conv_mma<<<dim3(8, 64), 256, SM_TOTAL>>>(XH[s], CWH, CWL, PART);
        conv_reduce_ln<<<1024, 128>>>(PART, srb, lnG[s], lnB[s], XLNH);
        G3(8, XLNH, 1, bkv,       nullptr, nullptr, KB, nullptr, 0);
        G3(8, XLNH, 2, bkv + 128, nullptr, nullptr, VB, nullptr, 0);
        kv_pack<<<512, 256>>>(KB, VB, KH, VT);
        attn_s<<<dim3(128, 8), 256, SM_S_TOTAL>>>(QH, KH, PB);
        attn_pv<<<dim3(128, 8), 256, SM_PV_TOTAL>>>(PB, VT, XA[s], XAH[s]);
    }

    // --- Stage B + C per stream ---
    for (int s = 0; s < 2; s++) {
        G3(GM, XAH[s],     3, nullptr, nullptr, nullptr, T0, nullptr, 0);
        G3(GM, XAH[s ^ 1], 4, rjb1,    T0,      nullptr, nullptr, T1H, 1);
        G3(GM, T1H,        5, rjb2,    nullptr, XA[s],   nullptr, XASH, 2);
        const float* Bb = cabI[s];
        float* bmk = BM + (2 * s) * kC;
        float* bmv = BM + (2 * s + 1) * kC;
        G3(GM, XAH[s],     6 + 3 * s, Bb,       nullptr, nullptr, nullptr, PT0, 0);
        G3(GM, XAH[s],     7 + 3 * s, bmk,      nullptr, nullptr, nullptr, PT1, 0);
        G3(GM, XASH,       7 + 3 * s, Bb + 128, nullptr, nullptr, nullptr, PT2, 0);
        G3(GM, XAH[s],     8 + 3 * s, bmv,      nullptr, nullptr, nullptr, PT3, 0);
        G3(GM, XAH[s ^ 1], 8 + 3 * s, Bb + 256, nullptr, nullptr, nullptr, PT4, 0);
        mha2_pw<<<2048, 256>>>(PT0, PT1, PT2, PT3, PT4, T5H);
        G3(GM, T5H, 12 + s, cabO[s], XA[s], nullptr, nullptr, NSH, 0);
        G3(GM, NSH, 14,     pb,      nullptr, nullptr, out + (size_t)s * SZ, nullptr, 0);
    }
#undef G3
#undef WB
}

// round 11
// speedup vs baseline: 2.9774x; 1.2025x over previous
#include <cuda_runtime.h>
#include <cuda_fp16.h>
#include <math.h>
#include <stdint.h>

#define FULLMASK 0xffffffffu

namespace {
constexpr int kB = 4, kN = 16384, kC = 128, kMTOK = 65536, kMR = 1024;
constexpr size_t SZ = (size_t)kMTOK * kC;   // 8,388,608

// fp32 scratch
constexpr size_t O_XA0 = 0;
constexpr size_t O_XA1 = SZ;
constexpr size_t O_T0  = 2 * SZ;
constexpr size_t O_PART = 3 * SZ;           // 64*1024*128 == SZ
constexpr size_t O_KB  = 4 * SZ;
constexpr size_t O_VB  = O_KB + 131072;
constexpr size_t O_BM  = O_VB + 131072;
constexpr size_t TOTF  = O_BM + 512;

// fp16 buffers (element offsets in h_mem)
constexpr size_t H_X0  = 0;
constexpr size_t H_X1  = SZ;
constexpr size_t H_XA0 = 2 * SZ;
constexpr size_t H_XA1 = 3 * SZ;
constexpr size_t H_T1  = 4 * SZ;            // judger hidden
constexpr size_t H_XAS = 5 * SZ;
constexpr size_t H_T5  = 6 * SZ;
constexpr size_t H_NS  = 7 * SZ;
constexpr size_t H_XLN = 8 * SZ;                     // 131072
constexpr size_t H_WS  = H_XLN + 131072;             // 15 weight blocks (fp16)
constexpr size_t H_CW  = H_WS + 15 * 16384;          // 64 conv blocks (fp16)
constexpr size_t H_QH  = H_CW + 64 * 16384;          // q fp16 (one stream)
constexpr size_t H_P   = H_QH + SZ;                  // P [8][16384][256] = 4*SZ
constexpr size_t H_KH  = H_P + 4 * SZ;               // K fp16 [8][256][64]
constexpr size_t H_VT  = H_KH + 131072;              // V^T fp16 [8][64][256]
constexpr size_t H_PT0 = H_VT + 131072;              // stage-C fp16 temps
constexpr size_t H_PT1 = H_PT0 + SZ;
constexpr size_t H_PT2 = H_PT1 + SZ;
constexpr size_t H_PT3 = H_PT2 + SZ;
constexpr size_t H_PT4 = H_PT3 + SZ;
constexpr size_t TOTH  = H_PT4 + SZ;

// gemm smem: 2 fp16 tiles [128][72] (row stride 144 B), one 64-col K chunk
constexpr int TROW   = 144;
constexpr int TBYTES = 128 * TROW;          // 18432
constexpr int SM_A  = 0;
constexpr int SM_B  = TBYTES;
constexpr int SM_G_SMALL = 2 * TBYTES;      // 36864 (epi 0/1)
constexpr int SM_G_BIG   = 69632;           // epi 2 (softmax staging 68096)

// attn_s smem: A 128x144 + B 256x144
constexpr int SMB_S = TBYTES;
constexpr int SM_S_TOTAL = TBYTES + 256 * TROW;   // 55296
// attn_pv smem: A 128x144 + B 64x144
constexpr int SMB_PV = TBYTES;
constexpr int SM_PV_TOTAL = TBYTES + 64 * TROW;   // 27648
}

__device__ float g_mem[TOTF];
__device__ __half h_mem[TOTH];

// ---------------------------------------------------------------------------
__device__ __forceinline__ uint32_t smem_u32(const void* p) {
    uint32_t a;
    asm("{ .reg .u64 t; cvta.to.shared.u64 t, %1; cvt.u32.u64 %0, t; }"
        : "=r"(a) : "l"(p));
    return a;
}
__device__ __forceinline__ uint32_t pack_h2(float a, float b) {
    __half2 h = __floats2half2_rn(a, b);
    return *(uint32_t*)&h;
}
__device__ __forceinline__ void mma16816(float* d, const uint32_t* a,
                                         uint32_t b0, uint32_t b1) {
    asm volatile(
        "mma.sync.aligned.m16n8k16.row.col.f32.f16.f16.f32 "
        "{%0,%1,%2,%3}, {%4,%5,%6,%7}, {%8,%9}, {%0,%1,%2,%3};"
        : "+f"(d[0]), "+f"(d[1]), "+f"(d[2]), "+f"(d[3])
        : "r"(a[0]), "r"(a[1]), "r"(a[2]), "r"(a[3]), "r"(b0), "r"(b1));
}
__device__ __forceinline__ void ldsm4(uint32_t& r0, uint32_t& r1,
                                      uint32_t& r2, uint32_t& r3, uint32_t addr) {
    asm volatile("ldmatrix.sync.aligned.m8n8.x4.shared.b16 {%0,%1,%2,%3}, [%4];"
                 : "=r"(r0), "=r"(r1), "=r"(r2), "=r"(r3) : "r"(addr));
}
__device__ __forceinline__ void cpa16(uint32_t dst, const void* src) {
    asm volatile("cp.async.cg.shared.global [%0], [%1], 16;"
                 :: "r"(dst), "l"(src));
}
__device__ __forceinline__ void cpa_wait() {
    asm volatile("cp.async.commit_group;\ncp.async.wait_group 0;" ::: "memory");
}
__device__ __forceinline__ float dot8h(uint4 a, uint4 b) {
    const __half2* pa = (const __half2*)&a;
    const __half2* pb = (const __half2*)&b;
    float s = 0.0f;
#pragma unroll
    for (int i = 0; i < 4; i++) {
        float2 fa = __half22float2(pa[i]);
        float2 fb = __half22float2(pb[i]);
        s += fa.x * fb.x + fa.y * fb.y;
    }
    return s;
}

// ---------------------------------------------------------------------------
struct FragCtx {
    uint32_t aoff[2];
    uint32_t boff[4];
};
__device__ __forceinline__ FragCtx make_frag_ctx(int lane, int wm, int wn) {
    FragCtx fc;
    const int rA = (lane & 7) + ((lane >> 3) & 1) * 8;
    const int cA = (lane >> 4) * 16;
#pragma unroll
    for (int mt = 0; mt < 2; mt++)
        fc.aoff[mt] = (uint32_t)((wm * 32 + mt * 16 + rA) * TROW + cA);
    const int rB = (lane & 7) + ((lane >> 4) & 1) * 8;
    const int cB = ((lane >> 3) & 1) * 16;
#pragma unroll
    for (int np = 0; np < 4; np++)
        fc.boff[np] = (uint32_t)((wn * 64 + np * 16 + rB) * TROW + cB);
    return fc;
}
// one 64-col K chunk staged in smem: C += A·B (single fp16 term)
__device__ __forceinline__ void mainloop_chunk(uint32_t smb, const FragCtx& fc,
                                               float acc[2][8][4]) {
#pragma unroll
    for (int kc = 0; kc < 4; kc++) {
        const uint32_t kb = (uint32_t)kc * 32;
        uint32_t ah[2][4];
#pragma unroll
        for (int mt = 0; mt < 2; mt++)
            ldsm4(ah[mt][0], ah[mt][1], ah[mt][2], ah[mt][3],
                  smb + SM_A + fc.aoff[mt] + kb);
#pragma unroll
        for (int np = 0; np < 4; np++) {
            uint32_t b0, b1, b2, b3;
            ldsm4(b0, b1, b2, b3, smb + SM_B + fc.boff[np] + kb);
#pragma unroll
            for (int mt = 0; mt < 2; mt++) {
                mma16816(acc[mt][np * 2],     ah[mt], b0, b1);
                mma16816(acc[mt][np * 2 + 1], ah[mt], b2, b3);
            }
        }
    }
}

// ---------------------------------------------------------------------------
// GEMM v4: A fp16, B fp16 (single term). Y = epi(A @ B^T + bias? + resid?)
// epi 0: none, 1: GELU, 2: row-softmax then *postmul (needs SM_G_BIG smem).
// ---------------------------------------------------------------------------
__global__ __launch_bounds__(256, 2) void gemm4(
    const __half* __restrict__ A, const __half* __restrict__ Bw,
    const float* __restrict__ bias, const float* __restrict__ resid,
    const float* __restrict__ postmul,
    float* __restrict__ Yf, __half* __restrict__ Yh, int epi)
{
    extern __shared__ char sm[];
    const uint32_t smb = smem_u32(sm);
    const int tid = threadIdx.x;
    const int lane = tid & 31, wid = tid >> 5;
    const int t4 = lane & 3, r8 = lane >> 2;
    const int wm = wid >> 1, wn = wid & 1;
    const int bm = blockIdx.x * 128;
    const FragCtx fc = make_frag_ctx(lane, wm, wn);

    float acc[2][8][4];
#pragma unroll
    for (int mt = 0; mt < 2; mt++)
#pragma unroll
        for (int nt = 0; nt < 8; nt++)
#pragma unroll
            for (int e = 0; e < 4; e++) acc[mt][nt][e] = 0.0f;

    const int pr = tid >> 1, hf = tid & 1;

    for (int ch = 0; ch < 2; ch++) {
        const size_t arow = (size_t)(bm + pr) * kC + ch * 64 + hf * 32;
        const size_t brow = (size_t)pr * kC + ch * 64 + hf * 32;
        const uint32_t so = (uint32_t)(pr * TROW + hf * 64);
#pragma unroll
        for (int gq = 0; gq < 4; gq++) {
            cpa16(smb + SM_A + so + gq * 16, A  + arow + gq * 8);
            cpa16(smb + SM_B + so + gq * 16, Bw + brow + gq * 8);
        }
        cpa_wait();
        __syncthreads();
        mainloop_chunk(smb, fc, acc);
        __syncthreads();
    }

    if (epi != 2) {
#pragma unroll
        for (int mt = 0; mt < 2; mt++)
#pragma unroll
            for (int p = 0; p < 2; p++) {
                const int r = bm + wm * 32 + mt * 16 + r8 + p * 8;
#pragma unroll
                for (int nt = 0; nt < 8; nt++) {
                    const int c = wn * 64 + nt * 8 + 2 * t4;
                    float v0 = acc[mt][nt][2 * p];
                    float v1 = acc[mt][nt][2 * p + 1];
                    if (bias) {
                        float2 bv = *(const float2*)(bias + c);
                        v0 += bv.x; v1 += bv.y;
                    }
                    if (resid) {
                        float2 rv = *(const float2*)(resid + (size_t)r * kC + c);
                        v0 += rv.x; v1 += rv.y;
                    }
                    if (epi == 1) {
                        v0 = 0.5f * v0 * (1.0f + erff(v0 * 0.70710678118654752f));
                        v1 = 0.5f * v1 * (1.0f + erff(v1 * 0.70710678118654752f));
                    }
                    if (Yf)
                        *(float2*)(Yf + (size_t)r * kC + c) = make_float2(v0, v1);
                    if (Yh)
                        *(uint32_t*)(Yh + (size_t)r * kC + c) = pack_h2(v0, v1);
                }
            }
    } else {
        float* Csm = (float*)sm;
        __syncthreads();
#pragma unroll
        for (int mt = 0; mt < 2; mt++)
#pragma unroll
            for (int p = 0; p < 2; p++) {
                const int lr = wm * 32 + mt * 16 + r8 + p * 8;
#pragma unroll
                for (int nt = 0; nt < 8; nt++) {
                    const int c = wn * 64 + nt * 8 + 2 * t4;
                    float v0 = acc[mt][nt][2 * p];
                    float v1 = acc[mt][nt][2 * p + 1];
                    if (bias) {
                        float2 bv = *(const float2*)(bias + c);
                        v0 += bv.x; v1 += bv.y;
                    }
                    Csm[(size_t)lr * 133 + c]     = v0;
                    Csm[(size_t)lr * 133 + c + 1] = v1;
                }
            }
        __syncthreads();
        if (tid < 128) {
            float* rp = Csm + (size_t)tid * 133;
            float mx = rp[0];
#pragma unroll 4
            for (int c = 1; c < 128; c++) mx = fmaxf(mx, rp[c]);
            float s = 0.0f;
#pragma unroll 4
            for (int c = 0; c < 128; c++) { rp[c] = __expf(rp[c] - mx); s += rp[c]; }
            const float inv = 1.0f / s;
#pragma unroll 4
            for (int c = 0; c < 128; c++) rp[c] *= inv;
        }
        __syncthreads();
        for (int idx = tid; idx < 128 * 64; idx += 256) {
            const int lr = idx >> 6, c = (idx & 63) * 2;
            const size_t go = (size_t)(bm + lr) * kC + c;
            float v0 = Csm[(size_t)lr * 133 + c]     * postmul[go];
            float v1 = Csm[(size_t)lr * 133 + c + 1] * postmul[go + 1];
            *(uint32_t*)(Yh + go) = pack_h2(v0, v1);
        }
    }
}

// ---------------------------------------------------------------------------
// Conv via mma: grid (8, 64), one kernel position per block, single term.
// ---------------------------------------------------------------------------
__global__ __launch_bounds__(256, 2) void conv_mma(
    const __half* __restrict__ xh, const __half* __restrict__ cwh,
    float* __restrict__ part)
{
    extern __shared__ char sm[];
    const uint32_t smb = smem_u32(sm);
    const int tid = threadIdx.x;
    const int lane = tid & 31, wid = tid >> 5;
    const int t4 = lane & 3, r8 = lane >> 2;
    const int wm = wid >> 1, wn = wid & 1;
    const int b = blockIdx.x >> 1, rt = blockIdx.x & 1, pos = blockIdx.y;
    const FragCtx fc = make_frag_ctx(lane, wm, wn);

    float acc[2][8][4];
#pragma unroll
    for (int mt = 0; mt < 2; mt++)
#pragma unroll
        for (int nt = 0; nt < 8; nt++)
#pragma unroll
            for (int e = 0; e < 4; e++) acc[mt][nt][e] = 0.0f;

    const int pr = tid >> 1, hf = tid & 1;
    const int p = rt * 128 + pr;
    const int ph = p >> 4, pwd = p & 15;
    const int kh = pos >> 3, kw = pos & 7;
    const size_t xrow = ((size_t)b * kN + (ph * 8 + kh) * 128 + pwd * 8 + kw) * kC;
    const size_t wbase = (size_t)pos * 16384 + (size_t)pr * kC;

    for (int ch = 0; ch < 2; ch++) {
        const size_t arow = xrow + ch * 64 + hf * 32;
        const size_t brow = wbase + ch * 64 + hf * 32;
        const uint32_t so = (uint32_t)(pr * TROW + hf * 64);
#pragma unroll
        for (int gq = 0; gq < 4; gq++) {
            cpa16(smb + SM_A + so + gq * 16, xh  + arow + gq * 8);
            cpa16(smb + SM_B + so + gq * 16, cwh + brow + gq * 8);
        }
        cpa_wait();
        __syncthreads();
        mainloop_chunk(smb, fc, acc);
        __syncthreads();
    }

    const size_t base = ((size_t)pos * kMR + (size_t)b * 256 + rt * 128) * kC;
#pragma unroll
    for (int mt = 0; mt < 2; mt++)
#pragma unroll
        for (int pq = 0; pq < 2; pq++) {
            const int lr = wm * 32 + mt * 16 + r8 + pq * 8;
#pragma unroll
            for (int nt = 0; nt < 8; nt++) {
                const int c = wn * 64 + nt * 8 + 2 * t4;
                *(float2*)(part + base + (size_t)lr * kC + c) =
                    make_float2(acc[mt][nt][2 * pq], acc[mt][nt][2 * pq + 1]);
            }
        }
}

// ---------------------------------------------------------------------------
__global__ void conv_reduce_ln(const float* __restrict__ part,
                               const float* __restrict__ srb,
                               const float* __restrict__ gam,
                               const float* __restrict__ bet,
                               __half* __restrict__ xlnh)
{
    const int row = blockIdx.x;
    const int c = threadIdx.x;
    float v = srb[c];
#pragma unroll 8
    for (int sp = 0; sp < 64; sp++)
        v += part[((size_t)sp * kMR + row) * kC + c];

    __shared__ float red[4];
    float s = v;
#pragma unroll
    for (int o = 16; o > 0; o >>= 1) s += __shfl_xor_sync(FULLMASK, s, o);
    if ((c & 31) == 0) red[c >> 5] = s;
    __syncthreads();
    const float mean = (red[0] + red[1] + red[2] + red[3]) * (1.0f / 128.0f);
    __syncthreads();
    const float d = v - mean;
    float s2 = d * d;
#pragma unroll
    for (int o = 16; o > 0; o >>= 1) s2 += __shfl_xor_sync(FULLMASK, s2, o);
    if ((c & 31) == 0) red[c >> 5] = s2;
    __syncthreads();
    const float var = (red[0] + red[1] + red[2] + red[3]) * (1.0f / 128.0f);
    xlnh[(size_t)row * kC + c] =
        __float2half_rn(d * rsqrtf(var + 1e-5f) * gam[c] + bet[c]);
}

// ---------------------------------------------------------------------------
__global__ void kv_pack(const float* __restrict__ KB, const float* __restrict__ VB,
                        __half* __restrict__ Kh, __half* __restrict__ Vt)
{
    const int idx = blockIdx.x * 256 + threadIdx.x;   // 131072
    const int b = idx >> 15, rem = idx & 32767;
    const int m = rem >> 7, c = rem & 127;
    const int h = c >> 6, d = c & 63;
    const int bh = b * 2 + h;
    Kh[((size_t)bh * 256 + m) * 64 + d] = __float2half_rn(KB[idx]);
    Vt[((size_t)bh * 64 + d) * 256 + m] = __float2half_rn(VB[idx]);
}

// ---------------------------------------------------------------------------
// attn_s: per CTA 128 q-rows x 256 keys, K=64; fused softmax; P fp16.
// ---------------------------------------------------------------------------
__global__ __launch_bounds__(256, 1) void attn_s(
    const __half* __restrict__ Qh, const __half* __restrict__ Kh,
    __half* __restrict__ P)
{
    extern __shared__ char sm[];
    const uint32_t smb = smem_u32(sm);
    const int tid = threadIdx.x;
    const int lane = tid & 31, wid = tid >> 5;
    const int t4 = lane & 3, r8 = lane >> 2;
    const int bh = blockIdx.y;
    const int b = bh >> 1, h = bh & 1;
    const int qt = blockIdx.x;

    const int rA = (lane & 7) + ((lane >> 3) & 1) * 8;
    const int cA = (lane >> 4) * 16;
    const uint32_t aoff = (uint32_t)((wid * 16 + rA) * TROW + cA);
    const int rB = (lane & 7) + ((lane >> 4) & 1) * 8;
    const int cB = ((lane >> 3) & 1) * 16;
    const uint32_t boffb = (uint32_t)(rB * TROW + cB);

    {
        const int pr = tid >> 1, hf = tid & 1;
        const __half* qsrc = Qh +
            ((size_t)(b * kN + qt * 128 + pr) * kC + h * 64 + hf * 32);
        const uint32_t so = (uint32_t)(pr * TROW + hf * 64);
#pragma unroll
        for (int gq = 0; gq < 4; gq++)
            cpa16(smb + so + gq * 16, qsrc + gq * 8);
        const __half* ksrc = Kh + ((size_t)bh * 256 + tid) * 64;
        const uint32_t sob = (uint32_t)(tid * TROW);
#pragma unroll
        for (int gq = 0; gq < 8; gq++)
            cpa16(smb + SMB_S + sob + gq * 16, ksrc + gq * 8);
    }
    cpa_wait();
    __syncthreads();

    float acc[32][4];
#pragma unroll
    for (int nt = 0; nt < 32; nt++)
#pragma unroll
        for (int e = 0; e < 4; e++) acc[nt][e] = 0.0f;

#pragma unroll
    for (int kc = 0; kc < 4; kc++) {
        uint32_t af[4];
        ldsm4(af[0], af[1], af[2], af[3], smb + aoff + kc * 32);
#pragma unroll
        for (int np = 0; np < 16; np++) {
            uint32_t b0, b1, b2, b3;
            ldsm4(b0, b1, b2, b3, smb + SMB_S + boffb + np * (16 * TROW) + kc * 32);
            mma16816(acc[np * 2],     af, b0, b1);
            mma16816(acc[np * 2 + 1], af, b2, b3);
        }
    }

    float mx0 = -1e30f, mx1 = -1e30f;
#pragma unroll
    for (int nt = 0; nt < 32; nt++) {
#pragma unroll
        for (int e = 0; e < 4; e++) acc[nt][e] *= 0.125f;
        mx0 = fmaxf(mx0, fmaxf(acc[nt][0], acc[nt][1]));
        mx1 = fmaxf(mx1, fmaxf(acc[nt][2], acc[nt][3]));
    }
    mx0 = fmaxf(mx0, __shfl_xor_sync(FULLMASK, mx0, 1));
    mx0 = fmaxf(mx0, __shfl_xor_sync(FULLMASK, mx0, 2));
    mx1 = fmaxf(mx1, __shfl_xor_sync(FULLMASK, mx1, 1));
    mx1 = fmaxf(mx1, __shfl_xor_sync(FULLMASK, mx1, 2));
    float s0 = 0.0f, s1 = 0.0f;
#pragma unroll
    for (int nt = 0; nt < 32; nt++) {
        acc[nt][0] = __expf(acc[nt][0] - mx0);
        acc[nt][1] = __expf(acc[nt][1] - mx0);
        acc[nt][2] = __expf(acc[nt][2] - mx1);
        acc[nt][3] = __expf(acc[nt][3] - mx1);
        s0 += acc[nt][0] + acc[nt][1];
        s1 += acc[nt][2] + acc[nt][3];
    }
    s0 += __shfl_xor_sync(FULLMASK, s0, 1);
    s0 += __shfl_xor_sync(FULLMASK, s0, 2);
    s1 += __shfl_xor_sync(FULLMASK, s1, 1);
    s1 += __shfl_xor_sync(FULLMASK, s1, 2);
    const float i0 = 1.0f / s0, i1 = 1.0f / s1;

    const size_t p0 = ((size_t)bh * kN + qt * 128 + wid * 16 + r8) * 256;
    const size_t p1 = p0 + 8 * 256;
#pragma unroll
    for (int nt = 0; nt < 32; nt++) {
        const int c = nt * 8 + 2 * t4;
        *(uint32_t*)(P + p0 + c) = pack_h2(acc[nt][0] * i0, acc[nt][1] * i0);
        *(uint32_t*)(P + p1 + c) = pack_h2(acc[nt][2] * i1, acc[nt][3] * i1);
    }
}

// ---------------------------------------------------------------------------
// attn_pv: XA[128 x 64] = P(128x256) @ Vt^T, K=256 in 4 chunks.
// ---------------------------------------------------------------------------
__global__ __launch_bounds__(256, 2) void attn_pv(
    const __half* __restrict__ P, const __half* __restrict__ Vt,
    float* __restrict__ XA, __half* __restrict__ XAh)
{
    extern __shared__ char sm[];
    const uint32_t smb = smem_u32(sm);
    const int tid = threadIdx.x;
    const int lane = tid & 31, wid = tid >> 5;
    const int t4 = lane & 3, r8 = lane >> 2;
    const int wm = wid >> 1, wn = wid & 1;
    const int bh = blockIdx.y;
    const int b = bh >> 1, h = bh & 1;
    const int qt = blockIdx.x;

    const int rA = (lane & 7) + ((lane >> 3) & 1) * 8;
    const int cA = (lane >> 4) * 16;
    uint32_t aoff[2];
#pragma unroll
    for (int mt = 0; mt < 2; mt++)
        aoff[mt] = (uint32_t)((wm * 32 + mt * 16 + rA) * TROW + cA);
    const int rB = (lane & 7) + ((lane >> 4) & 1) * 8;
    const int cB = ((lane >> 3) & 1) * 16;
    uint32_t boff[2];
#pragma unroll
    for (int np = 0; np < 2; np++)
        boff[np] = (uint32_t)((wn * 32 + np * 16 + rB) * TROW + cB);

    float acc[2][4][4];
#pragma unroll
    for (int mt = 0; mt < 2; mt++)
#pragma unroll
        for (int nt = 0; nt < 4; nt++)
#pragma unroll
            for (int e = 0; e < 4; e++) acc[mt][nt][e] = 0.0f;

    const int pr = tid >> 1, hf = tid & 1;

    for (int ch = 0; ch < 4; ch++) {
        const __half* asrc = P +
            (((size_t)bh * kN + qt * 128 + pr) * 256 + ch * 64 + hf * 32);
        const uint32_t so = (uint32_t)(pr * TROW + hf * 64);
#pragma unroll
        for (int gq = 0; gq < 4; gq++)
            cpa16(smb + so + gq * 16, asrc + gq * 8);
        if (tid < 128) {
            const int d = tid >> 1, hfb = tid & 1;
            const __half* vsrc = Vt +
                (((size_t)bh * 64 + d) * 256 + ch * 64 + hfb * 32);
            const uint32_t sob = (uint32_t)(d * TROW + hfb * 64);
#pragma unroll
            for (int gq = 0; gq < 4; gq++)
                cpa16(smb + SMB_PV + sob + gq * 16, vsrc + gq * 8);
        }
        cpa_wait();
        __syncthreads();
#pragma unroll
        for (int kc = 0; kc < 4; kc++) {
            const uint32_t kb = (uint32_t)kc * 32;
            uint32_t ah[2][4];
#pragma unroll
            for (int mt = 0; mt < 2; mt++)
                ldsm4(ah[mt][0], ah[mt][1], ah[mt][2], ah[mt][3],
                      smb + aoff[mt] + kb);
#pragma unroll
            for (int np = 0; np < 2; np++) {
                uint32_t b0, b1, b2, b3;
                ldsm4(b0, b1, b2, b3, smb + SMB_PV + boff[np] + kb);
#pragma unroll
                for (int mt = 0; mt < 2; mt++) {
                    mma16816(acc[mt][np * 2],     ah[mt], b0, b1);
                    mma16816(acc[mt][np * 2 + 1], ah[mt], b2, b3);
                }
            }
        }
        __syncthreads();
    }

#pragma unroll
    for (int mt = 0; mt < 2; mt++)
#pragma unroll
        for (int p = 0; p < 2; p++) {
            const int lr = qt * 128 + wm * 32 + mt * 16 + r8 + p * 8;
            const size_t g = ((size_t)b * kN + lr) * kC + h * 64;
#pragma unroll
            for (int nt = 0; nt < 4; nt++) {
                const int c = wn * 32 + nt * 8 + 2 * t4;
                float v0 = acc[mt][nt][2 * p];
                float v1 = acc[mt][nt][2 * p + 1];
                *(float2*)(XA + g + c) = make_float2(v0, v1);
                *(uint32_t*)(XAh + g + c) = pack_h2(v0, v1);
            }
        }
}

// ---------------------------------------------------------------------------
__global__ __launch_bounds__(256) void mha2_pw(
    const __half* __restrict__ qp, const __half* __restrict__ k0,
    const __half* __restrict__ k1, const __half* __restrict__ v0,
    const __half* __restrict__ v1, __half* __restrict__ oh)
{
    const int idx = blockIdx.x * 256 + threadIdx.x;
    const size_t base = (size_t)(idx >> 3) * kC + (idx & 7) * 16;
    const uint4* qg  = (const uint4*)(qp + base);
    const uint4* k0g = (const uint4*)(k0 + base);
    const uint4* k1g = (const uint4*)(k1 + base);
    uint4 qa = qg[0], qb = qg[1];
    float s0 = dot8h(qa, k0g[0]) + dot8h(qb, k0g[1]);
    float s1 = dot8h(qa, k1g[0]) + dot8h(qb, k1g[1]);
    s0 *= 0.25f; s1 *= 0.25f;
    const float m = fmaxf(s0, s1);
    float e0 = __expf(s0 - m), e1 = __expf(s1 - m);
    const float inv = 1.0f / (e0 + e1);
    e0 *= inv; e1 *= inv;
    const uint4* v0g = (const uint4*)(v0 + base);
    const uint4* v1g = (const uint4*)(v1 + base);
    uint4* ohg = (uint4*)(oh + base);
#pragma unroll
    for (int t = 0; t < 2; t++) {
        uint4 a = v0g[t], bb = v1g[t];
        const __half2* pa = (const __half2*)&a;
        const __half2* pb = (const __half2*)&bb;
        uint4 o;
        uint32_t* po = (uint32_t*)&o;
#pragma unroll
        for (int i = 0; i < 4; i++) {
            float2 fa = __half22float2(pa[i]);
            float2 fb = __half22float2(pb[i]);
            po[i] = pack_h2(e0 * fa.x + e1 * fb.x, e0 * fa.y + e1 * fb.y);
        }
        ohg[t] = o;
    }
}

// ---------------------------------------------------------------------------
__global__ void cvt_half(const float* __restrict__ src, __half* __restrict__ dst)
{
    const int i = blockIdx.x * 256 + threadIdx.x;
    float4 v = ((const float4*)src)[i];
    ((uint2*)dst)[i] = make_uint2(pack_h2(v.x, v.y), pack_h2(v.z, v.w));
}

__global__ void cvt_w(const float* __restrict__ src, int ldW,
                      __half* __restrict__ dh)
{
    const int i = blockIdx.x * 256 + threadIdx.x;   // 8192 pairs
    const int o = i >> 6, k = (i & 63) * 2;
    *(uint32_t*)(dh + o * kC + k) =
        pack_h2(src[(size_t)o * ldW + k], src[(size_t)o * ldW + k + 1]);
}

__global__ void cvt_convw(const float* __restrict__ srw, __half* __restrict__ dh)
{
    const int t = blockIdx.x * 256 + threadIdx.x;   // 64*8192
    const int pos = t >> 13, o = (t >> 6) & 127, i2 = (t & 63) * 2;
    const size_t d = (size_t)pos * 16384 + (size_t)o * kC + i2;
    *(uint32_t*)(dh + d) =
        pack_h2(srw[(size_t)o * 8192 + i2 * 64 + pos],
                srw[(size_t)o * 8192 + (i2 + 1) * 64 + pos]);
}

__global__ void fold_bias(
    const float* __restrict__ w01, const float* __restrict__ b01,
    const float* __restrict__ w10, const float* __restrict__ b10,
    const float* __restrict__ kn, const float* __restrict__ vn,
    float* __restrict__ bm)
{
    const int which = blockIdx.x, c = threadIdx.x;
    const float* W  = (which < 2) ? w01 : w10;
    const float* Bb = (which < 2) ? b01 : b10;
    const float* nz = ((which & 1) ? vn : kn) + (which >> 1) * kC;
    const int off = (which & 1) ? 256 : 128;
    float acc = Bb[off + c];
    const float* wr = W + (size_t)(off + c) * kC;
    for (int k = 0; k < kC; k++) acc += nz[k] * wr[k];
    bm[which * kC + c] = acc;
}

// ---------------------------------------------------------------------------
extern "C" void kernel_launch(void* const* d_in, const int* in_sizes, int n_in,
                              void* d_out, int out_size)
{
    (void)in_sizes; (void)n_in; (void)out_size;
    const float* x0   = (const float*)d_in[0];
    const float* x1   = (const float*)d_in[1];
    const float* Wq   = (const float*)d_in[2];
    const float* bq   = (const float*)d_in[3];
    const float* Wkv  = (const float*)d_in[4];
    const float* bkv  = (const float*)d_in[5];
    const float* srw  = (const float*)d_in[6];
    const float* srb  = (const float*)d_in[7];
    const float* lnG[2] = {(const float*)d_in[8],  (const float*)d_in[10]};
    const float* lnB[2] = {(const float*)d_in[9],  (const float*)d_in[11]};
    const float* cawI[2] = {(const float*)d_in[12], (const float*)d_in[16]};
    const float* cabI[2] = {(const float*)d_in[13], (const float*)d_in[17]};
    const float* cawO[2] = {(const float*)d_in[14], (const float*)d_in[18]};
    const float* cabO[2] = {(const float*)d_in[15], (const float*)d_in[19]};
    const float* rjw1 = (const float*)d_in[20];
    const float* rjb1 = (const float*)d_in[21];
    const float* rjw2 = (const float*)d_in[22];
    const float* rjb2 = (const float*)d_in[23];
    const float* kn   = (const float*)d_in[24];
    const float* vn   = (const float*)d_in[25];
    const float* pw   = (const float*)d_in[26];
    const float* pb   = (const float*)d_in[27];
    float* out = (float*)d_out;

    float* g = nullptr;
    cudaGetSymbolAddress((void**)&g, g_mem);
    __half* hm = nullptr;
    cudaGetSymbolAddress((void**)&hm, h_mem);

    float* XA[2] = {g + O_XA0, g + O_XA1};
    float* T0 = g + O_T0;
    float *PART = g + O_PART, *KB = g + O_KB, *VB = g + O_VB, *BM = g + O_BM;

    __half *XH[2]  = {hm + H_X0, hm + H_X1};
    __half *XAH[2] = {hm + H_XA0, hm + H_XA1};
    __half *T1H = hm + H_T1, *XASH = hm + H_XAS;
    __half *T5H = hm + H_T5, *NSH = hm + H_NS;
    __half *XLNH = hm + H_XLN;
    __half *WSH = hm + H_WS;
    __half *CWH = hm + H_CW;
    __half *QH = hm + H_QH, *PB = hm + H_P;
    __half *KH = hm + H_KH, *VT = hm + H_VT;
    __half *PT0 = hm + H_PT0, *PT1 = hm + H_PT1, *PT2 = hm + H_PT2;
    __half *PT3 = hm + H_PT3, *PT4 = hm + H_PT4;

    cudaFuncSetAttribute(gemm4, cudaFuncAttributeMaxDynamicSharedMemorySize, SM_G_BIG);
    cudaFuncSetAttribute(conv_mma, cudaFuncAttributeMaxDynamicSharedMemorySize, SM_G_SMALL);
    cudaFuncSetAttribute(attn_s, cudaFuncAttributeMaxDynamicSharedMemorySize, SM_S_TOTAL);
    cudaFuncSetAttribute(attn_pv, cudaFuncAttributeMaxDynamicSharedMemorySize, SM_PV_TOTAL);

    // --- one-time prep ---
    fold_bias<<<4, 128>>>(cawI[0], cabI[0], cawI[1], cabI[1], kn, vn, BM);
    cvt_half<<<8192, 256>>>(x0, XH[0]);
    cvt_half<<<8192, 256>>>(x1, XH[1]);
    cvt_convw<<<2048, 256>>>(srw, CWH);
#define SW(SRC, LD, IDX) cvt_w<<<32, 256>>>(SRC, LD, WSH + (IDX) * 16384)
    SW(Wq, 128, 0);
    SW(Wkv, 128, 1);          SW(Wkv + 16384, 128, 2);
    SW(rjw1, 256, 3);         SW(rjw1 + 128, 256, 4);
    SW(rjw2, 128, 5);
    SW(cawI[0], 128, 6);      SW(cawI[0] + 16384, 128, 7);  SW(cawI[0] + 32768, 128, 8);
    SW(cawI[1], 128, 9);      SW(cawI[1] + 16384, 128, 10); SW(cawI[1] + 32768, 128, 11);
    SW(cawO[0], 128, 12);     SW(cawO[1], 128, 13);
    SW(pw, 128, 14);
#undef SW

    const int GM = kMTOK / 128;
#define G4(GRID, AH, WI, BIAS, RESID, YF, YH, EPI) \
    gemm4<<<GRID, 256, SM_G_SMALL>>>(AH, WSH + (WI) * 16384, BIAS, RESID, \
                                     nullptr, YF, YH, EPI)
#define G4S(GRID, AH, WI, BIAS, PMUL, YH) \
    gemm4<<<GRID, 256, SM_G_BIG>>>(AH, WSH + (WI) * 16384, BIAS, nullptr, \
                                   PMUL, nullptr, YH, 2)

    // --- Stage A: SR attention per stream (tensor-core path) ---
    for (int s = 0; s < 2; s++) {
        G4(GM, XH[s], 0, bq, nullptr, nullptr, QH, 0);          // q fp16
        conv_mma<<<dim3(8, 64), 256, SM_G_SMALL>>>(XH[s], CWH, PART);
        conv_reduce_ln<<<1024, 128>>>(PART, srb, lnG[s], lnB[s], XLNH);
        G4(8, XLNH, 1, bkv,       nullptr, KB, nullptr, 0);
        G4(8, XLNH, 2, bkv + 128, nullptr, VB, nullptr, 0);
        kv_pack<<<512, 256>>>(KB, VB, KH, VT);
        attn_s<<<dim3(128, 8), 256, SM_S_TOTAL>>>(QH, KH, PB);
        attn_pv<<<dim3(128, 8), 256, SM_PV_TOTAL>>>(PB, VT, XA[s], XAH[s]);
    }

    // --- Stage B + C per stream ---
    for (int s = 0; s < 2; s++) {
        G4(GM, XAH[s],     3, nullptr, nullptr, T0, nullptr, 0);
        G4(GM, XAH[s ^ 1], 4, rjb1,    T0,      nullptr, T1H, 1);
        G4S(GM, T1H,       5, rjb2,    XA[s],   XASH);
        const float* Bb = cabI[s];
        float* bmk = BM + (2 * s) * kC;
        float* bmv = BM + (2 * s + 1) * kC;
        G4(GM, XAH[s],     6 + 3 * s, Bb,       nullptr, nullptr, PT0, 0);
        G4(GM, XAH[s],     7 + 3 * s, bmk,      nullptr, nullptr, PT1, 0);
        G4(GM, XASH,       7 + 3 * s, Bb + 128, nullptr, nullptr, PT2, 0);
        G4(GM, XAH[s],     8 + 3 * s, bmv,      nullptr, nullptr, PT3, 0);
        G4(GM, XAH[s ^ 1], 8 + 3 * s, Bb + 256, nullptr, nullptr, PT4, 0);
        mha2_pw<<<2048, 256>>>(PT0, PT1, PT2, PT3, PT4, T5H);
        G4(GM, T5H, 12 + s, cabO[s], XA[s], nullptr, NSH, 0);
        G4(GM, NSH, 14,     pb,      nullptr, out + (size_t)s * SZ, nullptr, 0);
    }
#undef G4
#undef G4S
}

// round 12
// speedup vs baseline: 3.0366x; 1.0199x over previous
#include <cuda_runtime.h>
#include <cuda_fp16.h>
#include <math.h>
#include <stdint.h>

#define FULLMASK 0xffffffffu

namespace {
constexpr int kB = 4, kN = 16384, kC = 128, kMTOK = 65536, kMR = 1024;
constexpr size_t SZ = (size_t)kMTOK * kC;   // 8,388,608

// fp32 scratch
constexpr size_t O_XA0 = 0;
constexpr size_t O_XA1 = SZ;
constexpr size_t O_T0  = 2 * SZ;
constexpr size_t O_PART = 3 * SZ;           // 64*1024*128 == SZ
constexpr size_t O_KB  = 4 * SZ;
constexpr size_t O_VB  = O_KB + 131072;
constexpr size_t O_BM  = O_VB + 131072;
constexpr size_t TOTF  = O_BM + 512;

// fp16 buffers (element offsets in h_mem)
constexpr size_t H_X0  = 0;
constexpr size_t H_X1  = SZ;
constexpr size_t H_XA0 = 2 * SZ;
constexpr size_t H_XA1 = 3 * SZ;
constexpr size_t H_T1  = 4 * SZ;            // judger hidden
constexpr size_t H_XAS = 5 * SZ;
constexpr size_t H_T5  = 6 * SZ;
constexpr size_t H_NS  = 7 * SZ;
constexpr size_t H_XLN = 8 * SZ;                     // 131072
constexpr size_t H_WS  = H_XLN + 131072;             // 15 weight blocks (fp16)
constexpr size_t H_CW  = H_WS + 15 * 16384;          // 64 conv blocks (fp16)
constexpr size_t H_QH  = H_CW + 64 * 16384;          // q fp16 (one stream)
constexpr size_t H_P   = H_QH + SZ;                  // P [8][16384][256] = 4*SZ
constexpr size_t H_KH  = H_P + 4 * SZ;               // K fp16 [8][256][64]
constexpr size_t H_VT  = H_KH + 131072;              // V^T fp16 [8][64][256]
constexpr size_t H_PT0 = H_VT + 131072;              // stage-C fp16 temps
constexpr size_t H_PT1 = H_PT0 + SZ;
constexpr size_t H_PT2 = H_PT1 + SZ;
constexpr size_t H_PT3 = H_PT2 + SZ;
constexpr size_t H_PT4 = H_PT3 + SZ;
constexpr size_t TOTH  = H_PT4 + SZ;

// tile geometry
constexpr int TROW   = 144;                 // bytes per 64-col fp16 row
constexpr int TBYTES = 128 * TROW;          // 18432

// gemm5 smem: B chunk0, B chunk1, A chunk0, A chunk1, 2KB reduce buf
constexpr int SM_B0 = 0;
constexpr int SM_B1 = TBYTES;
constexpr int SM_A0 = 2 * TBYTES;
constexpr int SM_A1 = 3 * TBYTES;
constexpr int SM_RED = 4 * TBYTES;          // 73728
constexpr int SM_G   = SM_RED + 2048;       // 75776

// conv smem (2 tiles)
constexpr int SM_CONV = 2 * TBYTES;         // 36864
// attn_s smem: A 128x144 + B 256x144
constexpr int SMB_S = TBYTES;
constexpr int SM_S_TOTAL = TBYTES + 256 * TROW;   // 55296
// attn_pv smem: A 128x144 + B 64x144
constexpr int SMB_PV = TBYTES;
constexpr int SM_PV_TOTAL = TBYTES + 64 * TROW;   // 27648
}

__device__ float g_mem[TOTF];
__device__ __half h_mem[TOTH];

// ---------------------------------------------------------------------------
__device__ __forceinline__ uint32_t smem_u32(const void* p) {
    uint32_t a;
    asm("{ .reg .u64 t; cvta.to.shared.u64 t, %1; cvt.u32.u64 %0, t; }"
        : "=r"(a) : "l"(p));
    return a;
}
__device__ __forceinline__ uint32_t pack_h2(float a, float b) {
    __half2 h = __floats2half2_rn(a, b);
    return *(uint32_t*)&h;
}
__device__ __forceinline__ void mma16816(float* d, const uint32_t* a,
                                         uint32_t b0, uint32_t b1) {
    asm volatile(
        "mma.sync.aligned.m16n8k16.row.col.f32.f16.f16.f32 "
        "{%0,%1,%2,%3}, {%4,%5,%6,%7}, {%8,%9}, {%0,%1,%2,%3};"
        : "+f"(d[0]), "+f"(d[1]), "+f"(d[2]), "+f"(d[3])
        : "r"(a[0]), "r"(a[1]), "r"(a[2]), "r"(a[3]), "r"(b0), "r"(b1));
}
__device__ __forceinline__ void ldsm4(uint32_t& r0, uint32_t& r1,
                                      uint32_t& r2, uint32_t& r3, uint32_t addr) {
    asm volatile("ldmatrix.sync.aligned.m8n8.x4.shared.b16 {%0,%1,%2,%3}, [%4];"
                 : "=r"(r0), "=r"(r1), "=r"(r2), "=r"(r3) : "r"(addr));
}
__device__ __forceinline__ void cpa16(uint32_t dst, const void* src) {
    asm volatile("cp.async.cg.shared.global [%0], [%1], 16;"
                 :: "r"(dst), "l"(src));
}
__device__ __forceinline__ void cpa_wait() {
    asm volatile("cp.async.commit_group;\ncp.async.wait_group 0;" ::: "memory");
}
__device__ __forceinline__ float dot8h(uint4 a, uint4 b) {
    const __half2* pa = (const __half2*)&a;
    const __half2* pb = (const __half2*)&b;
    float s = 0.0f;
#pragma unroll
    for (int i = 0; i < 4; i++) {
        float2 fa = __half22float2(pa[i]);
        float2 fb = __half22float2(pb[i]);
        s += fa.x * fb.x + fa.y * fb.y;
    }
    return s;
}

// ---------------------------------------------------------------------------
struct FragCtx {
    uint32_t aoff[2];
    uint32_t boff[4];
};
__device__ __forceinline__ FragCtx make_frag_ctx(int lane, int wm, int wn) {
    FragCtx fc;
    const int rA = (lane & 7) + ((lane >> 3) & 1) * 8;
    const int cA = (lane >> 4) * 16;
#pragma unroll
    for (int mt = 0; mt < 2; mt++)
        fc.aoff[mt] = (uint32_t)((wm * 32 + mt * 16 + rA) * TROW + cA);
    const int rB = (lane & 7) + ((lane >> 4) & 1) * 8;
    const int cB = ((lane >> 3) & 1) * 16;
#pragma unroll
    for (int np = 0; np < 4; np++)
        fc.boff[np] = (uint32_t)((wn * 64 + np * 16 + rB) * TROW + cB);
    return fc;
}
// one 64-col K chunk: C += A·B (A tile at aBase, B tile at bBase)
__device__ __forceinline__ void mainloop_chunk(uint32_t aBase, uint32_t bBase,
                                               const FragCtx& fc,
                                               float acc[2][8][4]) {
#pragma unroll
    for (int kc = 0; kc < 4; kc++) {
        const uint32_t kb = (uint32_t)kc * 32;
        uint32_t ah[2][4];
#pragma unroll
        for (int mt = 0; mt < 2; mt++)
            ldsm4(ah[mt][0], ah[mt][1], ah[mt][2], ah[mt][3],
                  aBase + fc.aoff[mt] + kb);
#pragma unroll
        for (int np = 0; np < 4; np++) {
            uint32_t b0, b1, b2, b3;
            ldsm4(b0, b1, b2, b3, bBase + fc.boff[np] + kb);
#pragma unroll
            for (int mt = 0; mt < 2; mt++) {
                mma16816(acc[mt][np * 2],     ah[mt], b0, b1);
                mma16816(acc[mt][np * 2 + 1], ah[mt], b2, b3);
            }
        }
    }
}

// ---------------------------------------------------------------------------
// GEMM v5: 256 rows per CTA, B resident in smem, A tile-1 prefetched under
// tile-0 epilogue. Y = epi(A @ B^T + bias? + resid?)
// epi 0: none, 1: GELU, 2: row-softmax * postmul (2KB shuffle+smem reduce).
// ---------------------------------------------------------------------------
__global__ __launch_bounds__(256, 2) void gemm5(
    const __half* __restrict__ A, const __half* __restrict__ Bw,
    const float* __restrict__ bias, const float* __restrict__ resid,
    const float* __restrict__ postmul,
    float* __restrict__ Yf, __half* __restrict__ Yh, int epi)
{
    extern __shared__ char sm[];
    const uint32_t smb = smem_u32(sm);
    const int tid = threadIdx.x;
    const int lane = tid & 31, wid = tid >> 5;
    const int t4 = lane & 3, r8 = lane >> 2;
    const int wm = wid >> 1, wn = wid & 1;
    const int bm0 = blockIdx.x * 256;
    const FragCtx fc = make_frag_ctx(lane, wm, wn);
    const int pr = tid >> 1, hf = tid & 1;
    const uint32_t so = (uint32_t)(pr * TROW + hf * 64);

    // load B (both chunks) + A tile 0 (both chunks)
#pragma unroll
    for (int ch = 0; ch < 2; ch++) {
        const size_t brow = (size_t)pr * kC + ch * 64 + hf * 32;
        const size_t arow = (size_t)(bm0 + pr) * kC + ch * 64 + hf * 32;
#pragma unroll
        for (int gq = 0; gq < 4; gq++) {
            cpa16(smb + SM_B0 + ch * TBYTES + so + gq * 16, Bw + brow + gq * 8);
            cpa16(smb + SM_A0 + ch * TBYTES + so + gq * 16, A  + arow + gq * 8);
        }
    }
    cpa_wait();
    __syncthreads();

    float* redm = (float*)(sm + SM_RED);          // [128][2]
    float* reds = (float*)(sm + SM_RED + 1024);   // [128][2]

    for (int mt = 0; mt < 2; mt++) {
        const int bm = bm0 + mt * 128;
        float acc[2][8][4];
#pragma unroll
        for (int mp = 0; mp < 2; mp++)
#pragma unroll
            for (int nt = 0; nt < 8; nt++)
#pragma unroll
                for (int e = 0; e < 4; e++) acc[mp][nt][e] = 0.0f;

        mainloop_chunk(smb + SM_A0, smb + SM_B0, fc, acc);
        mainloop_chunk(smb + SM_A1, smb + SM_B1, fc, acc);
        __syncthreads();          // all warps done reading A tile

        if (mt == 0) {            // prefetch A tile 1 under epilogue
#pragma unroll
            for (int ch = 0; ch < 2; ch++) {
                const size_t arow = (size_t)(bm0 + 128 + pr) * kC + ch * 64 + hf * 32;
#pragma unroll
                for (int gq = 0; gq < 4; gq++)
                    cpa16(smb + SM_A0 + ch * TBYTES + so + gq * 16, A + arow + gq * 8);
            }
        }

        // --- bias add (in-register) ---
        if (bias) {
#pragma unroll
            for (int nt = 0; nt < 8; nt++) {
                float2 bv = *(const float2*)(bias + wn * 64 + nt * 8 + 2 * t4);
#pragma unroll
                for (int mp = 0; mp < 2; mp++) {
                    acc[mp][nt][0] += bv.x; acc[mp][nt][1] += bv.y;
                    acc[mp][nt][2] += bv.x; acc[mp][nt][3] += bv.y;
                }
            }
        }

        if (epi != 2) {
#pragma unroll
            for (int mp = 0; mp < 2; mp++)
#pragma unroll
                for (int p = 0; p < 2; p++) {
                    const int r = bm + wm * 32 + mp * 16 + r8 + p * 8;
#pragma unroll
                    for (int nt = 0; nt < 8; nt++) {
                        const int c = wn * 64 + nt * 8 + 2 * t4;
                        float v0 = acc[mp][nt][2 * p];
                        float v1 = acc[mp][nt][2 * p + 1];
                        if (resid) {
                            float2 rv = *(const float2*)(resid + (size_t)r * kC + c);
                            v0 += rv.x; v1 += rv.y;
                        }
                        if (epi == 1) {
                            v0 = 0.5f * v0 * (1.0f + erff(v0 * 0.70710678118654752f));
                            v1 = 0.5f * v1 * (1.0f + erff(v1 * 0.70710678118654752f));
                        }
                        if (Yf)
                            *(float2*)(Yf + (size_t)r * kC + c) = make_float2(v0, v1);
                        if (Yh)
                            *(uint32_t*)(Yh + (size_t)r * kC + c) = pack_h2(v0, v1);
                    }
                }
        } else {
            // row softmax * postmul, writes fp16.
            float pm[2][2];
#pragma unroll
            for (int mp = 0; mp < 2; mp++) {
                float a0 = -1e30f, a1 = -1e30f;
#pragma unroll
                for (int nt = 0; nt < 8; nt++) {
                    a0 = fmaxf(a0, fmaxf(acc[mp][nt][0], acc[mp][nt][1]));
                    a1 = fmaxf(a1, fmaxf(acc[mp][nt][2], acc[mp][nt][3]));
                }
                pm[mp][0] = a0; pm[mp][1] = a1;
            }
#pragma unroll
            for (int mp = 0; mp < 2; mp++)
#pragma unroll
                for (int p = 0; p < 2; p++) {
                    pm[mp][p] = fmaxf(pm[mp][p], __shfl_xor_sync(FULLMASK, pm[mp][p], 1));
                    pm[mp][p] = fmaxf(pm[mp][p], __shfl_xor_sync(FULLMASK, pm[mp][p], 2));
                }
            if (t4 == 0) {
#pragma unroll
                for (int mp = 0; mp < 2; mp++)
#pragma unroll
                    for (int p = 0; p < 2; p++)
                        redm[(wm * 32 + mp * 16 + r8 + p * 8) * 2 + wn] = pm[mp][p];
            }
            __syncthreads();
            float M[2][2], ps[2][2];
#pragma unroll
            for (int mp = 0; mp < 2; mp++)
#pragma unroll
                for (int p = 0; p < 2; p++) {
                    const int lr = wm * 32 + mp * 16 + r8 + p * 8;
                    M[mp][p] = fmaxf(redm[lr * 2], redm[lr * 2 + 1]);
                    ps[mp][p] = 0.0f;
                }
#pragma unroll
            for (int mp = 0; mp < 2; mp++)
#pragma unroll
                for (int nt = 0; nt < 8; nt++) {
                    acc[mp][nt][0] = __expf(acc[mp][nt][0] - M[mp][0]);
                    acc[mp][nt][1] = __expf(acc[mp][nt][1] - M[mp][0]);
                    acc[mp][nt][2] = __expf(acc[mp][nt][2] - M[mp][1]);
                    acc[mp][nt][3] = __expf(acc[mp][nt][3] - M[mp][1]);
                    ps[mp][0] += acc[mp][nt][0] + acc[mp][nt][1];
                    ps[mp][1] += acc[mp][nt][2] + acc[mp][nt][3];
                }
#pragma unroll
            for (int mp = 0; mp < 2; mp++)
#pragma unroll
                for (int p = 0; p < 2; p++) {
                    ps[mp][p] += __shfl_xor_sync(FULLMASK, ps[mp][p], 1);
                    ps[mp][p] += __shfl_xor_sync(FULLMASK, ps[mp][p], 2);
                }
            if (t4 == 0) {
#pragma unroll
                for (int mp = 0; mp < 2; mp++)
#pragma unroll
                    for (int p = 0; p < 2; p++)
                        reds[(wm * 32 + mp * 16 + r8 + p * 8) * 2 + wn] = ps[mp][p];
            }
            __syncthreads();
#pragma unroll
            for (int mp = 0; mp < 2; mp++)
#pragma unroll
                for (int p = 0; p < 2; p++) {
                    const int lr = wm * 32 + mp * 16 + r8 + p * 8;
                    const float inv = 1.0f / (reds[lr * 2] + reds[lr * 2 + 1]);
                    const size_t gr = (size_t)(bm + lr) * kC;
#pragma unroll
                    for (int nt = 0; nt < 8; nt++) {
                        const int c = wn * 64 + nt * 8 + 2 * t4;
                        float2 pmv = *(const float2*)(postmul + gr + c);
                        float v0 = acc[mp][nt][2 * p]     * inv * pmv.x;
                        float v1 = acc[mp][nt][2 * p + 1] * inv * pmv.y;
                        *(uint32_t*)(Yh + gr + c) = pack_h2(v0, v1);
                    }
                }
        }

        if (mt == 0) {
            cpa_wait();
            __syncthreads();
        }
    }
}

// ---------------------------------------------------------------------------
// Conv via mma: grid (8, 64), one kernel position per block, single term.
// ---------------------------------------------------------------------------
__global__ __launch_bounds__(256, 2) void conv_mma(
    const __half* __restrict__ xh, const __half* __restrict__ cwh,
    float* __restrict__ part)
{
    extern __shared__ char sm[];
    const uint32_t smb = smem_u32(sm);
    const int tid = threadIdx.x;
    const int lane = tid & 31, wid = tid >> 5;
    const int t4 = lane & 3, r8 = lane >> 2;
    const int wm = wid >> 1, wn = wid & 1;
    const int b = blockIdx.x >> 1, rt = blockIdx.x & 1, pos = blockIdx.y;
    const FragCtx fc = make_frag_ctx(lane, wm, wn);

    float acc[2][8][4];
#pragma unroll
    for (int mt = 0; mt < 2; mt++)
#pragma unroll
        for (int nt = 0; nt < 8; nt++)
#pragma unroll
            for (int e = 0; e < 4; e++) acc[mt][nt][e] = 0.0f;

    const int pr = tid >> 1, hf = tid & 1;
    const int p = rt * 128 + pr;
    const int ph = p >> 4, pwd = p & 15;
    const int kh = pos >> 3, kw = pos & 7;
    const size_t xrow = ((size_t)b * kN + (ph * 8 + kh) * 128 + pwd * 8 + kw) * kC;
    const size_t wbase = (size_t)pos * 16384 + (size_t)pr * kC;

    for (int ch = 0; ch < 2; ch++) {
        const size_t arow = xrow + ch * 64 + hf * 32;
        const size_t brow = wbase + ch * 64 + hf * 32;
        const uint32_t so = (uint32_t)(pr * TROW + hf * 64);
#pragma unroll
        for (int gq = 0; gq < 4; gq++) {
            cpa16(smb + so + gq * 16,          xh  + arow + gq * 8);
            cpa16(smb + TBYTES + so + gq * 16, cwh + brow + gq * 8);
        }
        cpa_wait();
        __syncthreads();
        mainloop_chunk(smb, smb + TBYTES, fc, acc);
        __syncthreads();
    }

    const size_t base = ((size_t)pos * kMR + (size_t)b * 256 + rt * 128) * kC;
#pragma unroll
    for (int mt = 0; mt < 2; mt++)
#pragma unroll
        for (int pq = 0; pq < 2; pq++) {
            const int lr = wm * 32 + mt * 16 + r8 + pq * 8;
#pragma unroll
            for (int nt = 0; nt < 8; nt++) {
                const int c = wn * 64 + nt * 8 + 2 * t4;
                *(float2*)(part + base + (size_t)lr * kC + c) =
                    make_float2(acc[mt][nt][2 * pq], acc[mt][nt][2 * pq + 1]);
            }
        }
}

// ---------------------------------------------------------------------------
__global__ void conv_reduce_ln(const float* __restrict__ part,
                               const float* __restrict__ srb,
                               const float* __restrict__ gam,
                               const float* __restrict__ bet,
                               __half* __restrict__ xlnh)
{
    const int row = blockIdx.x;
    const int c = threadIdx.x;
    float v = srb[c];
#pragma unroll 8
    for (int sp = 0; sp < 64; sp++)
        v += part[((size_t)sp * kMR + row) * kC + c];

    __shared__ float red[4];
    float s = v;
#pragma unroll
    for (int o = 16; o > 0; o >>= 1) s += __shfl_xor_sync(FULLMASK, s, o);
    if ((c & 31) == 0) red[c >> 5] = s;
    __syncthreads();
    const float mean = (red[0] + red[1] + red[2] + red[3]) * (1.0f / 128.0f);
    __syncthreads();
    const float d = v - mean;
    float s2 = d * d;
#pragma unroll
    for (int o = 16; o > 0; o >>= 1) s2 += __shfl_xor_sync(FULLMASK, s2, o);
    if ((c & 31) == 0) red[c >> 5] = s2;
    __syncthreads();
    const float var = (red[0] + red[1] + red[2] + red[3]) * (1.0f / 128.0f);
    xlnh[(size_t)row * kC + c] =
        __float2half_rn(d * rsqrtf(var + 1e-5f) * gam[c] + bet[c]);
}

// ---------------------------------------------------------------------------
__global__ void kv_pack(const float* __restrict__ KB, const float* __restrict__ VB,
                        __half* __restrict__ Kh, __half* __restrict__ Vt)
{
    const int idx = blockIdx.x * 256 + threadIdx.x;   // 131072
    const int b = idx >> 15, rem = idx & 32767;
    const int m = rem >> 7, c = rem & 127;
    const int h = c >> 6, d = c & 63;
    const int bh = b * 2 + h;
    Kh[((size_t)bh * 256 + m) * 64 + d] = __float2half_rn(KB[idx]);
    Vt[((size_t)bh * 64 + d) * 256 + m] = __float2half_rn(VB[idx]);
}

// ---------------------------------------------------------------------------
// attn_s: per CTA 128 q-rows x 256 keys, K=64; fused softmax; P fp16.
// ---------------------------------------------------------------------------
__global__ __launch_bounds__(256, 1) void attn_s(
    const __half* __restrict__ Qh, const __half* __restrict__ Kh,
    __half* __restrict__ P)
{
    extern __shared__ char sm[];
    const uint32_t smb = smem_u32(sm);
    const int tid = threadIdx.x;
    const int lane = tid & 31, wid = tid >> 5;
    const int t4 = lane & 3, r8 = lane >> 2;
    const int bh = blockIdx.y;
    const int b = bh >> 1, h = bh & 1;
    const int qt = blockIdx.x;

    const int rA = (lane & 7) + ((lane >> 3) & 1) * 8;
    const int cA = (lane >> 4) * 16;
    const uint32_t aoff = (uint32_t)((wid * 16 + rA) * TROW + cA);
    const int rB = (lane & 7) + ((lane >> 4) & 1) * 8;
    const int cB = ((lane >> 3) & 1) * 16;
    const uint32_t boffb = (uint32_t)(rB * TROW + cB);

    {
        const int pr = tid >> 1, hf = tid & 1;
        const __half* qsrc = Qh +
            ((size_t)(b * kN + qt * 128 + pr) * kC + h * 64 + hf * 32);
        const uint32_t so = (uint32_t)(pr * TROW + hf * 64);
#pragma unroll
        for (int gq = 0; gq < 4; gq++)
            cpa16(smb + so + gq * 16, qsrc + gq * 8);
        const __half* ksrc = Kh + ((size_t)bh * 256 + tid) * 64;
        const uint32_t sob = (uint32_t)(tid * TROW);
#pragma unroll
        for (int gq = 0; gq < 8; gq++)
            cpa16(smb + SMB_S + sob + gq * 16, ksrc + gq * 8);
    }
    cpa_wait();
    __syncthreads();

    float acc[32][4];
#pragma unroll
    for (int nt = 0; nt < 32; nt++)
#pragma unroll
        for (int e = 0; e < 4; e++) acc[nt][e] = 0.0f;

#pragma unroll
    for (int kc = 0; kc < 4; kc++) {
        uint32_t af[4];
        ldsm4(af[0], af[1], af[2], af[3], smb + aoff + kc * 32);
#pragma unroll
        for (int np = 0; np < 16; np++) {
            uint32_t b0, b1, b2, b3;
            ldsm4(b0, b1, b2, b3, smb + SMB_S + boffb + np * (16 * TROW) + kc * 32);
            mma16816(acc[np * 2],     af, b0, b1);
            mma16816(acc[np * 2 + 1], af, b2, b3);
        }
    }

    float mx0 = -1e30f, mx1 = -1e30f;
#pragma unroll
    for (int nt = 0; nt < 32; nt++) {
#pragma unroll
        for (int e = 0; e < 4; e++) acc[nt][e] *= 0.125f;
        mx0 = fmaxf(mx0, fmaxf(acc[nt][0], acc[nt][1]));
        mx1 = fmaxf(mx1, fmaxf(acc[nt][2], acc[nt][3]));
    }
    mx0 = fmaxf(mx0, __shfl_xor_sync(FULLMASK, mx0, 1));
    mx0 = fmaxf(mx0, __shfl_xor_sync(FULLMASK, mx0, 2));
    mx1 = fmaxf(mx1, __shfl_xor_sync(FULLMASK, mx1, 1));
    mx1 = fmaxf(mx1, __shfl_xor_sync(FULLMASK, mx1, 2));
    float s0 = 0.0f, s1 = 0.0f;
#pragma unroll
    for (int nt = 0; nt < 32; nt++) {
        acc[nt][0] = __expf(acc[nt][0] - mx0);
        acc[nt][1] = __expf(acc[nt][1] - mx0);
        acc[nt][2] = __expf(acc[nt][2] - mx1);
        acc[nt][3] = __expf(acc[nt][3] - mx1);
        s0 += acc[nt][0] + acc[nt][1];
        s1 += acc[nt][2] + acc[nt][3];
    }
    s0 += __shfl_xor_sync(FULLMASK, s0, 1);
    s0 += __shfl_xor_sync(FULLMASK, s0, 2);
    s1 += __shfl_xor_sync(FULLMASK, s1, 1);
    s1 += __shfl_xor_sync(FULLMASK, s1, 2);
    const float i0 = 1.0f / s0, i1 = 1.0f / s1;

    const size_t p0 = ((size_t)bh * kN + qt * 128 + wid * 16 + r8) * 256;
    const size_t p1 = p0 + 8 * 256;
#pragma unroll
    for (int nt = 0; nt < 32; nt++) {
        const int c = nt * 8 + 2 * t4;
        *(uint32_t*)(P + p0 + c) = pack_h2(acc[nt][0] * i0, acc[nt][1] * i0);
        *(uint32_t*)(P + p1 + c) = pack_h2(acc[nt][2] * i1, acc[nt][3] * i1);
    }
}

// ---------------------------------------------------------------------------
// attn_pv: XA[128 x 64] = P(128x256) @ Vt^T, K=256 in 4 chunks.
// ---------------------------------------------------------------------------
__global__ __launch_bounds__(256, 2) void attn_pv(
    const __half* __restrict__ P, const __half* __restrict__ Vt,
    float* __restrict__ XA, __half* __restrict__ XAh)
{
    extern __shared__ char sm[];
    const uint32_t smb = smem_u32(sm);
    const int tid = threadIdx.x;
    const int lane = tid & 31, wid = tid >> 5;
    const int t4 = lane & 3, r8 = lane >> 2;
    const int wm = wid >> 1, wn = wid & 1;
    const int bh = blockIdx.y;
    const int b = bh >> 1, h = bh & 1;
    const int qt = blockIdx.x;

    const int rA = (lane & 7) + ((lane >> 3) & 1) * 8;
    const int cA = (lane >> 4) * 16;
    uint32_t aoff[2];
#pragma unroll
    for (int mt = 0; mt < 2; mt++)
        aoff[mt] = (uint32_t)((wm * 32 + mt * 16 + rA) * TROW + cA);
    const int rB = (lane & 7) + ((lane >> 4) & 1) * 8;
    const int cB = ((lane >> 3) & 1) * 16;
    uint32_t boff[2];
#pragma unroll
    for (int np = 0; np < 2; np++)
        boff[np] = (uint32_t)((wn * 32 + np * 16 + rB) * TROW + cB);

    float acc[2][4][4];
#pragma unroll
    for (int mt = 0; mt < 2; mt++)
#pragma unroll
        for (int nt = 0; nt < 4; nt++)
#pragma unroll
            for (int e = 0; e < 4; e++) acc[mt][nt][e] = 0.0f;

    const int pr = tid >> 1, hf = tid & 1;

    for (int ch = 0; ch < 4; ch++) {
        const __half* asrc = P +
            (((size_t)bh * kN + qt * 128 + pr) * 256 + ch * 64 + hf * 32);
        const uint32_t so = (uint32_t)(pr * TROW + hf * 64);
#pragma unroll
        for (int gq = 0; gq < 4; gq++)
            cpa16(smb + so + gq * 16, asrc + gq * 8);
        if (tid < 128) {
            const int d = tid >> 1, hfb = tid & 1;
            const __half* vsrc = Vt +
                (((size_t)bh * 64 + d) * 256 + ch * 64 + hfb * 32);
            const uint32_t sob = (uint32_t)(d * TROW + hfb * 64);
#pragma unroll
            for (int gq = 0; gq < 4; gq++)
                cpa16(smb + SMB_PV + sob + gq * 16, vsrc + gq * 8);
        }
        cpa_wait();
        __syncthreads();
#pragma unroll
        for (int kc = 0; kc < 4; kc++) {
            const uint32_t kb = (uint32_t)kc * 32;
            uint32_t ah[2][4];
#pragma unroll
            for (int mt = 0; mt < 2; mt++)
                ldsm4(ah[mt][0], ah[mt][1], ah[mt][2], ah[mt][3],
                      smb + aoff[mt] + kb);
#pragma unroll
            for (int np = 0; np < 2; np++) {
                uint32_t b0, b1, b2, b3;
                ldsm4(b0, b1, b2, b3, smb + SMB_PV + boff[np] + kb);
#pragma unroll
                for (int mt = 0; mt < 2; mt++) {
                    mma16816(acc[mt][np * 2],     ah[mt], b0, b1);
                    mma16816(acc[mt][np * 2 + 1], ah[mt], b2, b3);
                }
            }
        }
        __syncthreads();
    }

#pragma unroll
    for (int mt = 0; mt < 2; mt++)
#pragma unroll
        for (int p = 0; p < 2; p++) {
            const int lr = qt * 128 + wm * 32 + mt * 16 + r8 + p * 8;
            const size_t g = ((size_t)b * kN + lr) * kC + h * 64;
#pragma unroll
            for (int nt = 0; nt < 4; nt++) {
                const int c = wn * 32 + nt * 8 + 2 * t4;
                float v0 = acc[mt][nt][2 * p];
                float v1 = acc[mt][nt][2 * p + 1];
                *(float2*)(XA + g + c) = make_float2(v0, v1);
                *(uint32_t*)(XAh + g + c) = pack_h2(v0, v1);
            }
        }
}

// ---------------------------------------------------------------------------
__global__ __launch_bounds__(256) void mha2_pw(
    const __half* __restrict__ qp, const __half* __restrict__ k0,
    const __half* __restrict__ k1, const __half* __restrict__ v0,
    const __half* __restrict__ v1, __half* __restrict__ oh)
{
    const int idx = blockIdx.x * 256 + threadIdx.x;
    const size_t base = (size_t)(idx >> 3) * kC + (idx & 7) * 16;
    const uint4* qg  = (const uint4*)(qp + base);
    const uint4* k0g = (const uint4*)(k0 + base);
    const uint4* k1g = (const uint4*)(k1 + base);
    uint4 qa = qg[0], qb = qg[1];
    float s0 = dot8h(qa, k0g[0]) + dot8h(qb, k0g[1]);
    float s1 = dot8h(qa, k1g[0]) + dot8h(qb, k1g[1]);
    s0 *= 0.25f; s1 *= 0.25f;
    const float m = fmaxf(s0, s1);
    float e0 = __expf(s0 - m), e1 = __expf(s1 - m);
    const float inv = 1.0f / (e0 + e1);
    e0 *= inv; e1 *= inv;
    const uint4* v0g = (const uint4*)(v0 + base);
    const uint4* v1g = (const uint4*)(v1 + base);
    uint4* ohg = (uint4*)(oh + base);
#pragma unroll
    for (int t = 0; t < 2; t++) {
        uint4 a = v0g[t], bb = v1g[t];
        const __half2* pa = (const __half2*)&a;
        const __half2* pb = (const __half2*)&bb;
        uint4 o;
        uint32_t* po = (uint32_t*)&o;
#pragma unroll
        for (int i = 0; i < 4; i++) {
            float2 fa = __half22float2(pa[i]);
            float2 fb = __half22float2(pb[i]);
            po[i] = pack_h2(e0 * fa.x + e1 * fb.x, e0 * fa.y + e1 * fb.y);
        }
        ohg[t] = o;
    }
}

// ---------------------------------------------------------------------------
__global__ void cvt_half(const float* __restrict__ src, __half* __restrict__ dst)
{
    const int i = blockIdx.x * 256 + threadIdx.x;
    float4 v = ((const float4*)src)[i];
    ((uint2*)dst)[i] = make_uint2(pack_h2(v.x, v.y), pack_h2(v.z, v.w));
}

__global__ void cvt_w(const float* __restrict__ src, int ldW,
                      __half* __restrict__ dh)
{
    const int i = blockIdx.x * 256 + threadIdx.x;   // 8192 pairs
    const int o = i >> 6, k = (i & 63) * 2;
    *(uint32_t*)(dh + o * kC + k) =
        pack_h2(src[(size_t)o * ldW + k], src[(size_t)o * ldW + k + 1]);
}

__global__ void cvt_convw(const float* __restrict__ srw, __half* __restrict__ dh)
{
    const int t = blockIdx.x * 256 + threadIdx.x;   // 64*8192
    const int pos = t >> 13, o = (t >> 6) & 127, i2 = (t & 63) * 2;
    const size_t d = (size_t)pos * 16384 + (size_t)o * kC + i2;
    *(uint32_t*)(dh + d) =
        pack_h2(srw[(size_t)o * 8192 + i2 * 64 + pos],
                srw[(size_t)o * 8192 + (i2 + 1) * 64 + pos]);
}

__global__ void fold_bias(
    const float* __restrict__ w01, const float* __restrict__ b01,
    const float* __restrict__ w10, const float* __restrict__ b10,
    const float* __restrict__ kn, const float* __restrict__ vn,
    float* __restrict__ bm)
{
    const int which = blockIdx.x, c = threadIdx.x;
    const float* W  = (which < 2) ? w01 : w10;
    const float* Bb = (which < 2) ? b01 : b10;
    const float* nz = ((which & 1) ? vn : kn) + (which >> 1) * kC;
    const int off = (which & 1) ? 256 : 128;
    float acc = Bb[off + c];
    const float* wr = W + (size_t)(off + c) * kC;
    for (int k = 0; k < kC; k++) acc += nz[k] * wr[k];
    bm[which * kC + c] = acc;
}

// ---------------------------------------------------------------------------
extern "C" void kernel_launch(void* const* d_in, const int* in_sizes, int n_in,
                              void* d_out, int out_size)
{
    (void)in_sizes; (void)n_in; (void)out_size;
    const float* x0   = (const float*)d_in[0];
    const float* x1   = (const float*)d_in[1];
    const float* Wq   = (const float*)d_in[2];
    const float* bq   = (const float*)d_in[3];
    const float* Wkv  = (const float*)d_in[4];
    const float* bkv  = (const float*)d_in[5];
    const float* srw  = (const float*)d_in[6];
    const float* srb  = (const float*)d_in[7];
    const float* lnG[2] = {(const float*)d_in[8],  (const float*)d_in[10]};
    const float* lnB[2] = {(const float*)d_in[9],  (const float*)d_in[11]};
    const float* cawI[2] = {(const float*)d_in[12], (const float*)d_in[16]};
    const float* cabI[2] = {(const float*)d_in[13], (const float*)d_in[17]};
    const float* cawO[2] = {(const float*)d_in[14], (const float*)d_in[18]};
    const float* cabO[2] = {(const float*)d_in[15], (const float*)d_in[19]};
    const float* rjw1 = (const float*)d_in[20];
    const float* rjb1 = (const float*)d_in[21];
    const float* rjw2 = (const float*)d_in[22];
    const float* rjb2 = (const float*)d_in[23];
    const float* kn   = (const float*)d_in[24];
    const float* vn   = (const float*)d_in[25];
    const float* pw   = (const float*)d_in[26];
    const float* pb   = (const float*)d_in[27];
    float* out = (float*)d_out;

    float* g = nullptr;
    cudaGetSymbolAddress((void**)&g, g_mem);
    __half* hm = nullptr;
    cudaGetSymbolAddress((void**)&hm, h_mem);

    float* XA[2] = {g + O_XA0, g + O_XA1};
    float* T0 = g + O_T0;
    float *PART = g + O_PART, *KB = g + O_KB, *VB = g + O_VB, *BM = g + O_BM;

    __half *XH[2]  = {hm + H_X0, hm + H_X1};
    __half *XAH[2] = {hm + H_XA0, hm + H_XA1};
    __half *T1H = hm + H_T1, *XASH = hm + H_XAS;
    __half *T5H = hm + H_T5, *NSH = hm + H_NS;
    __half *XLNH = hm + H_XLN;
    __half *WSH = hm + H_WS;
    __half *CWH = hm + H_CW;
    __half *QH = hm + H_QH, *PB = hm + H_P;
    __half *KH = hm + H_KH, *VT = hm + H_VT;
    __half *PT0 = hm + H_PT0, *PT1 = hm + H_PT1, *PT2 = hm + H_PT2;
    __half *PT3 = hm + H_PT3, *PT4 = hm + H_PT4;

    cudaFuncSetAttribute(gemm5, cudaFuncAttributeMaxDynamicSharedMemorySize, SM_G);
    cudaFuncSetAttribute(conv_mma, cudaFuncAttributeMaxDynamicSharedMemorySize, SM_CONV);
    cudaFuncSetAttribute(attn_s, cudaFuncAttributeMaxDynamicSharedMemorySize, SM_S_TOTAL);
    cudaFuncSetAttribute(attn_pv, cudaFuncAttributeMaxDynamicSharedMemorySize, SM_PV_TOTAL);

    // --- one-time prep ---
    fold_bias<<<4, 128>>>(cawI[0], cabI[0], cawI[1], cabI[1], kn, vn, BM);
    cvt_half<<<8192, 256>>>(x0, XH[0]);
    cvt_half<<<8192, 256>>>(x1, XH[1]);
    cvt_convw<<<2048, 256>>>(srw, CWH);
#define SW(SRC, LD, IDX) cvt_w<<<32, 256>>>(SRC, LD, WSH + (IDX) * 16384)
    SW(Wq, 128, 0);
    SW(Wkv, 128, 1);          SW(Wkv + 16384, 128, 2);
    SW(rjw1, 256, 3);         SW(rjw1 + 128, 256, 4);
    SW(rjw2, 128, 5);
    SW(cawI[0], 128, 6);      SW(cawI[0] + 16384, 128, 7);  SW(cawI[0] + 32768, 128, 8);
    SW(cawI[1], 128, 9);      SW(cawI[1] + 16384, 128, 10); SW(cawI[1] + 32768, 128, 11);
    SW(cawO[0], 128, 12);     SW(cawO[1], 128, 13);
    SW(pw, 128, 14);
#undef SW

    const int GM = kMTOK / 256;   // 256 CTAs per big GEMM
#define G5(GRID, AH, WI, BIAS, RESID, YF, YH, EPI) \
    gemm5<<<GRID, 256, SM_G>>>(AH, WSH + (WI) * 16384, BIAS, RESID, \
                               nullptr, YF, YH, EPI)
#define G5S(GRID, AH, WI, BIAS, PMUL, YH) \
    gemm5<<<GRID, 256, SM_G>>>(AH, WSH + (WI) * 16384, BIAS, nullptr, \
                               PMUL, nullptr, YH, 2)

    // --- Stage A: SR attention per stream (tensor-core path) ---
    for (int s = 0; s < 2; s++) {
        G5(GM, XH[s], 0, bq, nullptr, nullptr, QH, 0);          // q fp16
        conv_mma<<<dim3(8, 64), 256, SM_CONV>>>(XH[s], CWH, PART);
        conv_reduce_ln<<<1024, 128>>>(PART, srb, lnG[s], lnB[s], XLNH);
        G5(4, XLNH, 1, bkv,       nullptr, KB, nullptr, 0);
        G5(4, XLNH, 2, bkv + 128, nullptr, VB, nullptr, 0);
        kv_pack<<<512, 256>>>(KB, VB, KH, VT);
        attn_s<<<dim3(128, 8), 256, SM_S_TOTAL>>>(QH, KH, PB);
        attn_pv<<<dim3(128, 8), 256, SM_PV_TOTAL>>>(PB, VT, XA[s], XAH[s]);
    }

    // --- Stage B + C per stream ---
    for (int s = 0; s < 2; s++) {
        G5(GM, XAH[s],     3, nullptr, nullptr, T0, nullptr, 0);
        G5(GM, XAH[s ^ 1], 4, rjb1,    T0,      nullptr, T1H, 1);
        G5S(GM, T1H,       5, rjb2,    XA[s],   XASH);
        const float* Bb = cabI[s];
        float* bmk = BM + (2 * s) * kC;
        float* bmv = BM + (2 * s + 1) * kC;
        G5(GM, XAH[s],     6 + 3 * s, Bb,       nullptr, nullptr, PT0, 0);
        G5(GM, XAH[s],     7 + 3 * s, bmk,      nullptr, nullptr, PT1, 0);
        G5(GM, XASH,       7 + 3 * s, Bb + 128, nullptr, nullptr, PT2, 0);
        G5(GM, XAH[s],     8 + 3 * s, bmv,      nullptr, nullptr, PT3, 0);
        G5(GM, XAH[s ^ 1], 8 + 3 * s, Bb + 256, nullptr, nullptr, PT4, 0);
        mha2_pw<<<2048, 256>>>(PT0, PT1, PT2, PT3, PT4, T5H);
        G5(GM, T5H, 12 + s, cabO[s], XA[s], nullptr, NSH, 0);
        G5(GM, NSH, 14,     pb,      nullptr, out + (size_t)s * SZ, nullptr, 0);
    }
#undef G5
#undef G5S
}

// round 14
// speedup vs baseline: 3.1397x; 1.0340x over previous
#include <cuda_runtime.h>
#include <cuda_fp16.h>
#include <math.h>
#include <stdint.h>

#define FULLMASK 0xffffffffu

namespace {
constexpr int kB = 4, kN = 16384, kC = 128, kMTOK = 65536, kMR = 1024;
constexpr size_t SZ = (size_t)kMTOK * kC;   // 8,388,608

// fp32 scratch
constexpr size_t O_XA0 = 0;
constexpr size_t O_XA1 = SZ;
constexpr size_t O_PART = 2 * SZ;           // 64*1024*128 == SZ
constexpr size_t O_KB  = 3 * SZ;
constexpr size_t O_VB  = O_KB + 131072;
constexpr size_t O_BM  = O_VB + 131072;
constexpr size_t O_FB  = O_BM + 512;        // fused out biases (2*128)
constexpr size_t TOTF  = O_FB + 512;

// fp16 buffers (element offsets in h_mem)
constexpr size_t H_X0  = 0;
constexpr size_t H_X1  = SZ;
constexpr size_t H_XA0 = 2 * SZ;
constexpr size_t H_XA1 = 3 * SZ;
constexpr size_t H_T1  = 4 * SZ;            // judger hidden
constexpr size_t H_XAS = 5 * SZ;
constexpr size_t H_T5  = 6 * SZ;
constexpr size_t H_XLN = 7 * SZ;                     // 131072
constexpr size_t H_WS  = H_XLN + 131072;             // 15 weight blocks (fp16)
constexpr size_t H_CW  = H_WS + 15 * 16384;          // 64 conv blocks
constexpr size_t H_WJ  = H_CW + 64 * 16384;          // judger W [128][256]
constexpr size_t H_WO  = H_WJ + 32768;               // 2 x [128][256] fused out W
constexpr size_t H_QH  = H_WO + 2 * 32768;           // q fp16 (one stream)
constexpr size_t H_P   = H_QH + SZ;                  // P [8][16384][256] = 4*SZ
constexpr size_t H_KH  = H_P + 4 * SZ;               // K fp16 [8][256][64]
constexpr size_t H_VT  = H_KH + 131072;              // V^T fp16 [8][64][256]
constexpr size_t H_PT0 = H_VT + 131072;              // stage-C fp16 temps
constexpr size_t H_PT1 = H_PT0 + SZ;
constexpr size_t H_PT2 = H_PT1 + SZ;
constexpr size_t H_PT3 = H_PT2 + SZ;
constexpr size_t H_PT4 = H_PT3 + SZ;
constexpr size_t TOTH  = H_PT4 + SZ;

// tile geometry
constexpr int TROW   = 144;                 // bytes per 64-col fp16 row
constexpr int TBYTES = 128 * TROW;          // 18432

// gemm5 smem: B chunk0, B chunk1, A chunk0, A chunk1, 2KB reduce buf
constexpr int SM_B0 = 0;
constexpr int SM_B1 = TBYTES;
constexpr int SM_A0 = 2 * TBYTES;
constexpr int SM_A1 = 3 * TBYTES;
constexpr int SM_RED = 4 * TBYTES;          // 73728
constexpr int SM_G   = SM_RED + 2048;       // 75776

constexpr int SM_G6  = 2 * TBYTES;          // gemm6 streaming (36864)
constexpr int SM_CONV = 2 * TBYTES;
constexpr int SMB_S = TBYTES;
constexpr int SM_S_TOTAL = TBYTES + 256 * TROW;   // 55296
constexpr int SMB_PV = TBYTES;
constexpr int SM_PV_TOTAL = TBYTES + 64 * TROW;   // 27648
}

__device__ float g_mem[TOTF];
__device__ __half h_mem[TOTH];

// ---------------------------------------------------------------------------
__device__ __forceinline__ uint32_t smem_u32(const void* p) {
    uint32_t a;
    asm("{ .reg .u64 t; cvta.to.shared.u64 t, %1; cvt.u32.u64 %0, t; }"
        : "=r"(a) : "l"(p));
    return a;
}
__device__ __forceinline__ uint32_t pack_h2(float a, float b) {
    __half2 h = __floats2half2_rn(a, b);
    return *(uint32_t*)&h;
}
__device__ __forceinline__ void mma16816(float* d, const uint32_t* a,
                                         uint32_t b0, uint32_t b1) {
    asm volatile(
        "mma.sync.aligned.m16n8k16.row.col.f32.f16.f16.f32 "
        "{%0,%1,%2,%3}, {%4,%5,%6,%7}, {%8,%9}, {%0,%1,%2,%3};"
        : "+f"(d[0]), "+f"(d[1]), "+f"(d[2]), "+f"(d[3])
        : "r"(a[0]), "r"(a[1]), "r"(a[2]), "r"(a[3]), "r"(b0), "r"(b1));
}
__device__ __forceinline__ void ldsm4(uint32_t& r0, uint32_t& r1,
                                      uint32_t& r2, uint32_t& r3, uint32_t addr) {
    asm volatile("ldmatrix.sync.aligned.m8n8.x4.shared.b16 {%0,%1,%2,%3}, [%4];"
                 : "=r"(r0), "=r"(r1), "=r"(r2), "=r"(r3) : "r"(addr));
}
__device__ __forceinline__ void cpa16(uint32_t dst, const void* src) {
    asm volatile("cp.async.cg.shared.global [%0], [%1], 16;"
                 :: "r"(dst), "l"(src));
}
__device__ __forceinline__ void cpa_wait() {
    asm volatile("cp.async.commit_group;\ncp.async.wait_group 0;" ::: "memory");
}
__device__ __forceinline__ float dot8h(uint4 a, uint4 b) {
    const __half2* pa = (const __half2*)&a;
    const __half2* pb = (const __half2*)&b;
    float s = 0.0f;
#pragma unroll
    for (int i = 0; i < 4; i++) {
        float2 fa = __half22float2(pa[i]);
        float2 fb = __half22float2(pb[i]);
        s += fa.x * fb.x + fa.y * fb.y;
    }
    return s;
}

// ---------------------------------------------------------------------------
struct FragCtx {
    uint32_t aoff[2];
    uint32_t boff[4];
};
__device__ __forceinline__ FragCtx make_frag_ctx(int lane, int wm, int wn) {
    FragCtx fc;
    const int rA = (lane & 7) + ((lane >> 3) & 1) * 8;
    const int cA = (lane >> 4) * 16;
#pragma unroll
    for (int mt = 0; mt < 2; mt++)
        fc.aoff[mt] = (uint32_t)((wm * 32 + mt * 16 + rA) * TROW + cA);
    const int rB = (lane & 7) + ((lane >> 4) & 1) * 8;
    const int cB = ((lane >> 3) & 1) * 16;
#pragma unroll
    for (int np = 0; np < 4; np++)
        fc.boff[np] = (uint32_t)((wn * 64 + np * 16 + rB) * TROW + cB);
    return fc;
}
__device__ __forceinline__ void mainloop_chunk(uint32_t aBase, uint32_t bBase,
                                               const FragCtx& fc,
                                               float acc[2][8][4]) {
#pragma unroll
    for (int kc = 0; kc < 4; kc++) {
        const uint32_t kb = (uint32_t)kc * 32;
        uint32_t ah[2][4];
#pragma unroll
        for (int mt = 0; mt < 2; mt++)
            ldsm4(ah[mt][0], ah[mt][1], ah[mt][2], ah[mt][3],
                  aBase + fc.aoff[mt] + kb);
#pragma unroll
        for (int np = 0; np < 4; np++) {
            uint32_t b0, b1, b2, b3;
            ldsm4(b0, b1, b2, b3, bBase + fc.boff[np] + kb);
#pragma unroll
            for (int mt = 0; mt < 2; mt++) {
                mma16816(acc[mt][np * 2],     ah[mt], b0, b1);
                mma16816(acc[mt][np * 2 + 1], ah[mt], b2, b3);
            }
        }
    }
}

// ---------------------------------------------------------------------------
// GEMM v5: 256 rows/CTA, resident B, K=128.
// ---------------------------------------------------------------------------
__global__ __launch_bounds__(256, 2) void gemm5(
    const __half* __restrict__ A, const __half* __restrict__ Bw,
    const float* __restrict__ bias, const float* __restrict__ resid,
    const float* __restrict__ postmul,
    float* __restrict__ Yf, __half* __restrict__ Yh, int epi)
{
    extern __shared__ char sm[];
    const uint32_t smb = smem_u32(sm);
    const int tid = threadIdx.x;
    const int lane = tid & 31, wid = tid >> 5;
    const int t4 = lane & 3, r8 = lane >> 2;
    const int wm = wid >> 1, wn = wid & 1;
    const int bm0 = blockIdx.x * 256;
    const FragCtx fc = make_frag_ctx(lane, wm, wn);
    const int pr = tid >> 1, hf = tid & 1;
    const uint32_t so = (uint32_t)(pr * TROW + hf * 64);

#pragma unroll
    for (int ch = 0; ch < 2; ch++) {
        const size_t brow = (size_t)pr * kC + ch * 64 + hf * 32;
        const size_t arow = (size_t)(bm0 + pr) * kC + ch * 64 + hf * 32;
#pragma unroll
        for (int gq = 0; gq < 4; gq++) {
            cpa16(smb + SM_B0 + ch * TBYTES + so + gq * 16, Bw + brow + gq * 8);
            cpa16(smb + SM_A0 + ch * TBYTES + so + gq * 16, A  + arow + gq * 8);
        }
    }
    cpa_wait();
    __syncthreads();

    float* redm = (float*)(sm + SM_RED);
    float* reds = (float*)(sm + SM_RED + 1024);

    for (int mt = 0; mt < 2; mt++) {
        const int bm = bm0 + mt * 128;
        float acc[2][8][4];
#pragma unroll
        for (int mp = 0; mp < 2; mp++)
#pragma unroll
            for (int nt = 0; nt < 8; nt++)
#pragma unroll
                for (int e = 0; e < 4; e++) acc[mp][nt][e] = 0.0f;

        mainloop_chunk(smb + SM_A0, smb + SM_B0, fc, acc);
        mainloop_chunk(smb + SM_A1, smb + SM_B1, fc, acc);
        __syncthreads();

        if (mt == 0) {
#pragma unroll
            for (int ch = 0; ch < 2; ch++) {
                const size_t arow = (size_t)(bm0 + 128 + pr) * kC + ch * 64 + hf * 32;
#pragma unroll
                for (int gq = 0; gq < 4; gq++)
                    cpa16(smb + SM_A0 + ch * TBYTES + so + gq * 16, A + arow + gq * 8);
            }
        }

        if (bias) {
#pragma unroll
            for (int nt = 0; nt < 8; nt++) {
                float2 bv = *(const float2*)(bias + wn * 64 + nt * 8 + 2 * t4);
#pragma unroll
                for (int mp = 0; mp < 2; mp++) {
                    acc[mp][nt][0] += bv.x; acc[mp][nt][1] += bv.y;
                    acc[mp][nt][2] += bv.x; acc[mp][nt][3] += bv.y;
                }
            }
        }

        if (epi != 2) {
#pragma unroll
            for (int mp = 0; mp < 2; mp++)
#pragma unroll
                for (int p = 0; p < 2; p++) {
                    const int r = bm + wm * 32 + mp * 16 + r8 + p * 8;
#pragma unroll
                    for (int nt = 0; nt < 8; nt++) {
                        const int c = wn * 64 + nt * 8 + 2 * t4;
                        float v0 = acc[mp][nt][2 * p];
                        float v1 = acc[mp][nt][2 * p + 1];
                        if (resid) {
                            float2 rv = *(const float2*)(resid + (size_t)r * kC + c);
                            v0 += rv.x; v1 += rv.y;
                        }
                        if (epi == 1) {
                            v0 = 0.5f * v0 * (1.0f + erff(v0 * 0.70710678118654752f));
                            v1 = 0.5f * v1 * (1.0f + erff(v1 * 0.70710678118654752f));
                        }
                        if (Yf)
                            *(float2*)(Yf + (size_t)r * kC + c) = make_float2(v0, v1);
                        if (Yh)
                            *(uint32_t*)(Yh + (size_t)r * kC + c) = pack_h2(v0, v1);
                    }
                }
        } else {
            float pm[2][2];
#pragma unroll
            for (int mp = 0; mp < 2; mp++) {
                float a0 = -1e30f, a1 = -1e30f;
#pragma unroll
                for (int nt = 0; nt < 8; nt++) {
                    a0 = fmaxf(a0, fmaxf(acc[mp][nt][0], acc[mp][nt][1]));
                    a1 = fmaxf(a1, fmaxf(acc[mp][nt][2], acc[mp][nt][3]));
                }
                pm[mp][0] = a0; pm[mp][1] = a1;
            }
#pragma unroll
            for (int mp = 0; mp < 2; mp++)
#pragma unroll
                for (int p = 0; p < 2; p++) {
                    pm[mp][p] = fmaxf(pm[mp][p], __shfl_xor_sync(FULLMASK, pm[mp][p], 1));
                    pm[mp][p] = fmaxf(pm[mp][p], __shfl_xor_sync(FULLMASK, pm[mp][p], 2));
                }
            if (t4 == 0) {
#pragma unroll
                for (int mp = 0; mp < 2; mp++)
#pragma unroll
                    for (int p = 0; p < 2; p++)
                        redm[(wm * 32 + mp * 16 + r8 + p * 8) * 2 + wn] = pm[mp][p];
            }
            __syncthreads();
            float M[2][2], ps[2][2];
#pragma unroll
            for (int mp = 0; mp < 2; mp++)
#pragma unroll
                for (int p = 0; p < 2; p++) {
                    const int lr = wm * 32 + mp * 16 + r8 + p * 8;
                    M[mp][p] = fmaxf(redm[lr * 2], redm[lr * 2 + 1]);
                    ps[mp][p] = 0.0f;
                }
#pragma unroll
            for (int mp = 0; mp < 2; mp++)
#pragma unroll
                for (int nt = 0; nt < 8; nt++) {
                    acc[mp][nt][0] = __expf(acc[mp][nt][0] - M[mp][0]);
                    acc[mp][nt][1] = __expf(acc[mp][nt][1] - M[mp][0]);
                    acc[mp][nt][2] = __expf(acc[mp][nt][2] - M[mp][1]);
                    acc[mp][nt][3] = __expf(acc[mp][nt][3] - M[mp][1]);
                    ps[mp][0] += acc[mp][nt][0] + acc[mp][nt][1];
                    ps[mp][1] += acc[mp][nt][2] + acc[mp][nt][3];
                }
#pragma unroll
            for (int mp = 0; mp < 2; mp++)
#pragma unroll
                for (int p = 0; p < 2; p++) {
                    ps[mp][p] += __shfl_xor_sync(FULLMASK, ps[mp][p], 1);
                    ps[mp][p] += __shfl_xor_sync(FULLMASK, ps[mp][p], 2);
                }
            if (t4 == 0) {
#pragma unroll
                for (int mp = 0; mp < 2; mp++)
#pragma unroll
                    for (int p = 0; p < 2; p++)
                        reds[(wm * 32 + mp * 16 + r8 + p * 8) * 2 + wn] = ps[mp][p];
            }
            __syncthreads();
#pragma unroll
            for (int mp = 0; mp < 2; mp++)
#pragma unroll
                for (int p = 0; p < 2; p++) {
                    const int lr = wm * 32 + mp * 16 + r8 + p * 8;
                    const float inv = 1.0f / (reds[lr * 2] + reds[lr * 2 + 1]);
                    const size_t gr = (size_t)(bm + lr) * kC;
#pragma unroll
                    for (int nt = 0; nt < 8; nt++) {
                        const int c = wn * 64 + nt * 8 + 2 * t4;
                        float2 pmv = *(const float2*)(postmul + gr + c);
                        float v0 = acc[mp][nt][2 * p]     * inv * pmv.x;
                        float v1 = acc[mp][nt][2 * p + 1] * inv * pmv.y;
                        *(uint32_t*)(Yh + gr + c) = pack_h2(v0, v1);
                    }
                }
        }

        if (mt == 0) {
            cpa_wait();
            __syncthreads();
        }
    }
}

// ---------------------------------------------------------------------------
// GEMM v6: K=256 over two A sources. B is [128][256] fp16 row-major.
// Y = epi(concat(A1,A2) @ B^T + bias). epi 0: none, 1: GELU.
// ---------------------------------------------------------------------------
__global__ __launch_bounds__(256, 2) void gemm6(
    const __half* __restrict__ A1, const __half* __restrict__ A2,
    const __half* __restrict__ Bw, const float* __restrict__ bias,
    float* __restrict__ Yf, __half* __restrict__ Yh, int epi)
{
    extern __shared__ char sm[];
    const uint32_t smb = smem_u32(sm);
    const int tid = threadIdx.x;
    const int lane = tid & 31, wid = tid >> 5;
    const int t4 = lane & 3, r8 = lane >> 2;
    const int wm = wid >> 1, wn = wid & 1;
    const int bm = blockIdx.x * 128;
    const FragCtx fc = make_frag_ctx(lane, wm, wn);
    const int pr = tid >> 1, hf = tid & 1;
    const uint32_t so = (uint32_t)(pr * TROW + hf * 64);

    float acc[2][8][4];
#pragma unroll
    for (int mp = 0; mp < 2; mp++)
#pragma unroll
        for (int nt = 0; nt < 8; nt++)
#pragma unroll
            for (int e = 0; e < 4; e++) acc[mp][nt][e] = 0.0f;

    for (int ch = 0; ch < 4; ch++) {
        const __half* A = (ch < 2) ? A1 : A2;
        const int acol = (ch & 1) * 64;
        const size_t arow = (size_t)(bm + pr) * kC + acol + hf * 32;
        const size_t brow = (size_t)pr * 256 + ch * 64 + hf * 32;
#pragma unroll
        for (int gq = 0; gq < 4; gq++) {
            cpa16(smb + so + gq * 16,          A  + arow + gq * 8);
            cpa16(smb + TBYTES + so + gq * 16, Bw + brow + gq * 8);
        }
        cpa_wait();
        __syncthreads();
        mainloop_chunk(smb, smb + TBYTES, fc, acc);
        __syncthreads();
    }

#pragma unroll
    for (int mp = 0; mp < 2; mp++)
#pragma unroll
        for (int p = 0; p < 2; p++) {
            const int r = bm + wm * 32 + mp * 16 + r8 + p * 8;
#pragma unroll
            for (int nt = 0; nt < 8; nt++) {
                const int c = wn * 64 + nt * 8 + 2 * t4;
                float v0 = acc[mp][nt][2 * p];
                float v1 = acc[mp][nt][2 * p + 1];
                if (bias) {
                    float2 bv = *(const float2*)(bias + c);
                    v0 += bv.x; v1 += bv.y;
                }
                if (epi == 1) {
                    v0 = 0.5f * v0 * (1.0f + erff(v0 * 0.70710678118654752f));
                    v1 = 0.5f * v1 * (1.0f + erff(v1 * 0.70710678118654752f));
                }
                if (Yf)
                    *(float2*)(Yf + (size_t)r * kC + c) = make_float2(v0, v1);
                if (Yh)
                    *(uint32_t*)(Yh + (size_t)r * kC + c) = pack_h2(v0, v1);
            }
        }
}

// ---------------------------------------------------------------------------
__global__ __launch_bounds__(256, 2) void conv_mma(
    const __half* __restrict__ xh, const __half* __restrict__ cwh,
    float* __restrict__ part)
{
    extern __shared__ char sm[];
    const uint32_t smb = smem_u32(sm);
    const int tid = threadIdx.x;
    const int lane = tid & 31, wid = tid >> 5;
    const int t4 = lane & 3, r8 = lane >> 2;
    const int wm = wid >> 1, wn = wid & 1;
    const int b = blockIdx.x >> 1, rt = blockIdx.x & 1, pos = blockIdx.y;
    const FragCtx fc = make_frag_ctx(lane, wm, wn);

    float acc[2][8][4];
#pragma unroll
    for (int mt = 0; mt < 2; mt++)
#pragma unroll
        for (int nt = 0; nt < 8; nt++)
#pragma unroll
            for (int e = 0; e < 4; e++) acc[mt][nt][e] = 0.0f;

    const int pr = tid >> 1, hf = tid & 1;
    const int p = rt * 128 + pr;
    const int ph = p >> 4, pwd = p & 15;
    const int kh = pos >> 3, kw = pos & 7;
    const size_t xrow = ((size_t)b * kN + (ph * 8 + kh) * 128 + pwd * 8 + kw) * kC;
    const size_t wbase = (size_t)pos * 16384 + (size_t)pr * kC;

    for (int ch = 0; ch < 2; ch++) {
        const size_t arow = xrow + ch * 64 + hf * 32;
        const size_t brow = wbase + ch * 64 + hf * 32;
        const uint32_t so = (uint32_t)(pr * TROW + hf * 64);
#pragma unroll
        for (int gq = 0; gq < 4; gq++) {
            cpa16(smb + so + gq * 16,          xh  + arow + gq * 8);
            cpa16(smb + TBYTES + so + gq * 16, cwh + brow + gq * 8);
        }
        cpa_wait();
        __syncthreads();
        mainloop_chunk(smb, smb + TBYTES, fc, acc);
        __syncthreads();
    }

    const size_t base = ((size_t)pos * kMR + (size_t)b * 256 + rt * 128) * kC;
#pragma unroll
    for (int mt = 0; mt < 2; mt++)
#pragma unroll
        for (int pq = 0; pq < 2; pq++) {
            const int lr = wm * 32 + mt * 16 + r8 + pq * 8;
#pragma unroll
            for (int nt = 0; nt < 8; nt++) {
                const int c = wn * 64 + nt * 8 + 2 * t4;
                *(float2*)(part + base + (size_t)lr * kC + c) =
                    make_float2(acc[mt][nt][2 * pq], acc[mt][nt][2 * pq + 1]);
            }
        }
}

// ---------------------------------------------------------------------------
__global__ void conv_reduce_ln(const float* __restrict__ part,
                               const float* __restrict__ srb,
                               const float* __restrict__ gam,
                               const float* __restrict__ bet,
                               __half* __restrict__ xlnh)
{
    const int row = blockIdx.x;
    const int c = threadIdx.x;
    float v = srb[c];
#pragma unroll 8
    for (int sp = 0; sp < 64; sp++)
        v += part[((size_t)sp * kMR + row) * kC + c];

    __shared__ float red[4];
    float s = v;
#pragma unroll
    for (int o = 16; o > 0; o >>= 1) s += __shfl_xor_sync(FULLMASK, s, o);
    if ((c & 31) == 0) red[c >> 5] = s;
    __syncthreads();
    const float mean = (red[0] + red[1] + red[2] + red[3]) * (1.0f / 128.0f);
    __syncthreads();
    const float d = v - mean;
    float s2 = d * d;
#pragma unroll
    for (int o = 16; o > 0; o >>= 1) s2 += __shfl_xor_sync(FULLMASK, s2, o);
    if ((c & 31) == 0) red[c >> 5] = s2;
    __syncthreads();
    const float var = (red[0] + red[1] + red[2] + red[3]) * (1.0f / 128.0f);
    xlnh[(size_t)row * kC + c] =
        __float2half_rn(d * rsqrtf(var + 1e-5f) * gam[c] + bet[c]);
}

// ---------------------------------------------------------------------------
__global__ void kv_pack(const float* __restrict__ KB, const float* __restrict__ VB,
                        __half* __restrict__ Kh, __half* __restrict__ Vt)
{
    const int idx = blockIdx.x * 256 + threadIdx.x;
    const int b = idx >> 15, rem = idx & 32767;
    const int m = rem >> 7, c = rem & 127;
    const int h = c >> 6, d = c & 63;
    const int bh = b * 2 + h;
    Kh[((size_t)bh * 256 + m) * 64 + d] = __float2half_rn(KB[idx]);
    Vt[((size_t)bh * 64 + d) * 256 + m] = __float2half_rn(VB[idx]);
}

// ---------------------------------------------------------------------------
__global__ __launch_bounds__(256, 1) void attn_s(
    const __half* __restrict__ Qh, const __half* __restrict__ Kh,
    __half* __restrict__ P)
{
    extern __shared__ char sm[];
    const uint32_t smb = smem_u32(sm);
    const int tid = threadIdx.x;
    const int lane = tid & 31, wid = tid >> 5;
    const int t4 = lane & 3, r8 = lane >> 2;
    const int bh = blockIdx.y;
    const int b = bh >> 1, h = bh & 1;
    const int qt = blockIdx.x;

    const int rA = (lane & 7) + ((lane >> 3) & 1) * 8;
    const int cA = (lane >> 4) * 16;
    const uint32_t aoff = (uint32_t)((wid * 16 + rA) * TROW + cA);
    const int rB = (lane & 7) + ((lane >> 4) & 1) * 8;
    const int cB = ((lane >> 3) & 1) * 16;
    const uint32_t boffb = (uint32_t)(rB * TROW + cB);

    {
        const int pr = tid >> 1, hf = tid & 1;
        const __half* qsrc = Qh +
            ((size_t)(b * kN + qt * 128 + pr) * kC + h * 64 + hf * 32);
        const uint32_t so = (uint32_t)(pr * TROW + hf * 64);
#pragma unroll
        for (int gq = 0; gq < 4; gq++)
            cpa16(smb + so + gq * 16, qsrc + gq * 8);
        const __half* ksrc = Kh + ((size_t)bh * 256 + tid) * 64;
        const uint32_t sob = (uint32_t)(tid * TROW);
#pragma unroll
        for (int gq = 0; gq < 8; gq++)
            cpa16(smb + SMB_S + sob + gq * 16, ksrc + gq * 8);
    }
    cpa_wait();
    __syncthreads();

    float acc[32][4];
#pragma unroll
    for (int nt = 0; nt < 32; nt++)
#pragma unroll
        for (int e = 0; e < 4; e++) acc[nt][e] = 0.0f;

#pragma unroll
    for (int kc = 0; kc < 4; kc++) {
        uint32_t af[4];
        ldsm4(af[0], af[1], af[2], af[3], smb + aoff + kc * 32);
#pragma unroll
        for (int np = 0; np < 16; np++) {
            uint32_t b0, b1, b2, b3;
            ldsm4(b0, b1, b2, b3, smb + SMB_S + boffb + np * (16 * TROW) + kc * 32);
            mma16816(acc[np * 2],     af, b0, b1);
            mma16816(acc[np * 2 + 1], af, b2, b3);
        }
    }

    float mx0 = -1e30f, mx1 = -1e30f;
#pragma unroll
    for (int nt = 0; nt < 32; nt++) {
#pragma unroll
        for (int e = 0; e < 4; e++) acc[nt][e] *= 0.125f;
        mx0 = fmaxf(mx0, fmaxf(acc[nt][0], acc[nt][1]));
        mx1 = fmaxf(mx1, fmaxf(acc[nt][2], acc[nt][3]));
    }
    mx0 = fmaxf(mx0, __shfl_xor_sync(FULLMASK, mx0, 1));
    mx0 = fmaxf(mx0, __shfl_xor_sync(FULLMASK, mx0, 2));
    mx1 = fmaxf(mx1, __shfl_xor_sync(FULLMASK, mx1, 1));
    mx1 = fmaxf(mx1, __shfl_xor_sync(FULLMASK, mx1, 2));
    float s0 = 0.0f, s1 = 0.0f;
#pragma unroll
    for (int nt = 0; nt < 32; nt++) {
        acc[nt][0] = __expf(acc[nt][0] - mx0);
        acc[nt][1] = __expf(acc[nt][1] - mx0);
        acc[nt][2] = __expf(acc[nt][2] - mx1);
        acc[nt][3] = __expf(acc[nt][3] - mx1);
        s0 += acc[nt][0] + acc[nt][1];
        s1 += acc[nt][2] + acc[nt][3];
    }
    s0 += __shfl_xor_sync(FULLMASK, s0, 1);
    s0 += __shfl_xor_sync(FULLMASK, s0, 2);
    s1 += __shfl_xor_sync(FULLMASK, s1, 1);
    s1 += __shfl_xor_sync(FULLMASK, s1, 2);
    const float i0 = 1.0f / s0, i1 = 1.0f / s1;

    const size_t p0 = ((size_t)bh * kN + qt * 128 + wid * 16 + r8) * 256;
    const size_t p1 = p0 + 8 * 256;
#pragma unroll
    for (int nt = 0; nt < 32; nt++) {
        const int c = nt * 8 + 2 * t4;
        *(uint32_t*)(P + p0 + c) = pack_h2(acc[nt][0] * i0, acc[nt][1] * i0);
        *(uint32_t*)(P + p1 + c) = pack_h2(acc[nt][2] * i1, acc[nt][3] * i1);
    }
}

// ---------------------------------------------------------------------------
__global__ __launch_bounds__(256, 2) void attn_pv(
    const __half* __restrict__ P, const __half* __restrict__ Vt,
    float* __restrict__ XA, __half* __restrict__ XAh)
{
    extern __shared__ char sm[];
    const uint32_t smb = smem_u32(sm);
    const int tid = threadIdx.x;
    const int lane = tid & 31, wid = tid >> 5;
    const int t4 = lane & 3, r8 = lane >> 2;
    const int wm = wid >> 1, wn = wid & 1;
    const int bh = blockIdx.y;
    const int b = bh >> 1, h = bh & 1;
    const int qt = blockIdx.x;

    const int rA = (lane & 7) + ((lane >> 3) & 1) * 8;
    const int cA = (lane >> 4) * 16;
    uint32_t aoff[2];
#pragma unroll
    for (int mt = 0; mt < 2; mt++)
        aoff[mt] = (uint32_t)((wm * 32 + mt * 16 + rA) * TROW + cA);
    const int rB = (lane & 7) + ((lane >> 4) & 1) * 8;
    const int cB = ((lane >> 3) & 1) * 16;
    uint32_t boff[2];
#pragma unroll
    for (int np = 0; np < 2; np++)
        boff[np] = (uint32_t)((wn * 32 + np * 16 + rB) * TROW + cB);

    float acc[2][4][4];
#pragma unroll
    for (int mt = 0; mt < 2; mt++)
#pragma unroll
        for (int nt = 0; nt < 4; nt++)
#pragma unroll
            for (int e = 0; e < 4; e++) acc[mt][nt][e] = 0.0f;

    const int pr = tid >> 1, hf = tid & 1;

    for (int ch = 0; ch < 4; ch++) {
        const __half* asrc = P +
            (((size_t)bh * kN + qt * 128 + pr) * 256 + ch * 64 + hf * 32);
        const uint32_t so = (uint32_t)(pr * TROW + hf * 64);
#pragma unroll
        for (int gq = 0; gq < 4; gq++)
            cpa16(smb + so + gq * 16, asrc + gq * 8);
        if (tid < 128) {
            const int d = tid >> 1, hfb = tid & 1;
            const __half* vsrc = Vt +
                (((size_t)bh * 64 + d) * 256 + ch * 64 + hfb * 32);
            const uint32_t sob = (uint32_t)(d * TROW + hfb * 64);
#pragma unroll
            for (int gq = 0; gq < 4; gq++)
                cpa16(smb + SMB_PV + sob + gq * 16, vsrc + gq * 8);
        }
        cpa_wait();
        __syncthreads();
#pragma unroll
        for (int kc = 0; kc < 4; kc++) {
            const uint32_t kb = (uint32_t)kc * 32;
            uint32_t ah[2][4];
#pragma unroll
            for (int mt = 0; mt < 2; mt++)
                ldsm4(ah[mt][0], ah[mt][1], ah[mt][2], ah[mt][3],
                      smb + aoff[mt] + kb);
#pragma unroll
            for (int np = 0; np < 2; np++) {
                uint32_t b0, b1, b2, b3;
                ldsm4(b0, b1, b2, b3, smb + SMB_PV + boff[np] + kb);
#pragma unroll
                for (int mt = 0; mt < 2; mt++) {
                    mma16816(acc[mt][np * 2],     ah[mt], b0, b1);
                    mma16816(acc[mt][np * 2 + 1], ah[mt], b2, b3);
                }
            }
        }
        __syncthreads();
    }

#pragma unroll
    for (int mt = 0; mt < 2; mt++)
#pragma unroll
        for (int p = 0; p < 2; p++) {
            const int lr = qt * 128 + wm * 32 + mt * 16 + r8 + p * 8;
            const size_t g = ((size_t)b * kN + lr) * kC + h * 64;
#pragma unroll
            for (int nt = 0; nt < 4; nt++) {
                const int c = wn * 32 + nt * 8 + 2 * t4;
                float v0 = acc[mt][nt][2 * p];
                float v1 = acc[mt][nt][2 * p + 1];
                *(float2*)(XA + g + c) = make_float2(v0, v1);
                *(uint32_t*)(XAh + g + c) = pack_h2(v0, v1);
            }
        }
}

// ---------------------------------------------------------------------------
__global__ __launch_bounds__(256) void mha2_pw(
    const __half* __restrict__ qp, const __half* __restrict__ k0,
    const __half* __restrict__ k1, const __half* __restrict__ v0,
    const __half* __restrict__ v1, __half* __restrict__ oh)
{
    const int idx = blockIdx.x * 256 + threadIdx.x;
    const size_t base = (size_t)(idx >> 3) * kC + (idx & 7) * 16;
    const uint4* qg  = (const uint4*)(qp + base);
    const uint4* k0g = (const uint4*)(k0 + base);
    const uint4* k1g = (const uint4*)(k1 + base);
    uint4 qa = qg[0], qb = qg[1];
    float s0 = dot8h(qa, k0g[0]) + dot8h(qb, k0g[1]);
    float s1 = dot8h(qa, k1g[0]) + dot8h(qb, k1g[1]);
    s0 *= 0.25f; s1 *= 0.25f;
    const float m = fmaxf(s0, s1);
    float e0 = __expf(s0 - m), e1 = __expf(s1 - m);
    const float inv = 1.0f / (e0 + e1);
    e0 *= inv; e1 *= inv;
    const uint4* v0g = (const uint4*)(v0 + base);
    const uint4* v1g = (const uint4*)(v1 + base);
    uint4* ohg = (uint4*)(oh + base);
#pragma unroll
    for (int t = 0; t < 2; t++) {
        uint4 a = v0g[t], bb = v1g[t];
        const __half2* pa = (const __half2*)&a;
        const __half2* pb = (const __half2*)&bb;
        uint4 o;
        uint32_t* po = (uint32_t*)&o;
#pragma unroll
        for (int i = 0; i < 4; i++) {
            float2 fa = __half22float2(pa[i]);
            float2 fb = __half22float2(pb[i]);
            po[i] = pack_h2(e0 * fa.x + e1 * fb.x, e0 * fa.y + e1 * fb.y);
        }
        ohg[t] = o;
    }
}

// ---------------------------------------------------------------------------
__global__ void cvt_half(const float* __restrict__ src, __half* __restrict__ dst)
{
    const int i = blockIdx.x * 256 + threadIdx.x;
    float4 v = ((const float4*)src)[i];
    ((uint2*)dst)[i] = make_uint2(pack_h2(v.x, v.y), pack_h2(v.z, v.w));
}

__global__ void cvt_w(const float* __restrict__ src, int ldW,
                      __half* __restrict__ dh)
{
    const int i = blockIdx.x * 256 + threadIdx.x;
    const int o = i >> 6, k = (i & 63) * 2;
    *(uint32_t*)(dh + o * kC + k) =
        pack_h2(src[(size_t)o * ldW + k], src[(size_t)o * ldW + k + 1]);
}

// judger weight [128][256] fp16, direct
__global__ void cvt_w256(const float* __restrict__ src, __half* __restrict__ dh)
{
    const int i = blockIdx.x * 256 + threadIdx.x;   // 16384 pairs
    const int o = i >> 7, k = (i & 127) * 2;
    *(uint32_t*)(dh + o * 256 + k) =
        pack_h2(src[(size_t)o * 256 + k], src[(size_t)o * 256 + k + 1]);
}

__global__ void cvt_convw(const float* __restrict__ srw, __half* __restrict__ dh)
{
    const int t = blockIdx.x * 256 + threadIdx.x;
    const int pos = t >> 13, o = (t >> 6) & 127, i2 = (t & 63) * 2;
    const size_t d = (size_t)pos * 16384 + (size_t)o * kC + i2;
    *(uint32_t*)(dh + d) =
        pack_h2(srw[(size_t)o * 8192 + i2 * 64 + pos],
                srw[(size_t)o * 8192 + (i2 + 1) * 64 + pos]);
}

// fused out weight: WO[o][0:128] = pw[o][:], WO[o][128+j] = sum_c pw[o][c]*cawO[c][j]
__global__ void fuse_out_w(const float* __restrict__ pw,
                           const float* __restrict__ cawO,
                           __half* __restrict__ WO)
{
    const int i = blockIdx.x * 256 + threadIdx.x;   // 16384
    const int o = i >> 7, j = i & 127;
    float acc = 0.0f;
    for (int c = 0; c < 128; c++)
        acc += pw[(size_t)o * 128 + c] * cawO[(size_t)c * 128 + j];
    WO[(size_t)o * 256 + j]       = __float2half_rn(pw[(size_t)o * 128 + j]);
    WO[(size_t)o * 256 + 128 + j] = __float2half_rn(acc);
}

// fused out bias: fb[o] = pb[o] + sum_c pw[o][c]*cabO[c]
__global__ void fuse_out_b(const float* __restrict__ pw,
                           const float* __restrict__ cabO,
                           const float* __restrict__ pb,
                           float* __restrict__ fb)
{
    const int o = threadIdx.x;
    float acc = pb[o];
    for (int c = 0; c < 128; c++) acc += pw[(size_t)o * 128 + c] * cabO[c];
    fb[o] = acc;
}

__global__ void fold_bias(
    const float* __restrict__ w01, const float* __restrict__ b01,
    const float* __restrict__ w10, const float* __restrict__ b10,
    const float* __restrict__ kn, const float* __restrict__ vn,
    float* __restrict__ bm)
{
    const int which = blockIdx.x, c = threadIdx.x;
    const float* W  = (which < 2) ? w01 : w10;
    const float* Bb = (which < 2) ? b01 : b10;
    const float* nz = ((which & 1) ? vn : kn) + (which >> 1) * kC;
    const int off = (which & 1) ? 256 : 128;
    float acc = Bb[off + c];
    const float* wr = W + (size_t)(off + c) * kC;
    for (int k = 0; k < kC; k++) acc += nz[k] * wr[k];
    bm[which * kC + c] = acc;
}

// ---------------------------------------------------------------------------
extern "C" void kernel_launch(void* const* d_in, const int* in_sizes, int n_in,
                              void* d_out, int out_size)
{
    (void)in_sizes; (void)n_in; (void)out_size;
    const float* x0   = (const float*)d_in[0];
    const float* x1   = (const float*)d_in[1];
    const float* Wq   = (const float*)d_in[2];
    const float* bq   = (const float*)d_in[3];
    const float* Wkv  = (const float*)d_in[4];
    const float* bkv  = (const float*)d_in[5];
    const float* srw  = (const float*)d_in[6];
    const float* srb  = (const float*)d_in[7];
    const float* lnG[2] = {(const float*)d_in[8],  (const float*)d_in[10]};
    const float* lnB[2] = {(const float*)d_in[9],  (const float*)d_in[11]};
    const float* cawI[2] = {(const float*)d_in[12], (const float*)d_in[16]};
    const float* cabI[2] = {(const float*)d_in[13], (const float*)d_in[17]};
    const float* cawO[2] = {(const float*)d_in[14], (const float*)d_in[18]};
    const float* cabO[2] = {(const float*)d_in[15], (const float*)d_in[19]};
    const float* rjw1 = (const float*)d_in[20];
    const float* rjb1 = (const float*)d_in[21];
    const float* rjw2 = (const float*)d_in[22];
    const float* rjb2 = (const float*)d_in[23];
    const float* kn   = (const float*)d_in[24];
    const float* vn   = (const float*)d_in[25];
    const float* pw   = (const float*)d_in[26];
    const float* pb   = (const float*)d_in[27];
    float* out = (float*)d_out;

    float* g = nullptr;
    cudaGetSymbolAddress((void**)&g, g_mem);
    __half* hm = nullptr;
    cudaGetSymbolAddress((void**)&hm, h_mem);

    float* XA[2] = {g + O_XA0, g + O_XA1};
    float *PART = g + O_PART, *KBp = g + O_KB, *VBp = g + O_VB;
    float *BM = g + O_BM, *FB = g + O_FB;

    __half *XH[2]  = {hm + H_X0, hm + H_X1};
    __half *XAH[2] = {hm + H_XA0, hm + H_XA1};
    __half *T1H = hm + H_T1, *XASH = hm + H_XAS, *T5H = hm + H_T5;
    __half *XLNH = hm + H_XLN;
    __half *WSH = hm + H_WS, *CWH = hm + H_CW;
    __half *WJH = hm + H_WJ;
    __half *WOH[2] = {hm + H_WO, hm + H_WO + 32768};
    __half *QH = hm + H_QH, *PB = hm + H_P;
    __half *KH = hm + H_KH, *VT = hm + H_VT;
    __half *PT0 = hm + H_PT0, *PT1 = hm + H_PT1, *PT2 = hm + H_PT2;
    __half *PT3 = hm + H_PT3, *PT4 = hm + H_PT4;

    cudaFuncSetAttribute(gemm5, cudaFuncAttributeMaxDynamicSharedMemorySize, SM_G);
    cudaFuncSetAttribute(gemm6, cudaFuncAttributeMaxDynamicSharedMemorySize, SM_G6);
    cudaFuncSetAttribute(conv_mma, cudaFuncAttributeMaxDynamicSharedMemorySize, SM_CONV);
    cudaFuncSetAttribute(attn_s, cudaFuncAttributeMaxDynamicSharedMemorySize, SM_S_TOTAL);
    cudaFuncSetAttribute(attn_pv, cudaFuncAttributeMaxDynamicSharedMemorySize, SM_PV_TOTAL);

    // --- one-time prep ---
    fold_bias<<<4, 128>>>(cawI[0], cabI[0], cawI[1], cabI[1], kn, vn, BM);
    cvt_half<<<8192, 256>>>(x0, XH[0]);
    cvt_half<<<8192, 256>>>(x1, XH[1]);
    cvt_convw<<<2048, 256>>>(srw, CWH);
    cvt_w256<<<64, 256>>>(rjw1, WJH);
    fuse_out_w<<<64, 256>>>(pw, cawO[0], WOH[0]);
    fuse_out_w<<<64, 256>>>(pw, cawO[1], WOH[1]);
    fuse_out_b<<<1, 128>>>(pw, cabO[0], pb, FB);
    fuse_out_b<<<1, 128>>>(pw, cabO[1], pb, FB + 128);
#define SW(SRC, LD, IDX) cvt_w<<<32, 256>>>(SRC, LD, WSH + (IDX) * 16384)
    SW(Wq, 128, 0);
    SW(Wkv, 128, 1);          SW(Wkv + 16384, 128, 2);
    SW(rjw2, 128, 5);
    SW(cawI[0], 128, 6);      SW(cawI[0] + 16384, 128, 7);  SW(cawI[0] + 32768, 128, 8);
    SW(cawI[1], 128, 9);      SW(cawI[1] + 16384, 128, 10); SW(cawI[1] + 32768, 128, 11);
#undef SW

    const int GM = kMTOK / 256;   // gemm5 grid
    const int G6M = kMTOK / 128;  // gemm6 grid
#define G5(GRID, AH, WI, BIAS, RESID, YF, YH, EPI) \
    gemm5<<<GRID, 256, SM_G>>>(AH, WSH + (WI) * 16384, BIAS, RESID, \
                               nullptr, YF, YH, EPI)
#define G5S(GRID, AH, WI, BIAS, PMUL, YH) \
    gemm5<<<GRID, 256, SM_G>>>(AH, WSH + (WI) * 16384, BIAS, nullptr, \
                               PMUL, nullptr, YH, 2)

    // --- Stage A: SR attention per stream ---
    for (int s = 0; s < 2; s++) {
        G5(GM, XH[s], 0, bq, nullptr, nullptr, QH, 0);
        conv_mma<<<dim3(8, 64), 256, SM_CONV>>>(XH[s], CWH, PART);
        conv_reduce_ln<<<1024, 128>>>(PART, srb, lnG[s], lnB[s], XLNH);
        G5(4, XLNH, 1, bkv,       nullptr, KBp, nullptr, 0);
        G5(4, XLNH, 2, bkv + 128, nullptr, VBp, nullptr, 0);
        kv_pack<<<512, 256>>>(KBp, VBp, KH, VT);
        attn_s<<<dim3(128, 8), 256, SM_S_TOTAL>>>(QH, KH, PB);
        attn_pv<<<dim3(128, 8), 256, SM_PV_TOTAL>>>(PB, VT, XA[s], XAH[s]);
    }

    // --- Stage B + C per stream ---
    for (int s = 0; s < 2; s++) {
        // fused judger first layer: T1 = GELU([XA_s | XA_s^1] @ rjw1^T + rjb1)
        gemm6<<<G6M, 256, SM_G6>>>(XAH[s], XAH[s ^ 1], WJH, rjb1,
                                   nullptr, T1H, 1);
        G5S(GM, T1H, 5, rjb2, XA[s], XASH);
        const float* Bb = cabI[s];
        float* bmk = BM + (2 * s) * kC;
        float* bmv = BM + (2 * s + 1) * kC;
        G5(GM, XAH[s],     6 + 3 * s, Bb,       nullptr, nullptr, PT0, 0);
        G5(GM, XAH[s],     7 + 3 * s, bmk,      nullptr, nullptr, PT1, 0);
        G5(GM, XASH,       7 + 3 * s, Bb + 128, nullptr, nullptr, PT2, 0);
        G5(GM, XAH[s],     8 + 3 * s, bmv,      nullptr, nullptr, PT3, 0);
        G5(GM, XAH[s ^ 1], 8 + 3 * s, Bb + 256, nullptr, nullptr, PT4, 0);
        mha2_pw<<<2048, 256>>>(PT0, PT1, PT2, PT3, PT4, T5H);
        // fused residual + out-proj + final-proj:
        // out = [XA_s | T5] @ [pw | pw@cawO]^T + (pb + pw@cabO)
        gemm6<<<G6M, 256, SM_G6>>>(XAH[s], T5H, WOH[s], FB + s * 128,
                                   out + (size_t)s * SZ, nullptr, 0);
    }
#undef G5
#undef G5S
}

// round 15
// speedup vs baseline: 3.3631x; 1.0711x over previous
#include <cuda_runtime.h>
#include <cuda_fp16.h>
#include <math.h>
#include <stdint.h>

#define FULLMASK 0xffffffffu

namespace {
constexpr int kB = 4, kN = 16384, kC = 128, kMTOK = 65536, kMR = 1024;
constexpr size_t SZ = (size_t)kMTOK * kC;   // 8,388,608

// fp32 scratch
constexpr size_t O_PART = 0;                 // 8*1024*128 = 1,048,576
constexpr size_t O_KB  = O_PART + 8 * 1024 * 128;
constexpr size_t O_VB  = O_KB + 131072;
constexpr size_t O_BM  = O_VB + 131072;
constexpr size_t O_FB  = O_BM + 512;
constexpr size_t TOTF  = O_FB + 512;

// fp16 buffers
constexpr size_t H_X0  = 0;
constexpr size_t H_X1  = SZ;
constexpr size_t H_XA0 = 2 * SZ;
constexpr size_t H_XA1 = 3 * SZ;
constexpr size_t H_T1  = 4 * SZ;
constexpr size_t H_XAS = 5 * SZ;
constexpr size_t H_T5  = 6 * SZ;
constexpr size_t H_XLN = 7 * SZ;                     // 131072
constexpr size_t H_WS  = H_XLN + 131072;
constexpr size_t H_CW  = H_WS + 15 * 16384;
constexpr size_t H_WJ  = H_CW + 64 * 16384;
constexpr size_t H_WO  = H_WJ + 32768;
constexpr size_t H_QH  = H_WO + 2 * 32768;
constexpr size_t H_KH  = H_QH + SZ;
constexpr size_t H_VT  = H_KH + 131072;
constexpr size_t H_PT0 = H_VT + 131072;
constexpr size_t H_PT1 = H_PT0 + SZ;
constexpr size_t H_PT2 = H_PT1 + SZ;
constexpr size_t H_PT3 = H_PT2 + SZ;
constexpr size_t H_PT4 = H_PT3 + SZ;
constexpr size_t TOTH  = H_PT4 + SZ;

// tile geometry
constexpr int TROW   = 144;
constexpr int TBYTES = 128 * TROW;          // 18432

// gemm5 smem
constexpr int SM_B0 = 0;
constexpr int SM_B1 = TBYTES;
constexpr int SM_A0 = 2 * TBYTES;
constexpr int SM_A1 = 3 * TBYTES;
constexpr int SM_RED = 4 * TBYTES;
constexpr int SM_G   = SM_RED + 2048;       // 75776

constexpr int SM_G6  = 2 * TBYTES;          // 36864
constexpr int SM_CONV = 2 * TBYTES;

// fused attention smem:
// phase1: Q at 0 (18432), K at 18432 (256*144=36864) -> 55296
// phase2: P at 0 (128*528=67584), V at 67584 (64*528=33792) -> 101376
constexpr int SMB_K  = TBYTES;
constexpr int PROW   = 528;                 // 256 fp16 + 16B pad
constexpr int SM_V   = 128 * PROW;          // 67584
constexpr int SM_ATT = SM_V + 64 * PROW;    // 101376
}

__device__ float g_mem[TOTF];
__device__ __half h_mem[TOTH];

// ---------------------------------------------------------------------------
__device__ __forceinline__ uint32_t smem_u32(const void* p) {
    uint32_t a;
    asm("{ .reg .u64 t; cvta.to.shared.u64 t, %1; cvt.u32.u64 %0, t; }"
        : "=r"(a) : "l"(p));
    return a;
}
__device__ __forceinline__ uint32_t pack_h2(float a, float b) {
    __half2 h = __floats2half2_rn(a, b);
    return *(uint32_t*)&h;
}
__device__ __forceinline__ void mma16816(float* d, const uint32_t* a,
                                         uint32_t b0, uint32_t b1) {
    asm volatile(
        "mma.sync.aligned.m16n8k16.row.col.f32.f16.f16.f32 "
        "{%0,%1,%2,%3}, {%4,%5,%6,%7}, {%8,%9}, {%0,%1,%2,%3};"
        : "+f"(d[0]), "+f"(d[1]), "+f"(d[2]), "+f"(d[3])
        : "r"(a[0]), "r"(a[1]), "r"(a[2]), "r"(a[3]), "r"(b0), "r"(b1));
}
__device__ __forceinline__ void ldsm4(uint32_t& r0, uint32_t& r1,
                                      uint32_t& r2, uint32_t& r3, uint32_t addr) {
    asm volatile("ldmatrix.sync.aligned.m8n8.x4.shared.b16 {%0,%1,%2,%3}, [%4];"
                 : "=r"(r0), "=r"(r1), "=r"(r2), "=r"(r3) : "r"(addr));
}
__device__ __forceinline__ void cpa16(uint32_t dst, const void* src) {
    asm volatile("cp.async.cg.shared.global [%0], [%1], 16;"
                 :: "r"(dst), "l"(src));
}
__device__ __forceinline__ void cpa_wait() {
    asm volatile("cp.async.commit_group;\ncp.async.wait_group 0;" ::: "memory");
}
__device__ __forceinline__ float dot8h(uint4 a, uint4 b) {
    const __half2* pa = (const __half2*)&a;
    const __half2* pb = (const __half2*)&b;
    float s = 0.0f;
#pragma unroll
    for (int i = 0; i < 4; i++) {
        float2 fa = __half22float2(pa[i]);
        float2 fb = __half22float2(pb[i]);
        s += fa.x * fb.x + fa.y * fb.y;
    }
    return s;
}

// ---------------------------------------------------------------------------
struct FragCtx {
    uint32_t aoff[2];
    uint32_t boff[4];
};
__device__ __forceinline__ FragCtx make_frag_ctx(int lane, int wm, int wn) {
    FragCtx fc;
    const int rA = (lane & 7) + ((lane >> 3) & 1) * 8;
    const int cA = (lane >> 4) * 16;
#pragma unroll
    for (int mt = 0; mt < 2; mt++)
        fc.aoff[mt] = (uint32_t)((wm * 32 + mt * 16 + rA) * TROW + cA);
    const int rB = (lane & 7) + ((lane >> 4) & 1) * 8;
    const int cB = ((lane >> 3) & 1) * 16;
#pragma unroll
    for (int np = 0; np < 4; np++)
        fc.boff[np] = (uint32_t)((wn * 64 + np * 16 + rB) * TROW + cB);
    return fc;
}
__device__ __forceinline__ void mainloop_chunk(uint32_t aBase, uint32_t bBase,
                                               const FragCtx& fc,
                                               float acc[2][8][4]) {
#pragma unroll
    for (int kc = 0; kc < 4; kc++) {
        const uint32_t kb = (uint32_t)kc * 32;
        uint32_t ah[2][4];
#pragma unroll
        for (int mt = 0; mt < 2; mt++)
            ldsm4(ah[mt][0], ah[mt][1], ah[mt][2], ah[mt][3],
                  aBase + fc.aoff[mt] + kb);
#pragma unroll
        for (int np = 0; np < 4; np++) {
            uint32_t b0, b1, b2, b3;
            ldsm4(b0, b1, b2, b3, bBase + fc.boff[np] + kb);
#pragma unroll
            for (int mt = 0; mt < 2; mt++) {
                mma16816(acc[mt][np * 2],     ah[mt], b0, b1);
                mma16816(acc[mt][np * 2 + 1], ah[mt], b2, b3);
            }
        }
    }
}

// ---------------------------------------------------------------------------
// GEMM v5: 256 rows/CTA, resident B, K=128. postmul now fp16.
// ---------------------------------------------------------------------------
__global__ __launch_bounds__(256, 2) void gemm5(
    const __half* __restrict__ A, const __half* __restrict__ Bw,
    const float* __restrict__ bias, const float* __restrict__ resid,
    const __half* __restrict__ postmul,
    float* __restrict__ Yf, __half* __restrict__ Yh, int epi)
{
    extern __shared__ char sm[];
    const uint32_t smb = smem_u32(sm);
    const int tid = threadIdx.x;
    const int lane = tid & 31, wid = tid >> 5;
    const int t4 = lane & 3, r8 = lane >> 2;
    const int wm = wid >> 1, wn = wid & 1;
    const int bm0 = blockIdx.x * 256;
    const FragCtx fc = make_frag_ctx(lane, wm, wn);
    const int pr = tid >> 1, hf = tid & 1;
    const uint32_t so = (uint32_t)(pr * TROW + hf * 64);

#pragma unroll
    for (int ch = 0; ch < 2; ch++) {
        const size_t brow = (size_t)pr * kC + ch * 64 + hf * 32;
        const size_t arow = (size_t)(bm0 + pr) * kC + ch * 64 + hf * 32;
#pragma unroll
        for (int gq = 0; gq < 4; gq++) {
            cpa16(smb + SM_B0 + ch * TBYTES + so + gq * 16, Bw + brow + gq * 8);
            cpa16(smb + SM_A0 + ch * TBYTES + so + gq * 16, A  + arow + gq * 8);
        }
    }
    cpa_wait();
    __syncthreads();

    float* redm = (float*)(sm + SM_RED);
    float* reds = (float*)(sm + SM_RED + 1024);

    for (int mt = 0; mt < 2; mt++) {
        const int bm = bm0 + mt * 128;
        float acc[2][8][4];
#pragma unroll
        for (int mp = 0; mp < 2; mp++)
#pragma unroll
            for (int nt = 0; nt < 8; nt++)
#pragma unroll
                for (int e = 0; e < 4; e++) acc[mp][nt][e] = 0.0f;

        mainloop_chunk(smb + SM_A0, smb + SM_B0, fc, acc);
        mainloop_chunk(smb + SM_A1, smb + SM_B1, fc, acc);
        __syncthreads();

        if (mt == 0) {
#pragma unroll
            for (int ch = 0; ch < 2; ch++) {
                const size_t arow = (size_t)(bm0 + 128 + pr) * kC + ch * 64 + hf * 32;
#pragma unroll
                for (int gq = 0; gq < 4; gq++)
                    cpa16(smb + SM_A0 + ch * TBYTES + so + gq * 16, A + arow + gq * 8);
            }
        }

        if (bias) {
#pragma unroll
            for (int nt = 0; nt < 8; nt++) {
                float2 bv = *(const float2*)(bias + wn * 64 + nt * 8 + 2 * t4);
#pragma unroll
                for (int mp = 0; mp < 2; mp++) {
                    acc[mp][nt][0] += bv.x; acc[mp][nt][1] += bv.y;
                    acc[mp][nt][2] += bv.x; acc[mp][nt][3] += bv.y;
                }
            }
        }

        if (epi != 2) {
#pragma unroll
            for (int mp = 0; mp < 2; mp++)
#pragma unroll
                for (int p = 0; p < 2; p++) {
                    const int r = bm + wm * 32 + mp * 16 + r8 + p * 8;
#pragma unroll
                    for (int nt = 0; nt < 8; nt++) {
                        const int c = wn * 64 + nt * 8 + 2 * t4;
                        float v0 = acc[mp][nt][2 * p];
                        float v1 = acc[mp][nt][2 * p + 1];
                        if (resid) {
                            float2 rv = *(const float2*)(resid + (size_t)r * kC + c);
                            v0 += rv.x; v1 += rv.y;
                        }
                        if (epi == 1) {
                            v0 = 0.5f * v0 * (1.0f + erff(v0 * 0.70710678118654752f));
                            v1 = 0.5f * v1 * (1.0f + erff(v1 * 0.70710678118654752f));
                        }
                        if (Yf)
                            *(float2*)(Yf + (size_t)r * kC + c) = make_float2(v0, v1);
                        if (Yh)
                            *(uint32_t*)(Yh + (size_t)r * kC + c) = pack_h2(v0, v1);
                    }
                }
        } else {
            float pm[2][2];
#pragma unroll
            for (int mp = 0; mp < 2; mp++) {
                float a0 = -1e30f, a1 = -1e30f;
#pragma unroll
                for (int nt = 0; nt < 8; nt++) {
                    a0 = fmaxf(a0, fmaxf(acc[mp][nt][0], acc[mp][nt][1]));
                    a1 = fmaxf(a1, fmaxf(acc[mp][nt][2], acc[mp][nt][3]));
                }
                pm[mp][0] = a0; pm[mp][1] = a1;
            }
#pragma unroll
            for (int mp = 0; mp < 2; mp++)
#pragma unroll
                for (int p = 0; p < 2; p++) {
                    pm[mp][p] = fmaxf(pm[mp][p], __shfl_xor_sync(FULLMASK, pm[mp][p], 1));
                    pm[mp][p] = fmaxf(pm[mp][p], __shfl_xor_sync(FULLMASK, pm[mp][p], 2));
                }
            if (t4 == 0) {
#pragma unroll
                for (int mp = 0; mp < 2; mp++)
#pragma unroll
                    for (int p = 0; p < 2; p++)
                        redm[(wm * 32 + mp * 16 + r8 + p * 8) * 2 + wn] = pm[mp][p];
            }
            __syncthreads();
            float M[2][2], ps[2][2];
#pragma unroll
            for (int mp = 0; mp < 2; mp++)
#pragma unroll
                for (int p = 0; p < 2; p++) {
                    const int lr = wm * 32 + mp * 16 + r8 + p * 8;
                    M[mp][p] = fmaxf(redm[lr * 2], redm[lr * 2 + 1]);
                    ps[mp][p] = 0.0f;
                }
#pragma unroll
            for (int mp = 0; mp < 2; mp++)
#pragma unroll
                for (int nt = 0; nt < 8; nt++) {
                    acc[mp][nt][0] = __expf(acc[mp][nt][0] - M[mp][0]);
                    acc[mp][nt][1] = __expf(acc[mp][nt][1] - M[mp][0]);
                    acc[mp][nt][2] = __expf(acc[mp][nt][2] - M[mp][1]);
                    acc[mp][nt][3] = __expf(acc[mp][nt][3] - M[mp][1]);
                    ps[mp][0] += acc[mp][nt][0] + acc[mp][nt][1];
                    ps[mp][1] += acc[mp][nt][2] + acc[mp][nt][3];
                }
#pragma unroll
            for (int mp = 0; mp < 2; mp++)
#pragma unroll
                for (int p = 0; p < 2; p++) {
                    ps[mp][p] += __shfl_xor_sync(FULLMASK, ps[mp][p], 1);
                    ps[mp][p] += __shfl_xor_sync(FULLMASK, ps[mp][p], 2);
                }
            if (t4 == 0) {
#pragma unroll
                for (int mp = 0; mp < 2; mp++)
#pragma unroll
                    for (int p = 0; p < 2; p++)
                        reds[(wm * 32 + mp * 16 + r8 + p * 8) * 2 + wn] = ps[mp][p];
            }
            __syncthreads();
#pragma unroll
            for (int mp = 0; mp < 2; mp++)
#pragma unroll
                for (int p = 0; p < 2; p++) {
                    const int lr = wm * 32 + mp * 16 + r8 + p * 8;
                    const float inv = 1.0f / (reds[lr * 2] + reds[lr * 2 + 1]);
                    const size_t gr = (size_t)(bm + lr) * kC;
#pragma unroll
                    for (int nt = 0; nt < 8; nt++) {
                        const int c = wn * 64 + nt * 8 + 2 * t4;
                        float2 pmv = __half22float2(*(const __half2*)(postmul + gr + c));
                        float v0 = acc[mp][nt][2 * p]     * inv * pmv.x;
                        float v1 = acc[mp][nt][2 * p + 1] * inv * pmv.y;
                        *(uint32_t*)(Yh + gr + c) = pack_h2(v0, v1);
                    }
                }
        }

        if (mt == 0) {
            cpa_wait();
            __syncthreads();
        }
    }
}

// ---------------------------------------------------------------------------
// GEMM v6: K=256 over two A sources. B is [128][256] fp16 row-major.
// ---------------------------------------------------------------------------
__global__ __launch_bounds__(256, 2) void gemm6(
    const __half* __restrict__ A1, const __half* __restrict__ A2,
    const __half* __restrict__ Bw, const float* __restrict__ bias,
    float* __restrict__ Yf, __half* __restrict__ Yh, int epi)
{
    extern __shared__ char sm[];
    const uint32_t smb = smem_u32(sm);
    const int tid = threadIdx.x;
    const int lane = tid & 31, wid = tid >> 5;
    const int t4 = lane & 3, r8 = lane >> 2;
    const int wm = wid >> 1, wn = wid & 1;
    const int bm = blockIdx.x * 128;
    const FragCtx fc = make_frag_ctx(lane, wm, wn);
    const int pr = tid >> 1, hf = tid & 1;
    const uint32_t so = (uint32_t)(pr * TROW + hf * 64);

    float acc[2][8][4];
#pragma unroll
    for (int mp = 0; mp < 2; mp++)
#pragma unroll
        for (int nt = 0; nt < 8; nt++)
#pragma unroll
            for (int e = 0; e < 4; e++) acc[mp][nt][e] = 0.0f;

    for (int ch = 0; ch < 4; ch++) {
        const __half* A = (ch < 2) ? A1 : A2;
        const int acol = (ch & 1) * 64;
        const size_t arow = (size_t)(bm + pr) * kC + acol + hf * 32;
        const size_t brow = (size_t)pr * 256 + ch * 64 + hf * 32;
#pragma unroll
        for (int gq = 0; gq < 4; gq++) {
            cpa16(smb + so + gq * 16,          A  + arow + gq * 8);
            cpa16(smb + TBYTES + so + gq * 16, Bw + brow + gq * 8);
        }
        cpa_wait();
        __syncthreads();
        mainloop_chunk(smb, smb + TBYTES, fc, acc);
        __syncthreads();
    }

#pragma unroll
    for (int mp = 0; mp < 2; mp++)
#pragma unroll
        for (int p = 0; p < 2; p++) {
            const int r = bm + wm * 32 + mp * 16 + r8 + p * 8;
#pragma unroll
            for (int nt = 0; nt < 8; nt++) {
                const int c = wn * 64 + nt * 8 + 2 * t4;
                float v0 = acc[mp][nt][2 * p];
                float v1 = acc[mp][nt][2 * p + 1];
                if (bias) {
                    float2 bv = *(const float2*)(bias + c);
                    v0 += bv.x; v1 += bv.y;
                }
                if (epi == 1) {
                    v0 = 0.5f * v0 * (1.0f + erff(v0 * 0.70710678118654752f));
                    v1 = 0.5f * v1 * (1.0f + erff(v1 * 0.70710678118654752f));
                }
                if (Yf)
                    *(float2*)(Yf + (size_t)r * kC + c) = make_float2(v0, v1);
                if (Yh)
                    *(uint32_t*)(Yh + (size_t)r * kC + c) = pack_h2(v0, v1);
            }
        }
}

// ---------------------------------------------------------------------------
// Conv via mma: grid (8, 8), each block accumulates 8 kernel positions.
// ---------------------------------------------------------------------------
__global__ __launch_bounds__(256, 2) void conv_mma(
    const __half* __restrict__ xh, const __half* __restrict__ cwh,
    float* __restrict__ part)
{
    extern __shared__ char sm[];
    const uint32_t smb = smem_u32(sm);
    const int tid = threadIdx.x;
    const int lane = tid & 31, wid = tid >> 5;
    const int t4 = lane & 3, r8 = lane >> 2;
    const int wm = wid >> 1, wn = wid & 1;
    const int b = blockIdx.x >> 1, rt = blockIdx.x & 1, pg = blockIdx.y;
    const FragCtx fc = make_frag_ctx(lane, wm, wn);

    float acc[2][8][4];
#pragma unroll
    for (int mt = 0; mt < 2; mt++)
#pragma unroll
        for (int nt = 0; nt < 8; nt++)
#pragma unroll
            for (int e = 0; e < 4; e++) acc[mt][nt][e] = 0.0f;

    const int pr = tid >> 1, hf = tid & 1;
    const int p = rt * 128 + pr;
    const int ph = p >> 4, pwd = p & 15;
    const uint32_t so = (uint32_t)(pr * TROW + hf * 64);

    for (int q = 0; q < 8; q++) {
        const int pos = pg * 8 + q;
        const int kh = pos >> 3, kw = pos & 7;
        const size_t xrow = ((size_t)b * kN + (ph * 8 + kh) * 128 + pwd * 8 + kw) * kC;
        const size_t wbase = (size_t)pos * 16384 + (size_t)pr * kC;
        for (int ch = 0; ch < 2; ch++) {
            const size_t arow = xrow + ch * 64 + hf * 32;
            const size_t brow = wbase + ch * 64 + hf * 32;
#pragma unroll
            for (int gq = 0; gq < 4; gq++) {
                cpa16(smb + so + gq * 16,          xh  + arow + gq * 8);
                cpa16(smb + TBYTES + so + gq * 16, cwh + brow + gq * 8);
            }
            cpa_wait();
            __syncthreads();
            mainloop_chunk(smb, smb + TBYTES, fc, acc);
            __syncthreads();
        }
    }

    const size_t base = ((size_t)pg * kMR + (size_t)b * 256 + rt * 128) * kC;
#pragma unroll
    for (int mt = 0; mt < 2; mt++)
#pragma unroll
        for (int pq = 0; pq < 2; pq++) {
            const int lr = wm * 32 + mt * 16 + r8 + pq * 8;
#pragma unroll
            for (int nt = 0; nt < 8; nt++) {
                const int c = wn * 64 + nt * 8 + 2 * t4;
                *(float2*)(part + base + (size_t)lr * kC + c) =
                    make_float2(acc[mt][nt][2 * pq], acc[mt][nt][2 * pq + 1]);
            }
        }
}

// ---------------------------------------------------------------------------
__global__ void conv_reduce_ln(const float* __restrict__ part,
                               const float* __restrict__ srb,
                               const float* __restrict__ gam,
                               const float* __restrict__ bet,
                               __half* __restrict__ xlnh)
{
    const int row = blockIdx.x;
    const int c = threadIdx.x;
    float v = srb[c];
#pragma unroll
    for (int sp = 0; sp < 8; sp++)
        v += part[((size_t)sp * kMR + row) * kC + c];

    __shared__ float red[4];
    float s = v;
#pragma unroll
    for (int o = 16; o > 0; o >>= 1) s += __shfl_xor_sync(FULLMASK, s, o);
    if ((c & 31) == 0) red[c >> 5] = s;
    __syncthreads();
    const float mean = (red[0] + red[1] + red[2] + red[3]) * (1.0f / 128.0f);
    __syncthreads();
    const float d = v - mean;
    float s2 = d * d;
#pragma unroll
    for (int o = 16; o > 0; o >>= 1) s2 += __shfl_xor_sync(FULLMASK, s2, o);
    if ((c & 31) == 0) red[c >> 5] = s2;
    __syncthreads();
    const float var = (red[0] + red[1] + red[2] + red[3]) * (1.0f / 128.0f);
    xlnh[(size_t)row * kC + c] =
        __float2half_rn(d * rsqrtf(var + 1e-5f) * gam[c] + bet[c]);
}

// ---------------------------------------------------------------------------
__global__ void kv_pack(const float* __restrict__ KB, const float* __restrict__ VB,
                        __half* __restrict__ Kh, __half* __restrict__ Vt)
{
    const int idx = blockIdx.x * 256 + threadIdx.x;
    const int b = idx >> 15, rem = idx & 32767;
    const int m = rem >> 7, c = rem & 127;
    const int h = c >> 6, d = c & 63;
    const int bh = b * 2 + h;
    Kh[((size_t)bh * 256 + m) * 64 + d] = __float2half_rn(KB[idx]);
    Vt[((size_t)bh * 64 + d) * 256 + m] = __float2half_rn(VB[idx]);
}

// ---------------------------------------------------------------------------
// Fused SR attention: S=QK^T + softmax (phase 1), P kept in smem, PV (phase 2).
// Grid (128, 8), 256 threads, 1 CTA/SM (101 KB smem).
// ---------------------------------------------------------------------------
__global__ __launch_bounds__(256, 1) void attn_fused(
    const __half* __restrict__ Qh, const __half* __restrict__ Kh,
    const __half* __restrict__ Vt, __half* __restrict__ XAh)
{
    extern __shared__ char sm[];
    const uint32_t smb = smem_u32(sm);
    const int tid = threadIdx.x;
    const int lane = tid & 31, wid = tid >> 5;
    const int t4 = lane & 3, r8 = lane >> 2;
    const int bh = blockIdx.y;
    const int b = bh >> 1, h = bh & 1;
    const int qt = blockIdx.x;

    const int rA = (lane & 7) + ((lane >> 3) & 1) * 8;
    const int cA = (lane >> 4) * 16;
    const uint32_t aoff = (uint32_t)((wid * 16 + rA) * TROW + cA);
    const int rB = (lane & 7) + ((lane >> 4) & 1) * 8;
    const int cB = ((lane >> 3) & 1) * 16;
    const uint32_t boffb = (uint32_t)(rB * TROW + cB);

    // --- loads: Q (128x64), K (256x64), and V (64x256, non-overlapping region)
    {
        const int pr = tid >> 1, hf = tid & 1;
        const __half* qsrc = Qh +
            ((size_t)(b * kN + qt * 128 + pr) * kC + h * 64 + hf * 32);
        const uint32_t so = (uint32_t)(pr * TROW + hf * 64);
#pragma unroll
        for (int gq = 0; gq < 4; gq++)
            cpa16(smb + so + gq * 16, qsrc + gq * 8);
        const __half* ksrc = Kh + ((size_t)bh * 256 + tid) * 64;
        const uint32_t sob = (uint32_t)(tid * TROW);
#pragma unroll
        for (int gq = 0; gq < 8; gq++)
            cpa16(smb + SMB_K + sob + gq * 16, ksrc + gq * 8);
        // V: row = tid>>2 (0..63), quarter = tid&3 (64 cols each = 128 B)
        const int vr = tid >> 2, vq = tid & 3;
        const __half* vsrc = Vt + ((size_t)bh * 64 + vr) * 256 + vq * 64;
        const uint32_t sov = (uint32_t)(SM_V + vr * PROW + vq * 128);
#pragma unroll
        for (int gq = 0; gq < 8; gq++)
            cpa16(smb + sov + gq * 16, vsrc + gq * 8);
    }
    cpa_wait();
    __syncthreads();

    // --- phase 1: S = Q K^T over K=64 ---
    float acc[32][4];
#pragma unroll
    for (int nt = 0; nt < 32; nt++)
#pragma unroll
        for (int e = 0; e < 4; e++) acc[nt][e] = 0.0f;

#pragma unroll
    for (int kc = 0; kc < 4; kc++) {
        uint32_t af[4];
        ldsm4(af[0], af[1], af[2], af[3], smb + aoff + kc * 32);
#pragma unroll
        for (int np = 0; np < 16; np++) {
            uint32_t b0, b1, b2, b3;
            ldsm4(b0, b1, b2, b3, smb + SMB_K + boffb + np * (16 * TROW) + kc * 32);
            mma16816(acc[np * 2],     af, b0, b1);
            mma16816(acc[np * 2 + 1], af, b2, b3);
        }
    }

    // softmax over 256 (rows r0 = wid*16 + r8 and r0+8)
    float mx0 = -1e30f, mx1 = -1e30f;
#pragma unroll
    for (int nt = 0; nt < 32; nt++) {
#pragma unroll
        for (int e = 0; e < 4; e++) acc[nt][e] *= 0.125f;
        mx0 = fmaxf(mx0, fmaxf(acc[nt][0], acc[nt][1]));
        mx1 = fmaxf(mx1, fmaxf(acc[nt][2], acc[nt][3]));
    }
    mx0 = fmaxf(mx0, __shfl_xor_sync(FULLMASK, mx0, 1));
    mx0 = fmaxf(mx0, __shfl_xor_sync(FULLMASK, mx0, 2));
    mx1 = fmaxf(mx1, __shfl_xor_sync(FULLMASK, mx1, 1));
    mx1 = fmaxf(mx1, __shfl_xor_sync(FULLMASK, mx1, 2));
    float s0 = 0.0f, s1 = 0.0f;
#pragma unroll
    for (int nt = 0; nt < 32; nt++) {
        acc[nt][0] = __expf(acc[nt][0] - mx0);
        acc[nt][1] = __expf(acc[nt][1] - mx0);
        acc[nt][2] = __expf(acc[nt][2] - mx1);
        acc[nt][3] = __expf(acc[nt][3] - mx1);
        s0 += acc[nt][0] + acc[nt][1];
        s1 += acc[nt][2] + acc[nt][3];
    }
    s0 += __shfl_xor_sync(FULLMASK, s0, 1);
    s0 += __shfl_xor_sync(FULLMASK, s0, 2);
    s1 += __shfl_xor_sync(FULLMASK, s1, 1);
    s1 += __shfl_xor_sync(FULLMASK, s1, 2);
    const float i0 = 1.0f / s0, i1 = 1.0f / s1;

    __syncthreads();   // all warps done reading Q/K smem

    // --- store P fp16 to smem (stride PROW, overwrites Q/K region) ---
    {
        const uint32_t p0 = (uint32_t)((wid * 16 + r8) * PROW);
        const uint32_t p1 = p0 + 8 * PROW;
#pragma unroll
        for (int nt = 0; nt < 32; nt++) {
            const int c = nt * 8 + 2 * t4;
            *(uint32_t*)(sm + p0 + c * 2) = pack_h2(acc[nt][0] * i0, acc[nt][1] * i0);
            *(uint32_t*)(sm + p1 + c * 2) = pack_h2(acc[nt][2] * i1, acc[nt][3] * i1);
        }
    }
    __syncthreads();

    // --- phase 2: XA = P @ V^T  (128x64, K=256) ---
    const int wm = wid >> 1, wn = wid & 1;
    uint32_t aoffP[2];
#pragma unroll
    for (int mt = 0; mt < 2; mt++)
        aoffP[mt] = (uint32_t)((wm * 32 + mt * 16 + rA) * PROW + cA);
    uint32_t boffV[2];
#pragma unroll
    for (int np = 0; np < 2; np++)
        boffV[np] = (uint32_t)(SM_V + (wn * 32 + np * 16 + rB) * PROW + cB);

    float acc2[2][4][4];
#pragma unroll
    for (int mt = 0; mt < 2; mt++)
#pragma unroll
        for (int nt = 0; nt < 4; nt++)
#pragma unroll
            for (int e = 0; e < 4; e++) acc2[mt][nt][e] = 0.0f;

#pragma unroll
    for (int kc = 0; kc < 16; kc++) {
        const uint32_t kb = (uint32_t)kc * 32;
        uint32_t ah[2][4];
#pragma unroll
        for (int mt = 0; mt < 2; mt++)
            ldsm4(ah[mt][0], ah[mt][1], ah[mt][2], ah[mt][3],
                  smb + aoffP[mt] + kb);
#pragma unroll
        for (int np = 0; np < 2; np++) {
            uint32_t b0, b1, b2, b3;
            ldsm4(b0, b1, b2, b3, smb + boffV[np] + kb);
#pragma unroll
            for (int mt = 0; mt < 2; mt++) {
                mma16816(acc2[mt][np * 2],     ah[mt], b0, b1);
                mma16816(acc2[mt][np * 2 + 1], ah[mt], b2, b3);
            }
        }
    }

#pragma unroll
    for (int mt = 0; mt < 2; mt++)
#pragma unroll
        for (int p = 0; p < 2; p++) {
            const int lr = qt * 128 + wm * 32 + mt * 16 + r8 + p * 8;
            const size_t g = ((size_t)b * kN + lr) * kC + h * 64;
#pragma unroll
            for (int nt = 0; nt < 4; nt++) {
                const int c = wn * 32 + nt * 8 + 2 * t4;
                *(uint32_t*)(XAh + g + c) =
                    pack_h2(acc2[mt][nt][2 * p], acc2[mt][nt][2 * p + 1]);
            }
        }
}

// ---------------------------------------------------------------------------
__global__ __launch_bounds__(256) void mha2_pw(
    const __half* __restrict__ qp, const __half* __restrict__ k0,
    const __half* __restrict__ k1, const __half* __restrict__ v0,
    const __half* __restrict__ v1, __half* __restrict__ oh)
{
    const int idx = blockIdx.x * 256 + threadIdx.x;
    const size_t base = (size_t)(idx >> 3) * kC + (idx & 7) * 16;
    const uint4* qg  = (const uint4*)(qp + base);
    const uint4* k0g = (const uint4*)(k0 + base);
    const uint4* k1g = (const uint4*)(k1 + base);
    uint4 qa = qg[0], qb = qg[1];
    float s0 = dot8h(qa, k0g[0]) + dot8h(qb, k0g[1]);
    float s1 = dot8h(qa, k1g[0]) + dot8h(qb, k1g[1]);
    s0 *= 0.25f; s1 *= 0.25f;
    const float m = fmaxf(s0, s1);
    float e0 = __expf(s0 - m), e1 = __expf(s1 - m);
    const float inv = 1.0f / (e0 + e1);
    e0 *= inv; e1 *= inv;
    const uint4* v0g = (const uint4*)(v0 + base);
    const uint4* v1g = (const uint4*)(v1 + base);
    uint4* ohg = (uint4*)(oh + base);
#pragma unroll
    for (int t = 0; t < 2; t++) {
        uint4 a = v0g[t], bb = v1g[t];
        const __half2* pa = (const __half2*)&a;
        const __half2* pb = (const __half2*)&bb;
        uint4 o;
        uint32_t* po = (uint32_t*)&o;
#pragma unroll
        for (int i = 0; i < 4; i++) {
            float2 fa = __half22float2(pa[i]);
            float2 fb = __half22float2(pb[i]);
            po[i] = pack_h2(e0 * fa.x + e1 * fb.x, e0 * fa.y + e1 * fb.y);
        }
        ohg[t] = o;
    }
}

// ---------------------------------------------------------------------------
__global__ void cvt_half(const float* __restrict__ src, __half* __restrict__ dst)
{
    const int i = blockIdx.x * 256 + threadIdx.x;
    float4 v = ((const float4*)src)[i];
    ((uint2*)dst)[i] = make_uint2(pack_h2(v.x, v.y), pack_h2(v.z, v.w));
}

__global__ void cvt_w(const float* __restrict__ src, int ldW,
                      __half* __restrict__ dh)
{
    const int i = blockIdx.x * 256 + threadIdx.x;
    const int o = i >> 6, k = (i & 63) * 2;
    *(uint32_t*)(dh + o * kC + k) =
        pack_h2(src[(size_t)o * ldW + k], src[(size_t)o * ldW + k + 1]);
}

__global__ void cvt_w256(const float* __restrict__ src, __half* __restrict__ dh)
{
    const int i = blockIdx.x * 256 + threadIdx.x;
    const int o = i >> 7, k = (i & 127) * 2;
    *(uint32_t*)(dh + o * 256 + k) =
        pack_h2(src[(size_t)o * 256 + k], src[(size_t)o * 256 + k + 1]);
}

__global__ void cvt_convw(const float* __restrict__ srw, __half* __restrict__ dh)
{
    const int t = blockIdx.x * 256 + threadIdx.x;
    const int pos = t >> 13, o = (t >> 6) & 127, i2 = (t & 63) * 2;
    const size_t d = (size_t)pos * 16384 + (size_t)o * kC + i2;
    *(uint32_t*)(dh + d) =
        pack_h2(srw[(size_t)o * 8192 + i2 * 64 + pos],
                srw[(size_t)o * 8192 + (i2 + 1) * 64 + pos]);
}

__global__ void fuse_out_w(const float* __restrict__ pw,
                           const float* __restrict__ cawO,
                           __half* __restrict__ WO)
{
    const int i = blockIdx.x * 256 + threadIdx.x;
    const int o = i >> 7, j = i & 127;
    float acc = 0.0f;
    for (int c = 0; c < 128; c++)
        acc += pw[(size_t)o * 128 + c] * cawO[(size_t)c * 128 + j];
    WO[(size_t)o * 256 + j]       = __float2half_rn(pw[(size_t)o * 128 + j]);
    WO[(size_t)o * 256 + 128 + j] = __float2half_rn(acc);
}

__global__ void fuse_out_b(const float* __restrict__ pw,
                           const float* __restrict__ cabO,
                           const float* __restrict__ pb,
                           float* __restrict__ fb)
{
    const int o = threadIdx.x;
    float acc = pb[o];
    for (int c = 0; c < 128; c++) acc += pw[(size_t)o * 128 + c] * cabO[c];
    fb[o] = acc;
}

__global__ void fold_bias(
    const float* __restrict__ w01, const float* __restrict__ b01,
    const float* __restrict__ w10, const float* __restrict__ b10,
    const float* __restrict__ kn, const float* __restrict__ vn,
    float* __restrict__ bm)
{
    const int which = blockIdx.x, c = threadIdx.x;
    const float* W  = (which < 2) ? w01 : w10;
    const float* Bb = (which < 2) ? b01 : b10;
    const float* nz = ((which & 1) ? vn : kn) + (which >> 1) * kC;
    const int off = (which & 1) ? 256 : 128;
    float acc = Bb[off + c];
    const float* wr = W + (size_t)(off + c) * kC;
    for (int k = 0; k < kC; k++) acc += nz[k] * wr[k];
    bm[which * kC + c] = acc;
}

// ---------------------------------------------------------------------------
extern "C" void kernel_launch(void* const* d_in, const int* in_sizes, int n_in,
                              void* d_out, int out_size)
{
    (void)in_sizes; (void)n_in; (void)out_size;
    const float* x0   = (const float*)d_in[0];
    const float* x1   = (const float*)d_in[1];
    const float* Wq   = (const float*)d_in[2];
    const float* bq   = (const float*)d_in[3];
    const float* Wkv  = (const float*)d_in[4];
    const float* bkv  = (const float*)d_in[5];
    const float* srw  = (const float*)d_in[6];
    const float* srb  = (const float*)d_in[7];
    const float* lnG[2] = {(const float*)d_in[8],  (const float*)d_in[10]};
    const float* lnB[2] = {(const float*)d_in[9],  (const float*)d_in[11]};
    const float* cawI[2] = {(const float*)d_in[12], (const float*)d_in[16]};
    const float* cabI[2] = {(const float*)d_in[13], (const float*)d_in[17]};
    const float* cawO[2] = {(const float*)d_in[14], (const float*)d_in[18]};
    const float* cabO[2] = {(const float*)d_in[15], (const float*)d_in[19]};
    const float* rjw1 = (const float*)d_in[20];
    const float* rjb1 = (const float*)d_in[21];
    const float* rjw2 = (const float*)d_in[22];
    const float* rjb2 = (const float*)d_in[23];
    const float* kn   = (const float*)d_in[24];
    const float* vn   = (const float*)d_in[25];
    const float* pw   = (const float*)d_in[26];
    const float* pb   = (const float*)d_in[27];
    float* out = (float*)d_out;

    float* g = nullptr;
    cudaGetSymbolAddress((void**)&g, g_mem);
    __half* hm = nullptr;
    cudaGetSymbolAddress((void**)&hm, h_mem);

    float *PART = g + O_PART, *KBp = g + O_KB, *VBp = g + O_VB;
    float *BM = g + O_BM, *FB = g + O_FB;

    __half *XH[2]  = {hm + H_X0, hm + H_X1};
    __half *XAH[2] = {hm + H_XA0, hm + H_XA1};
    __half *T1H = hm + H_T1, *XASH = hm + H_XAS, *T5H = hm + H_T5;
    __half *XLNH = hm + H_XLN;
    __half *WSH = hm + H_WS, *CWH = hm + H_CW;
    __half *WJH = hm + H_WJ;
    __half *WOH[2] = {hm + H_WO, hm + H_WO + 32768};
    __half *QH = hm + H_QH;
    __half *KH = hm + H_KH, *VT = hm + H_VT;
    __half *PT0 = hm + H_PT0, *PT1 = hm + H_PT1, *PT2 = hm + H_PT2;
    __half *PT3 = hm + H_PT3, *PT4 = hm + H_PT4;

    cudaFuncSetAttribute(gemm5, cudaFuncAttributeMaxDynamicSharedMemorySize, SM_G);
    cudaFuncSetAttribute(gemm6, cudaFuncAttributeMaxDynamicSharedMemorySize, SM_G6);
    cudaFuncSetAttribute(conv_mma, cudaFuncAttributeMaxDynamicSharedMemorySize, SM_CONV);
    cudaFuncSetAttribute(attn_fused, cudaFuncAttributeMaxDynamicSharedMemorySize, SM_ATT);

    // --- one-time prep ---
    fold_bias<<<4, 128>>>(cawI[0], cabI[0], cawI[1], cabI[1], kn, vn, BM);
    cvt_half<<<8192, 256>>>(x0, XH[0]);
    cvt_half<<<8192, 256>>>(x1, XH[1]);
    cvt_convw<<<2048, 256>>>(srw, CWH);
    cvt_w256<<<64, 256>>>(rjw1, WJH);
    fuse_out_w<<<64, 256>>>(pw, cawO[0], WOH[0]);
    fuse_out_w<<<64, 256>>>(pw, cawO[1], WOH[1]);
    fuse_out_b<<<1, 128>>>(pw, cabO[0], pb, FB);
    fuse_out_b<<<1, 128>>>(pw, cabO[1], pb, FB + 128);
#define SW(SRC, LD, IDX) cvt_w<<<32, 256>>>(SRC, LD, WSH + (IDX) * 16384)
    SW(Wq, 128, 0);
    SW(Wkv, 128, 1);          SW(Wkv + 16384, 128, 2);
    SW(rjw2, 128, 5);
    SW(cawI[0], 128, 6);      SW(cawI[0] + 16384, 128, 7);  SW(cawI[0] + 32768, 128, 8);
    SW(cawI[1], 128, 9);      SW(cawI[1] + 16384, 128, 10); SW(cawI[1] + 32768, 128, 11);
#undef SW

    const int GM = kMTOK / 256;
    const int G6M = kMTOK / 128;
#define G5(GRID, AH, WI, BIAS, RESID, YF, YH, EPI) \
    gemm5<<<GRID, 256, SM_G>>>(AH, WSH + (WI) * 16384, BIAS, RESID, \
                               nullptr, YF, YH, EPI)
#define G5S(GRID, AH, WI, BIAS, PMUL, YH) \
    gemm5<<<GRID, 256, SM_G>>>(AH, WSH + (WI) * 16384, BIAS, nullptr, \
                               PMUL, nullptr, YH, 2)

    // --- Stage A: SR attention per stream ---
    for (int s = 0; s < 2; s++) {
        G5(GM, XH[s], 0, bq, nullptr, nullptr, QH, 0);
        conv_mma<<<dim3(8, 8), 256, SM_CONV>>>(XH[s], CWH, PART);
        conv_reduce_ln<<<1024, 128>>>(PART, srb, lnG[s], lnB[s], XLNH);
        G5(4, XLNH, 1, bkv,       nullptr, KBp, nullptr, 0);
        G5(4, XLNH, 2, bkv + 128, nullptr, VBp, nullptr, 0);
        kv_pack<<<512, 256>>>(KBp, VBp, KH, VT);
        attn_fused<<<dim3(128, 8), 256, SM_ATT>>>(QH, KH, VT, XAH[s]);
    }

    // --- Stage B + C per stream ---
    for (int s = 0; s < 2; s++) {
        gemm6<<<G6M, 256, SM_G6>>>(XAH[s], XAH[s ^ 1], WJH, rjb1,
                                   nullptr, T1H, 1);
        G5S(GM, T1H, 5, rjb2, XAH[s], XASH);
        const float* Bb = cabI[s];
        float* bmk = BM + (2 * s) * kC;
        float* bmv = BM + (2 * s + 1) * kC;
        G5(GM, XAH[s],     6 + 3 * s, Bb,       nullptr, nullptr, PT0, 0);
        G5(GM, XAH[s],     7 + 3 * s, bmk,      nullptr, nullptr, PT1, 0);
        G5(GM, XASH,       7 + 3 * s, Bb + 128, nullptr, nullptr, PT2, 0);
        G5(GM, XAH[s],     8 + 3 * s, bmv,      nullptr, nullptr, PT3, 0);
        G5(GM, XAH[s ^ 1], 8 + 3 * s, Bb + 256, nullptr, nullptr, PT4, 0);
        mha2_pw<<<2048, 256>>>(PT0, PT1, PT2, PT3, PT4, T5H);
        gemm6<<<G6M, 256, SM_G6>>>(XAH[s], T5H, WOH[s], FB + s * 128,
                                   out + (size_t)s * SZ, nullptr, 0);
    }
#undef G5
#undef G5S
}

// round 16
// speedup vs baseline: 3.5367x; 1.0516x over previous
#include <cuda_runtime.h>
#include <cuda_fp16.h>
#include <math.h>
#include <stdint.h>

#define FULLMASK 0xffffffffu

namespace {
constexpr int kB = 4, kN = 16384, kC = 128, kMTOK = 65536, kMR = 1024;
constexpr size_t SZ = (size_t)kMTOK * kC;

// fp32 scratch
constexpr size_t O_PART = 0;
constexpr size_t O_KB  = O_PART + 8 * 1024 * 128;
constexpr size_t O_VB  = O_KB + 131072;
constexpr size_t O_BM  = O_VB + 131072;
constexpr size_t O_FB  = O_BM + 512;
constexpr size_t TOTF  = O_FB + 512;

// fp16 buffers
constexpr size_t H_X0  = 0;
constexpr size_t H_X1  = SZ;
constexpr size_t H_XA0 = 2 * SZ;
constexpr size_t H_XA1 = 3 * SZ;
constexpr size_t H_T1  = 4 * SZ;
constexpr size_t H_XAS = 5 * SZ;
constexpr size_t H_T5  = 6 * SZ;
constexpr size_t H_XLN = 7 * SZ;
constexpr size_t H_WS  = H_XLN + 131072;
constexpr size_t H_CW  = H_WS + 15 * 16384;
constexpr size_t H_WJ  = H_CW + 64 * 16384;
constexpr size_t H_WO  = H_WJ + 32768;
constexpr size_t H_QH  = H_WO + 2 * 32768;
constexpr size_t H_KH  = H_QH + SZ;
constexpr size_t H_VT  = H_KH + 131072;
constexpr size_t TOTH  = H_VT + 131072;

// tile geometry
constexpr int TROW   = 144;
constexpr int TBYTES = 128 * TROW;          // 18432

// gemm5 smem
constexpr int SM_B0 = 0;
constexpr int SM_B1 = TBYTES;
constexpr int SM_A0 = 2 * TBYTES;
constexpr int SM_A1 = 3 * TBYTES;
constexpr int SM_RED = 4 * TBYTES;
constexpr int SM_G   = SM_RED + 2048;       // 75776

constexpr int SM_G6  = 2 * TBYTES;
constexpr int SM_CONV = 2 * TBYTES;

// fused attention smem
constexpr int SMB_K  = TBYTES;
constexpr int PROW   = 528;
constexpr int SM_V   = 128 * PROW;
constexpr int SM_ATT = SM_V + 64 * PROW;    // 101376

// mha2_fused smem: RA0/RA1 resident A, SA stream A, SB stream B,
// SQ q fp16 [128][136h], SV e0*v0 fp16 [128][136h], s0/s1 [128][8] f32
constexpr int M2_SA  = 2 * TBYTES;          // 36864
constexpr int M2_SB  = 3 * TBYTES;          // 55296
constexpr int M2_SQ  = 4 * TBYTES;          // 73728
constexpr int QROW   = 272;                 // bytes per q/v row
constexpr int M2_SV  = M2_SQ + 128 * QROW;  // 108544
constexpr int M2_S0  = M2_SV + 128 * QROW;  // 143360
constexpr int M2_S1  = M2_S0 + 4096;
constexpr int SM_M2  = M2_S1 + 4096;        // 151552
}

__device__ float g_mem[TOTF];
__device__ __half h_mem[TOTH];

// ---------------------------------------------------------------------------
__device__ __forceinline__ uint32_t smem_u32(const void* p) {
    uint32_t a;
    asm("{ .reg .u64 t; cvta.to.shared.u64 t, %1; cvt.u32.u64 %0, t; }"
        : "=r"(a) : "l"(p));
    return a;
}
__device__ __forceinline__ uint32_t pack_h2(float a, float b) {
    __half2 h = __floats2half2_rn(a, b);
    return *(uint32_t*)&h;
}
__device__ __forceinline__ void mma16816(float* d, const uint32_t* a,
                                         uint32_t b0, uint32_t b1) {
    asm volatile(
        "mma.sync.aligned.m16n8k16.row.col.f32.f16.f16.f32 "
        "{%0,%1,%2,%3}, {%4,%5,%6,%7}, {%8,%9}, {%0,%1,%2,%3};"
        : "+f"(d[0]), "+f"(d[1]), "+f"(d[2]), "+f"(d[3])
        : "r"(a[0]), "r"(a[1]), "r"(a[2]), "r"(a[3]), "r"(b0), "r"(b1));
}
__device__ __forceinline__ void ldsm4(uint32_t& r0, uint32_t& r1,
                                      uint32_t& r2, uint32_t& r3, uint32_t addr) {
    asm volatile("ldmatrix.sync.aligned.m8n8.x4.shared.b16 {%0,%1,%2,%3}, [%4];"
                 : "=r"(r0), "=r"(r1), "=r"(r2), "=r"(r3) : "r"(addr));
}
__device__ __forceinline__ void cpa16(uint32_t dst, const void* src) {
    asm volatile("cp.async.cg.shared.global [%0], [%1], 16;"
                 :: "r"(dst), "l"(src));
}
__device__ __forceinline__ void cpa_wait() {
    asm volatile("cp.async.commit_group;\ncp.async.wait_group 0;" ::: "memory");
}

// ---------------------------------------------------------------------------
struct FragCtx {
    uint32_t aoff[2];
    uint32_t boff[4];
};
__device__ __forceinline__ FragCtx make_frag_ctx(int lane, int wm, int wn) {
    FragCtx fc;
    const int rA = (lane & 7) + ((lane >> 3) & 1) * 8;
    const int cA = (lane >> 4) * 16;
#pragma unroll
    for (int mt = 0; mt < 2; mt++)
        fc.aoff[mt] = (uint32_t)((wm * 32 + mt * 16 + rA) * TROW + cA);
    const int rB = (lane & 7) + ((lane >> 4) & 1) * 8;
    const int cB = ((lane >> 3) & 1) * 16;
#pragma unroll
    for (int np = 0; np < 4; np++)
        fc.boff[np] = (uint32_t)((wn * 64 + np * 16 + rB) * TROW + cB);
    return fc;
}
__device__ __forceinline__ void mainloop_chunk(uint32_t aBase, uint32_t bBase,
                                               const FragCtx& fc,
                                               float acc[2][8][4]) {
#pragma unroll
    for (int kc = 0; kc < 4; kc++) {
        const uint32_t kb = (uint32_t)kc * 32;
        uint32_t ah[2][4];
#pragma unroll
        for (int mt = 0; mt < 2; mt++)
            ldsm4(ah[mt][0], ah[mt][1], ah[mt][2], ah[mt][3],
                  aBase + fc.aoff[mt] + kb);
#pragma unroll
        for (int np = 0; np < 4; np++) {
            uint32_t b0, b1, b2, b3;
            ldsm4(b0, b1, b2, b3, bBase + fc.boff[np] + kb);
#pragma unroll
            for (int mt = 0; mt < 2; mt++) {
                mma16816(acc[mt][np * 2],     ah[mt], b0, b1);
                mma16816(acc[mt][np * 2 + 1], ah[mt], b2, b3);
            }
        }
    }
}

// ---------------------------------------------------------------------------
// GEMM v5: 256 rows/CTA, resident B, K=128.
// ---------------------------------------------------------------------------
__global__ __launch_bounds__(256, 2) void gemm5(
    const __half* __restrict__ A, const __half* __restrict__ Bw,
    const float* __restrict__ bias, const float* __restrict__ resid,
    const __half* __restrict__ postmul,
    float* __restrict__ Yf, __half* __restrict__ Yh, int epi)
{
    extern __shared__ char sm[];
    const uint32_t smb = smem_u32(sm);
    const int tid = threadIdx.x;
    const int lane = tid & 31, wid = tid >> 5;
    const int t4 = lane & 3, r8 = lane >> 2;
    const int wm = wid >> 1, wn = wid & 1;
    const int bm0 = blockIdx.x * 256;
    const FragCtx fc = make_frag_ctx(lane, wm, wn);
    const int pr = tid >> 1, hf = tid & 1;
    const uint32_t so = (uint32_t)(pr * TROW + hf * 64);

#pragma unroll
    for (int ch = 0; ch < 2; ch++) {
        const size_t brow = (size_t)pr * kC + ch * 64 + hf * 32;
        const size_t arow = (size_t)(bm0 + pr) * kC + ch * 64 + hf * 32;
#pragma unroll
        for (int gq = 0; gq < 4; gq++) {
            cpa16(smb + SM_B0 + ch * TBYTES + so + gq * 16, Bw + brow + gq * 8);
            cpa16(smb + SM_A0 + ch * TBYTES + so + gq * 16, A  + arow + gq * 8);
        }
    }
    cpa_wait();
    __syncthreads();

    float* redm = (float*)(sm + SM_RED);
    float* reds = (float*)(sm + SM_RED + 1024);

    for (int mt = 0; mt < 2; mt++) {
        const int bm = bm0 + mt * 128;
        float acc[2][8][4];
#pragma unroll
        for (int mp = 0; mp < 2; mp++)
#pragma unroll
            for (int nt = 0; nt < 8; nt++)
#pragma unroll
                for (int e = 0; e < 4; e++) acc[mp][nt][e] = 0.0f;

        mainloop_chunk(smb + SM_A0, smb + SM_B0, fc, acc);
        mainloop_chunk(smb + SM_A1, smb + SM_B1, fc, acc);
        __syncthreads();

        if (mt == 0) {
#pragma unroll
            for (int ch = 0; ch < 2; ch++) {
                const size_t arow = (size_t)(bm0 + 128 + pr) * kC + ch * 64 + hf * 32;
#pragma unroll
                for (int gq = 0; gq < 4; gq++)
                    cpa16(smb + SM_A0 + ch * TBYTES + so + gq * 16, A + arow + gq * 8);
            }
        }

        if (bias) {
#pragma unroll
            for (int nt = 0; nt < 8; nt++) {
                float2 bv = *(const float2*)(bias + wn * 64 + nt * 8 + 2 * t4);
#pragma unroll
                for (int mp = 0; mp < 2; mp++) {
                    acc[mp][nt][0] += bv.x; acc[mp][nt][1] += bv.y;
                    acc[mp][nt][2] += bv.x; acc[mp][nt][3] += bv.y;
                }
            }
        }

        if (epi != 2) {
#pragma unroll
            for (int mp = 0; mp < 2; mp++)
#pragma unroll
                for (int p = 0; p < 2; p++) {
                    const int r = bm + wm * 32 + mp * 16 + r8 + p * 8;
#pragma unroll
                    for (int nt = 0; nt < 8; nt++) {
                        const int c = wn * 64 + nt * 8 + 2 * t4;
                        float v0 = acc[mp][nt][2 * p];
                        float v1 = acc[mp][nt][2 * p + 1];
                        if (resid) {
                            float2 rv = *(const float2*)(resid + (size_t)r * kC + c);
                            v0 += rv.x; v1 += rv.y;
                        }
                        if (epi == 1) {
                            v0 = 0.5f * v0 * (1.0f + erff(v0 * 0.70710678118654752f));
                            v1 = 0.5f * v1 * (1.0f + erff(v1 * 0.70710678118654752f));
                        }
                        if (Yf)
                            *(float2*)(Yf + (size_t)r * kC + c) = make_float2(v0, v1);
                        if (Yh)
                            *(uint32_t*)(Yh + (size_t)r * kC + c) = pack_h2(v0, v1);
                    }
                }
        } else {
            float pm[2][2];
#pragma unroll
            for (int mp = 0; mp < 2; mp++) {
                float a0 = -1e30f, a1 = -1e30f;
#pragma unroll
                for (int nt = 0; nt < 8; nt++) {
                    a0 = fmaxf(a0, fmaxf(acc[mp][nt][0], acc[mp][nt][1]));
                    a1 = fmaxf(a1, fmaxf(acc[mp][nt][2], acc[mp][nt][3]));
                }
                pm[mp][0] = a0; pm[mp][1] = a1;
            }
#pragma unroll
            for (int mp = 0; mp < 2; mp++)
#pragma unroll
                for (int p = 0; p < 2; p++) {
                    pm[mp][p] = fmaxf(pm[mp][p], __shfl_xor_sync(FULLMASK, pm[mp][p], 1));
                    pm[mp][p] = fmaxf(pm[mp][p], __shfl_xor_sync(FULLMASK, pm[mp][p], 2));
                }
            if (t4 == 0) {
#pragma unroll
                for (int mp = 0; mp < 2; mp++)
#pragma unroll
                    for (int p = 0; p < 2; p++)
                        redm[(wm * 32 + mp * 16 + r8 + p * 8) * 2 + wn] = pm[mp][p];
            }
            __syncthreads();
            float M[2][2], ps[2][2];
#pragma unroll
            for (int mp = 0; mp < 2; mp++)
#pragma unroll
                for (int p = 0; p < 2; p++) {
                    const int lr = wm * 32 + mp * 16 + r8 + p * 8;
                    M[mp][p] = fmaxf(redm[lr * 2], redm[lr * 2 + 1]);
                    ps[mp][p] = 0.0f;
                }
#pragma unroll
            for (int mp = 0; mp < 2; mp++)
#pragma unroll
                for (int nt = 0; nt < 8; nt++) {
                    acc[mp][nt][0] = __expf(acc[mp][nt][0] - M[mp][0]);
                    acc[mp][nt][1] = __expf(acc[mp][nt][1] - M[mp][0]);
                    acc[mp][nt][2] = __expf(acc[mp][nt][2] - M[mp][1]);
                    acc[mp][nt][3] = __expf(acc[mp][nt][3] - M[mp][1]);
                    ps[mp][0] += acc[mp][nt][0] + acc[mp][nt][1];
                    ps[mp][1] += acc[mp][nt][2] + acc[mp][nt][3];
                }
#pragma unroll
            for (int mp = 0; mp < 2; mp++)
#pragma unroll
                for (int p = 0; p < 2; p++) {
                    ps[mp][p] += __shfl_xor_sync(FULLMASK, ps[mp][p], 1);
                    ps[mp][p] += __shfl_xor_sync(FULLMASK, ps[mp][p], 2);
                }
            if (t4 == 0) {
#pragma unroll
                for (int mp = 0; mp < 2; mp++)
#pragma unroll
                    for (int p = 0; p < 2; p++)
                        reds[(wm * 32 + mp * 16 + r8 + p * 8) * 2 + wn] = ps[mp][p];
            }
            __syncthreads();
#pragma unroll
            for (int mp = 0; mp < 2; mp++)
#pragma unroll
                for (int p = 0; p < 2; p++) {
                    const int lr = wm * 32 + mp * 16 + r8 + p * 8;
                    const float inv = 1.0f / (reds[lr * 2] + reds[lr * 2 + 1]);
                    const size_t gr = (size_t)(bm + lr) * kC;
#pragma unroll
                    for (int nt = 0; nt < 8; nt++) {
                        const int c = wn * 64 + nt * 8 + 2 * t4;
                        float2 pmv = __half22float2(*(const __half2*)(postmul + gr + c));
                        float v0 = acc[mp][nt][2 * p]     * inv * pmv.x;
                        float v1 = acc[mp][nt][2 * p + 1] * inv * pmv.y;
                        *(uint32_t*)(Yh + gr + c) = pack_h2(v0, v1);
                    }
                }
        }

        if (mt == 0) {
            cpa_wait();
            __syncthreads();
        }
    }
}

// ---------------------------------------------------------------------------
// GEMM v6: K=256 over two A sources.
// ---------------------------------------------------------------------------
__global__ __launch_bounds__(256, 2) void gemm6(
    const __half* __restrict__ A1, const __half* __restrict__ A2,
    const __half* __restrict__ Bw, const float* __restrict__ bias,
    float* __restrict__ Yf, __half* __restrict__ Yh, int epi)
{
    extern __shared__ char sm[];
    const uint32_t smb = smem_u32(sm);
    const int tid = threadIdx.x;
    const int lane = tid & 31, wid = tid >> 5;
    const int t4 = lane & 3, r8 = lane >> 2;
    const int wm = wid >> 1, wn = wid & 1;
    const int bm = blockIdx.x * 128;
    const FragCtx fc = make_frag_ctx(lane, wm, wn);
    const int pr = tid >> 1, hf = tid & 1;
    const uint32_t so = (uint32_t)(pr * TROW + hf * 64);

    float acc[2][8][4];
#pragma unroll
    for (int mp = 0; mp < 2; mp++)
#pragma unroll
        for (int nt = 0; nt < 8; nt++)
#pragma unroll
            for (int e = 0; e < 4; e++) acc[mp][nt][e] = 0.0f;

    for (int ch = 0; ch < 4; ch++) {
        const __half* A = (ch < 2) ? A1 : A2;
        const int acol = (ch & 1) * 64;
        const size_t arow = (size_t)(bm + pr) * kC + acol + hf * 32;
        const size_t brow = (size_t)pr * 256 + ch * 64 + hf * 32;
#pragma unroll
        for (int gq = 0; gq < 4; gq++) {
            cpa16(smb + so + gq * 16,          A  + arow + gq * 8);
            cpa16(smb + TBYTES + so + gq * 16, Bw + brow + gq * 8);
        }
        cpa_wait();
        __syncthreads();
        mainloop_chunk(smb, smb + TBYTES, fc, acc);
        __syncthreads();
    }

#pragma unroll
    for (int mp = 0; mp < 2; mp++)
#pragma unroll
        for (int p = 0; p < 2; p++) {
            const int r = bm + wm * 32 + mp * 16 + r8 + p * 8;
#pragma unroll
            for (int nt = 0; nt < 8; nt++) {
                const int c = wn * 64 + nt * 8 + 2 * t4;
                float v0 = acc[mp][nt][2 * p];
                float v1 = acc[mp][nt][2 * p + 1];
                if (bias) {
                    float2 bv = *(const float2*)(bias + c);
                    v0 += bv.x; v1 += bv.y;
                }
                if (epi == 1) {
                    v0 = 0.5f * v0 * (1.0f + erff(v0 * 0.70710678118654752f));
                    v1 = 0.5f * v1 * (1.0f + erff(v1 * 0.70710678118654752f));
                }
                if (Yf)
                    *(float2*)(Yf + (size_t)r * kC + c) = make_float2(v0, v1);
                if (Yh)
                    *(uint32_t*)(Yh + (size_t)r * kC + c) = pack_h2(v0, v1);
            }
        }
}

// ---------------------------------------------------------------------------
// Fused mha2: q/k0/k1/v0/v1 projections + 2-key softmax combine, one kernel.
// Grid 512 x 256 thr, ~148KB smem, 1 CTA/SM.
// ---------------------------------------------------------------------------
__global__ __launch_bounds__(256, 1) void mha2_fused(
    const __half* __restrict__ Aq,   // XAH[s]   (q, k0, v0 source)
    const __half* __restrict__ Ak1,  // XASH     (k1 source)
    const __half* __restrict__ Av1,  // XAH[s^1] (v1 source)
    const __half* __restrict__ Wq, const __half* __restrict__ Wk,
    const __half* __restrict__ Wv,
    const float* __restrict__ Bb,    // q bias; +128 k1 bias; +256 v1 bias
    const float* __restrict__ bmk, const float* __restrict__ bmv,
    __half* __restrict__ T5)
{
    extern __shared__ char sm[];
    const uint32_t smb = smem_u32(sm);
    const int tid = threadIdx.x;
    const int lane = tid & 31, wid = tid >> 5;
    const int t4 = lane & 3, r8 = lane >> 2;
    const int wm = wid >> 1, wn = wid & 1;
    const int bm = blockIdx.x * 128;
    const FragCtx fc = make_frag_ctx(lane, wm, wn);
    const int pr = tid >> 1, hf = tid & 1;
    const uint32_t so = (uint32_t)(pr * TROW + hf * 64);

    float* s0buf = (float*)(sm + M2_S0);
    float* s1buf = (float*)(sm + M2_S1);

    // resident A = Aq, both chunks
#pragma unroll
    for (int ch = 0; ch < 2; ch++) {
        const size_t arow = (size_t)(bm + pr) * kC + ch * 64 + hf * 32;
#pragma unroll
        for (int gq = 0; gq < 4; gq++)
            cpa16(smb + ch * TBYTES + so + gq * 16, Aq + arow + gq * 8);
    }
    cpa_wait();
    __syncthreads();

    float acc[2][8][4];

#define CLR() do { \
    _Pragma("unroll") for (int mp = 0; mp < 2; mp++) \
    _Pragma("unroll") for (int nt = 0; nt < 8; nt++) \
    _Pragma("unroll") for (int e = 0; e < 4; e++) acc[mp][nt][e] = 0.0f; \
} while (0)

#define PROJ_RES(W) do { CLR(); \
    for (int ch = 0; ch < 2; ch++) { \
        const size_t brow = (size_t)pr * kC + ch * 64 + hf * 32; \
        _Pragma("unroll") for (int gq = 0; gq < 4; gq++) \
            cpa16(smb + M2_SB + so + gq * 16, (W) + brow + gq * 8); \
        cpa_wait(); __syncthreads(); \
        mainloop_chunk(smb + ch * TBYTES, smb + M2_SB, fc, acc); \
        __syncthreads(); \
    } } while (0)

#define PROJ_STR(AG, W) do { CLR(); \
    for (int ch = 0; ch < 2; ch++) { \
        const size_t arow = (size_t)(bm + pr) * kC + ch * 64 + hf * 32; \
        const size_t brow = (size_t)pr * kC + ch * 64 + hf * 32; \
        _Pragma("unroll") for (int gq = 0; gq < 4; gq++) { \
            cpa16(smb + M2_SA + so + gq * 16, (AG) + arow + gq * 8); \
            cpa16(smb + M2_SB + so + gq * 16, (W)  + brow + gq * 8); \
        } \
        cpa_wait(); __syncthreads(); \
        mainloop_chunk(smb + M2_SA, smb + M2_SB, fc, acc); \
        __syncthreads(); \
    } } while (0)

    // ---- step 1: q = Aq @ Wq^T + Bb  -> SQ (fp16) ----
    PROJ_RES(Wq);
#pragma unroll
    for (int mp = 0; mp < 2; mp++)
#pragma unroll
        for (int p = 0; p < 2; p++) {
            const int row = wm * 32 + mp * 16 + r8 + p * 8;
#pragma unroll
            for (int nt = 0; nt < 8; nt++) {
                const int c = wn * 64 + nt * 8 + 2 * t4;
                float2 bv = *(const float2*)(Bb + c);
                *(uint32_t*)(sm + M2_SQ + row * QROW + c * 2) =
                    pack_h2(acc[mp][nt][2 * p] + bv.x, acc[mp][nt][2 * p + 1] + bv.y);
            }
        }

    // ---- step 2: k0 = Aq @ Wk^T + bmk ; s0 = sum q*k0 per (row, head) ----
    PROJ_RES(Wk);
    {
        float sp[2][2][4];
#pragma unroll
        for (int mp = 0; mp < 2; mp++)
#pragma unroll
            for (int p = 0; p < 2; p++)
#pragma unroll
                for (int h = 0; h < 4; h++) sp[mp][p][h] = 0.0f;
#pragma unroll
        for (int mp = 0; mp < 2; mp++)
#pragma unroll
            for (int p = 0; p < 2; p++) {
                const int row = wm * 32 + mp * 16 + r8 + p * 8;
#pragma unroll
                for (int nt = 0; nt < 8; nt++) {
                    const int c = wn * 64 + nt * 8 + 2 * t4;
                    float2 bv = *(const float2*)(bmk + c);
                    float k0 = acc[mp][nt][2 * p] + bv.x;
                    float k1v = acc[mp][nt][2 * p + 1] + bv.y;
                    float2 qf = __half22float2(
                        *(const __half2*)(sm + M2_SQ + row * QROW + c * 2));
                    sp[mp][p][nt >> 1] += qf.x * k0 + qf.y * k1v;
                }
            }
#pragma unroll
        for (int mp = 0; mp < 2; mp++)
#pragma unroll
            for (int p = 0; p < 2; p++)
#pragma unroll
                for (int h = 0; h < 4; h++) {
                    float v = sp[mp][p][h];
                    v += __shfl_xor_sync(FULLMASK, v, 1);
                    v += __shfl_xor_sync(FULLMASK, v, 2);
                    if (t4 == 0)
                        s0buf[(wm * 32 + mp * 16 + r8 + p * 8) * 8 + wn * 4 + h] = v;
                }
    }

    // ---- step 3: k1 = Ak1 @ Wk^T + Bb[128:] ; s1 = sum q*k1 ----
    PROJ_STR(Ak1, Wk);
    {
        float sp[2][2][4];
#pragma unroll
        for (int mp = 0; mp < 2; mp++)
#pragma unroll
            for (int p = 0; p < 2; p++)
#pragma unroll
                for (int h = 0; h < 4; h++) sp[mp][p][h] = 0.0f;
#pragma unroll
        for (int mp = 0; mp < 2; mp++)
#pragma unroll
            for (int p = 0; p < 2; p++) {
                const int row = wm * 32 + mp * 16 + r8 + p * 8;
#pragma unroll
                for (int nt = 0; nt < 8; nt++) {
                    const int c = wn * 64 + nt * 8 + 2 * t4;
                    float2 bv = *(const float2*)(Bb + 128 + c);
                    float k0 = acc[mp][nt][2 * p] + bv.x;
                    float k1v = acc[mp][nt][2 * p + 1] + bv.y;
                    float2 qf = __half22float2(
                        *(const __half2*)(sm + M2_SQ + row * QROW + c * 2));
                    sp[mp][p][nt >> 1] += qf.x * k0 + qf.y * k1v;
                }
            }
#pragma unroll
        for (int mp = 0; mp < 2; mp++)
#pragma unroll
            for (int p = 0; p < 2; p++)
#pragma unroll
                for (int h = 0; h < 4; h++) {
                    float v = sp[mp][p][h];
                    v += __shfl_xor_sync(FULLMASK, v, 1);
                    v += __shfl_xor_sync(FULLMASK, v, 2);
                    if (t4 == 0)
                        s1buf[(wm * 32 + mp * 16 + r8 + p * 8) * 8 + wn * 4 + h] = v;
                }
    }
    __syncthreads();

    // ---- step 4: softmax over the two keys, per (row, head) ----
    for (int i = tid; i < 1024; i += 256) {
        float a = s0buf[i] * 0.25f, b2 = s1buf[i] * 0.25f;
        float m = fmaxf(a, b2);
        float e0 = __expf(a - m), e1 = __expf(b2 - m);
        float inv = 1.0f / (e0 + e1);
        s0buf[i] = e0 * inv;
        s1buf[i] = e1 * inv;
    }
    __syncthreads();

    // ---- step 5: v0 = Aq @ Wv^T + bmv ; SV = e0 * v0 (fp16) ----
    PROJ_RES(Wv);
#pragma unroll
    for (int mp = 0; mp < 2; mp++)
#pragma unroll
        for (int p = 0; p < 2; p++) {
            const int row = wm * 32 + mp * 16 + r8 + p * 8;
#pragma unroll
            for (int nt = 0; nt < 8; nt++) {
                const int c = wn * 64 + nt * 8 + 2 * t4;
                float2 bv = *(const float2*)(bmv + c);
                const float e0 = s0buf[row * 8 + wn * 4 + (nt >> 1)];
                *(uint32_t*)(sm + M2_SV + row * QROW + c * 2) =
                    pack_h2(e0 * (acc[mp][nt][2 * p] + bv.x),
                            e0 * (acc[mp][nt][2 * p + 1] + bv.y));
            }
        }

    // ---- step 6: v1 = Av1 @ Wv^T + Bb[256:] ; T5 = SV + e1*v1 ----
    PROJ_STR(Av1, Wv);
#pragma unroll
    for (int mp = 0; mp < 2; mp++)
#pragma unroll
        for (int p = 0; p < 2; p++) {
            const int row = wm * 32 + mp * 16 + r8 + p * 8;
            const size_t gr = (size_t)(bm + row) * kC;
#pragma unroll
            for (int nt = 0; nt < 8; nt++) {
                const int c = wn * 64 + nt * 8 + 2 * t4;
                float2 bv = *(const float2*)(Bb + 256 + c);
                const float e1 = s1buf[row * 8 + wn * 4 + (nt >> 1)];
                float2 svf = __half22float2(
                    *(const __half2*)(sm + M2_SV + row * QROW + c * 2));
                *(uint32_t*)(T5 + gr + c) =
                    pack_h2(svf.x + e1 * (acc[mp][nt][2 * p] + bv.x),
                            svf.y + e1 * (acc[mp][nt][2 * p + 1] + bv.y));
            }
        }
#undef PROJ_RES
#undef PROJ_STR
#undef CLR
}

// ---------------------------------------------------------------------------
// Conv via mma: grid (8, 8), each block accumulates 8 kernel positions.
// ---------------------------------------------------------------------------
__global__ __launch_bounds__(256, 2) void conv_mma(
    const __half* __restrict__ xh, const __half* __restrict__ cwh,
    float* __restrict__ part)
{
    extern __shared__ char sm[];
    const uint32_t smb = smem_u32(sm);
    const int tid = threadIdx.x;
    const int lane = tid & 31, wid = tid >> 5;
    const int t4 = lane & 3, r8 = lane >> 2;
    const int wm = wid >> 1, wn = wid & 1;
    const int b = blockIdx.x >> 1, rt = blockIdx.x & 1, pg = blockIdx.y;
    const FragCtx fc = make_frag_ctx(lane, wm, wn);

    float acc[2][8][4];
#pragma unroll
    for (int mt = 0; mt < 2; mt++)
#pragma unroll
        for (int nt = 0; nt < 8; nt++)
#pragma unroll
            for (int e = 0; e < 4; e++) acc[mt][nt][e] = 0.0f;

    const int pr = tid >> 1, hf = tid & 1;
    const int p = rt * 128 + pr;
    const int ph = p >> 4, pwd = p & 15;
    const uint32_t so = (uint32_t)(pr * TROW + hf * 64);

    for (int q = 0; q < 8; q++) {
        const int pos = pg * 8 + q;
        const int kh = pos >> 3, kw = pos & 7;
        const size_t xrow = ((size_t)b * kN + (ph * 8 + kh) * 128 + pwd * 8 + kw) * kC;
        const size_t wbase = (size_t)pos * 16384 + (size_t)pr * kC;
        for (int ch = 0; ch < 2; ch++) {
            const size_t arow = xrow + ch * 64 + hf * 32;
            const size_t brow = wbase + ch * 64 + hf * 32;
#pragma unroll
            for (int gq = 0; gq < 4; gq++) {
                cpa16(smb + so + gq * 16,          xh  + arow + gq * 8);
                cpa16(smb + TBYTES + so + gq * 16, cwh + brow + gq * 8);
            }
            cpa_wait();
            __syncthreads();
            mainloop_chunk(smb, smb + TBYTES, fc, acc);
            __syncthreads();
        }
    }

    const size_t base = ((size_t)pg * kMR + (size_t)b * 256 + rt * 128) * kC;
#pragma unroll
    for (int mt = 0; mt < 2; mt++)
#pragma unroll
        for (int pq = 0; pq < 2; pq++) {
            const int lr = wm * 32 + mt * 16 + r8 + pq * 8;
#pragma unroll
            for (int nt = 0; nt < 8; nt++) {
                const int c = wn * 64 + nt * 8 + 2 * t4;
                *(float2*)(part + base + (size_t)lr * kC + c) =
                    make_float2(acc[mt][nt][2 * pq], acc[mt][nt][2 * pq + 1]);
            }
        }
}

// ---------------------------------------------------------------------------
__global__ void conv_reduce_ln(const float* __restrict__ part,
                               const float* __restrict__ srb,
                               const float* __restrict__ gam,
                               const float* __restrict__ bet,
                               __half* __restrict__ xlnh)
{
    const int row = blockIdx.x;
    const int c = threadIdx.x;
    float v = srb[c];
#pragma unroll
    for (int sp = 0; sp < 8; sp++)
        v += part[((size_t)sp * kMR + row) * kC + c];

    __shared__ float red[4];
    float s = v;
#pragma unroll
    for (int o = 16; o > 0; o >>= 1) s += __shfl_xor_sync(FULLMASK, s, o);
    if ((c & 31) == 0) red[c >> 5] = s;
    __syncthreads();
    const float mean = (red[0] + red[1] + red[2] + red[3]) * (1.0f / 128.0f);
    __syncthreads();
    const float d = v - mean;
    float s2 = d * d;
#pragma unroll
    for (int o = 16; o > 0; o >>= 1) s2 += __shfl_xor_sync(FULLMASK, s2, o);
    if ((c & 31) == 0) red[c >> 5] = s2;
    __syncthreads();
    const float var = (red[0] + red[1] + red[2] + red[3]) * (1.0f / 128.0f);
    xlnh[(size_t)row * kC + c] =
        __float2half_rn(d * rsqrtf(var + 1e-5f) * gam[c] + bet[c]);
}

// ---------------------------------------------------------------------------
__global__ void kv_pack(const float* __restrict__ KB, const float* __restrict__ VB,
                        __half* __restrict__ Kh, __half* __restrict__ Vt)
{
    const int idx = blockIdx.x * 256 + threadIdx.x;
    const int b = idx >> 15, rem = idx & 32767;
    const int m = rem >> 7, c = rem & 127;
    const int h = c >> 6, d = c & 63;
    const int bh = b * 2 + h;
    Kh[((size_t)bh * 256 + m) * 64 + d] = __float2half_rn(KB[idx]);
    Vt[((size_t)bh * 64 + d) * 256 + m] = __float2half_rn(VB[idx]);
}

// ---------------------------------------------------------------------------
// Fused SR attention (unchanged from R14).
// ---------------------------------------------------------------------------
__global__ __launch_bounds__(256, 1) void attn_fused(
    const __half* __restrict__ Qh, const __half* __restrict__ Kh,
    const __half* __restrict__ Vt, __half* __restrict__ XAh)
{
    extern __shared__ char sm[];
    const uint32_t smb = smem_u32(sm);
    const int tid = threadIdx.x;
    const int lane = tid & 31, wid = tid >> 5;
    const int t4 = lane & 3, r8 = lane >> 2;
    const int bh = blockIdx.y;
    const int b = bh >> 1, h = bh & 1;
    const int qt = blockIdx.x;

    const int rA = (lane & 7) + ((lane >> 3) & 1) * 8;
    const int cA = (lane >> 4) * 16;
    const uint32_t aoff = (uint32_t)((wid * 16 + rA) * TROW + cA);
    const int rB = (lane & 7) + ((lane >> 4) & 1) * 8;
    const int cB = ((lane >> 3) & 1) * 16;
    const uint32_t boffb = (uint32_t)(rB * TROW + cB);

    {
        const int pr = tid >> 1, hf = tid & 1;
        const __half* qsrc = Qh +
            ((size_t)(b * kN + qt * 128 + pr) * kC + h * 64 + hf * 32);
        const uint32_t so = (uint32_t)(pr * TROW + hf * 64);
#pragma unroll
        for (int gq = 0; gq < 4; gq++)
            cpa16(smb + so + gq * 16, qsrc + gq * 8);
        const __half* ksrc = Kh + ((size_t)bh * 256 + tid) * 64;
        const uint32_t sob = (uint32_t)(tid * TROW);
#pragma unroll
        for (int gq = 0; gq < 8; gq++)
            cpa16(smb + SMB_K + sob + gq * 16, ksrc + gq * 8);
        const int vr = tid >> 2, vq = tid & 3;
        const __half* vsrc = Vt + ((size_t)bh * 64 + vr) * 256 + vq * 64;
        const uint32_t sov = (uint32_t)(SM_V + vr * PROW + vq * 128);
#pragma unroll
        for (int gq = 0; gq < 8; gq++)
            cpa16(smb + sov + gq * 16, vsrc + gq * 8);
    }
    cpa_wait();
    __syncthreads();

    float acc[32][4];
#pragma unroll
    for (int nt = 0; nt < 32; nt++)
#pragma unroll
        for (int e = 0; e < 4; e++) acc[nt][e] = 0.0f;

#pragma unroll
    for (int kc = 0; kc < 4; kc++) {
        uint32_t af[4];
        ldsm4(af[0], af[1], af[2], af[3], smb + aoff + kc * 32);
#pragma unroll
        for (int np = 0; np < 16; np++) {
            uint32_t b0, b1, b2, b3;
            ldsm4(b0, b1, b2, b3, smb + SMB_K + boffb + np * (16 * TROW) + kc * 32);
            mma16816(acc[np * 2],     af, b0, b1);
            mma16816(acc[np * 2 + 1], af, b2, b3);
        }
    }

    float mx0 = -1e30f, mx1 = -1e30f;
#pragma unroll
    for (int nt = 0; nt < 32; nt++) {
#pragma unroll
        for (int e = 0; e < 4; e++) acc[nt][e] *= 0.125f;
        mx0 = fmaxf(mx0, fmaxf(acc[nt][0], acc[nt][1]));
        mx1 = fmaxf(mx1, fmaxf(acc[nt][2], acc[nt][3]));
    }
    mx0 = fmaxf(mx0, __shfl_xor_sync(FULLMASK, mx0, 1));
    mx0 = fmaxf(mx0, __shfl_xor_sync(FULLMASK, mx0, 2));
    mx1 = fmaxf(mx1, __shfl_xor_sync(FULLMASK, mx1, 1));
    mx1 = fmaxf(mx1, __shfl_xor_sync(FULLMASK, mx1, 2));
    float s0 = 0.0f, s1 = 0.0f;
#pragma unroll
    for (int nt = 0; nt < 32; nt++) {
        acc[nt][0] = __expf(acc[nt][0] - mx0);
        acc[nt][1] = __expf(acc[nt][1] - mx0);
        acc[nt][2] = __expf(acc[nt][2] - mx1);
        acc[nt][3] = __expf(acc[nt][3] - mx1);
        s0 += acc[nt][0] + acc[nt][1];
        s1 += acc[nt][2] + acc[nt][3];
    }
    s0 += __shfl_xor_sync(FULLMASK, s0, 1);
    s0 += __shfl_xor_sync(FULLMASK, s0, 2);
    s1 += __shfl_xor_sync(FULLMASK, s1, 1);
    s1 += __shfl_xor_sync(FULLMASK, s1, 2);
    const float i0 = 1.0f / s0, i1 = 1.0f / s1;

    __syncthreads();

    {
        const uint32_t p0 = (uint32_t)((wid * 16 + r8) * PROW);
        const uint32_t p1 = p0 + 8 * PROW;
#pragma unroll
        for (int nt = 0; nt < 32; nt++) {
            const int c = nt * 8 + 2 * t4;
            *(uint32_t*)(sm + p0 + c * 2) = pack_h2(acc[nt][0] * i0, acc[nt][1] * i0);
            *(uint32_t*)(sm + p1 + c * 2) = pack_h2(acc[nt][2] * i1, acc[nt][3] * i1);
        }
    }
    __syncthreads();

    const int wm = wid >> 1, wn = wid & 1;
    uint32_t aoffP[2];
#pragma unroll
    for (int mt = 0; mt < 2; mt++)
        aoffP[mt] = (uint32_t)((wm * 32 + mt * 16 + rA) * PROW + cA);
    uint32_t boffV[2];
#pragma unroll
    for (int np = 0; np < 2; np++)
        boffV[np] = (uint32_t)(SM_V + (wn * 32 + np * 16 + rB) * PROW + cB);

    float acc2[2][4][4];
#pragma unroll
    for (int mt = 0; mt < 2; mt++)
#pragma unroll
        for (int nt = 0; nt < 4; nt++)
#pragma unroll
            for (int e = 0; e < 4; e++) acc2[mt][nt][e] = 0.0f;

#pragma unroll
    for (int kc = 0; kc < 16; kc++) {
        const uint32_t kb = (uint32_t)kc * 32;
        uint32_t ah[2][4];
#pragma unroll
        for (int mt = 0; mt < 2; mt++)
            ldsm4(ah[mt][0], ah[mt][1], ah[mt][2], ah[mt][3],
                  smb + aoffP[mt] + kb);
#pragma unroll
        for (int np = 0; np < 2; np++) {
            uint32_t b0, b1, b2, b3;
            ldsm4(b0, b1, b2, b3, smb + boffV[np] + kb);
#pragma unroll
            for (int mt = 0; mt < 2; mt++) {
                mma16816(acc2[mt][np * 2],     ah[mt], b0, b1);
                mma16816(acc2[mt][np * 2 + 1], ah[mt], b2, b3);
            }
        }
    }

#pragma unroll
    for (int mt = 0; mt < 2; mt++)
#pragma unroll
        for (int p = 0; p < 2; p++) {
            const int lr = qt * 128 + wm * 32 + mt * 16 + r8 + p * 8;
            const size_t g = ((size_t)b * kN + lr) * kC + h * 64;
#pragma unroll
            for (int nt = 0; nt < 4; nt++) {
                const int c = wn * 32 + nt * 8 + 2 * t4;
                *(uint32_t*)(XAh + g + c) =
                    pack_h2(acc2[mt][nt][2 * p], acc2[mt][nt][2 * p + 1]);
            }
        }
}

// ---------------------------------------------------------------------------
__global__ void cvt_half(const float* __restrict__ src, __half* __restrict__ dst)
{
    const int i = blockIdx.x * 256 + threadIdx.x;
    float4 v = ((const float4*)src)[i];
    ((uint2*)dst)[i] = make_uint2(pack_h2(v.x, v.y), pack_h2(v.z, v.w));
}

__global__ void cvt_w(const float* __restrict__ src, int ldW,
                      __half* __restrict__ dh)
{
    const int i = blockIdx.x * 256 + threadIdx.x;
    const int o = i >> 6, k = (i & 63) * 2;
    *(uint32_t*)(dh + o * kC + k) =
        pack_h2(src[(size_t)o * ldW + k], src[(size_t)o * ldW + k + 1]);
}

__global__ void cvt_w256(const float* __restrict__ src, __half* __restrict__ dh)
{
    const int i = blockIdx.x * 256 + threadIdx.x;
    const int o = i >> 7, k = (i & 127) * 2;
    *(uint32_t*)(dh + o * 256 + k) =
        pack_h2(src[(size_t)o * 256 + k], src[(size_t)o * 256 + k + 1]);
}

__global__ void cvt_convw(const float* __restrict__ srw, __half* __restrict__ dh)
{
    const int t = blockIdx.x * 256 + threadIdx.x;
    const int pos = t >> 13, o = (t >> 6) & 127, i2 = (t & 63) * 2;
    const size_t d = (size_t)pos * 16384 + (size_t)o * kC + i2;
    *(uint32_t*)(dh + d) =
        pack_h2(srw[(size_t)o * 8192 + i2 * 64 + pos],
                srw[(size_t)o * 8192 + (i2 + 1) * 64 + pos]);
}

__global__ void fuse_out_w(const float* __restrict__ pw,
                           const float* __restrict__ cawO,
                           __half* __restrict__ WO)
{
    const int i = blockIdx.x * 256 + threadIdx.x;
    const int o = i >> 7, j = i & 127;
    float acc = 0.0f;
    for (int c = 0; c < 128; c++)
        acc += pw[(size_t)o * 128 + c] * cawO[(size_t)c * 128 + j];
    WO[(size_t)o * 256 + j]       = __float2half_rn(pw[(size_t)o * 128 + j]);
    WO[(size_t)o * 256 + 128 + j] = __float2half_rn(acc);
}

__global__ void fuse_out_b(const float* __restrict__ pw,
                           const float* __restrict__ cabO,
                           const float* __restrict__ pb,
                           float* __restrict__ fb)
{
    const int o = threadIdx.x;
    float acc = pb[o];
    for (int c = 0; c < 128; c++) acc += pw[(size_t)o * 128 + c] * cabO[c];
    fb[o] = acc;
}

__global__ void fold_bias(
    const float* __restrict__ w01, const float* __restrict__ b01,
    const float* __restrict__ w10, const float* __restrict__ b10,
    const float* __restrict__ kn, const float* __restrict__ vn,
    float* __restrict__ bm)
{
    const int which = blockIdx.x, c = threadIdx.x;
    const float* W  = (which < 2) ? w01 : w10;
    const float* Bb = (which < 2) ? b01 : b10;
    const float* nz = ((which & 1) ? vn : kn) + (which >> 1) * kC;
    const int off = (which & 1) ? 256 : 128;
    float acc = Bb[off + c];
    const float* wr = W + (size_t)(off + c) * kC;
    for (int k = 0; k < kC; k++) acc += nz[k] * wr[k];
    bm[which * kC + c] = acc;
}

// ---------------------------------------------------------------------------
extern "C" void kernel_launch(void* const* d_in, const int* in_sizes, int n_in,
                              void* d_out, int out_size)
{
    (void)in_sizes; (void)n_in; (void)out_size;
    const float* x0   = (const float*)d_in[0];
    const float* x1   = (const float*)d_in[1];
    const float* Wq   = (const float*)d_in[2];
    const float* bq   = (const float*)d_in[3];
    const float* Wkv  = (const float*)d_in[4];
    const float* bkv  = (const float*)d_in[5];
    const float* srw  = (const float*)d_in[6];
    const float* srb  = (const float*)d_in[7];
    const float* lnG[2] = {(const float*)d_in[8],  (const float*)d_in[10]};
    const float* lnB[2] = {(const float*)d_in[9],  (const float*)d_in[11]};
    const float* cawI[2] = {(const float*)d_in[12], (const float*)d_in[16]};
    const float* cabI[2] = {(const float*)d_in[13], (const float*)d_in[17]};
    const float* cawO[2] = {(const float*)d_in[14], (const float*)d_in[18]};
    const float* cabO[2] = {(const float*)d_in[15], (const float*)d_in[19]};
    const float* rjw1 = (const float*)d_in[20];
    const float* rjb1 = (const float*)d_in[21];
    const float* rjw2 = (const float*)d_in[22];
    const float* rjb2 = (const float*)d_in[23];
    const float* kn   = (const float*)d_in[24];
    const float* vn   = (const float*)d_in[25];
    const float* pw   = (const float*)d_in[26];
    const float* pb   = (const float*)d_in[27];
    float* out = (float*)d_out;

    float* g = nullptr;
    cudaGetSymbolAddress((void**)&g, g_mem);
    __half* hm = nullptr;
    cudaGetSymbolAddress((void**)&hm, h_mem);

    float *PART = g + O_PART, *KBp = g + O_KB, *VBp = g + O_VB;
    float *BM = g + O_BM, *FB = g + O_FB;

    __half *XH[2]  = {hm + H_X0, hm + H_X1};
    __half *XAH[2] = {hm + H_XA0, hm + H_XA1};
    __half *T1H = hm + H_T1, *XASH = hm + H_XAS, *T5H = hm + H_T5;
    __half *XLNH = hm + H_XLN;
    __half *WSH = hm + H_WS, *CWH = hm + H_CW;
    __half *WJH = hm + H_WJ;
    __half *WOH[2] = {hm + H_WO, hm + H_WO + 32768};
    __half *QH = hm + H_QH;
    __half *KH = hm + H_KH, *VT = hm + H_VT;

    cudaFuncSetAttribute(gemm5, cudaFuncAttributeMaxDynamicSharedMemorySize, SM_G);
    cudaFuncSetAttribute(gemm6, cudaFuncAttributeMaxDynamicSharedMemorySize, SM_G6);
    cudaFuncSetAttribute(conv_mma, cudaFuncAttributeMaxDynamicSharedMemorySize, SM_CONV);
    cudaFuncSetAttribute(attn_fused, cudaFuncAttributeMaxDynamicSharedMemorySize, SM_ATT);
    cudaFuncSetAttribute(mha2_fused, cudaFuncAttributeMaxDynamicSharedMemorySize, SM_M2);

    // --- one-time prep ---
    fold_bias<<<4, 128>>>(cawI[0], cabI[0], cawI[1], cabI[1], kn, vn, BM);
    cvt_half<<<8192, 256>>>(x0, XH[0]);
    cvt_half<<<8192, 256>>>(x1, XH[1]);
    cvt_convw<<<2048, 256>>>(srw, CWH);
    cvt_w256<<<64, 256>>>(rjw1, WJH);
    fuse_out_w<<<64, 256>>>(pw, cawO[0], WOH[0]);
    fuse_out_w<<<64, 256>>>(pw, cawO[1], WOH[1]);
    fuse_out_b<<<1, 128>>>(pw, cabO[0], pb, FB);
    fuse_out_b<<<1, 128>>>(pw, cabO[1], pb, FB + 128);
#define SW(SRC, LD, IDX) cvt_w<<<32, 256>>>(SRC, LD, WSH + (IDX) * 16384)
    SW(Wq, 128, 0);
    SW(Wkv, 128, 1);          SW(Wkv + 16384, 128, 2);
    SW(rjw2, 128, 5);
    SW(cawI[0], 128, 6);      SW(cawI[0] + 16384, 128, 7);  SW(cawI[0] + 32768, 128, 8);
    SW(cawI[1], 128, 9);      SW(cawI[1] + 16384, 128, 10); SW(cawI[1] + 32768, 128, 11);
#undef SW

    const int GM = kMTOK / 256;
    const int G6M = kMTOK / 128;
#define G5(GRID, AH, WI, BIAS, RESID, YF, YH, EPI) \
    gemm5<<<GRID, 256, SM_G>>>(AH, WSH + (WI) * 16384, BIAS, RESID, \
                               nullptr, YF, YH, EPI)
#define G5S(GRID, AH, WI, BIAS, PMUL, YH) \
    gemm5<<<GRID, 256, SM_G>>>(AH, WSH + (WI) * 16384, BIAS, nullptr, \
                               PMUL, nullptr, YH, 2)

    // --- Stage A: SR attention per stream ---
    for (int s = 0; s < 2; s++) {
        G5(GM, XH[s], 0, bq, nullptr, nullptr, QH, 0);
        conv_mma<<<dim3(8, 8), 256, SM_CONV>>>(XH[s], CWH, PART);
        conv_reduce_ln<<<1024, 128>>>(PART, srb, lnG[s], lnB[s], XLNH);
        G5(4, XLNH, 1, bkv,       nullptr, KBp, nullptr, 0);
        G5(4, XLNH, 2, bkv + 128, nullptr, VBp, nullptr, 0);
        kv_pack<<<512, 256>>>(KBp, VBp, KH, VT);
        attn_fused<<<dim3(128, 8), 256, SM_ATT>>>(QH, KH, VT, XAH[s]);
    }

    // --- Stage B + C per stream ---
    for (int s = 0; s < 2; s++) {
        gemm6<<<G6M, 256, SM_G6>>>(XAH[s], XAH[s ^ 1], WJH, rjb1,
                                   nullptr, T1H, 1);
        G5S(GM, T1H, 5, rjb2, XAH[s], XASH);
        mha2_fused<<<512, 256, SM_M2>>>(XAH[s], XASH, XAH[s ^ 1],
                                        WSH + (6 + 3 * s) * 16384,
                                        WSH + (7 + 3 * s) * 16384,
                                        WSH + (8 + 3 * s) * 16384,
                                        cabI[s], BM + 2 * s * kC,
                                        BM + (2 * s + 1) * kC, T5H);
        gemm6<<<G6M, 256, SM_G6>>>(XAH[s], T5H, WOH[s], FB + s * 128,
                                   out + (size_t)s * SZ, nullptr, 0);
    }
#undef G5
#undef G5S
}

// round 17
// speedup vs baseline: 3.8667x; 1.0933x over previous
#include <cuda_runtime.h>
#include <cuda_fp16.h>
#include <math.h>
#include <stdint.h>

#define FULLMASK 0xffffffffu

namespace {
constexpr int kB = 4, kN = 16384, kC = 128, kMTOK = 65536;
constexpr size_t SZ = (size_t)kMTOK * kC;

// fp32 scratch (PART now 8 slices x 2048 rows: both streams batched)
constexpr size_t O_PART = 0;                         // 8*2048*128 = 2,097,152
constexpr size_t O_KB  = O_PART + 8 * 2048 * 128;    // 262144
constexpr size_t O_VB  = O_KB + 262144;
constexpr size_t O_BM  = O_VB + 262144;
constexpr size_t O_FB  = O_BM + 512;
constexpr size_t TOTF  = O_FB + 512;

// fp16 buffers (stream-contiguous where batched)
constexpr size_t H_X0  = 0;
constexpr size_t H_X1  = SZ;
constexpr size_t H_XA0 = 2 * SZ;
constexpr size_t H_XA1 = 3 * SZ;
constexpr size_t H_T1  = 4 * SZ;
constexpr size_t H_XAS = 5 * SZ;
constexpr size_t H_T5  = 6 * SZ;
constexpr size_t H_XLN = 7 * SZ;                     // 262144 (2 streams)
constexpr size_t H_WS  = H_XLN + 262144;
constexpr size_t H_CW  = H_WS + 15 * 16384;
constexpr size_t H_WJ  = H_CW + 64 * 16384;
constexpr size_t H_WO  = H_WJ + 32768;
constexpr size_t H_QH  = H_WO + 2 * 32768;           // 2*SZ (2 streams)
constexpr size_t H_KH  = H_QH + 2 * SZ;              // 262144
constexpr size_t H_VT  = H_KH + 262144;              // 262144
constexpr size_t TOTH  = H_VT + 262144;

// tile geometry
constexpr int TROW   = 144;
constexpr int TBYTES = 128 * TROW;          // 18432

// gemm5 smem
constexpr int SM_B0 = 0;
constexpr int SM_B1 = TBYTES;
constexpr int SM_A0 = 2 * TBYTES;
constexpr int SM_A1 = 3 * TBYTES;
constexpr int SM_RED = 4 * TBYTES;
constexpr int SM_G   = SM_RED + 2048;       // 75776

constexpr int SM_G6  = 2 * TBYTES;
constexpr int SM_CONV = 2 * TBYTES;

// fused attention smem
constexpr int SMB_K  = TBYTES;
constexpr int PROW   = 528;
constexpr int SM_V   = 128 * PROW;
constexpr int SM_ATT = SM_V + 64 * PROW;    // 101376

// mha2_fused smem
constexpr int M2_SA  = 2 * TBYTES;
constexpr int M2_SB  = 3 * TBYTES;
constexpr int M2_SQ  = 4 * TBYTES;
constexpr int QROW   = 272;
constexpr int M2_SV  = M2_SQ + 128 * QROW;
constexpr int M2_S0  = M2_SV + 128 * QROW;
constexpr int M2_S1  = M2_S0 + 4096;
constexpr int SM_M2  = M2_S1 + 4096;        // 151552
}

__device__ float g_mem[TOTF];
__device__ __half h_mem[TOTH];

// ---------------------------------------------------------------------------
__device__ __forceinline__ uint32_t smem_u32(const void* p) {
    uint32_t a;
    asm("{ .reg .u64 t; cvta.to.shared.u64 t, %1; cvt.u32.u64 %0, t; }"
        : "=r"(a) : "l"(p));
    return a;
}
__device__ __forceinline__ uint32_t pack_h2(float a, float b) {
    __half2 h = __floats2half2_rn(a, b);
    return *(uint32_t*)&h;
}
__device__ __forceinline__ void mma16816(float* d, const uint32_t* a,
                                         uint32_t b0, uint32_t b1) {
    asm volatile(
        "mma.sync.aligned.m16n8k16.row.col.f32.f16.f16.f32 "
        "{%0,%1,%2,%3}, {%4,%5,%6,%7}, {%8,%9}, {%0,%1,%2,%3};"
        : "+f"(d[0]), "+f"(d[1]), "+f"(d[2]), "+f"(d[3])
        : "r"(a[0]), "r"(a[1]), "r"(a[2]), "r"(a[3]), "r"(b0), "r"(b1));
}
__device__ __forceinline__ void ldsm4(uint32_t& r0, uint32_t& r1,
                                      uint32_t& r2, uint32_t& r3, uint32_t addr) {
    asm volatile("ldmatrix.sync.aligned.m8n8.x4.shared.b16 {%0,%1,%2,%3}, [%4];"
                 : "=r"(r0), "=r"(r1), "=r"(r2), "=r"(r3) : "r"(addr));
}
__device__ __forceinline__ void cpa16(uint32_t dst, const void* src) {
    asm volatile("cp.async.cg.shared.global [%0], [%1], 16;"
                 :: "r"(dst), "l"(src));
}
__device__ __forceinline__ void cpa_wait() {
    asm volatile("cp.async.commit_group;\ncp.async.wait_group 0;" ::: "memory");
}

// ---------------------------------------------------------------------------
struct FragCtx {
    uint32_t aoff[2];
    uint32_t boff[4];
};
__device__ __forceinline__ FragCtx make_frag_ctx(int lane, int wm, int wn) {
    FragCtx fc;
    const int rA = (lane & 7) + ((lane >> 3) & 1) * 8;
    const int cA = (lane >> 4) * 16;
#pragma unroll
    for (int mt = 0; mt < 2; mt++)
        fc.aoff[mt] = (uint32_t)((wm * 32 + mt * 16 + rA) * TROW + cA);
    const int rB = (lane & 7) + ((lane >> 4) & 1) * 8;
    const int cB = ((lane >> 3) & 1) * 16;
#pragma unroll
    for (int np = 0; np < 4; np++)
        fc.boff[np] = (uint32_t)((wn * 64 + np * 16 + rB) * TROW + cB);
    return fc;
}
__device__ __forceinline__ void mainloop_chunk(uint32_t aBase, uint32_t bBase,
                                               const FragCtx& fc,
                                               float acc[2][8][4]) {
#pragma unroll
    for (int kc = 0; kc < 4; kc++) {
        const uint32_t kb = (uint32_t)kc * 32;
        uint32_t ah[2][4];
#pragma unroll
        for (int mt = 0; mt < 2; mt++)
            ldsm4(ah[mt][0], ah[mt][1], ah[mt][2], ah[mt][3],
                  aBase + fc.aoff[mt] + kb);
#pragma unroll
        for (int np = 0; np < 4; np++) {
            uint32_t b0, b1, b2, b3;
            ldsm4(b0, b1, b2, b3, bBase + fc.boff[np] + kb);
#pragma unroll
            for (int mt = 0; mt < 2; mt++) {
                mma16816(acc[mt][np * 2],     ah[mt], b0, b1);
                mma16816(acc[mt][np * 2 + 1], ah[mt], b2, b3);
            }
        }
    }
}

// ---------------------------------------------------------------------------
// GEMM v5: 256 rows/CTA, resident B, K=128.
// ---------------------------------------------------------------------------
__global__ __launch_bounds__(256, 2) void gemm5(
    const __half* __restrict__ A, const __half* __restrict__ Bw,
    const float* __restrict__ bias, const float* __restrict__ resid,
    const __half* __restrict__ postmul,
    float* __restrict__ Yf, __half* __restrict__ Yh, int epi)
{
    extern __shared__ char sm[];
    const uint32_t smb = smem_u32(sm);
    const int tid = threadIdx.x;
    const int lane = tid & 31, wid = tid >> 5;
    const int t4 = lane & 3, r8 = lane >> 2;
    const int wm = wid >> 1, wn = wid & 1;
    const int bm0 = blockIdx.x * 256;
    const FragCtx fc = make_frag_ctx(lane, wm, wn);
    const int pr = tid >> 1, hf = tid & 1;
    const uint32_t so = (uint32_t)(pr * TROW + hf * 64);

#pragma unroll
    for (int ch = 0; ch < 2; ch++) {
        const size_t brow = (size_t)pr * kC + ch * 64 + hf * 32;
        const size_t arow = (size_t)(bm0 + pr) * kC + ch * 64 + hf * 32;
#pragma unroll
        for (int gq = 0; gq < 4; gq++) {
            cpa16(smb + SM_B0 + ch * TBYTES + so + gq * 16, Bw + brow + gq * 8);
            cpa16(smb + SM_A0 + ch * TBYTES + so + gq * 16, A  + arow + gq * 8);
        }
    }
    cpa_wait();
    __syncthreads();

    float* redm = (float*)(sm + SM_RED);
    float* reds = (float*)(sm + SM_RED + 1024);

    for (int mt = 0; mt < 2; mt++) {
        const int bm = bm0 + mt * 128;
        float acc[2][8][4];
#pragma unroll
        for (int mp = 0; mp < 2; mp++)
#pragma unroll
            for (int nt = 0; nt < 8; nt++)
#pragma unroll
                for (int e = 0; e < 4; e++) acc[mp][nt][e] = 0.0f;

        mainloop_chunk(smb + SM_A0, smb + SM_B0, fc, acc);
        mainloop_chunk(smb + SM_A1, smb + SM_B1, fc, acc);
        __syncthreads();

        if (mt == 0) {
#pragma unroll
            for (int ch = 0; ch < 2; ch++) {
                const size_t arow = (size_t)(bm0 + 128 + pr) * kC + ch * 64 + hf * 32;
#pragma unroll
                for (int gq = 0; gq < 4; gq++)
                    cpa16(smb + SM_A0 + ch * TBYTES + so + gq * 16, A + arow + gq * 8);
            }
        }

        if (bias) {
#pragma unroll
            for (int nt = 0; nt < 8; nt++) {
                float2 bv = *(const float2*)(bias + wn * 64 + nt * 8 + 2 * t4);
#pragma unroll
                for (int mp = 0; mp < 2; mp++) {
                    acc[mp][nt][0] += bv.x; acc[mp][nt][1] += bv.y;
                    acc[mp][nt][2] += bv.x; acc[mp][nt][3] += bv.y;
                }
            }
        }

        if (epi != 2) {
#pragma unroll
            for (int mp = 0; mp < 2; mp++)
#pragma unroll
                for (int p = 0; p < 2; p++) {
                    const int r = bm + wm * 32 + mp * 16 + r8 + p * 8;
#pragma unroll
                    for (int nt = 0; nt < 8; nt++) {
                        const int c = wn * 64 + nt * 8 + 2 * t4;
                        float v0 = acc[mp][nt][2 * p];
                        float v1 = acc[mp][nt][2 * p + 1];
                        if (resid) {
                            float2 rv = *(const float2*)(resid + (size_t)r * kC + c);
                            v0 += rv.x; v1 += rv.y;
                        }
                        if (epi == 1) {
                            v0 = 0.5f * v0 * (1.0f + erff(v0 * 0.70710678118654752f));
                            v1 = 0.5f * v1 * (1.0f + erff(v1 * 0.70710678118654752f));
                        }
                        if (Yf)
                            *(float2*)(Yf + (size_t)r * kC + c) = make_float2(v0, v1);
                        if (Yh)
                            *(uint32_t*)(Yh + (size_t)r * kC + c) = pack_h2(v0, v1);
                    }
                }
        } else {
            float pm[2][2];
#pragma unroll
            for (int mp = 0; mp < 2; mp++) {
                float a0 = -1e30f, a1 = -1e30f;
#pragma unroll
                for (int nt = 0; nt < 8; nt++) {
                    a0 = fmaxf(a0, fmaxf(acc[mp][nt][0], acc[mp][nt][1]));
                    a1 = fmaxf(a1, fmaxf(acc[mp][nt][2], acc[mp][nt][3]));
                }
                pm[mp][0] = a0; pm[mp][1] = a1;
            }
#pragma unroll
            for (int mp = 0; mp < 2; mp++)
#pragma unroll
                for (int p = 0; p < 2; p++) {
                    pm[mp][p] = fmaxf(pm[mp][p], __shfl_xor_sync(FULLMASK, pm[mp][p], 1));
                    pm[mp][p] = fmaxf(pm[mp][p], __shfl_xor_sync(FULLMASK, pm[mp][p], 2));
                }
            if (t4 == 0) {
#pragma unroll
                for (int mp = 0; mp < 2; mp++)
#pragma unroll
                    for (int p = 0; p < 2; p++)
                        redm[(wm * 32 + mp * 16 + r8 + p * 8) * 2 + wn] = pm[mp][p];
            }
            __syncthreads();
            float M[2][2], ps[2][2];
#pragma unroll
            for (int mp = 0; mp < 2; mp++)
#pragma unroll
                for (int p = 0; p < 2; p++) {
                    const int lr = wm * 32 + mp * 16 + r8 + p * 8;
                    M[mp][p] = fmaxf(redm[lr * 2], redm[lr * 2 + 1]);
                    ps[mp][p] = 0.0f;
                }
#pragma unroll
            for (int mp = 0; mp < 2; mp++)
#pragma unroll
                for (int nt = 0; nt < 8; nt++) {
                    acc[mp][nt][0] = __expf(acc[mp][nt][0] - M[mp][0]);
                    acc[mp][nt][1] = __expf(acc[mp][nt][1] - M[mp][0]);
                    acc[mp][nt][2] = __expf(acc[mp][nt][2] - M[mp][1]);
                    acc[mp][nt][3] = __expf(acc[mp][nt][3] - M[mp][1]);
                    ps[mp][0] += acc[mp][nt][0] + acc[mp][nt][1];
                    ps[mp][1] += acc[mp][nt][2] + acc[mp][nt][3];
                }
#pragma unroll
            for (int mp = 0; mp < 2; mp++)
#pragma unroll
                for (int p = 0; p < 2; p++) {
                    ps[mp][p] += __shfl_xor_sync(FULLMASK, ps[mp][p], 1);
                    ps[mp][p] += __shfl_xor_sync(FULLMASK, ps[mp][p], 2);
                }
            if (t4 == 0) {
#pragma unroll
                for (int mp = 0; mp < 2; mp++)
#pragma unroll
                    for (int p = 0; p < 2; p++)
                        reds[(wm * 32 + mp * 16 + r8 + p * 8) * 2 + wn] = ps[mp][p];
            }
            __syncthreads();
#pragma unroll
            for (int mp = 0; mp < 2; mp++)
#pragma unroll
                for (int p = 0; p < 2; p++) {
                    const int lr = wm * 32 + mp * 16 + r8 + p * 8;
                    const float inv = 1.0f / (reds[lr * 2] + reds[lr * 2 + 1]);
                    const size_t gr = (size_t)(bm + lr) * kC;
#pragma unroll
                    for (int nt = 0; nt < 8; nt++) {
                        const int c = wn * 64 + nt * 8 + 2 * t4;
                        float2 pmv = __half22float2(*(const __half2*)(postmul + gr + c));
                        float v0 = acc[mp][nt][2 * p]     * inv * pmv.x;
                        float v1 = acc[mp][nt][2 * p + 1] * inv * pmv.y;
                        *(uint32_t*)(Yh + gr + c) = pack_h2(v0, v1);
                    }
                }
        }

        if (mt == 0) {
            cpa_wait();
            __syncthreads();
        }
    }
}

// ---------------------------------------------------------------------------
// GEMM v6: K=256 over two A sources.
// ---------------------------------------------------------------------------
__global__ __launch_bounds__(256, 2) void gemm6(
    const __half* __restrict__ A1, const __half* __restrict__ A2,
    const __half* __restrict__ Bw, const float* __restrict__ bias,
    float* __restrict__ Yf, __half* __restrict__ Yh, int epi)
{
    extern __shared__ char sm[];
    const uint32_t smb = smem_u32(sm);
    const int tid = threadIdx.x;
    const int lane = tid & 31, wid = tid >> 5;
    const int t4 = lane & 3, r8 = lane >> 2;
    const int wm = wid >> 1, wn = wid & 1;
    const int bm = blockIdx.x * 128;
    const FragCtx fc = make_frag_ctx(lane, wm, wn);
    const int pr = tid >> 1, hf = tid & 1;
    const uint32_t so = (uint32_t)(pr * TROW + hf * 64);

    float acc[2][8][4];
#pragma unroll
    for (int mp = 0; mp < 2; mp++)
#pragma unroll
        for (int nt = 0; nt < 8; nt++)
#pragma unroll
            for (int e = 0; e < 4; e++) acc[mp][nt][e] = 0.0f;

    for (int ch = 0; ch < 4; ch++) {
        const __half* A = (ch < 2) ? A1 : A2;
        const int acol = (ch & 1) * 64;
        const size_t arow = (size_t)(bm + pr) * kC + acol + hf * 32;
        const size_t brow = (size_t)pr * 256 + ch * 64 + hf * 32;
#pragma unroll
        for (int gq = 0; gq < 4; gq++) {
            cpa16(smb + so + gq * 16,          A  + arow + gq * 8);
            cpa16(smb + TBYTES + so + gq * 16, Bw + brow + gq * 8);
        }
        cpa_wait();
        __syncthreads();
        mainloop_chunk(smb, smb + TBYTES, fc, acc);
        __syncthreads();
    }

#pragma unroll
    for (int mp = 0; mp < 2; mp++)
#pragma unroll
        for (int p = 0; p < 2; p++) {
            const int r = bm + wm * 32 + mp * 16 + r8 + p * 8;
#pragma unroll
            for (int nt = 0; nt < 8; nt++) {
                const int c = wn * 64 + nt * 8 + 2 * t4;
                float v0 = acc[mp][nt][2 * p];
                float v1 = acc[mp][nt][2 * p + 1];
                if (bias) {
                    float2 bv = *(const float2*)(bias + c);
                    v0 += bv.x; v1 += bv.y;
                }
                if (epi == 1) {
                    v0 = 0.5f * v0 * (1.0f + erff(v0 * 0.70710678118654752f));
                    v1 = 0.5f * v1 * (1.0f + erff(v1 * 0.70710678118654752f));
                }
                if (Yf)
                    *(float2*)(Yf + (size_t)r * kC + c) = make_float2(v0, v1);
                if (Yh)
                    *(uint32_t*)(Yh + (size_t)r * kC + c) = pack_h2(v0, v1);
            }
        }
}

// ---------------------------------------------------------------------------
// Fused mha2 (unchanged from R15).
// ---------------------------------------------------------------------------
__global__ __launch_bounds__(256, 1) void mha2_fused(
    const __half* __restrict__ Aq, const __half* __restrict__ Ak1,
    const __half* __restrict__ Av1,
    const __half* __restrict__ Wq, const __half* __restrict__ Wk,
    const __half* __restrict__ Wv,
    const float* __restrict__ Bb,
    const float* __restrict__ bmk, const float* __restrict__ bmv,
    __half* __restrict__ T5)
{
    extern __shared__ char sm[];
    const uint32_t smb = smem_u32(sm);
    const int tid = threadIdx.x;
    const int lane = tid & 31, wid = tid >> 5;
    const int t4 = lane & 3, r8 = lane >> 2;
    const int wm = wid >> 1, wn = wid & 1;
    const int bm = blockIdx.x * 128;
    const FragCtx fc = make_frag_ctx(lane, wm, wn);
    const int pr = tid >> 1, hf = tid & 1;
    const uint32_t so = (uint32_t)(pr * TROW + hf * 64);

    float* s0buf = (float*)(sm + M2_S0);
    float* s1buf = (float*)(sm + M2_S1);

#pragma unroll
    for (int ch = 0; ch < 2; ch++) {
        const size_t arow = (size_t)(bm + pr) * kC + ch * 64 + hf * 32;
#pragma unroll
        for (int gq = 0; gq < 4; gq++)
            cpa16(smb + ch * TBYTES + so + gq * 16, Aq + arow + gq * 8);
    }
    cpa_wait();
    __syncthreads();

    float acc[2][8][4];

#define CLR() do { \
    _Pragma("unroll") for (int mp = 0; mp < 2; mp++) \
    _Pragma("unroll") for (int nt = 0; nt < 8; nt++) \
    _Pragma("unroll") for (int e = 0; e < 4; e++) acc[mp][nt][e] = 0.0f; \
} while (0)

#define PROJ_RES(W) do { CLR(); \
    for (int ch = 0; ch < 2; ch++) { \
        const size_t brow = (size_t)pr * kC + ch * 64 + hf * 32; \
        _Pragma("unroll") for (int gq = 0; gq < 4; gq++) \
            cpa16(smb + M2_SB + so + gq * 16, (W) + brow + gq * 8); \
        cpa_wait(); __syncthreads(); \
        mainloop_chunk(smb + ch * TBYTES, smb + M2_SB, fc, acc); \
        __syncthreads(); \
    } } while (0)

#define PROJ_STR(AG, W) do { CLR(); \
    for (int ch = 0; ch < 2; ch++) { \
        const size_t arow = (size_t)(bm + pr) * kC + ch * 64 + hf * 32; \
        const size_t brow = (size_t)pr * kC + ch * 64 + hf * 32; \
        _Pragma("unroll") for (int gq = 0; gq < 4; gq++) { \
            cpa16(smb + M2_SA + so + gq * 16, (AG) + arow + gq * 8); \
            cpa16(smb + M2_SB + so + gq * 16, (W)  + brow + gq * 8); \
        } \
        cpa_wait(); __syncthreads(); \
        mainloop_chunk(smb + M2_SA, smb + M2_SB, fc, acc); \
        __syncthreads(); \
    } } while (0)

    PROJ_RES(Wq);
#pragma unroll
    for (int mp = 0; mp < 2; mp++)
#pragma unroll
        for (int p = 0; p < 2; p++) {
            const int row = wm * 32 + mp * 16 + r8 + p * 8;
#pragma unroll
            for (int nt = 0; nt < 8; nt++) {
                const int c = wn * 64 + nt * 8 + 2 * t4;
                float2 bv = *(const float2*)(Bb + c);
                *(uint32_t*)(sm + M2_SQ + row * QROW + c * 2) =
                    pack_h2(acc[mp][nt][2 * p] + bv.x, acc[mp][nt][2 * p + 1] + bv.y);
            }
        }

    PROJ_RES(Wk);
    {
        float sp[2][2][4];
#pragma unroll
        for (int mp = 0; mp < 2; mp++)
#pragma unroll
            for (int p = 0; p < 2; p++)
#pragma unroll
                for (int h = 0; h < 4; h++) sp[mp][p][h] = 0.0f;
#pragma unroll
        for (int mp = 0; mp < 2; mp++)
#pragma unroll
            for (int p = 0; p < 2; p++) {
                const int row = wm * 32 + mp * 16 + r8 + p * 8;
#pragma unroll
                for (int nt = 0; nt < 8; nt++) {
                    const int c = wn * 64 + nt * 8 + 2 * t4;
                    float2 bv = *(const float2*)(bmk + c);
                    float k0 = acc[mp][nt][2 * p] + bv.x;
                    float k1v = acc[mp][nt][2 * p + 1] + bv.y;
                    float2 qf = __half22float2(
                        *(const __half2*)(sm + M2_SQ + row * QROW + c * 2));
                    sp[mp][p][nt >> 1] += qf.x * k0 + qf.y * k1v;
                }
            }
#pragma unroll
        for (int mp = 0; mp < 2; mp++)
#pragma unroll
            for (int p = 0; p < 2; p++)
#pragma unroll
                for (int h = 0; h < 4; h++) {
                    float v = sp[mp][p][h];
                    v += __shfl_xor_sync(FULLMASK, v, 1);
                    v += __shfl_xor_sync(FULLMASK, v, 2);
                    if (t4 == 0)
                        s0buf[(wm * 32 + mp * 16 + r8 + p * 8) * 8 + wn * 4 + h] = v;
                }
    }

    PROJ_STR(Ak1, Wk);
    {
        float sp[2][2][4];
#pragma unroll
        for (int mp = 0; mp < 2; mp++)
#pragma unroll
            for (int p = 0; p < 2; p++)
#pragma unroll
                for (int h = 0; h < 4; h++) sp[mp][p][h] = 0.0f;
#pragma unroll
        for (int mp = 0; mp < 2; mp++)
#pragma unroll
            for (int p = 0; p < 2; p++) {
                const int row = wm * 32 + mp * 16 + r8 + p * 8;
#pragma unroll
                for (int nt = 0; nt < 8; nt++) {
                    const int c = wn * 64 + nt * 8 + 2 * t4;
                    float2 bv = *(const float2*)(Bb + 128 + c);
                    float k0 = acc[mp][nt][2 * p] + bv.x;
                    float k1v = acc[mp][nt][2 * p + 1] + bv.y;
                    float2 qf = __half22float2(
                        *(const __half2*)(sm + M2_SQ + row * QROW + c * 2));
                    sp[mp][p][nt >> 1] += qf.x * k0 + qf.y * k1v;
                }
            }
#pragma unroll
        for (int mp = 0; mp < 2; mp++)
#pragma unroll
            for (int p = 0; p < 2; p++)
#pragma unroll
                for (int h = 0; h < 4; h++) {
                    float v = sp[mp][p][h];
                    v += __shfl_xor_sync(FULLMASK, v, 1);
                    v += __shfl_xor_sync(FULLMASK, v, 2);
                    if (t4 == 0)
                        s1buf[(wm * 32 + mp * 16 + r8 + p * 8) * 8 + wn * 4 + h] = v;
                }
    }
    __syncthreads();

    for (int i = tid; i < 1024; i += 256) {
        float a = s0buf[i] * 0.25f, b2 = s1buf[i] * 0.25f;
        float m = fmaxf(a, b2);
        float e0 = __expf(a - m), e1 = __expf(b2 - m);
        float inv = 1.0f / (e0 + e1);
        s0buf[i] = e0 * inv;
        s1buf[i] = e1 * inv;
    }
    __syncthreads();

    PROJ_RES(Wv);
#pragma unroll
    for (int mp = 0; mp < 2; mp++)
#pragma unroll
        for (int p = 0; p < 2; p++) {
            const int row = wm * 32 + mp * 16 + r8 + p * 8;
#pragma unroll
            for (int nt = 0; nt < 8; nt++) {
                const int c = wn * 64 + nt * 8 + 2 * t4;
                float2 bv = *(const float2*)(bmv + c);
                const float e0 = s0buf[row * 8 + wn * 4 + (nt >> 1)];
                *(uint32_t*)(sm + M2_SV + row * QROW + c * 2) =
                    pack_h2(e0 * (acc[mp][nt][2 * p] + bv.x),
                            e0 * (acc[mp][nt][2 * p + 1] + bv.y));
            }
        }

    PROJ_STR(Av1, Wv);
#pragma unroll
    for (int mp = 0; mp < 2; mp++)
#pragma unroll
        for (int p = 0; p < 2; p++) {
            const int row = wm * 32 + mp * 16 + r8 + p * 8;
            const size_t gr = (size_t)(bm + row) * kC;
#pragma unroll
            for (int nt = 0; nt < 8; nt++) {
                const int c = wn * 64 + nt * 8 + 2 * t4;
                float2 bv = *(const float2*)(Bb + 256 + c);
                const float e1 = s1buf[row * 8 + wn * 4 + (nt >> 1)];
                float2 svf = __half22float2(
                    *(const __half2*)(sm + M2_SV + row * QROW + c * 2));
                *(uint32_t*)(T5 + gr + c) =
                    pack_h2(svf.x + e1 * (acc[mp][nt][2 * p] + bv.x),
                            svf.y + e1 * (acc[mp][nt][2 * p + 1] + bv.y));
            }
        }
#undef PROJ_RES
#undef PROJ_STR
#undef CLR
}

// ---------------------------------------------------------------------------
// Conv via mma: grid (16, 8) — both streams batched, 8 positions per CTA.
// part layout: [pg][gb*256 + rt*128 + row][128], gb = global batch (0..7).
// ---------------------------------------------------------------------------
__global__ __launch_bounds__(256, 2) void conv_mma(
    const __half* __restrict__ xh, const __half* __restrict__ cwh,
    float* __restrict__ part)
{
    extern __shared__ char sm[];
    const uint32_t smb = smem_u32(sm);
    const int tid = threadIdx.x;
    const int lane = tid & 31, wid = tid >> 5;
    const int t4 = lane & 3, r8 = lane >> 2;
    const int wm = wid >> 1, wn = wid & 1;
    const int b = blockIdx.x >> 1, rt = blockIdx.x & 1, pg = blockIdx.y;
    const FragCtx fc = make_frag_ctx(lane, wm, wn);

    float acc[2][8][4];
#pragma unroll
    for (int mt = 0; mt < 2; mt++)
#pragma unroll
        for (int nt = 0; nt < 8; nt++)
#pragma unroll
            for (int e = 0; e < 4; e++) acc[mt][nt][e] = 0.0f;

    const int pr = tid >> 1, hf = tid & 1;
    const int p = rt * 128 + pr;
    const int ph = p >> 4, pwd = p & 15;
    const uint32_t so = (uint32_t)(pr * TROW + hf * 64);

    for (int q = 0; q < 8; q++) {
        const int pos = pg * 8 + q;
        const int kh = pos >> 3, kw = pos & 7;
        const size_t xrow = ((size_t)b * kN + (ph * 8 + kh) * 128 + pwd * 8 + kw) * kC;
        const size_t wbase = (size_t)pos * 16384 + (size_t)pr * kC;
        for (int ch = 0; ch < 2; ch++) {
            const size_t arow = xrow + ch * 64 + hf * 32;
            const size_t brow = wbase + ch * 64 + hf * 32;
#pragma unroll
            for (int gq = 0; gq < 4; gq++) {
                cpa16(smb + so + gq * 16,          xh  + arow + gq * 8);
                cpa16(smb + TBYTES + so + gq * 16, cwh + brow + gq * 8);
            }
            cpa_wait();
            __syncthreads();
            mainloop_chunk(smb, smb + TBYTES, fc, acc);
            __syncthreads();
        }
    }

    const size_t base = ((size_t)pg * 2048 + (size_t)b * 256 + rt * 128) * kC;
#pragma unroll
    for (int mt = 0; mt < 2; mt++)
#pragma unroll
        for (int pq = 0; pq < 2; pq++) {
            const int lr = wm * 32 + mt * 16 + r8 + pq * 8;
#pragma unroll
            for (int nt = 0; nt < 8; nt++) {
                const int c = wn * 64 + nt * 8 + 2 * t4;
                *(float2*)(part + base + (size_t)lr * kC + c) =
                    make_float2(acc[mt][nt][2 * pq], acc[mt][nt][2 * pq + 1]);
            }
        }
}

// ---------------------------------------------------------------------------
// Reduce + LayerNorm, both streams (row >> 10 selects gamma/beta set).
// ---------------------------------------------------------------------------
__global__ void conv_reduce_ln(const float* __restrict__ part,
                               const float* __restrict__ srb,
                               const float* __restrict__ g0,
                               const float* __restrict__ b0,
                               const float* __restrict__ g1,
                               const float* __restrict__ b1,
                               __half* __restrict__ xlnh)
{
    const int row = blockIdx.x;           // 0..2047
    const int c = threadIdx.x;
    const float* gam = (row >> 10) ? g1 : g0;
    const float* bet = (row >> 10) ? b1 : b0;
    float v = srb[c];
#pragma unroll
    for (int sp = 0; sp < 8; sp++)
        v += part[((size_t)sp * 2048 + row) * kC + c];

    __shared__ float red[4];
    float s = v;
#pragma unroll
    for (int o = 16; o > 0; o >>= 1) s += __shfl_xor_sync(FULLMASK, s, o);
    if ((c & 31) == 0) red[c >> 5] = s;
    __syncthreads();
    const float mean = (red[0] + red[1] + red[2] + red[3]) * (1.0f / 128.0f);
    __syncthreads();
    const float d = v - mean;
    float s2 = d * d;
#pragma unroll
    for (int o = 16; o > 0; o >>= 1) s2 += __shfl_xor_sync(FULLMASK, s2, o);
    if ((c & 31) == 0) red[c >> 5] = s2;
    __syncthreads();
    const float var = (red[0] + red[1] + red[2] + red[3]) * (1.0f / 128.0f);
    xlnh[(size_t)row * kC + c] =
        __float2half_rn(d * rsqrtf(var + 1e-5f) * gam[c] + bet[c]);
}

// ---------------------------------------------------------------------------
__global__ void kv_pack(const float* __restrict__ KB, const float* __restrict__ VB,
                        __half* __restrict__ Kh, __half* __restrict__ Vt)
{
    const int idx = blockIdx.x * 256 + threadIdx.x;   // 262144 (both streams)
    const int b = idx >> 15, rem = idx & 32767;
    const int m = rem >> 7, c = rem & 127;
    const int h = c >> 6, d = c & 63;
    const int bh = b * 2 + h;
    Kh[((size_t)bh * 256 + m) * 64 + d] = __float2half_rn(KB[idx]);
    Vt[((size_t)bh * 64 + d) * 256 + m] = __float2half_rn(VB[idx]);
}

// ---------------------------------------------------------------------------
// Fused SR attention, both streams batched: grid (128, 16).
// ---------------------------------------------------------------------------
__global__ __launch_bounds__(256, 1) void attn_fused(
    const __half* __restrict__ Qh, const __half* __restrict__ Kh,
    const __half* __restrict__ Vt, __half* __restrict__ XAh)
{
    extern __shared__ char sm[];
    const uint32_t smb = smem_u32(sm);
    const int tid = threadIdx.x;
    const int lane = tid & 31, wid = tid >> 5;
    const int t4 = lane & 3, r8 = lane >> 2;
    const int bh = blockIdx.y;             // 0..15 (stream*8 + b*2 + h)
    const int b = bh >> 1, h = bh & 1;     // b = global batch 0..7
    const int qt = blockIdx.x;

    const int rA = (lane & 7) + ((lane >> 3) & 1) * 8;
    const int cA = (lane >> 4) * 16;
    const uint32_t aoff = (uint32_t)((wid * 16 + rA) * TROW + cA);
    const int rB = (lane & 7) + ((lane >> 4) & 1) * 8;
    const int cB = ((lane >> 3) & 1) * 16;
    const uint32_t boffb = (uint32_t)(rB * TROW + cB);

    {
        const int pr = tid >> 1, hf = tid & 1;
        const __half* qsrc = Qh +
            ((size_t)(b * kN + qt * 128 + pr) * kC + h * 64 + hf * 32);
        const uint32_t so = (uint32_t)(pr * TROW + hf * 64);
#pragma unroll
        for (int gq = 0; gq < 4; gq++)
            cpa16(smb + so + gq * 16, qsrc + gq * 8);
        const __half* ksrc = Kh + ((size_t)bh * 256 + tid) * 64;
        const uint32_t sob = (uint32_t)(tid * TROW);
#pragma unroll
        for (int gq = 0; gq < 8; gq++)
            cpa16(smb + SMB_K + sob + gq * 16, ksrc + gq * 8);
        const int vr = tid >> 2, vq = tid & 3;
        const __half* vsrc = Vt + ((size_t)bh * 64 + vr) * 256 + vq * 64;
        const uint32_t sov = (uint32_t)(SM_V + vr * PROW + vq * 128);
#pragma unroll
        for (int gq = 0; gq < 8; gq++)
            cpa16(smb + sov + gq * 16, vsrc + gq * 8);
    }
    cpa_wait();
    __syncthreads();

    float acc[32][4];
#pragma unroll
    for (int nt = 0; nt < 32; nt++)
#pragma unroll
        for (int e = 0; e < 4; e++) acc[nt][e] = 0.0f;

#pragma unroll
    for (int kc = 0; kc < 4; kc++) {
        uint32_t af[4];
        ldsm4(af[0], af[1], af[2], af[3], smb + aoff + kc * 32);
#pragma unroll
        for (int np = 0; np < 16; np++) {
            uint32_t b0, b1, b2, b3;
            ldsm4(b0, b1, b2, b3, smb + SMB_K + boffb + np * (16 * TROW) + kc * 32);
            mma16816(acc[np * 2],     af, b0, b1);
            mma16816(acc[np * 2 + 1], af, b2, b3);
        }
    }

    float mx0 = -1e30f, mx1 = -1e30f;
#pragma unroll
    for (int nt = 0; nt < 32; nt++) {
#pragma unroll
        for (int e = 0; e < 4; e++) acc[nt][e] *= 0.125f;
        mx0 = fmaxf(mx0, fmaxf(acc[nt][0], acc[nt][1]));
        mx1 = fmaxf(mx1, fmaxf(acc[nt][2], acc[nt][3]));
    }
    mx0 = fmaxf(mx0, __shfl_xor_sync(FULLMASK, mx0, 1));
    mx0 = fmaxf(mx0, __shfl_xor_sync(FULLMASK, mx0, 2));
    mx1 = fmaxf(mx1, __shfl_xor_sync(FULLMASK, mx1, 1));
    mx1 = fmaxf(mx1, __shfl_xor_sync(FULLMASK, mx1, 2));
    float s0 = 0.0f, s1 = 0.0f;
#pragma unroll
    for (int nt = 0; nt < 32; nt++) {
        acc[nt][0] = __expf(acc[nt][0] - mx0);
        acc[nt][1] = __expf(acc[nt][1] - mx0);
        acc[nt][2] = __expf(acc[nt][2] - mx1);
        acc[nt][3] = __expf(acc[nt][3] - mx1);
        s0 += acc[nt][0] + acc[nt][1];
        s1 += acc[nt][2] + acc[nt][3];
    }
    s0 += __shfl_xor_sync(FULLMASK, s0, 1);
    s0 += __shfl_xor_sync(FULLMASK, s0, 2);
    s1 += __shfl_xor_sync(FULLMASK, s1, 1);
    s1 += __shfl_xor_sync(FULLMASK, s1, 2);
    const float i0 = 1.0f / s0, i1 = 1.0f / s1;

    __syncthreads();

    {
        const uint32_t p0 = (uint32_t)((wid * 16 + r8) * PROW);
        const uint32_t p1 = p0 + 8 * PROW;
#pragma unroll
        for (int nt = 0; nt < 32; nt++) {
            const int c = nt * 8 + 2 * t4;
            *(uint32_t*)(sm + p0 + c * 2) = pack_h2(acc[nt][0] * i0, acc[nt][1] * i0);
            *(uint32_t*)(sm + p1 + c * 2) = pack_h2(acc[nt][2] * i1, acc[nt][3] * i1);
        }
    }
    __syncthreads();

    const int wm = wid >> 1, wn = wid & 1;
    uint32_t aoffP[2];
#pragma unroll
    for (int mt = 0; mt < 2; mt++)
        aoffP[mt] = (uint32_t)((wm * 32 + mt * 16 + rA) * PROW + cA);
    uint32_t boffV[2];
#pragma unroll
    for (int np = 0; np < 2; np++)
        boffV[np] = (uint32_t)(SM_V + (wn * 32 + np * 16 + rB) * PROW + cB);

    float acc2[2][4][4];
#pragma unroll
    for (int mt = 0; mt < 2; mt++)
#pragma unroll
        for (int nt = 0; nt < 4; nt++)
#pragma unroll
            for (int e = 0; e < 4; e++) acc2[mt][nt][e] = 0.0f;

#pragma unroll
    for (int kc = 0; kc < 16; kc++) {
        const uint32_t kb = (uint32_t)kc * 32;
        uint32_t ah[2][4];
#pragma unroll
        for (int mt = 0; mt < 2; mt++)
            ldsm4(ah[mt][0], ah[mt][1], ah[mt][2], ah[mt][3],
                  smb + aoffP[mt] + kb);
#pragma unroll
        for (int np = 0; np < 2; np++) {
            uint32_t b0, b1, b2, b3;
            ldsm4(b0, b1, b2, b3, smb + boffV[np] + kb);
#pragma unroll
            for (int mt = 0; mt < 2; mt++) {
                mma16816(acc2[mt][np * 2],     ah[mt], b0, b1);
                mma16816(acc2[mt][np * 2 + 1], ah[mt], b2, b3);
            }
        }
    }

#pragma unroll
    for (int mt = 0; mt < 2; mt++)
#pragma unroll
        for (int p = 0; p < 2; p++) {
            const int lr = qt * 128 + wm * 32 + mt * 16 + r8 + p * 8;
            const size_t g = ((size_t)b * kN + lr) * kC + h * 64;
#pragma unroll
            for (int nt = 0; nt < 4; nt++) {
                const int c = wn * 32 + nt * 8 + 2 * t4;
                *(uint32_t*)(XAh + g + c) =
                    pack_h2(acc2[mt][nt][2 * p], acc2[mt][nt][2 * p + 1]);
            }
        }
}

// ---------------------------------------------------------------------------
__global__ void cvt_half(const float* __restrict__ src, __half* __restrict__ dst)
{
    const int i = blockIdx.x * 256 + threadIdx.x;
    float4 v = ((const float4*)src)[i];
    ((uint2*)dst)[i] = make_uint2(pack_h2(v.x, v.y), pack_h2(v.z, v.w));
}

__global__ void cvt_w(const float* __restrict__ src, int ldW,
                      __half* __restrict__ dh)
{
    const int i = blockIdx.x * 256 + threadIdx.x;
    const int o = i >> 6, k = (i & 63) * 2;
    *(uint32_t*)(dh + o * kC + k) =
        pack_h2(src[(size_t)o * ldW + k], src[(size_t)o * ldW + k + 1]);
}

__global__ void cvt_w256(const float* __restrict__ src, __half* __restrict__ dh)
{
    const int i = blockIdx.x * 256 + threadIdx.x;
    const int o = i >> 7, k = (i & 127) * 2;
    *(uint32_t*)(dh + o * 256 + k) =
        pack_h2(src[(size_t)o * 256 + k], src[(size_t)o * 256 + k + 1]);
}

__global__ void cvt_convw(const float* __restrict__ srw, __half* __restrict__ dh)
{
    const int t = blockIdx.x * 256 + threadIdx.x;
    const int pos = t >> 13, o = (t >> 6) & 127, i2 = (t & 63) * 2;
    const size_t d = (size_t)pos * 16384 + (size_t)o * kC + i2;
    *(uint32_t*)(dh + d) =
        pack_h2(srw[(size_t)o * 8192 + i2 * 64 + pos],
                srw[(size_t)o * 8192 + (i2 + 1) * 64 + pos]);
}

__global__ void fuse_out_w(const float* __restrict__ pw,
                           const float* __restrict__ cawO,
                           __half* __restrict__ WO)
{
    const int i = blockIdx.x * 256 + threadIdx.x;
    const int o = i >> 7, j = i & 127;
    float acc = 0.0f;
    for (int c = 0; c < 128; c++)
        acc += pw[(size_t)o * 128 + c] * cawO[(size_t)c * 128 + j];
    WO[(size_t)o * 256 + j]       = __float2half_rn(pw[(size_t)o * 128 + j]);
    WO[(size_t)o * 256 + 128 + j] = __float2half_rn(acc);
}

__global__ void fuse_out_b(const float* __restrict__ pw,
                           const float* __restrict__ cabO,
                           const float* __restrict__ pb,
                           float* __restrict__ fb)
{
    const int o = threadIdx.x;
    float acc = pb[o];
    for (int c = 0; c < 128; c++) acc += pw[(size_t)o * 128 + c] * cabO[c];
    fb[o] = acc;
}

__global__ void fold_bias(
    const float* __restrict__ w01, const float* __restrict__ b01,
    const float* __restrict__ w10, const float* __restrict__ b10,
    const float* __restrict__ kn, const float* __restrict__ vn,
    float* __restrict__ bm)
{
    const int which = blockIdx.x, c = threadIdx.x;
    const float* W  = (which < 2) ? w01 : w10;
    const float* Bb = (which < 2) ? b01 : b10;
    const float* nz = ((which & 1) ? vn : kn) + (which >> 1) * kC;
    const int off = (which & 1) ? 256 : 128;
    float acc = Bb[off + c];
    const float* wr = W + (size_t)(off + c) * kC;
    for (int k = 0; k < kC; k++) acc += nz[k] * wr[k];
    bm[which * kC + c] = acc;
}

// ---------------------------------------------------------------------------
extern "C" void kernel_launch(void* const* d_in, const int* in_sizes, int n_in,
                              void* d_out, int out_size)
{
    (void)in_sizes; (void)n_in; (void)out_size;
    const float* x0   = (const float*)d_in[0];
    const float* x1   = (const float*)d_in[1];
    const float* Wq   = (const float*)d_in[2];
    const float* bq   = (const float*)d_in[3];
    const float* Wkv  = (const float*)d_in[4];
    const float* bkv  = (const float*)d_in[5];
    const float* srw  = (const float*)d_in[6];
    const float* srb  = (const float*)d_in[7];
    const float* lnG[2] = {(const float*)d_in[8],  (const float*)d_in[10]};
    const float* lnB[2] = {(const float*)d_in[9],  (const float*)d_in[11]};
    const float* cawI[2] = {(const float*)d_in[12], (const float*)d_in[16]};
    const float* cabI[2] = {(const float*)d_in[13], (const float*)d_in[17]};
    const float* cawO[2] = {(const float*)d_in[14], (const float*)d_in[18]};
    const float* cabO[2] = {(const float*)d_in[15], (const float*)d_in[19]};
    const float* rjw1 = (const float*)d_in[20];
    const float* rjb1 = (const float*)d_in[21];
    const float* rjw2 = (const float*)d_in[22];
    const float* rjb2 = (const float*)d_in[23];
    const float* kn   = (const float*)d_in[24];
    const float* vn   = (const float*)d_in[25];
    const float* pw   = (const float*)d_in[26];
    const float* pb   = (const float*)d_in[27];
    float* out = (float*)d_out;

    float* g = nullptr;
    cudaGetSymbolAddress((void**)&g, g_mem);
    __half* hm = nullptr;
    cudaGetSymbolAddress((void**)&hm, h_mem);

    float *PART = g + O_PART, *KBp = g + O_KB, *VBp = g + O_VB;
    float *BM = g + O_BM, *FB = g + O_FB;

    __half *XH  = hm + H_X0;                       // 2*SZ contiguous
    __half *XAH[2] = {hm + H_XA0, hm + H_XA1};     // contiguous pair
    __half *T1H = hm + H_T1, *XASH = hm + H_XAS, *T5H = hm + H_T5;
    __half *XLNH = hm + H_XLN;                     // 2048 rows
    __half *WSH = hm + H_WS, *CWH = hm + H_CW;
    __half *WJH = hm + H_WJ;
    __half *WOH[2] = {hm + H_WO, hm + H_WO + 32768};
    __half *QH = hm + H_QH;                        // 2*SZ
    __half *KH = hm + H_KH, *VT = hm + H_VT;

    cudaFuncSetAttribute(gemm5, cudaFuncAttributeMaxDynamicSharedMemorySize, SM_G);
    cudaFuncSetAttribute(gemm6, cudaFuncAttributeMaxDynamicSharedMemorySize, SM_G6);
    cudaFuncSetAttribute(conv_mma, cudaFuncAttributeMaxDynamicSharedMemorySize, SM_CONV);
    cudaFuncSetAttribute(attn_fused, cudaFuncAttributeMaxDynamicSharedMemorySize, SM_ATT);
    cudaFuncSetAttribute(mha2_fused, cudaFuncAttributeMaxDynamicSharedMemorySize, SM_M2);

    // --- one-time prep ---
    fold_bias<<<4, 128>>>(cawI[0], cabI[0], cawI[1], cabI[1], kn, vn, BM);
    cvt_half<<<8192, 256>>>(x0, XH);
    cvt_half<<<8192, 256>>>(x1, XH + SZ);
    cvt_convw<<<2048, 256>>>(srw, CWH);
    cvt_w256<<<64, 256>>>(rjw1, WJH);
    fuse_out_w<<<64, 256>>>(pw, cawO[0], WOH[0]);
    fuse_out_w<<<64, 256>>>(pw, cawO[1], WOH[1]);
    fuse_out_b<<<1, 128>>>(pw, cabO[0], pb, FB);
    fuse_out_b<<<1, 128>>>(pw, cabO[1], pb, FB + 128);
#define SW(SRC, LD, IDX) cvt_w<<<32, 256>>>(SRC, LD, WSH + (IDX) * 16384)
    SW(Wq, 128, 0);
    SW(Wkv, 128, 1);          SW(Wkv + 16384, 128, 2);
    SW(rjw2, 128, 5);
    SW(cawI[0], 128, 6);      SW(cawI[0] + 16384, 128, 7);  SW(cawI[0] + 32768, 128, 8);
    SW(cawI[1], 128, 9);      SW(cawI[1] + 16384, 128, 10); SW(cawI[1] + 32768, 128, 11);
#undef SW

    const int GM = kMTOK / 256;    // per-stream gemm5 grid
    const int G6M = kMTOK / 128;
#define G5(GRID, AH, WI, BIAS, RESID, YF, YH, EPI) \
    gemm5<<<GRID, 256, SM_G>>>(AH, WSH + (WI) * 16384, BIAS, RESID, \
                               nullptr, YF, YH, EPI)
#define G5S(GRID, AH, WI, BIAS, PMUL, YH) \
    gemm5<<<GRID, 256, SM_G>>>(AH, WSH + (WI) * 16384, BIAS, nullptr, \
                               PMUL, nullptr, YH, 2)

    // --- Stage A: both streams batched in one pass ---
    G5(2 * GM, XH, 0, bq, nullptr, nullptr, QH, 0);              // q fp16
    conv_mma<<<dim3(16, 8), 256, SM_CONV>>>(XH, CWH, PART);
    conv_reduce_ln<<<2048, 128>>>(PART, srb, lnG[0], lnB[0], lnG[1], lnB[1], XLNH);
    G5(8, XLNH, 1, bkv,       nullptr, KBp, nullptr, 0);
    G5(8, XLNH, 2, bkv + 128, nullptr, VBp, nullptr, 0);
    kv_pack<<<1024, 256>>>(KBp, VBp, KH, VT);
    attn_fused<<<dim3(128, 16), 256, SM_ATT>>>(QH, KH, VT, XAH[0]);

    // --- Stage B + C per stream ---
    for (int s = 0; s < 2; s++) {
        gemm6<<<G6M, 256, SM_G6>>>(XAH[s], XAH[s ^ 1], WJH, rjb1,
                                   nullptr, T1H, 1);
        G5S(GM, T1H, 5, rjb2, XAH[s], XASH);
        mha2_fused<<<512, 256, SM_M2>>>(XAH[s], XASH, XAH[s ^ 1],
                                        WSH + (6 + 3 * s) * 16384,
                                        WSH + (7 + 3 * s) * 16384,
                                        WSH + (8 + 3 * s) * 16384,
                                        cabI[s], BM + 2 * s * kC,
                                        BM + (2 * s + 1) * kC, T5H);
        gemm6<<<G6M, 256, SM_G6>>>(XAH[s], T5H, WOH[s], FB + s * 128,
                                   out + (size_t)s * SZ, nullptr, 0);
    }
#undef G5
#undef G5S
}